// round 2
// baseline (speedup 1.0000x reference)
#include <cuda_runtime.h>

#define N_R 50000
#define N_D 10000
#define HH  8
#define DH  32
#define CC  256
#define RNA_IN 256
#define D_FEAT 512
#define E_RD 200000
#define E_DR 200000
#define E_RR 400000
#define E_DD 50000

// ---------------- static device scratch (no allocations allowed) ------------
__device__ float    g_xd[N_D * RNA_IN];
__device__ float    g_hr[N_R * CC];
__device__ float    g_hd[N_D * CC];
__device__ float    g_out_rd[N_D * CC];
__device__ float    g_out_dr[N_R * CC];
__device__ float    g_out_rr[N_R * CC];
__device__ float    g_out_dd[N_D * CC];
__device__ float    g_ssrc[N_R * HH];
__device__ float    g_sdst[N_R * HH];
__device__ float    g_e[E_RR * HH];
__device__ unsigned g_m[N_R * HH];
__device__ float    g_sum[N_R * HH];
__device__ float    g_scores[4];   // [dr, rr, rd, dd]
__device__ float    g_attn[4];     // [attn_r0, attn_r1, attn_d0, attn_d1]

// ---------------- tiled SGEMM, 3 fused epilogues -----------------------------
// MODE 0: C = A0 @ B + bias
// MODE 1: score += sum_{n,c} q[c] * tanh( relu(A0) @ B + bias )   (no C write)
// MODE 2: C = ( w0*relu(A0) + w1*relu(A1) ) @ B + bias            (w from wts[])
#define BM 64
#define BN 64
#define BK 16
#define TM 4
#define TN 4

template <int MODE>
__global__ void __launch_bounds__(256)
sgemm_k(const float* __restrict__ A0, const float* __restrict__ A1,
        const float* __restrict__ B,  const float* __restrict__ bias,
        const float* __restrict__ wts, const float* __restrict__ qv,
        float* __restrict__ C, float* __restrict__ score,
        int M, int N, int K)
{
    __shared__ float As[BK][BM + 4];   // pad 4 -> float4-aligned, conflict-free
    __shared__ float Bs[BK][BN];
    __shared__ float red[256];

    const int tid = threadIdx.x;
    const int tx  = tid & 15;          // 0..15
    const int ty  = tid >> 4;          // 0..15
    const int blockRow = blockIdx.y * BM;
    const int blockCol = blockIdx.x * BN;

    float w0 = 0.f, w1 = 0.f;
    if (MODE == 2) { w0 = wts[0]; w1 = wts[1]; }

    // A load mapping: one float4 per thread along K
    const int arow = tid >> 2;          // 0..63
    const int acol = (tid & 3) * 4;     // 0,4,8,12
    // B load mapping: one float4 per thread along N
    const int brow = tid >> 4;          // 0..15
    const int bcol = (tid & 15) * 4;    // 0..60

    float acc[TM][TN];
#pragma unroll
    for (int i = 0; i < TM; i++)
#pragma unroll
        for (int j = 0; j < TN; j++) acc[i][j] = 0.f;

    const int grow = blockRow + arow;
    const bool rowOK = (grow < M);

    for (int k0 = 0; k0 < K; k0 += BK) {
        float4 av = make_float4(0.f, 0.f, 0.f, 0.f);
        if (rowOK) {
            av = *(const float4*)(A0 + (size_t)grow * K + k0 + acol);
            if (MODE == 1) {
                av.x = fmaxf(av.x, 0.f); av.y = fmaxf(av.y, 0.f);
                av.z = fmaxf(av.z, 0.f); av.w = fmaxf(av.w, 0.f);
            }
            if (MODE == 2) {
                float4 av1 = *(const float4*)(A1 + (size_t)grow * K + k0 + acol);
                av.x = w0 * fmaxf(av.x, 0.f) + w1 * fmaxf(av1.x, 0.f);
                av.y = w0 * fmaxf(av.y, 0.f) + w1 * fmaxf(av1.y, 0.f);
                av.z = w0 * fmaxf(av.z, 0.f) + w1 * fmaxf(av1.z, 0.f);
                av.w = w0 * fmaxf(av.w, 0.f) + w1 * fmaxf(av1.w, 0.f);
            }
        }
        As[acol + 0][arow] = av.x;
        As[acol + 1][arow] = av.y;
        As[acol + 2][arow] = av.z;
        As[acol + 3][arow] = av.w;

        float4 bv = *(const float4*)(B + (size_t)(k0 + brow) * N + blockCol + bcol);
        *(float4*)&Bs[brow][bcol] = bv;

        __syncthreads();
#pragma unroll
        for (int kk = 0; kk < BK; kk++) {
            float4 a4 = *(const float4*)&As[kk][ty * TM];
            float4 b4 = *(const float4*)&Bs[kk][tx * TN];
            float a[TM] = {a4.x, a4.y, a4.z, a4.w};
            float b[TN] = {b4.x, b4.y, b4.z, b4.w};
#pragma unroll
            for (int i = 0; i < TM; i++)
#pragma unroll
                for (int j = 0; j < TN; j++) acc[i][j] += a[i] * b[j];
        }
        __syncthreads();
    }

    if (MODE == 0 || MODE == 2) {
#pragma unroll
        for (int i = 0; i < TM; i++) {
            int row = blockRow + ty * TM + i;
            if (row < M) {
#pragma unroll
                for (int j = 0; j < TN; j++) {
                    int col = blockCol + tx * TN + j;
                    C[(size_t)row * N + col] = acc[i][j] + bias[col];
                }
            }
        }
    } else {  // MODE 1: semantic-attention reduction
        float local = 0.f;
#pragma unroll
        for (int i = 0; i < TM; i++) {
            int row = blockRow + ty * TM + i;
            if (row < M) {
#pragma unroll
                for (int j = 0; j < TN; j++) {
                    int col = blockCol + tx * TN + j;
                    local += qv[col] * tanhf(acc[i][j] + bias[col]);
                }
            }
        }
        red[tid] = local;
        __syncthreads();
        for (int s = 128; s > 0; s >>= 1) {
            if (tid < s) red[tid] += red[tid + s];
            __syncthreads();
        }
        if (tid == 0) atomicAdd(score, red[0]);
    }
}

// ---------------- per-node attention scores: s[n,h] = <h[n,h,:], a[h,:]> ----
__global__ void node_scores_k(const float* __restrict__ h,
                              const float* __restrict__ a,
                              float* __restrict__ s, int Nn)
{
    int idx = blockIdx.x * blockDim.x + threadIdx.x;
    int n = idx >> 3;
    int hh = idx & 7;
    if (n >= Nn) return;
    const float* hp = h + (size_t)n * CC + hh * DH;
    const float* ap = a + hh * DH;
    float acc = 0.f;
#pragma unroll
    for (int d = 0; d < DH; d++) acc += hp[d] * ap[d];
    s[n * HH + hh] = acc;
}

__device__ __forceinline__ unsigned f2ord(float f) {
    unsigned u = __float_as_uint(f);
    return (u & 0x80000000u) ? ~u : (u | 0x80000000u);
}
__device__ __forceinline__ float ord2f(unsigned e) {
    unsigned u = (e & 0x80000000u) ? (e ^ 0x80000000u) : ~e;
    return __uint_as_float(u);
}
__device__ __forceinline__ float lrelu(float x) {
    return x > 0.f ? x : 0.2f * x;
}

// pass A: per-dst-per-head running max of leaky-relu scores
__global__ void edge_max_k(const int* __restrict__ src, const int* __restrict__ dst,
                           const float* __restrict__ ssrc, const float* __restrict__ sdst,
                           unsigned* __restrict__ m, int E)
{
    int e = blockIdx.x * blockDim.x + threadIdx.x;
    if (e >= E) return;
    int s_ = src[e], d_ = dst[e];
#pragma unroll
    for (int h = 0; h < HH; h++) {
        float sc = lrelu(ssrc[s_ * HH + h] + sdst[d_ * HH + h]);
        atomicMax(&m[d_ * HH + h], f2ord(sc));
    }
}

// pass B: e = exp(score - max); sum per dst,h
__global__ void edge_exp_k(const int* __restrict__ src, const int* __restrict__ dst,
                           const float* __restrict__ ssrc, const float* __restrict__ sdst,
                           const unsigned* __restrict__ m,
                           float* __restrict__ ebuf, float* __restrict__ sum, int E)
{
    int e = blockIdx.x * blockDim.x + threadIdx.x;
    if (e >= E) return;
    int s_ = src[e], d_ = dst[e];
#pragma unroll
    for (int h = 0; h < HH; h++) {
        float sc = lrelu(ssrc[s_ * HH + h] + sdst[d_ * HH + h]);
        float mv = ord2f(m[d_ * HH + h]);
        float ev = expf(sc - mv);
        ebuf[(size_t)e * HH + h] = ev;
        atomicAdd(&sum[d_ * HH + h], ev);
    }
}

// pass C: out[dst] += x_src[src] * alpha
// one warp per edge, 8 edges per 256-thread block; each lane covers 8 channels
__global__ void edge_agg_k(const int* __restrict__ src, const int* __restrict__ dst,
                           const float* __restrict__ x,
                           const float* __restrict__ ebuf, const float* __restrict__ sum,
                           float* __restrict__ out, int E)
{
    int warp = (blockIdx.x * blockDim.x + threadIdx.x) >> 5;
    int lane = threadIdx.x & 31;
    if (warp >= E) return;
    int s_ = src[warp], d_ = dst[warp];

    // lane l covers channels [8l, 8l+8): heads (8l)>>5 = l>>2 (two halves same head)
    int h = lane >> 2;
    float alpha = ebuf[(size_t)warp * HH + h] / (sum[d_ * HH + h] + 1e-16f);

    const float* xp = x + (size_t)s_ * CC + lane * 8;
    float* op = out + (size_t)d_ * CC + lane * 8;
    float4 v0 = *(const float4*)(xp);
    float4 v1 = *(const float4*)(xp + 4);
    atomicAdd(op + 0, v0.x * alpha);
    atomicAdd(op + 1, v0.y * alpha);
    atomicAdd(op + 2, v0.z * alpha);
    atomicAdd(op + 3, v0.w * alpha);
    atomicAdd(op + 4, v1.x * alpha);
    atomicAdd(op + 5, v1.y * alpha);
    atomicAdd(op + 6, v1.z * alpha);
    atomicAdd(op + 7, v1.w * alpha);
}

// semantic softmax over 2 scores per node type (mean over nodes applied here)
__global__ void softmax2_k(const float* __restrict__ scores, float* __restrict__ attn,
                           float invNr, float invNd)
{
    if (threadIdx.x == 0 && blockIdx.x == 0) {
        float s0 = scores[0] * invNr, s1 = scores[1] * invNr;
        float mx = fmaxf(s0, s1);
        float e0 = expf(s0 - mx), e1 = expf(s1 - mx);
        attn[0] = e0 / (e0 + e1);
        attn[1] = e1 / (e0 + e1);
        s0 = scores[2] * invNd; s1 = scores[3] * invNd;
        mx = fmaxf(s0, s1);
        e0 = expf(s0 - mx); e1 = expf(s1 - mx);
        attn[2] = e0 / (e0 + e1);
        attn[3] = e1 / (e0 + e1);
    }
}

// ---------------------------------------------------------------------------
extern "C" void kernel_launch(void* const* d_in, const int* in_sizes, int n_in,
                              void* d_out, int out_size)
{
    const float* x_rna   = (const float*)d_in[0];
    const float* x_dis   = (const float*)d_in[1];
    const float* W_d     = (const float*)d_in[2];
    const float* b_d     = (const float*)d_in[3];
    const float* Wp_rna  = (const float*)d_in[4];
    const float* bp_rna  = (const float*)d_in[5];
    const float* Wp_dis  = (const float*)d_in[6];
    const float* bp_dis  = (const float*)d_in[7];
    const float* a_src_rd = (const float*)d_in[8];
    const float* a_dst_rd = (const float*)d_in[9];
    const float* a_src_dr = (const float*)d_in[10];
    const float* a_dst_dr = (const float*)d_in[11];
    const float* a_src_rr = (const float*)d_in[12];
    const float* a_dst_rr = (const float*)d_in[13];
    const float* a_src_dd = (const float*)d_in[14];
    const float* a_dst_dd = (const float*)d_in[15];
    const float* kW      = (const float*)d_in[16];
    const float* kb      = (const float*)d_in[17];
    const float* qv      = (const float*)d_in[18];
    const float* W_out   = (const float*)d_in[19];
    const float* b_out   = (const float*)d_in[20];
    const int* rd_src = (const int*)d_in[21];
    const int* rd_dst = (const int*)d_in[22];
    const int* dr_src = (const int*)d_in[23];
    const int* dr_dst = (const int*)d_in[24];
    const int* rr_src = (const int*)d_in[25];
    const int* rr_dst = (const int*)d_in[26];
    const int* dd_src = (const int*)d_in[27];
    const int* dd_dst = (const int*)d_in[28];

    float* out = (float*)d_out;

    float *p_xd, *p_hr, *p_hd, *p_ord, *p_odr, *p_orr, *p_odd;
    float *p_ssrc, *p_sdst, *p_e, *p_sum, *p_scores, *p_attn;
    unsigned* p_m;
    cudaGetSymbolAddress((void**)&p_xd, g_xd);
    cudaGetSymbolAddress((void**)&p_hr, g_hr);
    cudaGetSymbolAddress((void**)&p_hd, g_hd);
    cudaGetSymbolAddress((void**)&p_ord, g_out_rd);
    cudaGetSymbolAddress((void**)&p_odr, g_out_dr);
    cudaGetSymbolAddress((void**)&p_orr, g_out_rr);
    cudaGetSymbolAddress((void**)&p_odd, g_out_dd);
    cudaGetSymbolAddress((void**)&p_ssrc, g_ssrc);
    cudaGetSymbolAddress((void**)&p_sdst, g_sdst);
    cudaGetSymbolAddress((void**)&p_e, g_e);
    cudaGetSymbolAddress((void**)&p_m, g_m);
    cudaGetSymbolAddress((void**)&p_sum, g_sum);
    cudaGetSymbolAddress((void**)&p_scores, g_scores);
    cudaGetSymbolAddress((void**)&p_attn, g_attn);

    const dim3 thr(256);
    auto gyr = (N_R + BM - 1) / BM;   // 782
    auto gyd = (N_D + BM - 1) / BM;   // 157

    // ---- dense projections ----
    sgemm_k<0><<<dim3(CC / BN, gyd), thr>>>(x_dis, nullptr, W_d, b_d,
                                            nullptr, nullptr, p_xd, nullptr,
                                            N_D, RNA_IN, D_FEAT);
    sgemm_k<0><<<dim3(CC / BN, gyr), thr>>>(x_rna, nullptr, Wp_rna, bp_rna,
                                            nullptr, nullptr, p_hr, nullptr,
                                            N_R, CC, RNA_IN);
    sgemm_k<0><<<dim3(CC / BN, gyd), thr>>>(p_xd, nullptr, Wp_dis, bp_dis,
                                            nullptr, nullptr, p_hd, nullptr,
                                            N_D, CC, RNA_IN);

    // zero output accumulators
    cudaMemsetAsync(p_ord, 0, (size_t)N_D * CC * sizeof(float));
    cudaMemsetAsync(p_odr, 0, (size_t)N_R * CC * sizeof(float));
    cudaMemsetAsync(p_orr, 0, (size_t)N_R * CC * sizeof(float));
    cudaMemsetAsync(p_odd, 0, (size_t)N_D * CC * sizeof(float));

    // ---- per-edge-type GAT attention ----
    auto run_type = [&](const float* xs, int Ns, const float* xdn, int Nd2,
                        const float* asv, const float* adv,
                        const int* si, const int* di, int E, float* outp) {
        node_scores_k<<<(Ns * HH + 255) / 256, thr>>>(xs, asv, p_ssrc, Ns);
        node_scores_k<<<(Nd2 * HH + 255) / 256, thr>>>(xdn, adv, p_sdst, Nd2);
        cudaMemsetAsync(p_m, 0, (size_t)Nd2 * HH * sizeof(unsigned));
        cudaMemsetAsync(p_sum, 0, (size_t)Nd2 * HH * sizeof(float));
        edge_max_k<<<(E + 255) / 256, thr>>>(si, di, p_ssrc, p_sdst, p_m, E);
        edge_exp_k<<<(E + 255) / 256, thr>>>(si, di, p_ssrc, p_sdst, p_m, p_e, p_sum, E);
        edge_agg_k<<<(E * 32 + 255) / 256, thr>>>(si, di, xs, p_e, p_sum, outp, E);
    };

    run_type(p_hr, N_R, p_hd, N_D, a_src_rd, a_dst_rd, rd_src, rd_dst, E_RD, p_ord);
    run_type(p_hd, N_D, p_hr, N_R, a_src_dr, a_dst_dr, dr_src, dr_dst, E_DR, p_odr);
    run_type(p_hr, N_R, p_hr, N_R, a_src_rr, a_dst_rr, rr_src, rr_dst, E_RR, p_orr);
    run_type(p_hd, N_D, p_hd, N_D, a_src_dd, a_dst_dd, dd_src, dd_dst, E_DD, p_odd);

    // ---- semantic attention scores ----
    cudaMemsetAsync(p_scores, 0, 4 * sizeof(float));
    sgemm_k<1><<<dim3(CC / BN, gyr), thr>>>(p_odr, nullptr, kW, kb,
                                            nullptr, qv, nullptr, p_scores + 0,
                                            N_R, CC, CC);
    sgemm_k<1><<<dim3(CC / BN, gyr), thr>>>(p_orr, nullptr, kW, kb,
                                            nullptr, qv, nullptr, p_scores + 1,
                                            N_R, CC, CC);
    sgemm_k<1><<<dim3(CC / BN, gyd), thr>>>(p_ord, nullptr, kW, kb,
                                            nullptr, qv, nullptr, p_scores + 2,
                                            N_D, CC, CC);
    sgemm_k<1><<<dim3(CC / BN, gyd), thr>>>(p_odd, nullptr, kW, kb,
                                            nullptr, qv, nullptr, p_scores + 3,
                                            N_D, CC, CC);
    softmax2_k<<<1, 32>>>(p_scores, p_attn, 1.f / N_R, 1.f / N_D);

    // ---- final: h = (attn-weighted combo) @ W_out + b_out ----
    sgemm_k<2><<<dim3(CC / BN, gyr), thr>>>(p_odr, p_orr, W_out, b_out,
                                            p_attn + 0, nullptr, out, nullptr,
                                            N_R, CC, CC);
    sgemm_k<2><<<dim3(CC / BN, gyd), thr>>>(p_ord, p_odd, W_out, b_out,
                                            p_attn + 2, nullptr,
                                            out + (size_t)N_R * CC, nullptr,
                                            N_D, CC, CC);
}

// round 3
// speedup vs baseline: 2.6774x; 2.6774x over previous
#include <cuda_runtime.h>
#include <cstdint>

#define N_R 50000
#define N_D 10000
#define HH  8
#define DH  32
#define CC  256
#define RNA_IN 256
#define D_FEAT 512
#define E_RD 200000
#define E_DR 200000
#define E_RR 400000
#define E_DD 50000

// ---------------- static device scratch ------------------------------------
__device__ float    g_xd[N_D * RNA_IN];
__device__ float    g_hr[N_R * CC];
__device__ float    g_hd[N_D * CC];
__device__ float    g_out_rd[N_D * CC];
__device__ float    g_out_dr[N_R * CC];
__device__ float    g_out_rr[N_R * CC];
__device__ float    g_out_dd[N_D * CC];
__device__ float    g_s_rna[4 * N_R * HH];   // [a_src_rd, a_dst_dr, a_src_rr, a_dst_rr]
__device__ float    g_s_dis[4 * N_D * HH];   // [a_dst_rd, a_src_dr, a_src_dd, a_dst_dd]
__device__ float    g_e[(size_t)E_RR * HH];
__device__ unsigned g_m[N_R * HH];
__device__ float    g_sum[N_R * HH];
__device__ float    g_scores[4];
__device__ float    g_attn[4];

__device__ __forceinline__ uint32_t f2tf(float f) {
    uint32_t u;
    asm("cvt.rna.tf32.f32 %0, %1;" : "=r"(u) : "f"(f));
    return u;
}

// ================= TF32 tensor-core GEMM =====================================
// 128x128 block tile, BK=16, 256 threads (8 warps, 4(m) x 2(n)), warp 32x64.
// mma.sync.aligned.m16n8k8.row.col.f32.tf32.tf32.f32
// MODE 0: C = A0 @ B + bias
// MODE 1: score += sum q[c]*tanh( relu(A0)@B + bias )
// MODE 2: C = ( w0*relu(A0) + w1*relu(A1) ) @ B + bias
#define A_STRIDE 20            // 16 cols + pad 4 -> conflict-free frag loads
#define B_N8_STRIDE 66         // 32 lanes * 2 regs + pad 2

template <int MODE>
__global__ void __launch_bounds__(256)
gemm_tc(const float* __restrict__ A0, const float* __restrict__ A1,
        const float* __restrict__ B,  const float* __restrict__ bias,
        const float* __restrict__ wts, const float* __restrict__ qv,
        float* __restrict__ C, float* __restrict__ score,
        int M, int N, int K)
{
    __shared__ float As[2][128 * A_STRIDE];
    __shared__ float Bs[2][2 * 16 * B_N8_STRIDE];
    __shared__ float bias_s[128];
    __shared__ float q_s[128];
    __shared__ float red[256];

    const int tid  = threadIdx.x;
    const int lane = tid & 31;
    const int warp = tid >> 5;
    const int wm   = warp & 3;          // 0..3  (m-direction)
    const int wn   = warp >> 2;         // 0..1  (n-direction)
    const int g    = lane >> 2;         // groupID 0..7
    const int t    = lane & 3;          // threadID_in_group 0..3
    const int bRow = blockIdx.y * 128;
    const int bCol = blockIdx.x * 128;

    if (tid < 128) {
        bias_s[tid] = bias[bCol + tid];
        if (MODE == 1) q_s[tid] = qv[bCol + tid];
    }

    float w0 = 0.f, w1 = 0.f;
    if (MODE == 2) { w0 = wts[0]; w1 = wts[1]; }

    // A writer: thread -> row am (0..127), k-quarter akq in {0,8}; 2 float4 along k
    const int am  = tid >> 1;
    const int akq = (tid & 1) * 8;
    const size_t arow_off = (size_t)(bRow + am) * K;
    const bool arow_ok = (bRow + am) < M;

    // B writer: thread -> k-row bkr (0..15), n-octet bn8 (0..15); 2 float4 along n
    const int bkr = tid >> 4;
    const int bn8 = tid & 15;
    const int bks = bkr >> 3;           // kstep 0/1
    const int bt  = bkr & 3;            // k%4 within kstep
    const int brg = (bkr & 7) >> 2;     // reg 0/1
    const int bbase = (bks * 16 + bn8) * B_N8_STRIDE + brg;

    float acc[2][8][4];
#pragma unroll
    for (int mi = 0; mi < 2; mi++)
#pragma unroll
        for (int ni = 0; ni < 8; ni++)
#pragma unroll
            for (int r = 0; r < 4; r++) acc[mi][ni][r] = 0.f;

    const int S = K / 16;
    float4 la0, la1, lb0, lb1;

    // ---- prologue: load stage 0 ----
    {
        const int k0 = 0;
        if (arow_ok) {
            la0 = *(const float4*)(A0 + arow_off + k0 + akq);
            la1 = *(const float4*)(A0 + arow_off + k0 + akq + 4);
            if (MODE == 1) {
                la0.x = fmaxf(la0.x, 0.f); la0.y = fmaxf(la0.y, 0.f);
                la0.z = fmaxf(la0.z, 0.f); la0.w = fmaxf(la0.w, 0.f);
                la1.x = fmaxf(la1.x, 0.f); la1.y = fmaxf(la1.y, 0.f);
                la1.z = fmaxf(la1.z, 0.f); la1.w = fmaxf(la1.w, 0.f);
            }
            if (MODE == 2) {
                float4 m0 = *(const float4*)(A1 + arow_off + k0 + akq);
                float4 m1 = *(const float4*)(A1 + arow_off + k0 + akq + 4);
                la0.x = w0 * fmaxf(la0.x, 0.f) + w1 * fmaxf(m0.x, 0.f);
                la0.y = w0 * fmaxf(la0.y, 0.f) + w1 * fmaxf(m0.y, 0.f);
                la0.z = w0 * fmaxf(la0.z, 0.f) + w1 * fmaxf(m0.z, 0.f);
                la0.w = w0 * fmaxf(la0.w, 0.f) + w1 * fmaxf(m0.w, 0.f);
                la1.x = w0 * fmaxf(la1.x, 0.f) + w1 * fmaxf(m1.x, 0.f);
                la1.y = w0 * fmaxf(la1.y, 0.f) + w1 * fmaxf(m1.y, 0.f);
                la1.z = w0 * fmaxf(la1.z, 0.f) + w1 * fmaxf(m1.z, 0.f);
                la1.w = w0 * fmaxf(la1.w, 0.f) + w1 * fmaxf(m1.w, 0.f);
            }
        } else {
            la0 = make_float4(0.f, 0.f, 0.f, 0.f);
            la1 = la0;
        }
        lb0 = *(const float4*)(B + (size_t)(k0 + bkr) * N + bCol + bn8 * 8);
        lb1 = *(const float4*)(B + (size_t)(k0 + bkr) * N + bCol + bn8 * 8 + 4);
    }
    // store stage 0 into buf 0
    {
        float4 c0 = make_float4(__uint_as_float(f2tf(la0.x)), __uint_as_float(f2tf(la0.y)),
                                __uint_as_float(f2tf(la0.z)), __uint_as_float(f2tf(la0.w)));
        float4 c1 = make_float4(__uint_as_float(f2tf(la1.x)), __uint_as_float(f2tf(la1.y)),
                                __uint_as_float(f2tf(la1.z)), __uint_as_float(f2tf(la1.w)));
        *(float4*)&As[0][am * A_STRIDE + akq]     = c0;
        *(float4*)&As[0][am * A_STRIDE + akq + 4] = c1;
        float bv[8] = {lb0.x, lb0.y, lb0.z, lb0.w, lb1.x, lb1.y, lb1.z, lb1.w};
#pragma unroll
        for (int j = 0; j < 8; j++)
            Bs[0][bbase + (j * 4 + bt) * 2] = __uint_as_float(f2tf(bv[j]));
    }
    __syncthreads();

    for (int s = 0; s < S; s++) {
        // prefetch next stage
        if (s + 1 < S) {
            const int k0 = (s + 1) * 16;
            if (arow_ok) {
                la0 = *(const float4*)(A0 + arow_off + k0 + akq);
                la1 = *(const float4*)(A0 + arow_off + k0 + akq + 4);
                if (MODE == 1) {
                    la0.x = fmaxf(la0.x, 0.f); la0.y = fmaxf(la0.y, 0.f);
                    la0.z = fmaxf(la0.z, 0.f); la0.w = fmaxf(la0.w, 0.f);
                    la1.x = fmaxf(la1.x, 0.f); la1.y = fmaxf(la1.y, 0.f);
                    la1.z = fmaxf(la1.z, 0.f); la1.w = fmaxf(la1.w, 0.f);
                }
                if (MODE == 2) {
                    float4 m0 = *(const float4*)(A1 + arow_off + k0 + akq);
                    float4 m1 = *(const float4*)(A1 + arow_off + k0 + akq + 4);
                    la0.x = w0 * fmaxf(la0.x, 0.f) + w1 * fmaxf(m0.x, 0.f);
                    la0.y = w0 * fmaxf(la0.y, 0.f) + w1 * fmaxf(m0.y, 0.f);
                    la0.z = w0 * fmaxf(la0.z, 0.f) + w1 * fmaxf(m0.z, 0.f);
                    la0.w = w0 * fmaxf(la0.w, 0.f) + w1 * fmaxf(m0.w, 0.f);
                    la1.x = w0 * fmaxf(la1.x, 0.f) + w1 * fmaxf(m1.x, 0.f);
                    la1.y = w0 * fmaxf(la1.y, 0.f) + w1 * fmaxf(m1.y, 0.f);
                    la1.z = w0 * fmaxf(la1.z, 0.f) + w1 * fmaxf(m1.z, 0.f);
                    la1.w = w0 * fmaxf(la1.w, 0.f) + w1 * fmaxf(m1.w, 0.f);
                }
            } else {
                la0 = make_float4(0.f, 0.f, 0.f, 0.f);
                la1 = la0;
            }
            lb0 = *(const float4*)(B + (size_t)(k0 + bkr) * N + bCol + bn8 * 8);
            lb1 = *(const float4*)(B + (size_t)(k0 + bkr) * N + bCol + bn8 * 8 + 4);
        }

        // ---- compute from buf = s&1 ----
        const int buf = s & 1;
#pragma unroll
        for (int ks = 0; ks < 2; ks++) {
            uint32_t af[2][4];
#pragma unroll
            for (int mi = 0; mi < 2; mi++) {
                const int mr = wm * 32 + mi * 16;
                const float* ap = &As[buf][0];
                af[mi][0] = __float_as_uint(ap[(mr + g)     * A_STRIDE + ks * 8 + t]);
                af[mi][1] = __float_as_uint(ap[(mr + g + 8) * A_STRIDE + ks * 8 + t]);
                af[mi][2] = __float_as_uint(ap[(mr + g)     * A_STRIDE + ks * 8 + t + 4]);
                af[mi][3] = __float_as_uint(ap[(mr + g + 8) * A_STRIDE + ks * 8 + t + 4]);
            }
#pragma unroll
            for (int ni = 0; ni < 8; ni++) {
                const int n8 = wn * 8 + ni;
                uint2 bf = *(const uint2*)&Bs[buf][(ks * 16 + n8) * B_N8_STRIDE + lane * 2];
#pragma unroll
                for (int mi = 0; mi < 2; mi++) {
                    asm volatile(
                        "mma.sync.aligned.m16n8k8.row.col.f32.tf32.tf32.f32 "
                        "{%0,%1,%2,%3}, {%4,%5,%6,%7}, {%8,%9}, {%0,%1,%2,%3};"
                        : "+f"(acc[mi][ni][0]), "+f"(acc[mi][ni][1]),
                          "+f"(acc[mi][ni][2]), "+f"(acc[mi][ni][3])
                        : "r"(af[mi][0]), "r"(af[mi][1]), "r"(af[mi][2]), "r"(af[mi][3]),
                          "r"(bf.x), "r"(bf.y));
                }
            }
        }
        __syncthreads();
        if (s + 1 < S) {
            const int nb = (s + 1) & 1;
            float4 c0 = make_float4(__uint_as_float(f2tf(la0.x)), __uint_as_float(f2tf(la0.y)),
                                    __uint_as_float(f2tf(la0.z)), __uint_as_float(f2tf(la0.w)));
            float4 c1 = make_float4(__uint_as_float(f2tf(la1.x)), __uint_as_float(f2tf(la1.y)),
                                    __uint_as_float(f2tf(la1.z)), __uint_as_float(f2tf(la1.w)));
            *(float4*)&As[nb][am * A_STRIDE + akq]     = c0;
            *(float4*)&As[nb][am * A_STRIDE + akq + 4] = c1;
            float bv[8] = {lb0.x, lb0.y, lb0.z, lb0.w, lb1.x, lb1.y, lb1.z, lb1.w};
#pragma unroll
            for (int j = 0; j < 8; j++)
                Bs[nb][bbase + (j * 4 + bt) * 2] = __uint_as_float(f2tf(bv[j]));
            __syncthreads();
        }
    }

    // ---- epilogue ----
    if (MODE == 0 || MODE == 2) {
#pragma unroll
        for (int mi = 0; mi < 2; mi++) {
            const int r0 = bRow + wm * 32 + mi * 16 + g;
#pragma unroll
            for (int ni = 0; ni < 8; ni++) {
                const int cl = wn * 64 + ni * 8 + t * 2;
                const int c0 = bCol + cl;
                if (r0 < M) {
                    float2 v = make_float2(acc[mi][ni][0] + bias_s[cl],
                                           acc[mi][ni][1] + bias_s[cl + 1]);
                    *(float2*)&C[(size_t)r0 * N + c0] = v;
                }
                if (r0 + 8 < M) {
                    float2 v = make_float2(acc[mi][ni][2] + bias_s[cl],
                                           acc[mi][ni][3] + bias_s[cl + 1]);
                    *(float2*)&C[(size_t)(r0 + 8) * N + c0] = v;
                }
            }
        }
    } else {
        float local = 0.f;
#pragma unroll
        for (int mi = 0; mi < 2; mi++) {
            const int r0 = bRow + wm * 32 + mi * 16 + g;
#pragma unroll
            for (int ni = 0; ni < 8; ni++) {
                const int cl = wn * 64 + ni * 8 + t * 2;
                if (r0 < M)
                    local += q_s[cl]     * tanhf(acc[mi][ni][0] + bias_s[cl]) +
                             q_s[cl + 1] * tanhf(acc[mi][ni][1] + bias_s[cl + 1]);
                if (r0 + 8 < M)
                    local += q_s[cl]     * tanhf(acc[mi][ni][2] + bias_s[cl]) +
                             q_s[cl + 1] * tanhf(acc[mi][ni][3] + bias_s[cl + 1]);
            }
        }
        red[tid] = local;
        __syncthreads();
        for (int st = 128; st > 0; st >>= 1) {
            if (tid < st) red[tid] += red[tid + st];
            __syncthreads();
        }
        if (tid == 0) atomicAdd(score, red[0]);
    }
}

// ============== fused node-scores: 4 attention vectors per node type ========
// warp per node; lane holds 8 channels; outputs s_v[n*8+h]
__global__ void __launch_bounds__(256)
scores4_k(const float* __restrict__ h,
          const float* __restrict__ a0, const float* __restrict__ a1,
          const float* __restrict__ a2, const float* __restrict__ a3,
          float* __restrict__ s0, float* __restrict__ s1,
          float* __restrict__ s2, float* __restrict__ s3, int Nn)
{
    __shared__ float av[4][CC];
    const int tid = threadIdx.x;
    av[0][tid] = a0[tid]; av[1][tid] = a1[tid];
    av[2][tid] = a2[tid]; av[3][tid] = a3[tid];
    __syncthreads();

    const int lane = tid & 31;
    const int node = blockIdx.x * 8 + (tid >> 5);
    if (node >= Nn) return;

    const float* hp = h + (size_t)node * CC + lane * 8;
    float4 h0 = *(const float4*)hp;
    float4 h1 = *(const float4*)(hp + 4);

    float* outs[4] = {s0, s1, s2, s3};
#pragma unroll
    for (int v = 0; v < 4; v++) {
        const float* ap = &av[v][lane * 8];
        float p = h0.x * ap[0] + h0.y * ap[1] + h0.z * ap[2] + h0.w * ap[3] +
                  h1.x * ap[4] + h1.y * ap[5] + h1.z * ap[6] + h1.w * ap[7];
        p += __shfl_xor_sync(0xffffffffu, p, 1);
        p += __shfl_xor_sync(0xffffffffu, p, 2);
        if ((lane & 3) == 0) outs[v][node * HH + (lane >> 2)] = p;
    }
}

// ---------------- edge passes -----------------------------------------------
__device__ __forceinline__ unsigned f2ord(float f) {
    unsigned u = __float_as_uint(f);
    return (u & 0x80000000u) ? ~u : (u | 0x80000000u);
}
__device__ __forceinline__ float ord2f(unsigned e) {
    unsigned u = (e & 0x80000000u) ? (e ^ 0x80000000u) : ~e;
    return __uint_as_float(u);
}
__device__ __forceinline__ float lrelu(float x) { return x > 0.f ? x : 0.2f * x; }

__global__ void edge_max_k(const int* __restrict__ src, const int* __restrict__ dst,
                           const float* __restrict__ ssrc, const float* __restrict__ sdst,
                           unsigned* __restrict__ m, int E)
{
    int e = blockIdx.x * blockDim.x + threadIdx.x;
    if (e >= E) return;
    int s_ = src[e], d_ = dst[e];
    float4 a0 = *(const float4*)(ssrc + s_ * HH);
    float4 a1 = *(const float4*)(ssrc + s_ * HH + 4);
    float4 b0 = *(const float4*)(sdst + d_ * HH);
    float4 b1 = *(const float4*)(sdst + d_ * HH + 4);
    unsigned* mp = m + d_ * HH;
    atomicMax(mp + 0, f2ord(lrelu(a0.x + b0.x)));
    atomicMax(mp + 1, f2ord(lrelu(a0.y + b0.y)));
    atomicMax(mp + 2, f2ord(lrelu(a0.z + b0.z)));
    atomicMax(mp + 3, f2ord(lrelu(a0.w + b0.w)));
    atomicMax(mp + 4, f2ord(lrelu(a1.x + b1.x)));
    atomicMax(mp + 5, f2ord(lrelu(a1.y + b1.y)));
    atomicMax(mp + 6, f2ord(lrelu(a1.z + b1.z)));
    atomicMax(mp + 7, f2ord(lrelu(a1.w + b1.w)));
}

__global__ void edge_exp_k(const int* __restrict__ src, const int* __restrict__ dst,
                           const float* __restrict__ ssrc, const float* __restrict__ sdst,
                           const unsigned* __restrict__ m,
                           float* __restrict__ ebuf, float* __restrict__ sum, int E)
{
    int e = blockIdx.x * blockDim.x + threadIdx.x;
    if (e >= E) return;
    int s_ = src[e], d_ = dst[e];
    float4 a0 = *(const float4*)(ssrc + s_ * HH);
    float4 a1 = *(const float4*)(ssrc + s_ * HH + 4);
    float4 b0 = *(const float4*)(sdst + d_ * HH);
    float4 b1 = *(const float4*)(sdst + d_ * HH + 4);
    const unsigned* mp = m + d_ * HH;
    float* sp = sum + d_ * HH;
    float ev[8];
    ev[0] = expf(lrelu(a0.x + b0.x) - ord2f(mp[0]));
    ev[1] = expf(lrelu(a0.y + b0.y) - ord2f(mp[1]));
    ev[2] = expf(lrelu(a0.z + b0.z) - ord2f(mp[2]));
    ev[3] = expf(lrelu(a0.w + b0.w) - ord2f(mp[3]));
    ev[4] = expf(lrelu(a1.x + b1.x) - ord2f(mp[4]));
    ev[5] = expf(lrelu(a1.y + b1.y) - ord2f(mp[5]));
    ev[6] = expf(lrelu(a1.z + b1.z) - ord2f(mp[6]));
    ev[7] = expf(lrelu(a1.w + b1.w) - ord2f(mp[7]));
    *(float4*)(ebuf + (size_t)e * HH)     = make_float4(ev[0], ev[1], ev[2], ev[3]);
    *(float4*)(ebuf + (size_t)e * HH + 4) = make_float4(ev[4], ev[5], ev[6], ev[7]);
#pragma unroll
    for (int h = 0; h < 8; h++) atomicAdd(sp + h, ev[h]);
}

// warp per edge, v4 reductions
__global__ void edge_agg_k(const int* __restrict__ src, const int* __restrict__ dst,
                           const float* __restrict__ x,
                           const float* __restrict__ ebuf, const float* __restrict__ sum,
                           float* __restrict__ out, int E)
{
    int warp = (blockIdx.x * blockDim.x + threadIdx.x) >> 5;
    int lane = threadIdx.x & 31;
    if (warp >= E) return;
    int s_ = src[warp], d_ = dst[warp];
    int h = lane >> 2;
    float alpha = ebuf[(size_t)warp * HH + h] / (sum[d_ * HH + h] + 1e-16f);

    const float* xp = x + (size_t)s_ * CC + lane * 8;
    float* op = out + (size_t)d_ * CC + lane * 8;
    float4 v0 = *(const float4*)(xp);
    float4 v1 = *(const float4*)(xp + 4);
    v0.x *= alpha; v0.y *= alpha; v0.z *= alpha; v0.w *= alpha;
    v1.x *= alpha; v1.y *= alpha; v1.z *= alpha; v1.w *= alpha;
    asm volatile("red.global.add.v4.f32 [%0], {%1,%2,%3,%4};"
                 :: "l"(op), "f"(v0.x), "f"(v0.y), "f"(v0.z), "f"(v0.w) : "memory");
    asm volatile("red.global.add.v4.f32 [%0], {%1,%2,%3,%4};"
                 :: "l"(op + 4), "f"(v1.x), "f"(v1.y), "f"(v1.z), "f"(v1.w) : "memory");
}

__global__ void softmax2_k(const float* __restrict__ scores, float* __restrict__ attn,
                           float invNr, float invNd)
{
    if (threadIdx.x == 0 && blockIdx.x == 0) {
        float s0 = scores[0] * invNr, s1 = scores[1] * invNr;
        float mx = fmaxf(s0, s1);
        float e0 = expf(s0 - mx), e1 = expf(s1 - mx);
        attn[0] = e0 / (e0 + e1);
        attn[1] = e1 / (e0 + e1);
        s0 = scores[2] * invNd; s1 = scores[3] * invNd;
        mx = fmaxf(s0, s1);
        e0 = expf(s0 - mx); e1 = expf(s1 - mx);
        attn[2] = e0 / (e0 + e1);
        attn[3] = e1 / (e0 + e1);
    }
}

// ---------------------------------------------------------------------------
extern "C" void kernel_launch(void* const* d_in, const int* in_sizes, int n_in,
                              void* d_out, int out_size)
{
    const float* x_rna   = (const float*)d_in[0];
    const float* x_dis   = (const float*)d_in[1];
    const float* W_d     = (const float*)d_in[2];
    const float* b_d     = (const float*)d_in[3];
    const float* Wp_rna  = (const float*)d_in[4];
    const float* bp_rna  = (const float*)d_in[5];
    const float* Wp_dis  = (const float*)d_in[6];
    const float* bp_dis  = (const float*)d_in[7];
    const float* a_src_rd = (const float*)d_in[8];
    const float* a_dst_rd = (const float*)d_in[9];
    const float* a_src_dr = (const float*)d_in[10];
    const float* a_dst_dr = (const float*)d_in[11];
    const float* a_src_rr = (const float*)d_in[12];
    const float* a_dst_rr = (const float*)d_in[13];
    const float* a_src_dd = (const float*)d_in[14];
    const float* a_dst_dd = (const float*)d_in[15];
    const float* kW      = (const float*)d_in[16];
    const float* kb      = (const float*)d_in[17];
    const float* qv      = (const float*)d_in[18];
    const float* W_out   = (const float*)d_in[19];
    const float* b_out   = (const float*)d_in[20];
    const int* rd_src = (const int*)d_in[21];
    const int* rd_dst = (const int*)d_in[22];
    const int* dr_src = (const int*)d_in[23];
    const int* dr_dst = (const int*)d_in[24];
    const int* rr_src = (const int*)d_in[25];
    const int* rr_dst = (const int*)d_in[26];
    const int* dd_src = (const int*)d_in[27];
    const int* dd_dst = (const int*)d_in[28];

    float* out = (float*)d_out;

    float *p_xd, *p_hr, *p_hd, *p_ord, *p_odr, *p_orr, *p_odd;
    float *p_sr, *p_sd, *p_e, *p_sum, *p_scores, *p_attn;
    unsigned* p_m;
    cudaGetSymbolAddress((void**)&p_xd, g_xd);
    cudaGetSymbolAddress((void**)&p_hr, g_hr);
    cudaGetSymbolAddress((void**)&p_hd, g_hd);
    cudaGetSymbolAddress((void**)&p_ord, g_out_rd);
    cudaGetSymbolAddress((void**)&p_odr, g_out_dr);
    cudaGetSymbolAddress((void**)&p_orr, g_out_rr);
    cudaGetSymbolAddress((void**)&p_odd, g_out_dd);
    cudaGetSymbolAddress((void**)&p_sr, g_s_rna);
    cudaGetSymbolAddress((void**)&p_sd, g_s_dis);
    cudaGetSymbolAddress((void**)&p_e, g_e);
    cudaGetSymbolAddress((void**)&p_m, g_m);
    cudaGetSymbolAddress((void**)&p_sum, g_sum);
    cudaGetSymbolAddress((void**)&p_scores, g_scores);
    cudaGetSymbolAddress((void**)&p_attn, g_attn);

    const dim3 thr(256);
    const int mbr = (N_R + 127) / 128;   // 391
    const int mbd = (N_D + 127) / 128;   // 79

    // ---- dense projections (tf32 tensor cores) ----
    gemm_tc<0><<<dim3(2, mbd), thr>>>(x_dis, nullptr, W_d, b_d, nullptr, nullptr,
                                      p_xd, nullptr, N_D, RNA_IN, D_FEAT);
    gemm_tc<0><<<dim3(2, mbr), thr>>>(x_rna, nullptr, Wp_rna, bp_rna, nullptr, nullptr,
                                      p_hr, nullptr, N_R, CC, RNA_IN);
    gemm_tc<0><<<dim3(2, mbd), thr>>>(p_xd, nullptr, Wp_dis, bp_dis, nullptr, nullptr,
                                      p_hd, nullptr, N_D, CC, RNA_IN);

    // ---- fused per-node attention scores (one pass per node type) ----
    scores4_k<<<(N_R + 7) / 8, thr>>>(p_hr, a_src_rd, a_dst_dr, a_src_rr, a_dst_rr,
                                      p_sr + 0 * N_R * HH, p_sr + 1 * N_R * HH,
                                      p_sr + 2 * N_R * HH, p_sr + 3 * N_R * HH, N_R);
    scores4_k<<<(N_D + 7) / 8, thr>>>(p_hd, a_dst_rd, a_src_dr, a_src_dd, a_dst_dd,
                                      p_sd + 0 * N_D * HH, p_sd + 1 * N_D * HH,
                                      p_sd + 2 * N_D * HH, p_sd + 3 * N_D * HH, N_D);

    // zero output accumulators
    cudaMemsetAsync(p_ord, 0, (size_t)N_D * CC * sizeof(float));
    cudaMemsetAsync(p_odr, 0, (size_t)N_R * CC * sizeof(float));
    cudaMemsetAsync(p_orr, 0, (size_t)N_R * CC * sizeof(float));
    cudaMemsetAsync(p_odd, 0, (size_t)N_D * CC * sizeof(float));

    // ---- per-edge-type GAT attention ----
    auto run_type = [&](const float* xs, const float* ssrc, const float* sdst,
                        int Nd2, const int* si, const int* di, int E, float* outp) {
        cudaMemsetAsync(p_m, 0, (size_t)Nd2 * HH * sizeof(unsigned));
        cudaMemsetAsync(p_sum, 0, (size_t)Nd2 * HH * sizeof(float));
        edge_max_k<<<(E + 255) / 256, thr>>>(si, di, ssrc, sdst, p_m, E);
        edge_exp_k<<<(E + 255) / 256, thr>>>(si, di, ssrc, sdst, p_m, p_e, p_sum, E);
        edge_agg_k<<<(E * 32 + 255) / 256, thr>>>(si, di, xs, p_e, p_sum, outp, E);
    };

    run_type(p_hr, p_sr + 0 * N_R * HH, p_sd + 0 * N_D * HH, N_D, rd_src, rd_dst, E_RD, p_ord);
    run_type(p_hd, p_sd + 1 * N_D * HH, p_sr + 1 * N_R * HH, N_R, dr_src, dr_dst, E_DR, p_odr);
    run_type(p_hr, p_sr + 2 * N_R * HH, p_sr + 3 * N_R * HH, N_R, rr_src, rr_dst, E_RR, p_orr);
    run_type(p_hd, p_sd + 2 * N_D * HH, p_sd + 3 * N_D * HH, N_D, dd_src, dd_dst, E_DD, p_odd);

    // ---- semantic attention scores ----
    cudaMemsetAsync(p_scores, 0, 4 * sizeof(float));
    gemm_tc<1><<<dim3(2, mbr), thr>>>(p_odr, nullptr, kW, kb, nullptr, qv,
                                      nullptr, p_scores + 0, N_R, CC, CC);
    gemm_tc<1><<<dim3(2, mbr), thr>>>(p_orr, nullptr, kW, kb, nullptr, qv,
                                      nullptr, p_scores + 1, N_R, CC, CC);
    gemm_tc<1><<<dim3(2, mbd), thr>>>(p_ord, nullptr, kW, kb, nullptr, qv,
                                      nullptr, p_scores + 2, N_D, CC, CC);
    gemm_tc<1><<<dim3(2, mbd), thr>>>(p_odd, nullptr, kW, kb, nullptr, qv,
                                      nullptr, p_scores + 3, N_D, CC, CC);
    softmax2_k<<<1, 32>>>(p_scores, p_attn, 1.f / N_R, 1.f / N_D);

    // ---- final: h = (attn-weighted combo) @ W_out + b_out ----
    gemm_tc<2><<<dim3(2, mbr), thr>>>(p_odr, p_orr, W_out, b_out, p_attn + 0, nullptr,
                                      out, nullptr, N_R, CC, CC);
    gemm_tc<2><<<dim3(2, mbd), thr>>>(p_ord, p_odd, W_out, b_out, p_attn + 2, nullptr,
                                      out + (size_t)N_R * CC, nullptr, N_D, CC, CC);
}

// round 4
// speedup vs baseline: 3.3030x; 1.2336x over previous
#include <cuda_runtime.h>
#include <cstdint>
#include <math.h>

#define N_R 50000
#define N_D 10000
#define HH  8
#define DH  32
#define CC  256
#define RNA_IN 256
#define D_FEAT 512
#define E_RD 200000
#define E_DR 200000
#define E_RR 400000
#define E_DD 50000
#define E_TOT (E_RD + E_DR + E_RR + E_DD)

// ---------------- static device scratch ------------------------------------
__device__ float    g_xd[N_D * RNA_IN];
__device__ float    g_hr[N_R * CC];
__device__ float    g_hd[N_D * CC];
__device__ float    g_out_rd[N_D * CC];
__device__ float    g_out_dr[N_R * CC];
__device__ float    g_out_rr[N_R * CC];
__device__ float    g_out_dd[N_D * CC];
__device__ float    g_s_rna[4 * N_R * HH];   // [a_src_rd, a_dst_dr, a_src_rr, a_dst_rr]
__device__ float    g_s_dis[4 * N_D * HH];   // [a_dst_rd, a_src_dr, a_src_dd, a_dst_dd]
__device__ int      g_cnt[N_R];
__device__ int      g_fill[N_R];
__device__ int      g_rptr[4 * (N_R + 1)];
__device__ int      g_ssort[E_TOT];
__device__ float    g_scores[4];
__device__ float    g_attn[4];

__device__ __forceinline__ uint32_t f2tf(float f) {
    uint32_t u;
    asm("cvt.rna.tf32.f32 %0, %1;" : "=r"(u) : "f"(f));
    return u;
}

// ================= TF32 tensor-core GEMM =====================================
// 128x128 block tile, BK=16, 256 threads (8 warps, 4(m) x 2(n)), warp 32x64.
// MODE 0: C = A0 @ B + bias
// MODE 1: score += sum q[c]*tanh( relu(A0)@B + bias )
// MODE 2: C = ( w0*relu(A0) + w1*relu(A1) ) @ B + bias
#define A_STRIDE 20
#define B_N8_STRIDE 66

template <int MODE>
__global__ void __launch_bounds__(256)
gemm_tc(const float* __restrict__ A0, const float* __restrict__ A1,
        const float* __restrict__ B,  const float* __restrict__ bias,
        const float* __restrict__ wts, const float* __restrict__ qv,
        float* __restrict__ C, float* __restrict__ score,
        int M, int N, int K)
{
    __shared__ float As[2][128 * A_STRIDE];
    __shared__ float Bs[2][2 * 16 * B_N8_STRIDE];
    __shared__ float bias_s[128];
    __shared__ float q_s[128];
    __shared__ float red[256];

    const int tid  = threadIdx.x;
    const int lane = tid & 31;
    const int warp = tid >> 5;
    const int wm   = warp & 3;
    const int wn   = warp >> 2;
    const int g    = lane >> 2;
    const int t    = lane & 3;
    const int bRow = blockIdx.y * 128;
    const int bCol = blockIdx.x * 128;

    if (tid < 128) {
        bias_s[tid] = bias[bCol + tid];
        if (MODE == 1) q_s[tid] = qv[bCol + tid];
    }

    float w0 = 0.f, w1 = 0.f;
    if (MODE == 2) { w0 = wts[0]; w1 = wts[1]; }

    const int am  = tid >> 1;
    const int akq = (tid & 1) * 8;
    const size_t arow_off = (size_t)(bRow + am) * K;
    const bool arow_ok = (bRow + am) < M;

    const int bkr = tid >> 4;
    const int bn8 = tid & 15;
    const int bks = bkr >> 3;
    const int bt  = bkr & 3;
    const int brg = (bkr & 7) >> 2;
    const int bbase = (bks * 16 + bn8) * B_N8_STRIDE + brg;

    float acc[2][8][4];
#pragma unroll
    for (int mi = 0; mi < 2; mi++)
#pragma unroll
        for (int ni = 0; ni < 8; ni++)
#pragma unroll
            for (int r = 0; r < 4; r++) acc[mi][ni][r] = 0.f;

    const int S = K / 16;
    float4 la0, la1, lb0, lb1;

    {
        const int k0 = 0;
        if (arow_ok) {
            la0 = *(const float4*)(A0 + arow_off + k0 + akq);
            la1 = *(const float4*)(A0 + arow_off + k0 + akq + 4);
            if (MODE == 1) {
                la0.x = fmaxf(la0.x, 0.f); la0.y = fmaxf(la0.y, 0.f);
                la0.z = fmaxf(la0.z, 0.f); la0.w = fmaxf(la0.w, 0.f);
                la1.x = fmaxf(la1.x, 0.f); la1.y = fmaxf(la1.y, 0.f);
                la1.z = fmaxf(la1.z, 0.f); la1.w = fmaxf(la1.w, 0.f);
            }
            if (MODE == 2) {
                float4 m0 = *(const float4*)(A1 + arow_off + k0 + akq);
                float4 m1 = *(const float4*)(A1 + arow_off + k0 + akq + 4);
                la0.x = w0 * fmaxf(la0.x, 0.f) + w1 * fmaxf(m0.x, 0.f);
                la0.y = w0 * fmaxf(la0.y, 0.f) + w1 * fmaxf(m0.y, 0.f);
                la0.z = w0 * fmaxf(la0.z, 0.f) + w1 * fmaxf(m0.z, 0.f);
                la0.w = w0 * fmaxf(la0.w, 0.f) + w1 * fmaxf(m0.w, 0.f);
                la1.x = w0 * fmaxf(la1.x, 0.f) + w1 * fmaxf(m1.x, 0.f);
                la1.y = w0 * fmaxf(la1.y, 0.f) + w1 * fmaxf(m1.y, 0.f);
                la1.z = w0 * fmaxf(la1.z, 0.f) + w1 * fmaxf(m1.z, 0.f);
                la1.w = w0 * fmaxf(la1.w, 0.f) + w1 * fmaxf(m1.w, 0.f);
            }
        } else {
            la0 = make_float4(0.f, 0.f, 0.f, 0.f);
            la1 = la0;
        }
        lb0 = *(const float4*)(B + (size_t)(k0 + bkr) * N + bCol + bn8 * 8);
        lb1 = *(const float4*)(B + (size_t)(k0 + bkr) * N + bCol + bn8 * 8 + 4);
    }
    {
        float4 c0 = make_float4(__uint_as_float(f2tf(la0.x)), __uint_as_float(f2tf(la0.y)),
                                __uint_as_float(f2tf(la0.z)), __uint_as_float(f2tf(la0.w)));
        float4 c1 = make_float4(__uint_as_float(f2tf(la1.x)), __uint_as_float(f2tf(la1.y)),
                                __uint_as_float(f2tf(la1.z)), __uint_as_float(f2tf(la1.w)));
        *(float4*)&As[0][am * A_STRIDE + akq]     = c0;
        *(float4*)&As[0][am * A_STRIDE + akq + 4] = c1;
        float bv[8] = {lb0.x, lb0.y, lb0.z, lb0.w, lb1.x, lb1.y, lb1.z, lb1.w};
#pragma unroll
        for (int j = 0; j < 8; j++)
            Bs[0][bbase + (j * 4 + bt) * 2] = __uint_as_float(f2tf(bv[j]));
    }
    __syncthreads();

    for (int s = 0; s < S; s++) {
        if (s + 1 < S) {
            const int k0 = (s + 1) * 16;
            if (arow_ok) {
                la0 = *(const float4*)(A0 + arow_off + k0 + akq);
                la1 = *(const float4*)(A0 + arow_off + k0 + akq + 4);
                if (MODE == 1) {
                    la0.x = fmaxf(la0.x, 0.f); la0.y = fmaxf(la0.y, 0.f);
                    la0.z = fmaxf(la0.z, 0.f); la0.w = fmaxf(la0.w, 0.f);
                    la1.x = fmaxf(la1.x, 0.f); la1.y = fmaxf(la1.y, 0.f);
                    la1.z = fmaxf(la1.z, 0.f); la1.w = fmaxf(la1.w, 0.f);
                }
                if (MODE == 2) {
                    float4 m0 = *(const float4*)(A1 + arow_off + k0 + akq);
                    float4 m1 = *(const float4*)(A1 + arow_off + k0 + akq + 4);
                    la0.x = w0 * fmaxf(la0.x, 0.f) + w1 * fmaxf(m0.x, 0.f);
                    la0.y = w0 * fmaxf(la0.y, 0.f) + w1 * fmaxf(m0.y, 0.f);
                    la0.z = w0 * fmaxf(la0.z, 0.f) + w1 * fmaxf(m0.z, 0.f);
                    la0.w = w0 * fmaxf(la0.w, 0.f) + w1 * fmaxf(m0.w, 0.f);
                    la1.x = w0 * fmaxf(la1.x, 0.f) + w1 * fmaxf(m1.x, 0.f);
                    la1.y = w0 * fmaxf(la1.y, 0.f) + w1 * fmaxf(m1.y, 0.f);
                    la1.z = w0 * fmaxf(la1.z, 0.f) + w1 * fmaxf(m1.z, 0.f);
                    la1.w = w0 * fmaxf(la1.w, 0.f) + w1 * fmaxf(m1.w, 0.f);
                }
            } else {
                la0 = make_float4(0.f, 0.f, 0.f, 0.f);
                la1 = la0;
            }
            lb0 = *(const float4*)(B + (size_t)(k0 + bkr) * N + bCol + bn8 * 8);
            lb1 = *(const float4*)(B + (size_t)(k0 + bkr) * N + bCol + bn8 * 8 + 4);
        }

        const int buf = s & 1;
#pragma unroll
        for (int ks = 0; ks < 2; ks++) {
            uint32_t af[2][4];
#pragma unroll
            for (int mi = 0; mi < 2; mi++) {
                const int mr = wm * 32 + mi * 16;
                const float* ap = &As[buf][0];
                af[mi][0] = __float_as_uint(ap[(mr + g)     * A_STRIDE + ks * 8 + t]);
                af[mi][1] = __float_as_uint(ap[(mr + g + 8) * A_STRIDE + ks * 8 + t]);
                af[mi][2] = __float_as_uint(ap[(mr + g)     * A_STRIDE + ks * 8 + t + 4]);
                af[mi][3] = __float_as_uint(ap[(mr + g + 8) * A_STRIDE + ks * 8 + t + 4]);
            }
#pragma unroll
            for (int ni = 0; ni < 8; ni++) {
                const int n8 = wn * 8 + ni;
                uint2 bf = *(const uint2*)&Bs[buf][(ks * 16 + n8) * B_N8_STRIDE + lane * 2];
#pragma unroll
                for (int mi = 0; mi < 2; mi++) {
                    asm volatile(
                        "mma.sync.aligned.m16n8k8.row.col.f32.tf32.tf32.f32 "
                        "{%0,%1,%2,%3}, {%4,%5,%6,%7}, {%8,%9}, {%0,%1,%2,%3};"
                        : "+f"(acc[mi][ni][0]), "+f"(acc[mi][ni][1]),
                          "+f"(acc[mi][ni][2]), "+f"(acc[mi][ni][3])
                        : "r"(af[mi][0]), "r"(af[mi][1]), "r"(af[mi][2]), "r"(af[mi][3]),
                          "r"(bf.x), "r"(bf.y));
                }
            }
        }
        __syncthreads();
        if (s + 1 < S) {
            const int nb = (s + 1) & 1;
            float4 c0 = make_float4(__uint_as_float(f2tf(la0.x)), __uint_as_float(f2tf(la0.y)),
                                    __uint_as_float(f2tf(la0.z)), __uint_as_float(f2tf(la0.w)));
            float4 c1 = make_float4(__uint_as_float(f2tf(la1.x)), __uint_as_float(f2tf(la1.y)),
                                    __uint_as_float(f2tf(la1.z)), __uint_as_float(f2tf(la1.w)));
            *(float4*)&As[nb][am * A_STRIDE + akq]     = c0;
            *(float4*)&As[nb][am * A_STRIDE + akq + 4] = c1;
            float bv[8] = {lb0.x, lb0.y, lb0.z, lb0.w, lb1.x, lb1.y, lb1.z, lb1.w};
#pragma unroll
            for (int j = 0; j < 8; j++)
                Bs[nb][bbase + (j * 4 + bt) * 2] = __uint_as_float(f2tf(bv[j]));
            __syncthreads();
        }
    }

    if (MODE == 0 || MODE == 2) {
#pragma unroll
        for (int mi = 0; mi < 2; mi++) {
            const int r0 = bRow + wm * 32 + mi * 16 + g;
#pragma unroll
            for (int ni = 0; ni < 8; ni++) {
                const int cl = wn * 64 + ni * 8 + t * 2;
                const int c0 = bCol + cl;
                if (r0 < M) {
                    float2 v = make_float2(acc[mi][ni][0] + bias_s[cl],
                                           acc[mi][ni][1] + bias_s[cl + 1]);
                    *(float2*)&C[(size_t)r0 * N + c0] = v;
                }
                if (r0 + 8 < M) {
                    float2 v = make_float2(acc[mi][ni][2] + bias_s[cl],
                                           acc[mi][ni][3] + bias_s[cl + 1]);
                    *(float2*)&C[(size_t)(r0 + 8) * N + c0] = v;
                }
            }
        }
    } else {
        float local = 0.f;
#pragma unroll
        for (int mi = 0; mi < 2; mi++) {
            const int r0 = bRow + wm * 32 + mi * 16 + g;
#pragma unroll
            for (int ni = 0; ni < 8; ni++) {
                const int cl = wn * 64 + ni * 8 + t * 2;
                if (r0 < M)
                    local += q_s[cl]     * tanhf(acc[mi][ni][0] + bias_s[cl]) +
                             q_s[cl + 1] * tanhf(acc[mi][ni][1] + bias_s[cl + 1]);
                if (r0 + 8 < M)
                    local += q_s[cl]     * tanhf(acc[mi][ni][2] + bias_s[cl]) +
                             q_s[cl + 1] * tanhf(acc[mi][ni][3] + bias_s[cl + 1]);
            }
        }
        red[tid] = local;
        __syncthreads();
        for (int st = 128; st > 0; st >>= 1) {
            if (tid < st) red[tid] += red[tid + st];
            __syncthreads();
        }
        if (tid == 0) atomicAdd(score, red[0]);
    }
}

// ============== fused node-scores ============================================
__global__ void __launch_bounds__(256)
scores4_k(const float* __restrict__ h,
          const float* __restrict__ a0, const float* __restrict__ a1,
          const float* __restrict__ a2, const float* __restrict__ a3,
          float* __restrict__ s0, float* __restrict__ s1,
          float* __restrict__ s2, float* __restrict__ s3, int Nn)
{
    __shared__ float av[4][CC];
    const int tid = threadIdx.x;
    av[0][tid] = a0[tid]; av[1][tid] = a1[tid];
    av[2][tid] = a2[tid]; av[3][tid] = a3[tid];
    __syncthreads();

    const int lane = tid & 31;
    const int node = blockIdx.x * 8 + (tid >> 5);
    if (node >= Nn) return;

    const float* hp = h + (size_t)node * CC + lane * 8;
    float4 h0 = *(const float4*)hp;
    float4 h1 = *(const float4*)(hp + 4);

    float* outs[4] = {s0, s1, s2, s3};
#pragma unroll
    for (int v = 0; v < 4; v++) {
        const float* ap = &av[v][lane * 8];
        float p = h0.x * ap[0] + h0.y * ap[1] + h0.z * ap[2] + h0.w * ap[3] +
                  h1.x * ap[4] + h1.y * ap[5] + h1.z * ap[6] + h1.w * ap[7];
        p += __shfl_xor_sync(0xffffffffu, p, 1);
        p += __shfl_xor_sync(0xffffffffu, p, 2);
        if ((lane & 3) == 0) outs[v][node * HH + (lane >> 2)] = p;
    }
}

// ================= CSR build =================================================
__global__ void hist_k(const int* __restrict__ dst, int* __restrict__ cnt, int E)
{
    int e = blockIdx.x * blockDim.x + threadIdx.x;
    if (e < E) atomicAdd(&cnt[dst[e]], 1);
}

// single-block exclusive scan (n up to 50000), 1024 threads
__global__ void __launch_bounds__(1024)
scan_k(const int* __restrict__ cnt, int* __restrict__ rptr, int n)
{
    __shared__ int wsum[32];
    __shared__ int s_carry;
    const int tid = threadIdx.x;
    const int lane = tid & 31, wid = tid >> 5;
    if (tid == 0) s_carry = 0;
    __syncthreads();
    for (int base = 0; base < n; base += 1024) {
        int i = base + tid;
        int v = (i < n) ? cnt[i] : 0;
        int x = v;
#pragma unroll
        for (int o = 1; o < 32; o <<= 1) {
            int y = __shfl_up_sync(0xffffffffu, x, o);
            if (lane >= o) x += y;
        }
        if (lane == 31) wsum[wid] = x;
        __syncthreads();
        if (wid == 0) {
            int tv = wsum[lane];
#pragma unroll
            for (int o = 1; o < 32; o <<= 1) {
                int y = __shfl_up_sync(0xffffffffu, tv, o);
                if (lane >= o) tv += y;
            }
            wsum[lane] = tv;
        }
        __syncthreads();
        int incl = x + (wid > 0 ? wsum[wid - 1] : 0);
        int carry = s_carry;
        if (i < n) rptr[i] = carry + incl - v;
        __syncthreads();
        if (tid == 1023) s_carry = carry + incl;
        __syncthreads();
    }
    if (tid == 0) rptr[n] = s_carry;
}

__global__ void scatter_k(const int* __restrict__ src, const int* __restrict__ dst,
                          const int* __restrict__ rptr, int* __restrict__ fill,
                          int* __restrict__ ssort, int E)
{
    int e = blockIdx.x * blockDim.x + threadIdx.x;
    if (e >= E) return;
    int d = dst[e];
    int pos = rptr[d] + atomicAdd(&fill[d], 1);
    ssort[pos] = src[e];
}

// ============ fused edge aggregation: warp per dst node, online softmax =====
__device__ __forceinline__ float lrelu(float x) { return x > 0.f ? x : 0.2f * x; }

__global__ void __launch_bounds__(256)
agg_csr_k(const int* __restrict__ rptr, const int* __restrict__ ssort,
          const float* __restrict__ ssrc, const float* __restrict__ sdst,
          const float* __restrict__ x, float* __restrict__ out, int Nd)
{
    const int warp = (blockIdx.x * blockDim.x + threadIdx.x) >> 5;
    const int lane = threadIdx.x & 31;
    if (warp >= Nd) return;
    const int h = lane >> 2;

    const float sd = sdst[warp * HH + h];
    const int beg = rptr[warp], end = rptr[warp + 1];

    float m = -INFINITY, s = 0.f;
    float a0 = 0.f, a1 = 0.f, a2 = 0.f, a3 = 0.f;
    float a4 = 0.f, a5 = 0.f, a6 = 0.f, a7 = 0.f;

    for (int p = beg; p < end; p++) {
        int src = ssort[p];
        float sc = lrelu(ssrc[src * HH + h] + sd);
        float mn = fmaxf(m, sc);
        float corr = expf(m - mn);       // 0 on first edge (m=-inf)
        float w = expf(sc - mn);
        s = s * corr + w;
        m = mn;
        const float4* xp = (const float4*)(x + (size_t)src * CC + lane * 8);
        float4 v0 = xp[0], v1 = xp[1];
        a0 = a0 * corr + w * v0.x;
        a1 = a1 * corr + w * v0.y;
        a2 = a2 * corr + w * v0.z;
        a3 = a3 * corr + w * v0.w;
        a4 = a4 * corr + w * v1.x;
        a5 = a5 * corr + w * v1.y;
        a6 = a6 * corr + w * v1.z;
        a7 = a7 * corr + w * v1.w;
    }
    float inv = 1.f / (s + 1e-16f);
    float* op = out + (size_t)warp * CC + lane * 8;
    *(float4*)op       = make_float4(a0 * inv, a1 * inv, a2 * inv, a3 * inv);
    *(float4*)(op + 4) = make_float4(a4 * inv, a5 * inv, a6 * inv, a7 * inv);
}

__global__ void softmax2_k(const float* __restrict__ scores, float* __restrict__ attn,
                           float invNr, float invNd)
{
    if (threadIdx.x == 0 && blockIdx.x == 0) {
        float s0 = scores[0] * invNr, s1 = scores[1] * invNr;
        float mx = fmaxf(s0, s1);
        float e0 = expf(s0 - mx), e1 = expf(s1 - mx);
        attn[0] = e0 / (e0 + e1);
        attn[1] = e1 / (e0 + e1);
        s0 = scores[2] * invNd; s1 = scores[3] * invNd;
        mx = fmaxf(s0, s1);
        e0 = expf(s0 - mx); e1 = expf(s1 - mx);
        attn[2] = e0 / (e0 + e1);
        attn[3] = e1 / (e0 + e1);
    }
}

// ---------------------------------------------------------------------------
extern "C" void kernel_launch(void* const* d_in, const int* in_sizes, int n_in,
                              void* d_out, int out_size)
{
    const float* x_rna   = (const float*)d_in[0];
    const float* x_dis   = (const float*)d_in[1];
    const float* W_d     = (const float*)d_in[2];
    const float* b_d     = (const float*)d_in[3];
    const float* Wp_rna  = (const float*)d_in[4];
    const float* bp_rna  = (const float*)d_in[5];
    const float* Wp_dis  = (const float*)d_in[6];
    const float* bp_dis  = (const float*)d_in[7];
    const float* a_src_rd = (const float*)d_in[8];
    const float* a_dst_rd = (const float*)d_in[9];
    const float* a_src_dr = (const float*)d_in[10];
    const float* a_dst_dr = (const float*)d_in[11];
    const float* a_src_rr = (const float*)d_in[12];
    const float* a_dst_rr = (const float*)d_in[13];
    const float* a_src_dd = (const float*)d_in[14];
    const float* a_dst_dd = (const float*)d_in[15];
    const float* kW      = (const float*)d_in[16];
    const float* kb      = (const float*)d_in[17];
    const float* qv      = (const float*)d_in[18];
    const float* W_out   = (const float*)d_in[19];
    const float* b_out   = (const float*)d_in[20];
    const int* rd_src = (const int*)d_in[21];
    const int* rd_dst = (const int*)d_in[22];
    const int* dr_src = (const int*)d_in[23];
    const int* dr_dst = (const int*)d_in[24];
    const int* rr_src = (const int*)d_in[25];
    const int* rr_dst = (const int*)d_in[26];
    const int* dd_src = (const int*)d_in[27];
    const int* dd_dst = (const int*)d_in[28];

    float* out = (float*)d_out;

    float *p_xd, *p_hr, *p_hd, *p_ord, *p_odr, *p_orr, *p_odd;
    float *p_sr, *p_sd, *p_scores, *p_attn;
    int *p_cnt, *p_fill, *p_rptr, *p_ssort;
    cudaGetSymbolAddress((void**)&p_xd, g_xd);
    cudaGetSymbolAddress((void**)&p_hr, g_hr);
    cudaGetSymbolAddress((void**)&p_hd, g_hd);
    cudaGetSymbolAddress((void**)&p_ord, g_out_rd);
    cudaGetSymbolAddress((void**)&p_odr, g_out_dr);
    cudaGetSymbolAddress((void**)&p_orr, g_out_rr);
    cudaGetSymbolAddress((void**)&p_odd, g_out_dd);
    cudaGetSymbolAddress((void**)&p_sr, g_s_rna);
    cudaGetSymbolAddress((void**)&p_sd, g_s_dis);
    cudaGetSymbolAddress((void**)&p_cnt, g_cnt);
    cudaGetSymbolAddress((void**)&p_fill, g_fill);
    cudaGetSymbolAddress((void**)&p_rptr, g_rptr);
    cudaGetSymbolAddress((void**)&p_ssort, g_ssort);
    cudaGetSymbolAddress((void**)&p_scores, g_scores);
    cudaGetSymbolAddress((void**)&p_attn, g_attn);

    const dim3 thr(256);
    const int mbr = (N_R + 127) / 128;   // 391
    const int mbd = (N_D + 127) / 128;   // 79

    // ---- CSR builds (independent of everything else) ----
    // per-type rptr slices and ssort slices
    int* rp_rd = p_rptr + 0 * (N_R + 1);
    int* rp_dr = p_rptr + 1 * (N_R + 1);
    int* rp_rr = p_rptr + 2 * (N_R + 1);
    int* rp_dd = p_rptr + 3 * (N_R + 1);
    int* ss_rd = p_ssort;
    int* ss_dr = ss_rd + E_RD;
    int* ss_rr = ss_dr + E_DR;
    int* ss_dd = ss_rr + E_RR;

    auto build_csr = [&](const int* si, const int* di, int E, int Nd2,
                         int* rp, int* ss) {
        cudaMemsetAsync(p_cnt, 0, (size_t)Nd2 * sizeof(int));
        cudaMemsetAsync(p_fill, 0, (size_t)Nd2 * sizeof(int));
        hist_k<<<(E + 255) / 256, thr>>>(di, p_cnt, E);
        scan_k<<<1, 1024>>>(p_cnt, rp, Nd2);
        scatter_k<<<(E + 255) / 256, thr>>>(si, di, rp, p_fill, ss, E);
    };
    build_csr(rd_src, rd_dst, E_RD, N_D, rp_rd, ss_rd);
    build_csr(dr_src, dr_dst, E_DR, N_R, rp_dr, ss_dr);
    build_csr(rr_src, rr_dst, E_RR, N_R, rp_rr, ss_rr);
    build_csr(dd_src, dd_dst, E_DD, N_D, rp_dd, ss_dd);

    // ---- dense projections (tf32 tensor cores) ----
    gemm_tc<0><<<dim3(2, mbd), thr>>>(x_dis, nullptr, W_d, b_d, nullptr, nullptr,
                                      p_xd, nullptr, N_D, RNA_IN, D_FEAT);
    gemm_tc<0><<<dim3(2, mbr), thr>>>(x_rna, nullptr, Wp_rna, bp_rna, nullptr, nullptr,
                                      p_hr, nullptr, N_R, CC, RNA_IN);
    gemm_tc<0><<<dim3(2, mbd), thr>>>(p_xd, nullptr, Wp_dis, bp_dis, nullptr, nullptr,
                                      p_hd, nullptr, N_D, CC, RNA_IN);

    // ---- fused per-node attention scores ----
    scores4_k<<<(N_R + 7) / 8, thr>>>(p_hr, a_src_rd, a_dst_dr, a_src_rr, a_dst_rr,
                                      p_sr + 0 * N_R * HH, p_sr + 1 * N_R * HH,
                                      p_sr + 2 * N_R * HH, p_sr + 3 * N_R * HH, N_R);
    scores4_k<<<(N_D + 7) / 8, thr>>>(p_hd, a_dst_rd, a_src_dr, a_src_dd, a_dst_dd,
                                      p_sd + 0 * N_D * HH, p_sd + 1 * N_D * HH,
                                      p_sd + 2 * N_D * HH, p_sd + 3 * N_D * HH, N_D);

    // ---- fused edge aggregation (one kernel per type, no atomics) ----
    agg_csr_k<<<(N_D * 32 + 255) / 256, thr>>>(rp_rd, ss_rd,
                                               p_sr + 0 * N_R * HH, p_sd + 0 * N_D * HH,
                                               p_hr, p_ord, N_D);
    agg_csr_k<<<(N_R * 32 + 255) / 256, thr>>>(rp_dr, ss_dr,
                                               p_sd + 1 * N_D * HH, p_sr + 1 * N_R * HH,
                                               p_hd, p_odr, N_R);
    agg_csr_k<<<(N_R * 32 + 255) / 256, thr>>>(rp_rr, ss_rr,
                                               p_sr + 2 * N_R * HH, p_sr + 3 * N_R * HH,
                                               p_hr, p_orr, N_R);
    agg_csr_k<<<(N_D * 32 + 255) / 256, thr>>>(rp_dd, ss_dd,
                                               p_sd + 2 * N_D * HH, p_sd + 3 * N_D * HH,
                                               p_hd, p_odd, N_D);

    // ---- semantic attention scores ----
    cudaMemsetAsync(p_scores, 0, 4 * sizeof(float));
    gemm_tc<1><<<dim3(2, mbr), thr>>>(p_odr, nullptr, kW, kb, nullptr, qv,
                                      nullptr, p_scores + 0, N_R, CC, CC);
    gemm_tc<1><<<dim3(2, mbr), thr>>>(p_orr, nullptr, kW, kb, nullptr, qv,
                                      nullptr, p_scores + 1, N_R, CC, CC);
    gemm_tc<1><<<dim3(2, mbd), thr>>>(p_ord, nullptr, kW, kb, nullptr, qv,
                                      nullptr, p_scores + 2, N_D, CC, CC);
    gemm_tc<1><<<dim3(2, mbd), thr>>>(p_odd, nullptr, kW, kb, nullptr, qv,
                                      nullptr, p_scores + 3, N_D, CC, CC);
    softmax2_k<<<1, 32>>>(p_scores, p_attn, 1.f / N_R, 1.f / N_D);

    // ---- final: h = (attn-weighted combo) @ W_out + b_out ----
    gemm_tc<2><<<dim3(2, mbr), thr>>>(p_odr, p_orr, W_out, b_out, p_attn + 0, nullptr,
                                      out, nullptr, N_R, CC, CC);
    gemm_tc<2><<<dim3(2, mbd), thr>>>(p_ord, p_odd, W_out, b_out, p_attn + 2, nullptr,
                                      out + (size_t)N_R * CC, nullptr, N_D, CC, CC);
}

// round 5
// speedup vs baseline: 4.5428x; 1.3754x over previous
#include <cuda_runtime.h>
#include <cstdint>
#include <math.h>

#define N_R 50000
#define N_D 10000
#define HH  8
#define DH  32
#define CC  256
#define RNA_IN 256
#define D_FEAT 512
#define E_RD 200000
#define E_DR 200000
#define E_RR 400000
#define E_DD 50000
#define E_TOT (E_RD + E_DR + E_RR + E_DD)
#define CNT_TOT (2 * N_R + 2 * N_D)

// ---------------- static device scratch ------------------------------------
__device__ float    g_xd[N_D * RNA_IN];
__device__ float    g_hr[N_R * CC];
__device__ float    g_hd[N_D * CC];
__device__ float    g_out_rd[N_D * CC];
__device__ float    g_out_dr[N_R * CC];
__device__ float    g_out_rr[N_R * CC];
__device__ float    g_out_dd[N_D * CC];
__device__ float    g_s_rna[4 * N_R * HH];
__device__ float    g_s_dis[4 * N_D * HH];
__device__ int      g_cnt[CNT_TOT];    // layout [N_D | N_R | N_R | N_D] (rd,dr,rr,dd)
__device__ int      g_fill[CNT_TOT];
__device__ int      g_rptr[4 * (N_R + 1)];
__device__ int      g_ssort[E_TOT];
__device__ float    g_scores[4];
__device__ float    g_attn[4];

__device__ __forceinline__ uint32_t f2tf(float f) {
    uint32_t u;
    asm("cvt.rna.tf32.f32 %0, %1;" : "=r"(u) : "f"(f));
    return u;
}

// ================= TF32 tensor-core GEMM =====================================
#define A_STRIDE 20
#define B_N8_STRIDE 66

template <int MODE>
__global__ void __launch_bounds__(256)
gemm_tc(const float* __restrict__ A0, const float* __restrict__ A1,
        const float* __restrict__ B,  const float* __restrict__ bias,
        const float* __restrict__ wts, const float* __restrict__ qv,
        float* __restrict__ C, float* __restrict__ score,
        int M, int N, int K)
{
    __shared__ float As[2][128 * A_STRIDE];
    __shared__ float Bs[2][2 * 16 * B_N8_STRIDE];
    __shared__ float bias_s[128];
    __shared__ float q_s[128];
    __shared__ float red[256];

    const int tid  = threadIdx.x;
    const int lane = tid & 31;
    const int warp = tid >> 5;
    const int wm   = warp & 3;
    const int wn   = warp >> 2;
    const int g    = lane >> 2;
    const int t    = lane & 3;
    const int bRow = blockIdx.y * 128;
    const int bCol = blockIdx.x * 128;

    if (tid < 128) {
        bias_s[tid] = bias[bCol + tid];
        if (MODE == 1) q_s[tid] = qv[bCol + tid];
    }

    float w0 = 0.f, w1 = 0.f;
    if (MODE == 2) { w0 = wts[0]; w1 = wts[1]; }

    const int am  = tid >> 1;
    const int akq = (tid & 1) * 8;
    const size_t arow_off = (size_t)(bRow + am) * K;
    const bool arow_ok = (bRow + am) < M;

    const int bkr = tid >> 4;
    const int bn8 = tid & 15;
    const int bks = bkr >> 3;
    const int bt  = bkr & 3;
    const int brg = (bkr & 7) >> 2;
    const int bbase = (bks * 16 + bn8) * B_N8_STRIDE + brg;

    float acc[2][8][4];
#pragma unroll
    for (int mi = 0; mi < 2; mi++)
#pragma unroll
        for (int ni = 0; ni < 8; ni++)
#pragma unroll
            for (int r = 0; r < 4; r++) acc[mi][ni][r] = 0.f;

    const int S = K / 16;
    float4 la0, la1, lb0, lb1;

    {
        const int k0 = 0;
        if (arow_ok) {
            la0 = *(const float4*)(A0 + arow_off + k0 + akq);
            la1 = *(const float4*)(A0 + arow_off + k0 + akq + 4);
            if (MODE == 1) {
                la0.x = fmaxf(la0.x, 0.f); la0.y = fmaxf(la0.y, 0.f);
                la0.z = fmaxf(la0.z, 0.f); la0.w = fmaxf(la0.w, 0.f);
                la1.x = fmaxf(la1.x, 0.f); la1.y = fmaxf(la1.y, 0.f);
                la1.z = fmaxf(la1.z, 0.f); la1.w = fmaxf(la1.w, 0.f);
            }
            if (MODE == 2) {
                float4 m0 = *(const float4*)(A1 + arow_off + k0 + akq);
                float4 m1 = *(const float4*)(A1 + arow_off + k0 + akq + 4);
                la0.x = w0 * fmaxf(la0.x, 0.f) + w1 * fmaxf(m0.x, 0.f);
                la0.y = w0 * fmaxf(la0.y, 0.f) + w1 * fmaxf(m0.y, 0.f);
                la0.z = w0 * fmaxf(la0.z, 0.f) + w1 * fmaxf(m0.z, 0.f);
                la0.w = w0 * fmaxf(la0.w, 0.f) + w1 * fmaxf(m0.w, 0.f);
                la1.x = w0 * fmaxf(la1.x, 0.f) + w1 * fmaxf(m1.x, 0.f);
                la1.y = w0 * fmaxf(la1.y, 0.f) + w1 * fmaxf(m1.y, 0.f);
                la1.z = w0 * fmaxf(la1.z, 0.f) + w1 * fmaxf(m1.z, 0.f);
                la1.w = w0 * fmaxf(la1.w, 0.f) + w1 * fmaxf(m1.w, 0.f);
            }
        } else {
            la0 = make_float4(0.f, 0.f, 0.f, 0.f);
            la1 = la0;
        }
        lb0 = *(const float4*)(B + (size_t)(k0 + bkr) * N + bCol + bn8 * 8);
        lb1 = *(const float4*)(B + (size_t)(k0 + bkr) * N + bCol + bn8 * 8 + 4);
    }
    {
        float4 c0 = make_float4(__uint_as_float(f2tf(la0.x)), __uint_as_float(f2tf(la0.y)),
                                __uint_as_float(f2tf(la0.z)), __uint_as_float(f2tf(la0.w)));
        float4 c1 = make_float4(__uint_as_float(f2tf(la1.x)), __uint_as_float(f2tf(la1.y)),
                                __uint_as_float(f2tf(la1.z)), __uint_as_float(f2tf(la1.w)));
        *(float4*)&As[0][am * A_STRIDE + akq]     = c0;
        *(float4*)&As[0][am * A_STRIDE + akq + 4] = c1;
        float bv[8] = {lb0.x, lb0.y, lb0.z, lb0.w, lb1.x, lb1.y, lb1.z, lb1.w};
#pragma unroll
        for (int j = 0; j < 8; j++)
            Bs[0][bbase + (j * 4 + bt) * 2] = __uint_as_float(f2tf(bv[j]));
    }
    __syncthreads();

    for (int s = 0; s < S; s++) {
        if (s + 1 < S) {
            const int k0 = (s + 1) * 16;
            if (arow_ok) {
                la0 = *(const float4*)(A0 + arow_off + k0 + akq);
                la1 = *(const float4*)(A0 + arow_off + k0 + akq + 4);
                if (MODE == 1) {
                    la0.x = fmaxf(la0.x, 0.f); la0.y = fmaxf(la0.y, 0.f);
                    la0.z = fmaxf(la0.z, 0.f); la0.w = fmaxf(la0.w, 0.f);
                    la1.x = fmaxf(la1.x, 0.f); la1.y = fmaxf(la1.y, 0.f);
                    la1.z = fmaxf(la1.z, 0.f); la1.w = fmaxf(la1.w, 0.f);
                }
                if (MODE == 2) {
                    float4 m0 = *(const float4*)(A1 + arow_off + k0 + akq);
                    float4 m1 = *(const float4*)(A1 + arow_off + k0 + akq + 4);
                    la0.x = w0 * fmaxf(la0.x, 0.f) + w1 * fmaxf(m0.x, 0.f);
                    la0.y = w0 * fmaxf(la0.y, 0.f) + w1 * fmaxf(m0.y, 0.f);
                    la0.z = w0 * fmaxf(la0.z, 0.f) + w1 * fmaxf(m0.z, 0.f);
                    la0.w = w0 * fmaxf(la0.w, 0.f) + w1 * fmaxf(m0.w, 0.f);
                    la1.x = w0 * fmaxf(la1.x, 0.f) + w1 * fmaxf(m1.x, 0.f);
                    la1.y = w0 * fmaxf(la1.y, 0.f) + w1 * fmaxf(m1.y, 0.f);
                    la1.z = w0 * fmaxf(la1.z, 0.f) + w1 * fmaxf(m1.z, 0.f);
                    la1.w = w0 * fmaxf(la1.w, 0.f) + w1 * fmaxf(m1.w, 0.f);
                }
            } else {
                la0 = make_float4(0.f, 0.f, 0.f, 0.f);
                la1 = la0;
            }
            lb0 = *(const float4*)(B + (size_t)(k0 + bkr) * N + bCol + bn8 * 8);
            lb1 = *(const float4*)(B + (size_t)(k0 + bkr) * N + bCol + bn8 * 8 + 4);
        }

        const int buf = s & 1;
#pragma unroll
        for (int ks = 0; ks < 2; ks++) {
            uint32_t af[2][4];
#pragma unroll
            for (int mi = 0; mi < 2; mi++) {
                const int mr = wm * 32 + mi * 16;
                const float* ap = &As[buf][0];
                af[mi][0] = __float_as_uint(ap[(mr + g)     * A_STRIDE + ks * 8 + t]);
                af[mi][1] = __float_as_uint(ap[(mr + g + 8) * A_STRIDE + ks * 8 + t]);
                af[mi][2] = __float_as_uint(ap[(mr + g)     * A_STRIDE + ks * 8 + t + 4]);
                af[mi][3] = __float_as_uint(ap[(mr + g + 8) * A_STRIDE + ks * 8 + t + 4]);
            }
#pragma unroll
            for (int ni = 0; ni < 8; ni++) {
                const int n8 = wn * 8 + ni;
                uint2 bf = *(const uint2*)&Bs[buf][(ks * 16 + n8) * B_N8_STRIDE + lane * 2];
#pragma unroll
                for (int mi = 0; mi < 2; mi++) {
                    asm volatile(
                        "mma.sync.aligned.m16n8k8.row.col.f32.tf32.tf32.f32 "
                        "{%0,%1,%2,%3}, {%4,%5,%6,%7}, {%8,%9}, {%0,%1,%2,%3};"
                        : "+f"(acc[mi][ni][0]), "+f"(acc[mi][ni][1]),
                          "+f"(acc[mi][ni][2]), "+f"(acc[mi][ni][3])
                        : "r"(af[mi][0]), "r"(af[mi][1]), "r"(af[mi][2]), "r"(af[mi][3]),
                          "r"(bf.x), "r"(bf.y));
                }
            }
        }
        __syncthreads();
        if (s + 1 < S) {
            const int nb = (s + 1) & 1;
            float4 c0 = make_float4(__uint_as_float(f2tf(la0.x)), __uint_as_float(f2tf(la0.y)),
                                    __uint_as_float(f2tf(la0.z)), __uint_as_float(f2tf(la0.w)));
            float4 c1 = make_float4(__uint_as_float(f2tf(la1.x)), __uint_as_float(f2tf(la1.y)),
                                    __uint_as_float(f2tf(la1.z)), __uint_as_float(f2tf(la1.w)));
            *(float4*)&As[nb][am * A_STRIDE + akq]     = c0;
            *(float4*)&As[nb][am * A_STRIDE + akq + 4] = c1;
            float bv[8] = {lb0.x, lb0.y, lb0.z, lb0.w, lb1.x, lb1.y, lb1.z, lb1.w};
#pragma unroll
            for (int j = 0; j < 8; j++)
                Bs[nb][bbase + (j * 4 + bt) * 2] = __uint_as_float(f2tf(bv[j]));
            __syncthreads();
        }
    }

    if (MODE == 0 || MODE == 2) {
#pragma unroll
        for (int mi = 0; mi < 2; mi++) {
            const int r0 = bRow + wm * 32 + mi * 16 + g;
#pragma unroll
            for (int ni = 0; ni < 8; ni++) {
                const int cl = wn * 64 + ni * 8 + t * 2;
                const int c0 = bCol + cl;
                if (r0 < M) {
                    float2 v = make_float2(acc[mi][ni][0] + bias_s[cl],
                                           acc[mi][ni][1] + bias_s[cl + 1]);
                    *(float2*)&C[(size_t)r0 * N + c0] = v;
                }
                if (r0 + 8 < M) {
                    float2 v = make_float2(acc[mi][ni][2] + bias_s[cl],
                                           acc[mi][ni][3] + bias_s[cl + 1]);
                    *(float2*)&C[(size_t)(r0 + 8) * N + c0] = v;
                }
            }
        }
    } else {
        float local = 0.f;
#pragma unroll
        for (int mi = 0; mi < 2; mi++) {
            const int r0 = bRow + wm * 32 + mi * 16 + g;
#pragma unroll
            for (int ni = 0; ni < 8; ni++) {
                const int cl = wn * 64 + ni * 8 + t * 2;
                if (r0 < M)
                    local += q_s[cl]     * tanhf(acc[mi][ni][0] + bias_s[cl]) +
                             q_s[cl + 1] * tanhf(acc[mi][ni][1] + bias_s[cl + 1]);
                if (r0 + 8 < M)
                    local += q_s[cl]     * tanhf(acc[mi][ni][2] + bias_s[cl]) +
                             q_s[cl + 1] * tanhf(acc[mi][ni][3] + bias_s[cl + 1]);
            }
        }
        red[tid] = local;
        __syncthreads();
        for (int st = 128; st > 0; st >>= 1) {
            if (tid < st) red[tid] += red[tid + st];
            __syncthreads();
        }
        if (tid == 0) atomicAdd(score, red[0]);
    }
}

// ============== fused node-scores ============================================
__global__ void __launch_bounds__(256)
scores4_k(const float* __restrict__ h,
          const float* __restrict__ a0, const float* __restrict__ a1,
          const float* __restrict__ a2, const float* __restrict__ a3,
          float* __restrict__ s0, float* __restrict__ s1,
          float* __restrict__ s2, float* __restrict__ s3, int Nn)
{
    __shared__ float av[4][CC];
    const int tid = threadIdx.x;
    av[0][tid] = a0[tid]; av[1][tid] = a1[tid];
    av[2][tid] = a2[tid]; av[3][tid] = a3[tid];
    __syncthreads();

    const int lane = tid & 31;
    const int node = blockIdx.x * 8 + (tid >> 5);
    if (node >= Nn) return;

    const float* hp = h + (size_t)node * CC + lane * 8;
    float4 h0 = *(const float4*)hp;
    float4 h1 = *(const float4*)(hp + 4);

    float* outs[4] = {s0, s1, s2, s3};
#pragma unroll
    for (int v = 0; v < 4; v++) {
        const float* ap = &av[v][lane * 8];
        float p = h0.x * ap[0] + h0.y * ap[1] + h0.z * ap[2] + h0.w * ap[3] +
                  h1.x * ap[4] + h1.y * ap[5] + h1.z * ap[6] + h1.w * ap[7];
        p += __shfl_xor_sync(0xffffffffu, p, 1);
        p += __shfl_xor_sync(0xffffffffu, p, 2);
        if ((lane & 3) == 0) outs[v][node * HH + (lane >> 2)] = p;
    }
}

// ================= fused CSR build (all 4 types) =============================
// cnt/fill layout: [N_D (rd) | N_R (dr) | N_R (rr) | N_D (dd)]
__global__ void hist4_k(const int* __restrict__ d0, const int* __restrict__ d1,
                        const int* __restrict__ d2, const int* __restrict__ d3,
                        int* __restrict__ cnt)
{
    int i = blockIdx.x * blockDim.x + threadIdx.x;
    if (i < E_RD)                     atomicAdd(&cnt[d0[i]], 1);
    else if (i < E_RD + E_DR)         atomicAdd(&cnt[N_D + d1[i - E_RD]], 1);
    else if (i < E_RD + E_DR + E_RR)  atomicAdd(&cnt[N_D + N_R + d2[i - E_RD - E_DR]], 1);
    else if (i < E_TOT)               atomicAdd(&cnt[N_D + 2 * N_R + d3[i - E_RD - E_DR - E_RR]], 1);
}

// grid = 4 blocks; block b scans its own segment
__global__ void __launch_bounds__(1024)
scan4_k(const int* __restrict__ cnt, int* __restrict__ rptr_all)
{
    __shared__ int wsum[32];
    __shared__ int s_carry;
    const int b = blockIdx.x;
    const int n    = (b == 0 || b == 3) ? N_D : N_R;
    const int cofs = (b == 0) ? 0 : (b == 1) ? N_D : (b == 2) ? (N_D + N_R) : (N_D + 2 * N_R);
    const int* c = cnt + cofs;
    int* rptr = rptr_all + b * (N_R + 1);

    const int tid = threadIdx.x;
    const int lane = tid & 31, wid = tid >> 5;
    if (tid == 0) s_carry = 0;
    __syncthreads();
    for (int base = 0; base < n; base += 1024) {
        int i = base + tid;
        int v = (i < n) ? c[i] : 0;
        int x = v;
#pragma unroll
        for (int o = 1; o < 32; o <<= 1) {
            int y = __shfl_up_sync(0xffffffffu, x, o);
            if (lane >= o) x += y;
        }
        if (lane == 31) wsum[wid] = x;
        __syncthreads();
        if (wid == 0) {
            int tv = wsum[lane];
#pragma unroll
            for (int o = 1; o < 32; o <<= 1) {
                int y = __shfl_up_sync(0xffffffffu, tv, o);
                if (lane >= o) tv += y;
            }
            wsum[lane] = tv;
        }
        __syncthreads();
        int incl = x + (wid > 0 ? wsum[wid - 1] : 0);
        int carry = s_carry;
        if (i < n) rptr[i] = carry + incl - v;
        __syncthreads();
        if (tid == 1023) s_carry = carry + incl;
        __syncthreads();
    }
    if (tid == 0) rptr[n] = s_carry;
}

__global__ void scatter4_k(const int* __restrict__ s0, const int* __restrict__ d0,
                           const int* __restrict__ s1, const int* __restrict__ d1,
                           const int* __restrict__ s2, const int* __restrict__ d2,
                           const int* __restrict__ s3, const int* __restrict__ d3,
                           const int* __restrict__ rptr_all,
                           int* __restrict__ fill, int* __restrict__ ssort)
{
    int i = blockIdx.x * blockDim.x + threadIdx.x;
    const int* sp; const int* dp; const int* rp; int* fl; int* ss; int e;
    if (i < E_RD) {
        e = i; sp = s0; dp = d0; rp = rptr_all; fl = fill; ss = ssort;
    } else if (i < E_RD + E_DR) {
        e = i - E_RD; sp = s1; dp = d1; rp = rptr_all + (N_R + 1);
        fl = fill + N_D; ss = ssort + E_RD;
    } else if (i < E_RD + E_DR + E_RR) {
        e = i - E_RD - E_DR; sp = s2; dp = d2; rp = rptr_all + 2 * (N_R + 1);
        fl = fill + N_D + N_R; ss = ssort + E_RD + E_DR;
    } else if (i < E_TOT) {
        e = i - E_RD - E_DR - E_RR; sp = s3; dp = d3; rp = rptr_all + 3 * (N_R + 1);
        fl = fill + N_D + 2 * N_R; ss = ssort + E_RD + E_DR + E_RR;
    } else return;
    int d = dp[e];
    int pos = rp[d] + atomicAdd(&fl[d], 1);
    ss[pos] = sp[e];
}

// ============ fused edge aggregation: warp per dst node, online softmax =====
__device__ __forceinline__ float lrelu(float x) { return x > 0.f ? x : 0.2f * x; }

__global__ void __launch_bounds__(256)
agg_csr_k(const int* __restrict__ rptr, const int* __restrict__ ssort,
          const float* __restrict__ ssrc, const float* __restrict__ sdst,
          const float* __restrict__ x, float* __restrict__ out, int Nd)
{
    const int warp = (blockIdx.x * blockDim.x + threadIdx.x) >> 5;
    const int lane = threadIdx.x & 31;
    if (warp >= Nd) return;
    const int h = lane >> 2;

    const float sd = sdst[warp * HH + h];
    const int beg = rptr[warp], end = rptr[warp + 1];

    float m = -INFINITY, s = 0.f;
    float a0 = 0.f, a1 = 0.f, a2 = 0.f, a3 = 0.f;
    float a4 = 0.f, a5 = 0.f, a6 = 0.f, a7 = 0.f;

    for (int p = beg; p < end; p++) {
        int src = ssort[p];
        float sc = lrelu(ssrc[src * HH + h] + sd);
        float mn = fmaxf(m, sc);
        float corr = expf(m - mn);
        float w = expf(sc - mn);
        s = s * corr + w;
        m = mn;
        const float4* xp = (const float4*)(x + (size_t)src * CC + lane * 8);
        float4 v0 = xp[0], v1 = xp[1];
        a0 = a0 * corr + w * v0.x;
        a1 = a1 * corr + w * v0.y;
        a2 = a2 * corr + w * v0.z;
        a3 = a3 * corr + w * v0.w;
        a4 = a4 * corr + w * v1.x;
        a5 = a5 * corr + w * v1.y;
        a6 = a6 * corr + w * v1.z;
        a7 = a7 * corr + w * v1.w;
    }
    float inv = 1.f / (s + 1e-16f);
    float* op = out + (size_t)warp * CC + lane * 8;
    *(float4*)op       = make_float4(a0 * inv, a1 * inv, a2 * inv, a3 * inv);
    *(float4*)(op + 4) = make_float4(a4 * inv, a5 * inv, a6 * inv, a7 * inv);
}

__global__ void softmax2_k(const float* __restrict__ scores, float* __restrict__ attn,
                           float invNr, float invNd)
{
    if (threadIdx.x == 0 && blockIdx.x == 0) {
        float s0 = scores[0] * invNr, s1 = scores[1] * invNr;
        float mx = fmaxf(s0, s1);
        float e0 = expf(s0 - mx), e1 = expf(s1 - mx);
        attn[0] = e0 / (e0 + e1);
        attn[1] = e1 / (e0 + e1);
        s0 = scores[2] * invNd; s1 = scores[3] * invNd;
        mx = fmaxf(s0, s1);
        e0 = expf(s0 - mx); e1 = expf(s1 - mx);
        attn[2] = e0 / (e0 + e1);
        attn[3] = e1 / (e0 + e1);
    }
}

// ---------------------------------------------------------------------------
extern "C" void kernel_launch(void* const* d_in, const int* in_sizes, int n_in,
                              void* d_out, int out_size)
{
    const float* x_rna   = (const float*)d_in[0];
    const float* x_dis   = (const float*)d_in[1];
    const float* W_d     = (const float*)d_in[2];
    const float* b_d     = (const float*)d_in[3];
    const float* Wp_rna  = (const float*)d_in[4];
    const float* bp_rna  = (const float*)d_in[5];
    const float* Wp_dis  = (const float*)d_in[6];
    const float* bp_dis  = (const float*)d_in[7];
    const float* a_src_rd = (const float*)d_in[8];
    const float* a_dst_rd = (const float*)d_in[9];
    const float* a_src_dr = (const float*)d_in[10];
    const float* a_dst_dr = (const float*)d_in[11];
    const float* a_src_rr = (const float*)d_in[12];
    const float* a_dst_rr = (const float*)d_in[13];
    const float* a_src_dd = (const float*)d_in[14];
    const float* a_dst_dd = (const float*)d_in[15];
    const float* kW      = (const float*)d_in[16];
    const float* kb      = (const float*)d_in[17];
    const float* qv      = (const float*)d_in[18];
    const float* W_out   = (const float*)d_in[19];
    const float* b_out   = (const float*)d_in[20];
    const int* rd_src = (const int*)d_in[21];
    const int* rd_dst = (const int*)d_in[22];
    const int* dr_src = (const int*)d_in[23];
    const int* dr_dst = (const int*)d_in[24];
    const int* rr_src = (const int*)d_in[25];
    const int* rr_dst = (const int*)d_in[26];
    const int* dd_src = (const int*)d_in[27];
    const int* dd_dst = (const int*)d_in[28];

    float* out = (float*)d_out;

    float *p_xd, *p_hr, *p_hd, *p_ord, *p_odr, *p_orr, *p_odd;
    float *p_sr, *p_sd, *p_scores, *p_attn;
    int *p_cnt, *p_fill, *p_rptr, *p_ssort;
    cudaGetSymbolAddress((void**)&p_xd, g_xd);
    cudaGetSymbolAddress((void**)&p_hr, g_hr);
    cudaGetSymbolAddress((void**)&p_hd, g_hd);
    cudaGetSymbolAddress((void**)&p_ord, g_out_rd);
    cudaGetSymbolAddress((void**)&p_odr, g_out_dr);
    cudaGetSymbolAddress((void**)&p_orr, g_out_rr);
    cudaGetSymbolAddress((void**)&p_odd, g_out_dd);
    cudaGetSymbolAddress((void**)&p_sr, g_s_rna);
    cudaGetSymbolAddress((void**)&p_sd, g_s_dis);
    cudaGetSymbolAddress((void**)&p_cnt, g_cnt);
    cudaGetSymbolAddress((void**)&p_fill, g_fill);
    cudaGetSymbolAddress((void**)&p_rptr, g_rptr);
    cudaGetSymbolAddress((void**)&p_ssort, g_ssort);
    cudaGetSymbolAddress((void**)&p_scores, g_scores);
    cudaGetSymbolAddress((void**)&p_attn, g_attn);

    const dim3 thr(256);
    const int mbr = (N_R + 127) / 128;   // 391
    const int mbd = (N_D + 127) / 128;   // 79

    int* rp_rd = p_rptr + 0 * (N_R + 1);
    int* rp_dr = p_rptr + 1 * (N_R + 1);
    int* rp_rr = p_rptr + 2 * (N_R + 1);
    int* rp_dd = p_rptr + 3 * (N_R + 1);
    int* ss_rd = p_ssort;
    int* ss_dr = ss_rd + E_RD;
    int* ss_rr = ss_dr + E_DR;
    int* ss_dd = ss_rr + E_RR;

    // ---- streams & events (host objects; created/destroyed per call) ----
    cudaStream_t st0 = 0, st1, st2;
    cudaStreamCreateWithFlags(&st1, cudaStreamNonBlocking);
    cudaStreamCreateWithFlags(&st2, cudaStreamNonBlocking);
    cudaEvent_t ev[8];
    for (int i = 0; i < 8; i++) cudaEventCreateWithFlags(&ev[i], cudaEventDisableTiming);

    // fork
    cudaEventRecord(ev[0], st0);
    cudaStreamWaitEvent(st1, ev[0], 0);
    cudaStreamWaitEvent(st2, ev[0], 0);

    // st2: CSR build + score-accumulator clear (independent of GEMMs)
    cudaMemsetAsync(p_cnt, 0, CNT_TOT * sizeof(int), st2);
    cudaMemsetAsync(p_fill, 0, CNT_TOT * sizeof(int), st2);
    cudaMemsetAsync(p_scores, 0, 4 * sizeof(float), st2);
    hist4_k<<<(E_TOT + 255) / 256, thr, 0, st2>>>(rd_dst, dr_dst, rr_dst, dd_dst, p_cnt);
    scan4_k<<<4, 1024, 0, st2>>>(p_cnt, p_rptr);
    scatter4_k<<<(E_TOT + 255) / 256, thr, 0, st2>>>(rd_src, rd_dst, dr_src, dr_dst,
                                                     rr_src, rr_dst, dd_src, dd_dst,
                                                     p_rptr, p_fill, p_ssort);

    // st0: disease chain  (xd -> hd -> scores_dis)
    gemm_tc<0><<<dim3(2, mbd), thr, 0, st0>>>(x_dis, nullptr, W_d, b_d, nullptr, nullptr,
                                              p_xd, nullptr, N_D, RNA_IN, D_FEAT);
    gemm_tc<0><<<dim3(2, mbd), thr, 0, st0>>>(p_xd, nullptr, Wp_dis, bp_dis, nullptr, nullptr,
                                              p_hd, nullptr, N_D, CC, RNA_IN);
    scores4_k<<<(N_D + 7) / 8, thr, 0, st0>>>(p_hd, a_dst_rd, a_src_dr, a_src_dd, a_dst_dd,
                                              p_sd + 0 * N_D * HH, p_sd + 1 * N_D * HH,
                                              p_sd + 2 * N_D * HH, p_sd + 3 * N_D * HH, N_D);

    // st1: rna chain (hr -> scores_rna)
    gemm_tc<0><<<dim3(2, mbr), thr, 0, st1>>>(x_rna, nullptr, Wp_rna, bp_rna, nullptr, nullptr,
                                              p_hr, nullptr, N_R, CC, RNA_IN);
    scores4_k<<<(N_R + 7) / 8, thr, 0, st1>>>(p_hr, a_src_rd, a_dst_dr, a_src_rr, a_dst_rr,
                                              p_sr + 0 * N_R * HH, p_sr + 1 * N_R * HH,
                                              p_sr + 2 * N_R * HH, p_sr + 3 * N_R * HH, N_R);

    // join: aggs need everything above
    cudaEventRecord(ev[1], st0);
    cudaEventRecord(ev[2], st1);
    cudaEventRecord(ev[3], st2);
    cudaStreamWaitEvent(st0, ev[2], 0); cudaStreamWaitEvent(st0, ev[3], 0);
    cudaStreamWaitEvent(st1, ev[1], 0); cudaStreamWaitEvent(st1, ev[3], 0);
    cudaStreamWaitEvent(st2, ev[1], 0); cudaStreamWaitEvent(st2, ev[2], 0);

    // agg + MODE1, spread over 3 streams
    // st1: rr (largest)
    agg_csr_k<<<(N_R * 32 + 255) / 256, thr, 0, st1>>>(rp_rr, ss_rr,
                                                       p_sr + 2 * N_R * HH, p_sr + 3 * N_R * HH,
                                                       p_hr, p_orr, N_R);
    gemm_tc<1><<<dim3(2, mbr), thr, 0, st1>>>(p_orr, nullptr, kW, kb, nullptr, qv,
                                              nullptr, p_scores + 1, N_R, CC, CC);
    // st0: dr
    agg_csr_k<<<(N_R * 32 + 255) / 256, thr, 0, st0>>>(rp_dr, ss_dr,
                                                       p_sd + 1 * N_D * HH, p_sr + 1 * N_R * HH,
                                                       p_hd, p_odr, N_R);
    gemm_tc<1><<<dim3(2, mbr), thr, 0, st0>>>(p_odr, nullptr, kW, kb, nullptr, qv,
                                              nullptr, p_scores + 0, N_R, CC, CC);
    // st2: rd + dd (small)
    agg_csr_k<<<(N_D * 32 + 255) / 256, thr, 0, st2>>>(rp_rd, ss_rd,
                                                       p_sr + 0 * N_R * HH, p_sd + 0 * N_D * HH,
                                                       p_hr, p_ord, N_D);
    agg_csr_k<<<(N_D * 32 + 255) / 256, thr, 0, st2>>>(rp_dd, ss_dd,
                                                       p_sd + 2 * N_D * HH, p_sd + 3 * N_D * HH,
                                                       p_hd, p_odd, N_D);
    gemm_tc<1><<<dim3(2, mbd), thr, 0, st2>>>(p_ord, nullptr, kW, kb, nullptr, qv,
                                              nullptr, p_scores + 2, N_D, CC, CC);
    gemm_tc<1><<<dim3(2, mbd), thr, 0, st2>>>(p_odd, nullptr, kW, kb, nullptr, qv,
                                              nullptr, p_scores + 3, N_D, CC, CC);

    // join on st0 for softmax
    cudaEventRecord(ev[4], st1);
    cudaEventRecord(ev[5], st2);
    cudaStreamWaitEvent(st0, ev[4], 0);
    cudaStreamWaitEvent(st0, ev[5], 0);
    softmax2_k<<<1, 32, 0, st0>>>(p_scores, p_attn, 1.f / N_R, 1.f / N_D);

    // fork for the two final GEMMs
    cudaEventRecord(ev[6], st0);
    cudaStreamWaitEvent(st1, ev[6], 0);

    gemm_tc<2><<<dim3(2, mbr), thr, 0, st0>>>(p_odr, p_orr, W_out, b_out, p_attn + 0, nullptr,
                                              out, nullptr, N_R, CC, CC);
    gemm_tc<2><<<dim3(2, mbd), thr, 0, st1>>>(p_ord, p_odd, W_out, b_out, p_attn + 2, nullptr,
                                              out + (size_t)N_R * CC, nullptr, N_D, CC, CC);

    // final join back to the capture-origin stream
    cudaEventRecord(ev[7], st1);
    cudaStreamWaitEvent(st0, ev[7], 0);

    for (int i = 0; i < 8; i++) cudaEventDestroy(ev[i]);
    cudaStreamDestroy(st1);
    cudaStreamDestroy(st2);
}

// round 6
// speedup vs baseline: 5.2190x; 1.1489x over previous
#include <cuda_runtime.h>
#include <cstdint>
#include <math.h>

#define N_R 50000
#define N_D 10000
#define HH  8
#define DH  32
#define CC  256
#define RNA_IN 256
#define D_FEAT 512
#define E_RD 200000
#define E_DR 200000
#define E_RR 400000
#define E_DD 50000
#define E_TOT (E_RD + E_DR + E_RR + E_DD)
#define CNT_TOT (2 * N_R + 2 * N_D)

// ---------------- static device scratch ------------------------------------
__device__ float    g_xd[N_D * RNA_IN];
__device__ float    g_hr[N_R * CC];
__device__ float    g_hd[N_D * CC];
__device__ float    g_out_rd[N_D * CC];
__device__ float    g_out_dr[N_R * CC];
__device__ float    g_out_rr[N_R * CC];
__device__ float    g_out_dd[N_D * CC];
__device__ float    g_s_rna[4 * N_R * HH];
__device__ float    g_s_dis[4 * N_D * HH];
__device__ int      g_cnt[CNT_TOT];
__device__ int      g_fill[CNT_TOT];
__device__ int      g_rptr[4 * (N_R + 1)];
__device__ int      g_ssort[E_TOT];
__device__ float    g_scores[4];
__device__ float    g_attn[4];

__device__ __forceinline__ uint32_t f2tf(float f) {
    uint32_t u;
    asm("cvt.rna.tf32.f32 %0, %1;" : "=r"(u) : "f"(f));
    return u;
}

// =============================================================================
// GEMM v2 (MODE 0 / 1): cp.async, BK=32, raw fp32 smem, cvt(+relu) after LDS
// MODE 0: C = A0 @ B + bias
// MODE 1: score += sum q[c]*tanh( relu(A0)@B + bias )
// =============================================================================
#define AST 36     // A smem row stride (floats): banks (4g+t) conflict-free
#define BST 136    // B smem row stride (floats): banks (8*bt+j) conflict-free
#define SMEM_CA ((2 * 128 * AST + 2 * 32 * BST + 512) * 4)

template <int MODE>
__global__ void __launch_bounds__(256, 2)
gemm_ca(const float* __restrict__ A0, const float* __restrict__ B,
        const float* __restrict__ bias, const float* __restrict__ qv,
        float* __restrict__ C, float* __restrict__ score,
        int M, int N, int K)
{
    extern __shared__ float sm[];
    float* As     = sm;                              // [2][128*AST]
    float* Bs     = sm + 2 * 128 * AST;              // [2][32*BST]
    float* bias_s = sm + 2 * 128 * AST + 2 * 32 * BST;
    float* q_s    = bias_s + 128;
    float* red    = q_s + 128;                       // 256

    const int tid  = threadIdx.x;
    const int lane = tid & 31;
    const int warp = tid >> 5;
    const int wm   = warp & 3;
    const int wn   = warp >> 2;
    const int g    = lane >> 2;
    const int t    = lane & 3;
    const int bRow = blockIdx.y * 128;
    const int bCol = blockIdx.x * 128;

    if (tid < 128) {
        bias_s[tid] = bias[bCol + tid];
        if (MODE == 1) q_s[tid] = qv[bCol + tid];
    }

    float acc[2][8][4];
#pragma unroll
    for (int mi = 0; mi < 2; mi++)
#pragma unroll
        for (int ni = 0; ni < 8; ni++)
#pragma unroll
            for (int r = 0; r < 4; r++) acc[mi][ni][r] = 0.f;

    auto issue = [&](int k0, int buf) {
        float* a_dst = As + buf * 128 * AST;
        float* b_dst = Bs + buf * 32 * BST;
#pragma unroll
        for (int it = 0; it < 4; it++) {
            int idx = it * 256 + tid;
            int row = idx >> 3, ch = idx & 7;         // 8 chunks x 16B per A row
            const float* src = A0 + (size_t)(bRow + row) * K + k0 + ch * 4;
            unsigned d = (unsigned)__cvta_generic_to_shared(a_dst + row * AST + ch * 4);
            int sz = (bRow + row < M) ? 16 : 0;       // zfill OOB rows
            asm volatile("cp.async.ca.shared.global [%0], [%1], 16, %2;"
                         :: "r"(d), "l"(src), "r"(sz));
        }
#pragma unroll
        for (int it = 0; it < 4; it++) {
            int idx = it * 256 + tid;
            int k = idx >> 5, ch = idx & 31;          // 32 chunks x 16B per B row
            const float* src = B + (size_t)(k0 + k) * N + bCol + ch * 4;
            unsigned d = (unsigned)__cvta_generic_to_shared(b_dst + k * BST + ch * 4);
            asm volatile("cp.async.ca.shared.global [%0], [%1], 16;"
                         :: "r"(d), "l"(src));
        }
        asm volatile("cp.async.commit_group;");
    };

    const int S = K / 32;
    issue(0, 0);
    int buf = 0;

    for (int s = 0; s < S; s++) {
        asm volatile("cp.async.wait_group 0;");
        __syncthreads();
        if (s + 1 < S) issue((s + 1) * 32, buf ^ 1);

        const float* ap = As + buf * 128 * AST;
        const float* bp = Bs + buf * 32 * BST;
#pragma unroll
        for (int ks = 0; ks < 4; ks++) {
            uint32_t af[2][4];
#pragma unroll
            for (int mi = 0; mi < 2; mi++) {
                const int mr = wm * 32 + mi * 16;
                float v0 = ap[(mr + g)     * AST + ks * 8 + t];
                float v1 = ap[(mr + g + 8) * AST + ks * 8 + t];
                float v2 = ap[(mr + g)     * AST + ks * 8 + t + 4];
                float v3 = ap[(mr + g + 8) * AST + ks * 8 + t + 4];
                if (MODE == 1) {
                    v0 = fmaxf(v0, 0.f); v1 = fmaxf(v1, 0.f);
                    v2 = fmaxf(v2, 0.f); v3 = fmaxf(v3, 0.f);
                }
                af[mi][0] = f2tf(v0); af[mi][1] = f2tf(v1);
                af[mi][2] = f2tf(v2); af[mi][3] = f2tf(v3);
            }
#pragma unroll
            for (int ni = 0; ni < 8; ni++) {
                const int n8 = wn * 8 + ni;
                // lane -> (j = lane>>2 : n within octet, bt = lane&3 : k%4)
                float bxf = bp[(ks * 8 + t)     * BST + n8 * 8 + g];
                float byf = bp[(ks * 8 + t + 4) * BST + n8 * 8 + g];
                uint32_t bx = f2tf(bxf), by = f2tf(byf);
#pragma unroll
                for (int mi = 0; mi < 2; mi++) {
                    asm volatile(
                        "mma.sync.aligned.m16n8k8.row.col.f32.tf32.tf32.f32 "
                        "{%0,%1,%2,%3}, {%4,%5,%6,%7}, {%8,%9}, {%0,%1,%2,%3};"
                        : "+f"(acc[mi][ni][0]), "+f"(acc[mi][ni][1]),
                          "+f"(acc[mi][ni][2]), "+f"(acc[mi][ni][3])
                        : "r"(af[mi][0]), "r"(af[mi][1]), "r"(af[mi][2]), "r"(af[mi][3]),
                          "r"(bx), "r"(by));
                }
            }
        }
        buf ^= 1;
    }

    if (MODE == 0) {
#pragma unroll
        for (int mi = 0; mi < 2; mi++) {
            const int r0 = bRow + wm * 32 + mi * 16 + g;
#pragma unroll
            for (int ni = 0; ni < 8; ni++) {
                const int cl = wn * 64 + ni * 8 + t * 2;
                const int c0 = bCol + cl;
                if (r0 < M) {
                    float2 v = make_float2(acc[mi][ni][0] + bias_s[cl],
                                           acc[mi][ni][1] + bias_s[cl + 1]);
                    *(float2*)&C[(size_t)r0 * N + c0] = v;
                }
                if (r0 + 8 < M) {
                    float2 v = make_float2(acc[mi][ni][2] + bias_s[cl],
                                           acc[mi][ni][3] + bias_s[cl + 1]);
                    *(float2*)&C[(size_t)(r0 + 8) * N + c0] = v;
                }
            }
        }
    } else {
        float local = 0.f;
#pragma unroll
        for (int mi = 0; mi < 2; mi++) {
            const int r0 = bRow + wm * 32 + mi * 16 + g;
#pragma unroll
            for (int ni = 0; ni < 8; ni++) {
                const int cl = wn * 64 + ni * 8 + t * 2;
                if (r0 < M)
                    local += q_s[cl]     * tanhf(acc[mi][ni][0] + bias_s[cl]) +
                             q_s[cl + 1] * tanhf(acc[mi][ni][1] + bias_s[cl + 1]);
                if (r0 + 8 < M)
                    local += q_s[cl]     * tanhf(acc[mi][ni][2] + bias_s[cl]) +
                             q_s[cl + 1] * tanhf(acc[mi][ni][3] + bias_s[cl + 1]);
            }
        }
        red[tid] = local;
        __syncthreads();
        for (int st = 128; st > 0; st >>= 1) {
            if (tid < st) red[tid] += red[tid + st];
            __syncthreads();
        }
        if (tid == 0) atomicAdd(score, red[0]);
    }
}

// ================= old TF32 GEMM (MODE 2 only) ===============================
#define A_STRIDE 20
#define B_N8_STRIDE 66

template <int MODE>
__global__ void __launch_bounds__(256)
gemm_tc(const float* __restrict__ A0, const float* __restrict__ A1,
        const float* __restrict__ B,  const float* __restrict__ bias,
        const float* __restrict__ wts, const float* __restrict__ qv,
        float* __restrict__ C, float* __restrict__ score,
        int M, int N, int K)
{
    __shared__ float As[2][128 * A_STRIDE];
    __shared__ float Bs[2][2 * 16 * B_N8_STRIDE];
    __shared__ float bias_s[128];

    const int tid  = threadIdx.x;
    const int lane = tid & 31;
    const int warp = tid >> 5;
    const int wm   = warp & 3;
    const int wn   = warp >> 2;
    const int g    = lane >> 2;
    const int t    = lane & 3;
    const int bRow = blockIdx.y * 128;
    const int bCol = blockIdx.x * 128;

    if (tid < 128) bias_s[tid] = bias[bCol + tid];

    float w0 = wts[0], w1 = wts[1];

    const int am  = tid >> 1;
    const int akq = (tid & 1) * 8;
    const size_t arow_off = (size_t)(bRow + am) * K;
    const bool arow_ok = (bRow + am) < M;

    const int bkr = tid >> 4;
    const int bn8 = tid & 15;
    const int bks = bkr >> 3;
    const int bt  = bkr & 3;
    const int brg = (bkr & 7) >> 2;
    const int bbase = (bks * 16 + bn8) * B_N8_STRIDE + brg;

    float acc[2][8][4];
#pragma unroll
    for (int mi = 0; mi < 2; mi++)
#pragma unroll
        for (int ni = 0; ni < 8; ni++)
#pragma unroll
            for (int r = 0; r < 4; r++) acc[mi][ni][r] = 0.f;

    const int S = K / 16;
    float4 la0, la1, lb0, lb1;

    auto loadA = [&](int k0) {
        if (arow_ok) {
            la0 = *(const float4*)(A0 + arow_off + k0 + akq);
            la1 = *(const float4*)(A0 + arow_off + k0 + akq + 4);
            float4 m0 = *(const float4*)(A1 + arow_off + k0 + akq);
            float4 m1 = *(const float4*)(A1 + arow_off + k0 + akq + 4);
            la0.x = w0 * fmaxf(la0.x, 0.f) + w1 * fmaxf(m0.x, 0.f);
            la0.y = w0 * fmaxf(la0.y, 0.f) + w1 * fmaxf(m0.y, 0.f);
            la0.z = w0 * fmaxf(la0.z, 0.f) + w1 * fmaxf(m0.z, 0.f);
            la0.w = w0 * fmaxf(la0.w, 0.f) + w1 * fmaxf(m0.w, 0.f);
            la1.x = w0 * fmaxf(la1.x, 0.f) + w1 * fmaxf(m1.x, 0.f);
            la1.y = w0 * fmaxf(la1.y, 0.f) + w1 * fmaxf(m1.y, 0.f);
            la1.z = w0 * fmaxf(la1.z, 0.f) + w1 * fmaxf(m1.z, 0.f);
            la1.w = w0 * fmaxf(la1.w, 0.f) + w1 * fmaxf(m1.w, 0.f);
        } else {
            la0 = make_float4(0.f, 0.f, 0.f, 0.f);
            la1 = la0;
        }
        lb0 = *(const float4*)(B + (size_t)(k0 + bkr) * N + bCol + bn8 * 8);
        lb1 = *(const float4*)(B + (size_t)(k0 + bkr) * N + bCol + bn8 * 8 + 4);
    };
    auto storeS = [&](int nb) {
        float4 c0 = make_float4(__uint_as_float(f2tf(la0.x)), __uint_as_float(f2tf(la0.y)),
                                __uint_as_float(f2tf(la0.z)), __uint_as_float(f2tf(la0.w)));
        float4 c1 = make_float4(__uint_as_float(f2tf(la1.x)), __uint_as_float(f2tf(la1.y)),
                                __uint_as_float(f2tf(la1.z)), __uint_as_float(f2tf(la1.w)));
        *(float4*)&As[nb][am * A_STRIDE + akq]     = c0;
        *(float4*)&As[nb][am * A_STRIDE + akq + 4] = c1;
        float bv[8] = {lb0.x, lb0.y, lb0.z, lb0.w, lb1.x, lb1.y, lb1.z, lb1.w};
#pragma unroll
        for (int j = 0; j < 8; j++)
            Bs[nb][bbase + (j * 4 + bt) * 2] = __uint_as_float(f2tf(bv[j]));
    };

    loadA(0);
    storeS(0);
    __syncthreads();

    for (int s = 0; s < S; s++) {
        if (s + 1 < S) loadA((s + 1) * 16);

        const int buf = s & 1;
#pragma unroll
        for (int ks = 0; ks < 2; ks++) {
            uint32_t af[2][4];
#pragma unroll
            for (int mi = 0; mi < 2; mi++) {
                const int mr = wm * 32 + mi * 16;
                const float* ap = &As[buf][0];
                af[mi][0] = __float_as_uint(ap[(mr + g)     * A_STRIDE + ks * 8 + t]);
                af[mi][1] = __float_as_uint(ap[(mr + g + 8) * A_STRIDE + ks * 8 + t]);
                af[mi][2] = __float_as_uint(ap[(mr + g)     * A_STRIDE + ks * 8 + t + 4]);
                af[mi][3] = __float_as_uint(ap[(mr + g + 8) * A_STRIDE + ks * 8 + t + 4]);
            }
#pragma unroll
            for (int ni = 0; ni < 8; ni++) {
                const int n8 = wn * 8 + ni;
                uint2 bf = *(const uint2*)&Bs[buf][(ks * 16 + n8) * B_N8_STRIDE + lane * 2];
#pragma unroll
                for (int mi = 0; mi < 2; mi++) {
                    asm volatile(
                        "mma.sync.aligned.m16n8k8.row.col.f32.tf32.tf32.f32 "
                        "{%0,%1,%2,%3}, {%4,%5,%6,%7}, {%8,%9}, {%0,%1,%2,%3};"
                        : "+f"(acc[mi][ni][0]), "+f"(acc[mi][ni][1]),
                          "+f"(acc[mi][ni][2]), "+f"(acc[mi][ni][3])
                        : "r"(af[mi][0]), "r"(af[mi][1]), "r"(af[mi][2]), "r"(af[mi][3]),
                          "r"(bf.x), "r"(bf.y));
                }
            }
        }
        __syncthreads();
        if (s + 1 < S) {
            storeS((s + 1) & 1);
            __syncthreads();
        }
    }

#pragma unroll
    for (int mi = 0; mi < 2; mi++) {
        const int r0 = bRow + wm * 32 + mi * 16 + g;
#pragma unroll
        for (int ni = 0; ni < 8; ni++) {
            const int cl = wn * 64 + ni * 8 + t * 2;
            const int c0 = bCol + cl;
            if (r0 < M) {
                float2 v = make_float2(acc[mi][ni][0] + bias_s[cl],
                                       acc[mi][ni][1] + bias_s[cl + 1]);
                *(float2*)&C[(size_t)r0 * N + c0] = v;
            }
            if (r0 + 8 < M) {
                float2 v = make_float2(acc[mi][ni][2] + bias_s[cl],
                                       acc[mi][ni][3] + bias_s[cl + 1]);
                *(float2*)&C[(size_t)(r0 + 8) * N + c0] = v;
            }
        }
    }
}

// ============== fused node-scores ============================================
__global__ void __launch_bounds__(256)
scores4_k(const float* __restrict__ h,
          const float* __restrict__ a0, const float* __restrict__ a1,
          const float* __restrict__ a2, const float* __restrict__ a3,
          float* __restrict__ s0, float* __restrict__ s1,
          float* __restrict__ s2, float* __restrict__ s3, int Nn)
{
    __shared__ float av[4][CC];
    const int tid = threadIdx.x;
    av[0][tid] = a0[tid]; av[1][tid] = a1[tid];
    av[2][tid] = a2[tid]; av[3][tid] = a3[tid];
    __syncthreads();

    const int lane = tid & 31;
    const int node = blockIdx.x * 8 + (tid >> 5);
    if (node >= Nn) return;

    const float* hp = h + (size_t)node * CC + lane * 8;
    float4 h0 = *(const float4*)hp;
    float4 h1 = *(const float4*)(hp + 4);

    float* outs[4] = {s0, s1, s2, s3};
#pragma unroll
    for (int v = 0; v < 4; v++) {
        const float* ap = &av[v][lane * 8];
        float p = h0.x * ap[0] + h0.y * ap[1] + h0.z * ap[2] + h0.w * ap[3] +
                  h1.x * ap[4] + h1.y * ap[5] + h1.z * ap[6] + h1.w * ap[7];
        p += __shfl_xor_sync(0xffffffffu, p, 1);
        p += __shfl_xor_sync(0xffffffffu, p, 2);
        if ((lane & 3) == 0) outs[v][node * HH + (lane >> 2)] = p;
    }
}

// ================= fused CSR build ==========================================
__global__ void hist4_k(const int* __restrict__ d0, const int* __restrict__ d1,
                        const int* __restrict__ d2, const int* __restrict__ d3,
                        int* __restrict__ cnt)
{
    int i = blockIdx.x * blockDim.x + threadIdx.x;
    if (i < E_RD)                     atomicAdd(&cnt[d0[i]], 1);
    else if (i < E_RD + E_DR)         atomicAdd(&cnt[N_D + d1[i - E_RD]], 1);
    else if (i < E_RD + E_DR + E_RR)  atomicAdd(&cnt[N_D + N_R + d2[i - E_RD - E_DR]], 1);
    else if (i < E_TOT)               atomicAdd(&cnt[N_D + 2 * N_R + d3[i - E_RD - E_DR - E_RR]], 1);
}

__global__ void __launch_bounds__(1024)
scan4_k(const int* __restrict__ cnt, int* __restrict__ rptr_all)
{
    __shared__ int wsum[32];
    __shared__ int s_carry;
    const int b = blockIdx.x;
    const int n    = (b == 0 || b == 3) ? N_D : N_R;
    const int cofs = (b == 0) ? 0 : (b == 1) ? N_D : (b == 2) ? (N_D + N_R) : (N_D + 2 * N_R);
    const int* c = cnt + cofs;
    int* rptr = rptr_all + b * (N_R + 1);

    const int tid = threadIdx.x;
    const int lane = tid & 31, wid = tid >> 5;
    if (tid == 0) s_carry = 0;
    __syncthreads();
    for (int base = 0; base < n; base += 1024) {
        int i = base + tid;
        int v = (i < n) ? c[i] : 0;
        int x = v;
#pragma unroll
        for (int o = 1; o < 32; o <<= 1) {
            int y = __shfl_up_sync(0xffffffffu, x, o);
            if (lane >= o) x += y;
        }
        if (lane == 31) wsum[wid] = x;
        __syncthreads();
        if (wid == 0) {
            int tv = wsum[lane];
#pragma unroll
            for (int o = 1; o < 32; o <<= 1) {
                int y = __shfl_up_sync(0xffffffffu, tv, o);
                if (lane >= o) tv += y;
            }
            wsum[lane] = tv;
        }
        __syncthreads();
        int incl = x + (wid > 0 ? wsum[wid - 1] : 0);
        int carry = s_carry;
        if (i < n) rptr[i] = carry + incl - v;
        __syncthreads();
        if (tid == 1023) s_carry = carry + incl;
        __syncthreads();
    }
    if (tid == 0) rptr[n] = s_carry;
}

__global__ void scatter4_k(const int* __restrict__ s0, const int* __restrict__ d0,
                           const int* __restrict__ s1, const int* __restrict__ d1,
                           const int* __restrict__ s2, const int* __restrict__ d2,
                           const int* __restrict__ s3, const int* __restrict__ d3,
                           const int* __restrict__ rptr_all,
                           int* __restrict__ fill, int* __restrict__ ssort)
{
    int i = blockIdx.x * blockDim.x + threadIdx.x;
    const int* sp; const int* dp; const int* rp; int* fl; int* ss; int e;
    if (i < E_RD) {
        e = i; sp = s0; dp = d0; rp = rptr_all; fl = fill; ss = ssort;
    } else if (i < E_RD + E_DR) {
        e = i - E_RD; sp = s1; dp = d1; rp = rptr_all + (N_R + 1);
        fl = fill + N_D; ss = ssort + E_RD;
    } else if (i < E_RD + E_DR + E_RR) {
        e = i - E_RD - E_DR; sp = s2; dp = d2; rp = rptr_all + 2 * (N_R + 1);
        fl = fill + N_D + N_R; ss = ssort + E_RD + E_DR;
    } else if (i < E_TOT) {
        e = i - E_RD - E_DR - E_RR; sp = s3; dp = d3; rp = rptr_all + 3 * (N_R + 1);
        fl = fill + N_D + 2 * N_R; ss = ssort + E_RD + E_DR + E_RR;
    } else return;
    int d = dp[e];
    int pos = rp[d] + atomicAdd(&fl[d], 1);
    ss[pos] = sp[e];
}

// ============ fused edge aggregation =========================================
__device__ __forceinline__ float lrelu(float x) { return x > 0.f ? x : 0.2f * x; }

__global__ void __launch_bounds__(256)
agg_csr_k(const int* __restrict__ rptr, const int* __restrict__ ssort,
          const float* __restrict__ ssrc, const float* __restrict__ sdst,
          const float* __restrict__ x, float* __restrict__ out, int Nd)
{
    const int warp = (blockIdx.x * blockDim.x + threadIdx.x) >> 5;
    const int lane = threadIdx.x & 31;
    if (warp >= Nd) return;
    const int h = lane >> 2;

    const float sd = sdst[warp * HH + h];
    const int beg = rptr[warp], end = rptr[warp + 1];

    float m = -INFINITY, s = 0.f;
    float a0 = 0.f, a1 = 0.f, a2 = 0.f, a3 = 0.f;
    float a4 = 0.f, a5 = 0.f, a6 = 0.f, a7 = 0.f;

    for (int p = beg; p < end; p++) {
        int src = ssort[p];
        float sc = lrelu(ssrc[src * HH + h] + sd);
        float mn = fmaxf(m, sc);
        float corr = expf(m - mn);
        float w = expf(sc - mn);
        s = s * corr + w;
        m = mn;
        const float4* xp = (const float4*)(x + (size_t)src * CC + lane * 8);
        float4 v0 = xp[0], v1 = xp[1];
        a0 = a0 * corr + w * v0.x;
        a1 = a1 * corr + w * v0.y;
        a2 = a2 * corr + w * v0.z;
        a3 = a3 * corr + w * v0.w;
        a4 = a4 * corr + w * v1.x;
        a5 = a5 * corr + w * v1.y;
        a6 = a6 * corr + w * v1.z;
        a7 = a7 * corr + w * v1.w;
    }
    float inv = 1.f / (s + 1e-16f);
    float* op = out + (size_t)warp * CC + lane * 8;
    *(float4*)op       = make_float4(a0 * inv, a1 * inv, a2 * inv, a3 * inv);
    *(float4*)(op + 4) = make_float4(a4 * inv, a5 * inv, a6 * inv, a7 * inv);
}

__global__ void softmax2_k(const float* __restrict__ scores, float* __restrict__ attn,
                           float invNr, float invNd)
{
    if (threadIdx.x == 0 && blockIdx.x == 0) {
        float s0 = scores[0] * invNr, s1 = scores[1] * invNr;
        float mx = fmaxf(s0, s1);
        float e0 = expf(s0 - mx), e1 = expf(s1 - mx);
        attn[0] = e0 / (e0 + e1);
        attn[1] = e1 / (e0 + e1);
        s0 = scores[2] * invNd; s1 = scores[3] * invNd;
        mx = fmaxf(s0, s1);
        e0 = expf(s0 - mx); e1 = expf(s1 - mx);
        attn[2] = e0 / (e0 + e1);
        attn[3] = e1 / (e0 + e1);
    }
}

// ---------------------------------------------------------------------------
extern "C" void kernel_launch(void* const* d_in, const int* in_sizes, int n_in,
                              void* d_out, int out_size)
{
    const float* x_rna   = (const float*)d_in[0];
    const float* x_dis   = (const float*)d_in[1];
    const float* W_d     = (const float*)d_in[2];
    const float* b_d     = (const float*)d_in[3];
    const float* Wp_rna  = (const float*)d_in[4];
    const float* bp_rna  = (const float*)d_in[5];
    const float* Wp_dis  = (const float*)d_in[6];
    const float* bp_dis  = (const float*)d_in[7];
    const float* a_src_rd = (const float*)d_in[8];
    const float* a_dst_rd = (const float*)d_in[9];
    const float* a_src_dr = (const float*)d_in[10];
    const float* a_dst_dr = (const float*)d_in[11];
    const float* a_src_rr = (const float*)d_in[12];
    const float* a_dst_rr = (const float*)d_in[13];
    const float* a_src_dd = (const float*)d_in[14];
    const float* a_dst_dd = (const float*)d_in[15];
    const float* kW      = (const float*)d_in[16];
    const float* kb      = (const float*)d_in[17];
    const float* qv      = (const float*)d_in[18];
    const float* W_out   = (const float*)d_in[19];
    const float* b_out   = (const float*)d_in[20];
    const int* rd_src = (const int*)d_in[21];
    const int* rd_dst = (const int*)d_in[22];
    const int* dr_src = (const int*)d_in[23];
    const int* dr_dst = (const int*)d_in[24];
    const int* rr_src = (const int*)d_in[25];
    const int* rr_dst = (const int*)d_in[26];
    const int* dd_src = (const int*)d_in[27];
    const int* dd_dst = (const int*)d_in[28];

    float* out = (float*)d_out;

    float *p_xd, *p_hr, *p_hd, *p_ord, *p_odr, *p_orr, *p_odd;
    float *p_sr, *p_sd, *p_scores, *p_attn;
    int *p_cnt, *p_fill, *p_rptr, *p_ssort;
    cudaGetSymbolAddress((void**)&p_xd, g_xd);
    cudaGetSymbolAddress((void**)&p_hr, g_hr);
    cudaGetSymbolAddress((void**)&p_hd, g_hd);
    cudaGetSymbolAddress((void**)&p_ord, g_out_rd);
    cudaGetSymbolAddress((void**)&p_odr, g_out_dr);
    cudaGetSymbolAddress((void**)&p_orr, g_out_rr);
    cudaGetSymbolAddress((void**)&p_odd, g_out_dd);
    cudaGetSymbolAddress((void**)&p_sr, g_s_rna);
    cudaGetSymbolAddress((void**)&p_sd, g_s_dis);
    cudaGetSymbolAddress((void**)&p_cnt, g_cnt);
    cudaGetSymbolAddress((void**)&p_fill, g_fill);
    cudaGetSymbolAddress((void**)&p_rptr, g_rptr);
    cudaGetSymbolAddress((void**)&p_ssort, g_ssort);
    cudaGetSymbolAddress((void**)&p_scores, g_scores);
    cudaGetSymbolAddress((void**)&p_attn, g_attn);

    cudaFuncSetAttribute(gemm_ca<0>, cudaFuncAttributeMaxDynamicSharedMemorySize, SMEM_CA);
    cudaFuncSetAttribute(gemm_ca<1>, cudaFuncAttributeMaxDynamicSharedMemorySize, SMEM_CA);

    const dim3 thr(256);
    const int mbr = (N_R + 127) / 128;   // 391
    const int mbd = (N_D + 127) / 128;   // 79

    int* rp_rd = p_rptr + 0 * (N_R + 1);
    int* rp_dr = p_rptr + 1 * (N_R + 1);
    int* rp_rr = p_rptr + 2 * (N_R + 1);
    int* rp_dd = p_rptr + 3 * (N_R + 1);
    int* ss_rd = p_ssort;
    int* ss_dr = ss_rd + E_RD;
    int* ss_rr = ss_dr + E_DR;
    int* ss_dd = ss_rr + E_RR;

    cudaStream_t st0 = 0, st1, st2;
    cudaStreamCreateWithFlags(&st1, cudaStreamNonBlocking);
    cudaStreamCreateWithFlags(&st2, cudaStreamNonBlocking);
    cudaEvent_t ev[8];
    for (int i = 0; i < 8; i++) cudaEventCreateWithFlags(&ev[i], cudaEventDisableTiming);

    // fork
    cudaEventRecord(ev[0], st0);
    cudaStreamWaitEvent(st1, ev[0], 0);
    cudaStreamWaitEvent(st2, ev[0], 0);

    // st2: CSR build + score clear
    cudaMemsetAsync(p_cnt, 0, CNT_TOT * sizeof(int), st2);
    cudaMemsetAsync(p_fill, 0, CNT_TOT * sizeof(int), st2);
    cudaMemsetAsync(p_scores, 0, 4 * sizeof(float), st2);
    hist4_k<<<(E_TOT + 255) / 256, thr, 0, st2>>>(rd_dst, dr_dst, rr_dst, dd_dst, p_cnt);
    scan4_k<<<4, 1024, 0, st2>>>(p_cnt, p_rptr);
    scatter4_k<<<(E_TOT + 255) / 256, thr, 0, st2>>>(rd_src, rd_dst, dr_src, dr_dst,
                                                     rr_src, rr_dst, dd_src, dd_dst,
                                                     p_rptr, p_fill, p_ssort);

    // st0: disease chain
    gemm_ca<0><<<dim3(2, mbd), thr, SMEM_CA, st0>>>(x_dis, W_d, b_d, nullptr,
                                                    p_xd, nullptr, N_D, RNA_IN, D_FEAT);
    gemm_ca<0><<<dim3(2, mbd), thr, SMEM_CA, st0>>>(p_xd, Wp_dis, bp_dis, nullptr,
                                                    p_hd, nullptr, N_D, CC, RNA_IN);
    scores4_k<<<(N_D + 7) / 8, thr, 0, st0>>>(p_hd, a_dst_rd, a_src_dr, a_src_dd, a_dst_dd,
                                              p_sd + 0 * N_D * HH, p_sd + 1 * N_D * HH,
                                              p_sd + 2 * N_D * HH, p_sd + 3 * N_D * HH, N_D);

    // st1: rna chain
    gemm_ca<0><<<dim3(2, mbr), thr, SMEM_CA, st1>>>(x_rna, Wp_rna, bp_rna, nullptr,
                                                    p_hr, nullptr, N_R, CC, RNA_IN);
    scores4_k<<<(N_R + 7) / 8, thr, 0, st1>>>(p_hr, a_src_rd, a_dst_dr, a_src_rr, a_dst_rr,
                                              p_sr + 0 * N_R * HH, p_sr + 1 * N_R * HH,
                                              p_sr + 2 * N_R * HH, p_sr + 3 * N_R * HH, N_R);

    // join before aggs
    cudaEventRecord(ev[1], st0);
    cudaEventRecord(ev[2], st1);
    cudaEventRecord(ev[3], st2);
    cudaStreamWaitEvent(st0, ev[2], 0); cudaStreamWaitEvent(st0, ev[3], 0);
    cudaStreamWaitEvent(st1, ev[1], 0); cudaStreamWaitEvent(st1, ev[3], 0);
    cudaStreamWaitEvent(st2, ev[1], 0); cudaStreamWaitEvent(st2, ev[2], 0);

    // st1: rr
    agg_csr_k<<<(N_R * 32 + 255) / 256, thr, 0, st1>>>(rp_rr, ss_rr,
                                                       p_sr + 2 * N_R * HH, p_sr + 3 * N_R * HH,
                                                       p_hr, p_orr, N_R);
    gemm_ca<1><<<dim3(2, mbr), thr, SMEM_CA, st1>>>(p_orr, kW, kb, qv,
                                                    nullptr, p_scores + 1, N_R, CC, CC);
    // st0: dr
    agg_csr_k<<<(N_R * 32 + 255) / 256, thr, 0, st0>>>(rp_dr, ss_dr,
                                                       p_sd + 1 * N_D * HH, p_sr + 1 * N_R * HH,
                                                       p_hd, p_odr, N_R);
    gemm_ca<1><<<dim3(2, mbr), thr, SMEM_CA, st0>>>(p_odr, kW, kb, qv,
                                                    nullptr, p_scores + 0, N_R, CC, CC);
    // st2: rd + dd
    agg_csr_k<<<(N_D * 32 + 255) / 256, thr, 0, st2>>>(rp_rd, ss_rd,
                                                       p_sr + 0 * N_R * HH, p_sd + 0 * N_D * HH,
                                                       p_hr, p_ord, N_D);
    agg_csr_k<<<(N_D * 32 + 255) / 256, thr, 0, st2>>>(rp_dd, ss_dd,
                                                       p_sd + 2 * N_D * HH, p_sd + 3 * N_D * HH,
                                                       p_hd, p_odd, N_D);
    gemm_ca<1><<<dim3(2, mbd), thr, SMEM_CA, st2>>>(p_ord, kW, kb, qv,
                                                    nullptr, p_scores + 2, N_D, CC, CC);
    gemm_ca<1><<<dim3(2, mbd), thr, SMEM_CA, st2>>>(p_odd, kW, kb, qv,
                                                    nullptr, p_scores + 3, N_D, CC, CC);

    // join for softmax
    cudaEventRecord(ev[4], st1);
    cudaEventRecord(ev[5], st2);
    cudaStreamWaitEvent(st0, ev[4], 0);
    cudaStreamWaitEvent(st0, ev[5], 0);
    softmax2_k<<<1, 32, 0, st0>>>(p_scores, p_attn, 1.f / N_R, 1.f / N_D);

    // fork for final GEMMs
    cudaEventRecord(ev[6], st0);
    cudaStreamWaitEvent(st1, ev[6], 0);

    gemm_tc<2><<<dim3(2, mbr), thr, 0, st0>>>(p_odr, p_orr, W_out, b_out, p_attn + 0, nullptr,
                                              out, nullptr, N_R, CC, CC);
    gemm_tc<2><<<dim3(2, mbd), thr, 0, st1>>>(p_ord, p_odd, W_out, b_out, p_attn + 2, nullptr,
                                              out + (size_t)N_R * CC, nullptr, N_D, CC, CC);

    // final join
    cudaEventRecord(ev[7], st1);
    cudaStreamWaitEvent(st0, ev[7], 0);

    for (int i = 0; i < 8; i++) cudaEventDestroy(ev[i]);
    cudaStreamDestroy(st1);
    cudaStreamDestroy(st2);
}

// round 8
// speedup vs baseline: 5.5699x; 1.0672x over previous
#include <cuda_runtime.h>
#include <cstdint>
#include <math.h>

#define N_R 50000
#define N_D 10000
#define HH  8
#define DH  32
#define CC  256
#define RNA_IN 256
#define D_FEAT 512
#define E_RD 200000
#define E_DR 200000
#define E_RR 400000
#define E_DD 50000
#define E_TOT (E_RD + E_DR + E_RR + E_DD)
#define CNT_TOT (2 * N_R + 2 * N_D)

// ---------------- static device scratch ------------------------------------
__device__ float    g_xd[N_D * RNA_IN];
__device__ float    g_hr[N_R * CC];
__device__ float    g_hd[N_D * CC];
__device__ float    g_out_rd[N_D * CC];
__device__ float    g_out_dr[N_R * CC];
__device__ float    g_out_rr[N_R * CC];
__device__ float    g_out_dd[N_D * CC];
__device__ float    g_s_rna[4 * N_R * HH];
__device__ float    g_s_dis[4 * N_D * HH];
__device__ int      g_cnt[CNT_TOT];
__device__ int      g_fill[CNT_TOT];
__device__ int      g_rptr[4 * (N_R + 1)];
__device__ int      g_ssort[E_TOT];
__device__ float    g_scores[4];
__device__ float    g_attn[4];
// transformed weights (tf32-rounded, mma-native blocked layout)
__device__ float    g_wd_t[D_FEAT * RNA_IN];
__device__ float    g_wpr_t[RNA_IN * CC];
__device__ float    g_wpd_t[RNA_IN * CC];
__device__ float    g_kw_t[CC * CC];

__device__ __forceinline__ uint32_t f2tf(float f) {
    uint32_t u;
    asm("cvt.rna.tf32.f32 %0, %1;" : "=r"(u) : "f"(f));
    return u;
}

// ================= weight prep: W[K][N] -> blocked n-major tf32 ==============
// Wt[((k/32)*N + n)*32 + k'] where k' = (k%32/8)*8 + ((k%8)&3)*2 + ((k%8)>>2)
// (so consumer LDS.64 at offset ks*8+t*2 yields k = ks*8+t (reg0), ks*8+t+4 (reg1))
__global__ void __launch_bounds__(256)
prep_w_k(const float* __restrict__ wd,  const float* __restrict__ wpr,
         const float* __restrict__ wpd, const float* __restrict__ kw,
         float* __restrict__ wdt, float* __restrict__ wprt,
         float* __restrict__ wpdt, float* __restrict__ kwt)
{
    __shared__ float tile[32][129];
    int b = blockIdx.x;
    const float* src; float* dst; int N, base;
    if (b < 32)      { src = wd;  dst = wdt;  N = RNA_IN; base = 0;  }
    else if (b < 48) { src = wpr; dst = wprt; N = CC;     base = 32; }
    else if (b < 64) { src = wpd; dst = wpdt; N = CC;     base = 48; }
    else             { src = kw;  dst = kwt;  N = CC;     base = 64; }
    int lb = b - base;
    int ntl = N / 128;
    int kt = lb / ntl, nb = lb % ntl;
    int k0 = kt * 32, n0 = nb * 128;
    int tid = threadIdx.x;
#pragma unroll
    for (int it = 0; it < 16; it++) {
        int idx = it * 256 + tid;
        int k = idx >> 7, n = idx & 127;
        tile[k][n] = src[(size_t)(k0 + k) * N + n0 + n];
    }
    __syncthreads();
#pragma unroll
    for (int it = 0; it < 4; it++) {
        int cidx = it * 256 + tid;
        int n = cidx >> 3, c = cidx & 7;
        float4 v;
        float* vp = (float*)&v;
#pragma unroll
        for (int q = 0; q < 4; q++) {
            int kp = c * 4 + q;                 // k' within 32
            int ks = kp >> 3, r = kp & 7;       // r = t*2 + reg
            int kl = ks * 8 + (r >> 1) + 4 * (r & 1);   // source k within 32
            vp[q] = __uint_as_float(f2tf(tile[kl][n]));
        }
        *(float4*)&dst[((size_t)kt * N + n0 + n) * 32 + c * 4] = v;
    }
}

// =============================================================================
// GEMM v3 (MODE 0/1): cp.async, BK=32, B pre-transformed tf32 (no B cvt,
// LDS.64 B frags), A raw fp32 (cvt+optional relu after LDS)
// =============================================================================
#define AST 36     // A smem row stride
#define BST2 40    // B smem n-row stride (32 data + 8 pad)
#define SMEM_CA ((2 * 128 * AST + 2 * 128 * BST2 + 512) * 4)

template <int MODE>
__global__ void __launch_bounds__(256, 2)
gemm_ca(const float* __restrict__ A0, const float* __restrict__ Bt,
        const float* __restrict__ bias, const float* __restrict__ qv,
        float* __restrict__ C, float* __restrict__ score,
        int M, int N, int K)
{
    extern __shared__ float sm[];
    float* As     = sm;                               // [2][128*AST]
    float* Bs     = sm + 2 * 128 * AST;               // [2][128*BST2]
    float* bias_s = sm + 2 * 128 * AST + 2 * 128 * BST2;
    float* q_s    = bias_s + 128;
    float* red    = q_s + 128;

    const int tid  = threadIdx.x;
    const int lane = tid & 31;
    const int warp = tid >> 5;
    const int wm   = warp & 3;
    const int wn   = warp >> 2;
    const int g    = lane >> 2;
    const int t    = lane & 3;
    const int bRow = blockIdx.y * 128;
    const int bCol = blockIdx.x * 128;

    if (tid < 128) {
        bias_s[tid] = bias[bCol + tid];
        if (MODE == 1) q_s[tid] = qv[bCol + tid];
    }

    float acc[2][8][4];
#pragma unroll
    for (int mi = 0; mi < 2; mi++)
#pragma unroll
        for (int ni = 0; ni < 8; ni++)
#pragma unroll
            for (int r = 0; r < 4; r++) acc[mi][ni][r] = 0.f;

    auto issue = [&](int k0, int buf) {
        float* a_dst = As + buf * 128 * AST;
        float* b_dst = Bs + buf * 128 * BST2;
#pragma unroll
        for (int it = 0; it < 4; it++) {
            int idx = it * 256 + tid;
            int row = idx >> 3, ch = idx & 7;
            const float* src = A0 + (size_t)(bRow + row) * K + k0 + ch * 4;
            unsigned d = (unsigned)__cvta_generic_to_shared(a_dst + row * AST + ch * 4);
            int sz = (bRow + row < M) ? 16 : 0;
            asm volatile("cp.async.ca.shared.global [%0], [%1], 16, %2;"
                         :: "r"(d), "l"(src), "r"(sz));
        }
        const int kt = k0 >> 5;
#pragma unroll
        for (int it = 0; it < 4; it++) {
            int idx = it * 256 + tid;
            int n = idx >> 3, c = idx & 7;
            const float* src = Bt + ((size_t)kt * N + bCol + n) * 32 + c * 4;
            unsigned d = (unsigned)__cvta_generic_to_shared(b_dst + n * BST2 + c * 4);
            asm volatile("cp.async.ca.shared.global [%0], [%1], 16;"
                         :: "r"(d), "l"(src));
        }
        asm volatile("cp.async.commit_group;");
    };

    const int S = K / 32;
    issue(0, 0);
    int buf = 0;

    for (int s = 0; s < S; s++) {
        asm volatile("cp.async.wait_group 0;");
        __syncthreads();
        if (s + 1 < S) issue((s + 1) * 32, buf ^ 1);

        const float* ap = As + buf * 128 * AST;
        const float* bp = Bs + buf * 128 * BST2;
#pragma unroll
        for (int ks = 0; ks < 4; ks++) {
            uint32_t af[2][4];
#pragma unroll
            for (int mi = 0; mi < 2; mi++) {
                const int mr = wm * 32 + mi * 16;
                float v0 = ap[(mr + g)     * AST + ks * 8 + t];
                float v1 = ap[(mr + g + 8) * AST + ks * 8 + t];
                float v2 = ap[(mr + g)     * AST + ks * 8 + t + 4];
                float v3 = ap[(mr + g + 8) * AST + ks * 8 + t + 4];
                if (MODE == 1) {
                    v0 = fmaxf(v0, 0.f); v1 = fmaxf(v1, 0.f);
                    v2 = fmaxf(v2, 0.f); v3 = fmaxf(v3, 0.f);
                }
                af[mi][0] = f2tf(v0); af[mi][1] = f2tf(v1);
                af[mi][2] = f2tf(v2); af[mi][3] = f2tf(v3);
            }
#pragma unroll
            for (int ni = 0; ni < 8; ni++) {
                const int n8 = wn * 8 + ni;
                float2 bv = *(const float2*)&bp[(n8 * 8 + g) * BST2 + ks * 8 + t * 2];
                uint32_t bx = __float_as_uint(bv.x), by = __float_as_uint(bv.y);
#pragma unroll
                for (int mi = 0; mi < 2; mi++) {
                    asm volatile(
                        "mma.sync.aligned.m16n8k8.row.col.f32.tf32.tf32.f32 "
                        "{%0,%1,%2,%3}, {%4,%5,%6,%7}, {%8,%9}, {%0,%1,%2,%3};"
                        : "+f"(acc[mi][ni][0]), "+f"(acc[mi][ni][1]),
                          "+f"(acc[mi][ni][2]), "+f"(acc[mi][ni][3])
                        : "r"(af[mi][0]), "r"(af[mi][1]), "r"(af[mi][2]), "r"(af[mi][3]),
                          "r"(bx), "r"(by));
                }
            }
        }
        buf ^= 1;
    }

    if (MODE == 0) {
#pragma unroll
        for (int mi = 0; mi < 2; mi++) {
            const int r0 = bRow + wm * 32 + mi * 16 + g;
#pragma unroll
            for (int ni = 0; ni < 8; ni++) {
                const int cl = wn * 64 + ni * 8 + t * 2;
                const int c0 = bCol + cl;
                if (r0 < M) {
                    float2 v = make_float2(acc[mi][ni][0] + bias_s[cl],
                                           acc[mi][ni][1] + bias_s[cl + 1]);
                    *(float2*)&C[(size_t)r0 * N + c0] = v;
                }
                if (r0 + 8 < M) {
                    float2 v = make_float2(acc[mi][ni][2] + bias_s[cl],
                                           acc[mi][ni][3] + bias_s[cl + 1]);
                    *(float2*)&C[(size_t)(r0 + 8) * N + c0] = v;
                }
            }
        }
    } else {
        float local = 0.f;
#pragma unroll
        for (int mi = 0; mi < 2; mi++) {
            const int r0 = bRow + wm * 32 + mi * 16 + g;
#pragma unroll
            for (int ni = 0; ni < 8; ni++) {
                const int cl = wn * 64 + ni * 8 + t * 2;
                if (r0 < M)
                    local += q_s[cl]     * tanhf(acc[mi][ni][0] + bias_s[cl]) +
                             q_s[cl + 1] * tanhf(acc[mi][ni][1] + bias_s[cl + 1]);
                if (r0 + 8 < M)
                    local += q_s[cl]     * tanhf(acc[mi][ni][2] + bias_s[cl]) +
                             q_s[cl + 1] * tanhf(acc[mi][ni][3] + bias_s[cl + 1]);
            }
        }
        red[tid] = local;
        __syncthreads();
        for (int st = 128; st > 0; st >>= 1) {
            if (tid < st) red[tid] += red[tid + st];
            __syncthreads();
        }
        if (tid == 0) atomicAdd(score, red[0]);
    }
}

// ================= old TF32 GEMM (MODE 2 only, raw weights) ==================
#define A_STRIDE 20
#define B_N8_STRIDE 66

template <int MODE>
__global__ void __launch_bounds__(256)
gemm_tc(const float* __restrict__ A0, const float* __restrict__ A1,
        const float* __restrict__ B,  const float* __restrict__ bias,
        const float* __restrict__ wts, const float* __restrict__ qv,
        float* __restrict__ C, float* __restrict__ score,
        int M, int N, int K)
{
    __shared__ float As[2][128 * A_STRIDE];
    __shared__ float Bs[2][2 * 16 * B_N8_STRIDE];
    __shared__ float bias_s[128];

    const int tid  = threadIdx.x;
    const int lane = tid & 31;
    const int warp = tid >> 5;
    const int wm   = warp & 3;
    const int wn   = warp >> 2;
    const int g    = lane >> 2;
    const int t    = lane & 3;
    const int bRow = blockIdx.y * 128;
    const int bCol = blockIdx.x * 128;

    if (tid < 128) bias_s[tid] = bias[bCol + tid];

    float w0 = wts[0], w1 = wts[1];

    const int am  = tid >> 1;
    const int akq = (tid & 1) * 8;
    const size_t arow_off = (size_t)(bRow + am) * K;
    const bool arow_ok = (bRow + am) < M;

    const int bkr = tid >> 4;
    const int bn8 = tid & 15;
    const int bks = bkr >> 3;
    const int bt  = bkr & 3;
    const int brg = (bkr & 7) >> 2;
    const int bbase = (bks * 16 + bn8) * B_N8_STRIDE + brg;

    float acc[2][8][4];
#pragma unroll
    for (int mi = 0; mi < 2; mi++)
#pragma unroll
        for (int ni = 0; ni < 8; ni++)
#pragma unroll
            for (int r = 0; r < 4; r++) acc[mi][ni][r] = 0.f;

    const int S = K / 16;
    float4 la0, la1, lb0, lb1;

    auto loadA = [&](int k0) {
        if (arow_ok) {
            la0 = *(const float4*)(A0 + arow_off + k0 + akq);
            la1 = *(const float4*)(A0 + arow_off + k0 + akq + 4);
            float4 m0 = *(const float4*)(A1 + arow_off + k0 + akq);
            float4 m1 = *(const float4*)(A1 + arow_off + k0 + akq + 4);
            la0.x = w0 * fmaxf(la0.x, 0.f) + w1 * fmaxf(m0.x, 0.f);
            la0.y = w0 * fmaxf(la0.y, 0.f) + w1 * fmaxf(m0.y, 0.f);
            la0.z = w0 * fmaxf(la0.z, 0.f) + w1 * fmaxf(m0.z, 0.f);
            la0.w = w0 * fmaxf(la0.w, 0.f) + w1 * fmaxf(m0.w, 0.f);
            la1.x = w0 * fmaxf(la1.x, 0.f) + w1 * fmaxf(m1.x, 0.f);
            la1.y = w0 * fmaxf(la1.y, 0.f) + w1 * fmaxf(m1.y, 0.f);
            la1.z = w0 * fmaxf(la1.z, 0.f) + w1 * fmaxf(m1.z, 0.f);
            la1.w = w0 * fmaxf(la1.w, 0.f) + w1 * fmaxf(m1.w, 0.f);
        } else {
            la0 = make_float4(0.f, 0.f, 0.f, 0.f);
            la1 = la0;
        }
        lb0 = *(const float4*)(B + (size_t)(k0 + bkr) * N + bCol + bn8 * 8);
        lb1 = *(const float4*)(B + (size_t)(k0 + bkr) * N + bCol + bn8 * 8 + 4);
    };
    auto storeS = [&](int nb) {
        float4 c0 = make_float4(__uint_as_float(f2tf(la0.x)), __uint_as_float(f2tf(la0.y)),
                                __uint_as_float(f2tf(la0.z)), __uint_as_float(f2tf(la0.w)));
        float4 c1 = make_float4(__uint_as_float(f2tf(la1.x)), __uint_as_float(f2tf(la1.y)),
                                __uint_as_float(f2tf(la1.z)), __uint_as_float(f2tf(la1.w)));
        *(float4*)&As[nb][am * A_STRIDE + akq]     = c0;
        *(float4*)&As[nb][am * A_STRIDE + akq + 4] = c1;
        float bv[8] = {lb0.x, lb0.y, lb0.z, lb0.w, lb1.x, lb1.y, lb1.z, lb1.w};
#pragma unroll
        for (int j = 0; j < 8; j++)
            Bs[nb][bbase + (j * 4 + bt) * 2] = __uint_as_float(f2tf(bv[j]));
    };

    loadA(0);
    storeS(0);
    __syncthreads();

    for (int s = 0; s < S; s++) {
        if (s + 1 < S) loadA((s + 1) * 16);

        const int buf = s & 1;
#pragma unroll
        for (int ks = 0; ks < 2; ks++) {
            uint32_t af[2][4];
#pragma unroll
            for (int mi = 0; mi < 2; mi++) {
                const int mr = wm * 32 + mi * 16;
                const float* ap = &As[buf][0];
                af[mi][0] = __float_as_uint(ap[(mr + g)     * A_STRIDE + ks * 8 + t]);
                af[mi][1] = __float_as_uint(ap[(mr + g + 8) * A_STRIDE + ks * 8 + t]);
                af[mi][2] = __float_as_uint(ap[(mr + g)     * A_STRIDE + ks * 8 + t + 4]);
                af[mi][3] = __float_as_uint(ap[(mr + g + 8) * A_STRIDE + ks * 8 + t + 4]);
            }
#pragma unroll
            for (int ni = 0; ni < 8; ni++) {
                const int n8 = wn * 8 + ni;
                uint2 bf = *(const uint2*)&Bs[buf][(ks * 16 + n8) * B_N8_STRIDE + lane * 2];
#pragma unroll
                for (int mi = 0; mi < 2; mi++) {
                    asm volatile(
                        "mma.sync.aligned.m16n8k8.row.col.f32.tf32.tf32.f32 "
                        "{%0,%1,%2,%3}, {%4,%5,%6,%7}, {%8,%9}, {%0,%1,%2,%3};"
                        : "+f"(acc[mi][ni][0]), "+f"(acc[mi][ni][1]),
                          "+f"(acc[mi][ni][2]), "+f"(acc[mi][ni][3])
                        : "r"(af[mi][0]), "r"(af[mi][1]), "r"(af[mi][2]), "r"(af[mi][3]),
                          "r"(bf.x), "r"(bf.y));
                }
            }
        }
        __syncthreads();
        if (s + 1 < S) {
            storeS((s + 1) & 1);
            __syncthreads();
        }
    }

#pragma unroll
    for (int mi = 0; mi < 2; mi++) {
        const int r0 = bRow + wm * 32 + mi * 16 + g;
#pragma unroll
        for (int ni = 0; ni < 8; ni++) {
            const int cl = wn * 64 + ni * 8 + t * 2;
            const int c0 = bCol + cl;
            if (r0 < M) {
                float2 v = make_float2(acc[mi][ni][0] + bias_s[cl],
                                       acc[mi][ni][1] + bias_s[cl + 1]);
                *(float2*)&C[(size_t)r0 * N + c0] = v;
            }
            if (r0 + 8 < M) {
                float2 v = make_float2(acc[mi][ni][2] + bias_s[cl],
                                       acc[mi][ni][3] + bias_s[cl + 1]);
                *(float2*)&C[(size_t)(r0 + 8) * N + c0] = v;
            }
        }
    }
}

// ============== fused node-scores ============================================
__global__ void __launch_bounds__(256)
scores4_k(const float* __restrict__ h,
          const float* __restrict__ a0, const float* __restrict__ a1,
          const float* __restrict__ a2, const float* __restrict__ a3,
          float* __restrict__ s0, float* __restrict__ s1,
          float* __restrict__ s2, float* __restrict__ s3, int Nn)
{
    __shared__ float av[4][CC];
    const int tid = threadIdx.x;
    av[0][tid] = a0[tid]; av[1][tid] = a1[tid];
    av[2][tid] = a2[tid]; av[3][tid] = a3[tid];
    __syncthreads();

    const int lane = tid & 31;
    const int node = blockIdx.x * 8 + (tid >> 5);
    if (node >= Nn) return;

    const float* hp = h + (size_t)node * CC + lane * 8;
    float4 h0 = *(const float4*)hp;
    float4 h1 = *(const float4*)(hp + 4);

    float* outs[4] = {s0, s1, s2, s3};
#pragma unroll
    for (int v = 0; v < 4; v++) {
        const float* ap = &av[v][lane * 8];
        float p = h0.x * ap[0] + h0.y * ap[1] + h0.z * ap[2] + h0.w * ap[3] +
                  h1.x * ap[4] + h1.y * ap[5] + h1.z * ap[6] + h1.w * ap[7];
        p += __shfl_xor_sync(0xffffffffu, p, 1);
        p += __shfl_xor_sync(0xffffffffu, p, 2);
        if ((lane & 3) == 0) outs[v][node * HH + (lane >> 2)] = p;
    }
}

// ================= fused CSR build ==========================================
__global__ void hist4_k(const int* __restrict__ d0, const int* __restrict__ d1,
                        const int* __restrict__ d2, const int* __restrict__ d3,
                        int* __restrict__ cnt)
{
    int i = blockIdx.x * blockDim.x + threadIdx.x;
    if (i < E_RD)                     atomicAdd(&cnt[d0[i]], 1);
    else if (i < E_RD + E_DR)         atomicAdd(&cnt[N_D + d1[i - E_RD]], 1);
    else if (i < E_RD + E_DR + E_RR)  atomicAdd(&cnt[N_D + N_R + d2[i - E_RD - E_DR]], 1);
    else if (i < E_TOT)               atomicAdd(&cnt[N_D + 2 * N_R + d3[i - E_RD - E_DR - E_RR]], 1);
}

__global__ void __launch_bounds__(1024)
scan4_k(const int* __restrict__ cnt, int* __restrict__ rptr_all)
{
    __shared__ int wsum[32];
    __shared__ int s_carry;
    const int b = blockIdx.x;
    const int n    = (b == 0 || b == 3) ? N_D : N_R;
    const int cofs = (b == 0) ? 0 : (b == 1) ? N_D : (b == 2) ? (N_D + N_R) : (N_D + 2 * N_R);
    const int* c = cnt + cofs;
    int* rptr = rptr_all + b * (N_R + 1);

    const int tid = threadIdx.x;
    const int lane = tid & 31, wid = tid >> 5;
    if (tid == 0) s_carry = 0;
    __syncthreads();
    for (int base = 0; base < n; base += 1024) {
        int i = base + tid;
        int v = (i < n) ? c[i] : 0;
        int x = v;
#pragma unroll
        for (int o = 1; o < 32; o <<= 1) {
            int y = __shfl_up_sync(0xffffffffu, x, o);
            if (lane >= o) x += y;
        }
        if (lane == 31) wsum[wid] = x;
        __syncthreads();
        if (wid == 0) {
            int tv = wsum[lane];
#pragma unroll
            for (int o = 1; o < 32; o <<= 1) {
                int y = __shfl_up_sync(0xffffffffu, tv, o);
                if (lane >= o) tv += y;
            }
            wsum[lane] = tv;
        }
        __syncthreads();
        int incl = x + (wid > 0 ? wsum[wid - 1] : 0);
        int carry = s_carry;
        if (i < n) rptr[i] = carry + incl - v;
        __syncthreads();
        if (tid == 1023) s_carry = carry + incl;
        __syncthreads();
    }
    if (tid == 0) rptr[n] = s_carry;
}

__global__ void scatter4_k(const int* __restrict__ s0, const int* __restrict__ d0,
                           const int* __restrict__ s1, const int* __restrict__ d1,
                           const int* __restrict__ s2, const int* __restrict__ d2,
                           const int* __restrict__ s3, const int* __restrict__ d3,
                           const int* __restrict__ rptr_all,
                           int* __restrict__ fill, int* __restrict__ ssort)
{
    int i = blockIdx.x * blockDim.x + threadIdx.x;
    const int* sp; const int* dp; const int* rp; int* fl; int* ss; int e;
    if (i < E_RD) {
        e = i; sp = s0; dp = d0; rp = rptr_all; fl = fill; ss = ssort;
    } else if (i < E_RD + E_DR) {
        e = i - E_RD; sp = s1; dp = d1; rp = rptr_all + (N_R + 1);
        fl = fill + N_D; ss = ssort + E_RD;
    } else if (i < E_RD + E_DR + E_RR) {
        e = i - E_RD - E_DR; sp = s2; dp = d2; rp = rptr_all + 2 * (N_R + 1);
        fl = fill + N_D + N_R; ss = ssort + E_RD + E_DR;
    } else if (i < E_TOT) {
        e = i - E_RD - E_DR - E_RR; sp = s3; dp = d3; rp = rptr_all + 3 * (N_R + 1);
        fl = fill + N_D + 2 * N_R; ss = ssort + E_RD + E_DR + E_RR;
    } else return;
    int d = dp[e];
    int pos = rp[d] + atomicAdd(&fl[d], 1);
    ss[pos] = sp[e];
}

// ============ edge aggregation v2: exact max pass + parallel sum pass ========
__device__ __forceinline__ float lrelu(float x) { return x > 0.f ? x : 0.2f * x; }

__global__ void __launch_bounds__(256)
agg_csr_k(const int* __restrict__ rptr, const int* __restrict__ ssort,
          const float* __restrict__ ssrc, const float* __restrict__ sdst,
          const float* __restrict__ x, float* __restrict__ out, int Nd)
{
    const int warp = (blockIdx.x * blockDim.x + threadIdx.x) >> 5;
    const int lane = threadIdx.x & 31;
    if (warp >= Nd) return;
    const int beg = rptr[warp], end = rptr[warp + 1];

    // ---- pass 1: exact per-head max (4 edges in parallel per head) ----
    const int h1 = lane & 7;
    const int j  = lane >> 3;
    const float sd1 = sdst[warp * HH + h1];
    float mloc = -INFINITY;
    for (int p = beg + j; p < end; p += 4) {
        int src = ssort[p];
        mloc = fmaxf(mloc, lrelu(ssrc[src * HH + h1] + sd1));
    }
    mloc = fmaxf(mloc, __shfl_xor_sync(0xffffffffu, mloc, 8));
    mloc = fmaxf(mloc, __shfl_xor_sync(0xffffffffu, mloc, 16));
    // now lane l holds max of head (l & 7)

    // ---- pass 2: w = exp(sc - m), accumulate (no loop-carried exp chain) ----
    const int h2 = lane >> 2;
    const float m2  = __shfl_sync(0xffffffffu, mloc, h2);
    const float sd2 = __shfl_sync(0xffffffffu, sd1, h2);

    float s = 0.f;
    float a0 = 0.f, a1 = 0.f, a2 = 0.f, a3 = 0.f;
    float a4 = 0.f, a5 = 0.f, a6 = 0.f, a7 = 0.f;
    for (int p = beg; p < end; p++) {
        int src = ssort[p];
        float w = expf(lrelu(ssrc[src * HH + h2] + sd2) - m2);
        s += w;
        const float4* xp = (const float4*)(x + (size_t)src * CC + lane * 8);
        float4 v0 = xp[0], v1 = xp[1];
        a0 += w * v0.x; a1 += w * v0.y; a2 += w * v0.z; a3 += w * v0.w;
        a4 += w * v1.x; a5 += w * v1.y; a6 += w * v1.z; a7 += w * v1.w;
    }
    float inv = 1.f / (s + 1e-16f);
    float* op = out + (size_t)warp * CC + lane * 8;
    *(float4*)op       = make_float4(a0 * inv, a1 * inv, a2 * inv, a3 * inv);
    *(float4*)(op + 4) = make_float4(a4 * inv, a5 * inv, a6 * inv, a7 * inv);
}

__global__ void softmax2_k(const float* __restrict__ scores, float* __restrict__ attn,
                           float invNr, float invNd)
{
    if (threadIdx.x == 0 && blockIdx.x == 0) {
        float s0 = scores[0] * invNr, s1 = scores[1] * invNr;
        float mx = fmaxf(s0, s1);
        float e0 = expf(s0 - mx), e1 = expf(s1 - mx);
        attn[0] = e0 / (e0 + e1);
        attn[1] = e1 / (e0 + e1);
        s0 = scores[2] * invNd; s1 = scores[3] * invNd;
        mx = fmaxf(s0, s1);
        e0 = expf(s0 - mx); e1 = expf(s1 - mx);
        attn[2] = e0 / (e0 + e1);
        attn[3] = e1 / (e0 + e1);
    }
}

// ---------------------------------------------------------------------------
extern "C" void kernel_launch(void* const* d_in, const int* in_sizes, int n_in,
                              void* d_out, int out_size)
{
    const float* x_rna   = (const float*)d_in[0];
    const float* x_dis   = (const float*)d_in[1];
    const float* W_d     = (const float*)d_in[2];
    const float* b_d     = (const float*)d_in[3];
    const float* Wp_rna  = (const float*)d_in[4];
    const float* bp_rna  = (const float*)d_in[5];
    const float* Wp_dis  = (const float*)d_in[6];
    const float* bp_dis  = (const float*)d_in[7];
    const float* a_src_rd = (const float*)d_in[8];
    const float* a_dst_rd = (const float*)d_in[9];
    const float* a_src_dr = (const float*)d_in[10];
    const float* a_dst_dr = (const float*)d_in[11];
    const float* a_src_rr = (const float*)d_in[12];
    const float* a_dst_rr = (const float*)d_in[13];
    const float* a_src_dd = (const float*)d_in[14];
    const float* a_dst_dd = (const float*)d_in[15];
    const float* kW      = (const float*)d_in[16];
    const float* kb      = (const float*)d_in[17];
    const float* qv      = (const float*)d_in[18];
    const float* W_out   = (const float*)d_in[19];
    const float* b_out   = (const float*)d_in[20];
    const int* rd_src = (const int*)d_in[21];
    const int* rd_dst = (const int*)d_in[22];
    const int* dr_src = (const int*)d_in[23];
    const int* dr_dst = (const int*)d_in[24];
    const int* rr_src = (const int*)d_in[25];
    const int* rr_dst = (const int*)d_in[26];
    const int* dd_src = (const int*)d_in[27];
    const int* dd_dst = (const int*)d_in[28];

    float* out = (float*)d_out;

    float *p_xd, *p_hr, *p_hd, *p_ord, *p_odr, *p_orr, *p_odd;
    float *p_sr, *p_sd, *p_scores, *p_attn;
    float *p_wdt, *p_wprt, *p_wpdt, *p_kwt;
    int *p_cnt, *p_fill, *p_rptr, *p_ssort;
    cudaGetSymbolAddress((void**)&p_xd, g_xd);
    cudaGetSymbolAddress((void**)&p_hr, g_hr);
    cudaGetSymbolAddress((void**)&p_hd, g_hd);
    cudaGetSymbolAddress((void**)&p_ord, g_out_rd);
    cudaGetSymbolAddress((void**)&p_odr, g_out_dr);
    cudaGetSymbolAddress((void**)&p_orr, g_out_rr);
    cudaGetSymbolAddress((void**)&p_odd, g_out_dd);
    cudaGetSymbolAddress((void**)&p_sr, g_s_rna);
    cudaGetSymbolAddress((void**)&p_sd, g_s_dis);
    cudaGetSymbolAddress((void**)&p_cnt, g_cnt);
    cudaGetSymbolAddress((void**)&p_fill, g_fill);
    cudaGetSymbolAddress((void**)&p_rptr, g_rptr);
    cudaGetSymbolAddress((void**)&p_ssort, g_ssort);
    cudaGetSymbolAddress((void**)&p_scores, g_scores);
    cudaGetSymbolAddress((void**)&p_attn, g_attn);
    cudaGetSymbolAddress((void**)&p_wdt, g_wd_t);
    cudaGetSymbolAddress((void**)&p_wprt, g_wpr_t);
    cudaGetSymbolAddress((void**)&p_wpdt, g_wpd_t);
    cudaGetSymbolAddress((void**)&p_kwt, g_kw_t);

    cudaFuncSetAttribute(gemm_ca<0>, cudaFuncAttributeMaxDynamicSharedMemorySize, SMEM_CA);
    cudaFuncSetAttribute(gemm_ca<1>, cudaFuncAttributeMaxDynamicSharedMemorySize, SMEM_CA);

    const dim3 thr(256);
    const int mbr = (N_R + 127) / 128;   // 391
    const int mbd = (N_D + 127) / 128;   // 79

    int* rp_rd = p_rptr + 0 * (N_R + 1);
    int* rp_dr = p_rptr + 1 * (N_R + 1);
    int* rp_rr = p_rptr + 2 * (N_R + 1);
    int* rp_dd = p_rptr + 3 * (N_R + 1);
    int* ss_rd = p_ssort;
    int* ss_dr = ss_rd + E_RD;
    int* ss_rr = ss_dr + E_DR;
    int* ss_dd = ss_rr + E_RR;

    cudaStream_t st0 = 0, st1, st2;
    cudaStreamCreateWithFlags(&st1, cudaStreamNonBlocking);
    cudaStreamCreateWithFlags(&st2, cudaStreamNonBlocking);
    cudaEvent_t ev[10];
    for (int i = 0; i < 10; i++) cudaEventCreateWithFlags(&ev[i], cudaEventDisableTiming);

    // fork for CSR (does not need weight prep)
    cudaEventRecord(ev[0], st0);
    cudaStreamWaitEvent(st2, ev[0], 0);

    // st0: weight prep first, then fork to st1
    prep_w_k<<<80, thr, 0, st0>>>(W_d, Wp_rna, Wp_dis, kW, p_wdt, p_wprt, p_wpdt, p_kwt);
    cudaEventRecord(ev[8], st0);
    cudaStreamWaitEvent(st1, ev[8], 0);

    // st2: CSR build + score clear
    cudaMemsetAsync(p_cnt, 0, CNT_TOT * sizeof(int), st2);
    cudaMemsetAsync(p_fill, 0, CNT_TOT * sizeof(int), st2);
    cudaMemsetAsync(p_scores, 0, 4 * sizeof(float), st2);
    hist4_k<<<(E_TOT + 255) / 256, thr, 0, st2>>>(rd_dst, dr_dst, rr_dst, dd_dst, p_cnt);
    scan4_k<<<4, 1024, 0, st2>>>(p_cnt, p_rptr);
    scatter4_k<<<(E_TOT + 255) / 256, thr, 0, st2>>>(rd_src, rd_dst, dr_src, dr_dst,
                                                     rr_src, rr_dst, dd_src, dd_dst,
                                                     p_rptr, p_fill, p_ssort);

    // st0: disease chain
    gemm_ca<0><<<dim3(2, mbd), thr, SMEM_CA, st0>>>(x_dis, p_wdt, b_d, nullptr,
                                                    p_xd, nullptr, N_D, RNA_IN, D_FEAT);
    gemm_ca<0><<<dim3(2, mbd), thr, SMEM_CA, st0>>>(p_xd, p_wpdt, bp_dis, nullptr,
                                                    p_hd, nullptr, N_D, CC, RNA_IN);
    scores4_k<<<(N_D + 7) / 8, thr, 0, st0>>>(p_hd, a_dst_rd, a_src_dr, a_src_dd, a_dst_dd,
                                              p_sd + 0 * N_D * HH, p_sd + 1 * N_D * HH,
                                              p_sd + 2 * N_D * HH, p_sd + 3 * N_D * HH, N_D);

    // st1: rna chain
    gemm_ca<0><<<dim3(2, mbr), thr, SMEM_CA, st1>>>(x_rna, p_wprt, bp_rna, nullptr,
                                                    p_hr, nullptr, N_R, CC, RNA_IN);
    scores4_k<<<(N_R + 7) / 8, thr, 0, st1>>>(p_hr, a_src_rd, a_dst_dr, a_src_rr, a_dst_rr,
                                              p_sr + 0 * N_R * HH, p_sr + 1 * N_R * HH,
                                              p_sr + 2 * N_R * HH, p_sr + 3 * N_R * HH, N_R);

    // join before aggs
    cudaEventRecord(ev[1], st0);
    cudaEventRecord(ev[2], st1);
    cudaEventRecord(ev[3], st2);
    cudaStreamWaitEvent(st0, ev[2], 0); cudaStreamWaitEvent(st0, ev[3], 0);
    cudaStreamWaitEvent(st1, ev[1], 0); cudaStreamWaitEvent(st1, ev[3], 0);
    cudaStreamWaitEvent(st2, ev[1], 0); cudaStreamWaitEvent(st2, ev[2], 0);

    // st1: rr
    agg_csr_k<<<(N_R * 32 + 255) / 256, thr, 0, st1>>>(rp_rr, ss_rr,
                                                       p_sr + 2 * N_R * HH, p_sr + 3 * N_R * HH,
                                                       p_hr, p_orr, N_R);
    gemm_ca<1><<<dim3(2, mbr), thr, SMEM_CA, st1>>>(p_orr, p_kwt, kb, qv,
                                                    nullptr, p_scores + 1, N_R, CC, CC);
    // st0: dr
    agg_csr_k<<<(N_R * 32 + 255) / 256, thr, 0, st0>>>(rp_dr, ss_dr,
                                                       p_sd + 1 * N_D * HH, p_sr + 1 * N_R * HH,
                                                       p_hd, p_odr, N_R);
    gemm_ca<1><<<dim3(2, mbr), thr, SMEM_CA, st0>>>(p_odr, p_kwt, kb, qv,
                                                    nullptr, p_scores + 0, N_R, CC, CC);
    // st2: rd + dd
    agg_csr_k<<<(N_D * 32 + 255) / 256, thr, 0, st2>>>(rp_rd, ss_rd,
                                                       p_sr + 0 * N_R * HH, p_sd + 0 * N_D * HH,
                                                       p_hr, p_ord, N_D);
    agg_csr_k<<<(N_D * 32 + 255) / 256, thr, 0, st2>>>(rp_dd, ss_dd,
                                                       p_sd + 2 * N_D * HH, p_sd + 3 * N_D * HH,
                                                       p_hd, p_odd, N_D);
    gemm_ca<1><<<dim3(2, mbd), thr, SMEM_CA, st2>>>(p_ord, p_kwt, kb, qv,
                                                    nullptr, p_scores + 2, N_D, CC, CC);
    gemm_ca<1><<<dim3(2, mbd), thr, SMEM_CA, st2>>>(p_odd, p_kwt, kb, qv,
                                                    nullptr, p_scores + 3, N_D, CC, CC);

    // join for softmax
    cudaEventRecord(ev[4], st1);
    cudaEventRecord(ev[5], st2);
    cudaStreamWaitEvent(st0, ev[4], 0);
    cudaStreamWaitEvent(st0, ev[5], 0);
    softmax2_k<<<1, 32, 0, st0>>>(p_scores, p_attn, 1.f / N_R, 1.f / N_D);

    // fork for final GEMMs
    cudaEventRecord(ev[6], st0);
    cudaStreamWaitEvent(st1, ev[6], 0);

    gemm_tc<2><<<dim3(2, mbr), thr, 0, st0>>>(p_odr, p_orr, W_out, b_out, p_attn + 0, nullptr,
                                              out, nullptr, N_R, CC, CC);
    gemm_tc<2><<<dim3(2, mbd), thr, 0, st1>>>(p_ord, p_odd, W_out, b_out, p_attn + 2, nullptr,
                                              out + (size_t)N_R * CC, nullptr, N_D, CC, CC);

    // final join
    cudaEventRecord(ev[7], st1);
    cudaStreamWaitEvent(st0, ev[7], 0);

    for (int i = 0; i < 10; i++) cudaEventDestroy(ev[i]);
    cudaStreamDestroy(st1);
    cudaStreamDestroy(st2);
}

// round 9
// speedup vs baseline: 6.1252x; 1.0997x over previous
#include <cuda_runtime.h>
#include <cstdint>
#include <math.h>

#define N_R 50000
#define N_D 10000
#define HH  8
#define DH  32
#define CC  256
#define RNA_IN 256
#define D_FEAT 512
#define E_RD 200000
#define E_DR 200000
#define E_RR 400000
#define E_DD 50000
#define E_TOT (E_RD + E_DR + E_RR + E_DD)
#define CNT_TOT (2 * N_R + 2 * N_D)

// ---------------- static device scratch ------------------------------------
__device__ float    g_xd[N_D * RNA_IN];
__device__ float    g_hr[N_R * CC];
__device__ float    g_hd[N_D * CC];
__device__ float    g_out_rd[N_D * CC];
__device__ float    g_out_dr[N_R * CC];
__device__ float    g_out_rr[N_R * CC];
__device__ float    g_out_dd[N_D * CC];
__device__ float    g_s_rna[4 * N_R * HH];
__device__ float    g_s_dis[4 * N_D * HH];
__device__ int      g_cnt[CNT_TOT];
__device__ int      g_fill[CNT_TOT];
__device__ int      g_rptr[4 * (N_R + 1)];
__device__ int      g_ssort[E_TOT];
__device__ float    g_scores[4];
__device__ float    g_attn[4];
// transformed weights (tf32-rounded, mma-native blocked layout)
__device__ float    g_wd_t[D_FEAT * RNA_IN];
__device__ float    g_wpr_t[RNA_IN * CC];
__device__ float    g_wpd_t[RNA_IN * CC];
__device__ float    g_kw_t[CC * CC];
__device__ float    g_wo_t[CC * CC];

__device__ __forceinline__ uint32_t f2tf(float f) {
    uint32_t u;
    asm("cvt.rna.tf32.f32 %0, %1;" : "=r"(u) : "f"(f));
    return u;
}

// ================= weight prep: W[K][N] -> blocked n-major tf32 ==============
// Wt[((k/32)*N + n)*32 + k'] with k' = (k%32/8)*8 + ((k%8)&3)*2 + ((k%8)>>2)
__global__ void __launch_bounds__(256)
prep_w_k(const float* __restrict__ wd,  const float* __restrict__ wpr,
         const float* __restrict__ wpd, const float* __restrict__ kw,
         const float* __restrict__ wo,
         float* __restrict__ wdt, float* __restrict__ wprt,
         float* __restrict__ wpdt, float* __restrict__ kwt,
         float* __restrict__ wot)
{
    __shared__ float tile[32][129];
    int b = blockIdx.x;
    const float* src; float* dst; int N, base;
    if (b < 32)      { src = wd;  dst = wdt;  N = RNA_IN; base = 0;  }
    else if (b < 48) { src = wpr; dst = wprt; N = CC;     base = 32; }
    else if (b < 64) { src = wpd; dst = wpdt; N = CC;     base = 48; }
    else if (b < 80) { src = kw;  dst = kwt;  N = CC;     base = 64; }
    else             { src = wo;  dst = wot;  N = CC;     base = 80; }
    int lb = b - base;
    int ntl = N / 128;
    int kt = lb / ntl, nb = lb % ntl;
    int k0 = kt * 32, n0 = nb * 128;
    int tid = threadIdx.x;
#pragma unroll
    for (int it = 0; it < 16; it++) {
        int idx = it * 256 + tid;
        int k = idx >> 7, n = idx & 127;
        tile[k][n] = src[(size_t)(k0 + k) * N + n0 + n];
    }
    __syncthreads();
#pragma unroll
    for (int it = 0; it < 4; it++) {
        int cidx = it * 256 + tid;
        int n = cidx >> 3, c = cidx & 7;
        float4 v;
        float* vp = (float*)&v;
#pragma unroll
        for (int q = 0; q < 4; q++) {
            int kp = c * 4 + q;
            int ks = kp >> 3, r = kp & 7;
            int kl = ks * 8 + (r >> 1) + 4 * (r & 1);
            vp[q] = __uint_as_float(f2tf(tile[kl][n]));
        }
        *(float4*)&dst[((size_t)kt * N + n0 + n) * 32 + c * 4] = v;
    }
}

// =============================================================================
// GEMM (MODE 0/1/3): cp.async, BK=32, B pre-transformed tf32
// MODE 0: C = A0 @ B + bias
// MODE 1: score += sum q[c]*tanh( relu(A0)@B + bias )   (no C write)
// MODE 3: MODE 0 + per-head attention scores for 4 vectors (fused scores4)
// =============================================================================
#define AST 36
#define BST2 40
#define SMEM_CA ((2 * 128 * AST + 2 * 128 * BST2 + 128 + 128 + 256 + 512) * 4)

template <int MODE>
__global__ void __launch_bounds__(256, 2)
gemm_ca(const float* __restrict__ A0, const float* __restrict__ Bt,
        const float* __restrict__ bias, const float* __restrict__ qv,
        float* __restrict__ C, float* __restrict__ score,
        const float* __restrict__ av0, const float* __restrict__ av1,
        const float* __restrict__ av2, const float* __restrict__ av3,
        float* __restrict__ s0, float* __restrict__ s1,
        float* __restrict__ s2, float* __restrict__ s3,
        int M, int N, int K)
{
    extern __shared__ float sm[];
    float* As     = sm;                               // 2*128*AST
    float* Bs     = sm + 2 * 128 * AST;               // 2*128*BST2
    float* bias_s = sm + 2 * 128 * AST + 2 * 128 * BST2;
    float* q_s    = bias_s + 128;
    float* red    = q_s + 128;                        // 256
    float* avs    = red + 256;                        // 4*128

    const int tid  = threadIdx.x;
    const int lane = tid & 31;
    const int warp = tid >> 5;
    const int wm   = warp & 3;
    const int wn   = warp >> 2;
    const int g    = lane >> 2;
    const int t    = lane & 3;
    const int bRow = blockIdx.y * 128;
    const int bCol = blockIdx.x * 128;

    if (tid < 128) {
        bias_s[tid] = bias[bCol + tid];
        if (MODE == 1) q_s[tid] = qv[bCol + tid];
        if (MODE == 3) {
            avs[tid]       = av0[bCol + tid];
            avs[128 + tid] = av1[bCol + tid];
            avs[256 + tid] = av2[bCol + tid];
            avs[384 + tid] = av3[bCol + tid];
        }
    }

    float acc[2][8][4];
#pragma unroll
    for (int mi = 0; mi < 2; mi++)
#pragma unroll
        for (int ni = 0; ni < 8; ni++)
#pragma unroll
            for (int r = 0; r < 4; r++) acc[mi][ni][r] = 0.f;

    auto issue = [&](int k0, int buf) {
        float* a_dst = As + buf * 128 * AST;
        float* b_dst = Bs + buf * 128 * BST2;
#pragma unroll
        for (int it = 0; it < 4; it++) {
            int idx = it * 256 + tid;
            int row = idx >> 3, ch = idx & 7;
            const float* src = A0 + (size_t)(bRow + row) * K + k0 + ch * 4;
            unsigned d = (unsigned)__cvta_generic_to_shared(a_dst + row * AST + ch * 4);
            int sz = (bRow + row < M) ? 16 : 0;
            asm volatile("cp.async.ca.shared.global [%0], [%1], 16, %2;"
                         :: "r"(d), "l"(src), "r"(sz));
        }
        const int kt = k0 >> 5;
#pragma unroll
        for (int it = 0; it < 4; it++) {
            int idx = it * 256 + tid;
            int n = idx >> 3, c = idx & 7;
            const float* src = Bt + ((size_t)kt * N + bCol + n) * 32 + c * 4;
            unsigned d = (unsigned)__cvta_generic_to_shared(b_dst + n * BST2 + c * 4);
            asm volatile("cp.async.ca.shared.global [%0], [%1], 16;"
                         :: "r"(d), "l"(src));
        }
        asm volatile("cp.async.commit_group;");
    };

    const int S = K / 32;
    issue(0, 0);
    int buf = 0;

    for (int s = 0; s < S; s++) {
        asm volatile("cp.async.wait_group 0;");
        __syncthreads();
        if (s + 1 < S) issue((s + 1) * 32, buf ^ 1);

        const float* ap = As + buf * 128 * AST;
        const float* bp = Bs + buf * 128 * BST2;
#pragma unroll
        for (int ks = 0; ks < 4; ks++) {
            uint32_t af[2][4];
#pragma unroll
            for (int mi = 0; mi < 2; mi++) {
                const int mr = wm * 32 + mi * 16;
                float v0 = ap[(mr + g)     * AST + ks * 8 + t];
                float v1 = ap[(mr + g + 8) * AST + ks * 8 + t];
                float v2 = ap[(mr + g)     * AST + ks * 8 + t + 4];
                float v3 = ap[(mr + g + 8) * AST + ks * 8 + t + 4];
                if (MODE == 1) {
                    v0 = fmaxf(v0, 0.f); v1 = fmaxf(v1, 0.f);
                    v2 = fmaxf(v2, 0.f); v3 = fmaxf(v3, 0.f);
                }
                af[mi][0] = f2tf(v0); af[mi][1] = f2tf(v1);
                af[mi][2] = f2tf(v2); af[mi][3] = f2tf(v3);
            }
#pragma unroll
            for (int ni = 0; ni < 8; ni++) {
                const int n8 = wn * 8 + ni;
                float2 bv = *(const float2*)&bp[(n8 * 8 + g) * BST2 + ks * 8 + t * 2];
                uint32_t bx = __float_as_uint(bv.x), by = __float_as_uint(bv.y);
#pragma unroll
                for (int mi = 0; mi < 2; mi++) {
                    asm volatile(
                        "mma.sync.aligned.m16n8k8.row.col.f32.tf32.tf32.f32 "
                        "{%0,%1,%2,%3}, {%4,%5,%6,%7}, {%8,%9}, {%0,%1,%2,%3};"
                        : "+f"(acc[mi][ni][0]), "+f"(acc[mi][ni][1]),
                          "+f"(acc[mi][ni][2]), "+f"(acc[mi][ni][3])
                        : "r"(af[mi][0]), "r"(af[mi][1]), "r"(af[mi][2]), "r"(af[mi][3]),
                          "r"(bx), "r"(by));
                }
            }
        }
        buf ^= 1;
    }

    if (MODE == 0 || MODE == 3) {
#pragma unroll
        for (int mi = 0; mi < 2; mi++) {
            const int r0 = bRow + wm * 32 + mi * 16 + g;
#pragma unroll
            for (int ni = 0; ni < 8; ni++) {
                const int cl = wn * 64 + ni * 8 + t * 2;
                const int c0 = bCol + cl;
                if (r0 < M) {
                    float2 v = make_float2(acc[mi][ni][0] + bias_s[cl],
                                           acc[mi][ni][1] + bias_s[cl + 1]);
                    *(float2*)&C[(size_t)r0 * N + c0] = v;
                }
                if (r0 + 8 < M) {
                    float2 v = make_float2(acc[mi][ni][2] + bias_s[cl],
                                           acc[mi][ni][3] + bias_s[cl + 1]);
                    *(float2*)&C[(size_t)(r0 + 8) * N + c0] = v;
                }
            }
        }
        if (MODE == 3) {
            // per-head attention scores: head = 4*bx + wn*2 + (ni>=4)
            float* svs[4] = {s0, s1, s2, s3};
            const int headbase = 4 * blockIdx.x + wn * 2;
#pragma unroll
            for (int v = 0; v < 4; v++) {
#pragma unroll
                for (int mi = 0; mi < 2; mi++) {
                    float sA0 = 0.f, sA1 = 0.f, sB0 = 0.f, sB1 = 0.f;
#pragma unroll
                    for (int ni = 0; ni < 8; ni++) {
                        const int cl = wn * 64 + ni * 8 + t * 2;
                        float a0v = avs[v * 128 + cl];
                        float a1v = avs[v * 128 + cl + 1];
                        float dA = (acc[mi][ni][0] + bias_s[cl]) * a0v +
                                   (acc[mi][ni][1] + bias_s[cl + 1]) * a1v;
                        float dB = (acc[mi][ni][2] + bias_s[cl]) * a0v +
                                   (acc[mi][ni][3] + bias_s[cl + 1]) * a1v;
                        if (ni < 4) { sA0 += dA; sB0 += dB; }
                        else        { sA1 += dA; sB1 += dB; }
                    }
                    sA0 += __shfl_xor_sync(0xffffffffu, sA0, 1);
                    sA0 += __shfl_xor_sync(0xffffffffu, sA0, 2);
                    sA1 += __shfl_xor_sync(0xffffffffu, sA1, 1);
                    sA1 += __shfl_xor_sync(0xffffffffu, sA1, 2);
                    sB0 += __shfl_xor_sync(0xffffffffu, sB0, 1);
                    sB0 += __shfl_xor_sync(0xffffffffu, sB0, 2);
                    sB1 += __shfl_xor_sync(0xffffffffu, sB1, 1);
                    sB1 += __shfl_xor_sync(0xffffffffu, sB1, 2);
                    if (t == 0) {
                        int nodeA = bRow + wm * 32 + mi * 16 + g;
                        int nodeB = nodeA + 8;
                        if (nodeA < M) {
                            svs[v][nodeA * HH + headbase]     = sA0;
                            svs[v][nodeA * HH + headbase + 1] = sA1;
                        }
                        if (nodeB < M) {
                            svs[v][nodeB * HH + headbase]     = sB0;
                            svs[v][nodeB * HH + headbase + 1] = sB1;
                        }
                    }
                }
            }
        }
    } else {
        float local = 0.f;
#pragma unroll
        for (int mi = 0; mi < 2; mi++) {
            const int r0 = bRow + wm * 32 + mi * 16 + g;
#pragma unroll
            for (int ni = 0; ni < 8; ni++) {
                const int cl = wn * 64 + ni * 8 + t * 2;
                if (r0 < M)
                    local += q_s[cl]     * tanhf(acc[mi][ni][0] + bias_s[cl]) +
                             q_s[cl + 1] * tanhf(acc[mi][ni][1] + bias_s[cl + 1]);
                if (r0 + 8 < M)
                    local += q_s[cl]     * tanhf(acc[mi][ni][2] + bias_s[cl]) +
                             q_s[cl + 1] * tanhf(acc[mi][ni][3] + bias_s[cl + 1]);
            }
        }
        red[tid] = local;
        __syncthreads();
        for (int st = 128; st > 0; st >>= 1) {
            if (tid < st) red[tid] += red[tid + st];
            __syncthreads();
        }
        if (tid == 0) atomicAdd(score, red[0]);
    }
}

// =============================================================================
// MODE2 GEMM: C = (w0*relu(A0)+w1*relu(A1)) @ B + bias, dual-A cp.async
// =============================================================================
#define SMEM_CA2 ((2 * 2 * 128 * AST + 2 * 128 * BST2 + 128) * 4)

__global__ void __launch_bounds__(256, 1)
gemm_ca2(const float* __restrict__ A0, const float* __restrict__ A1,
         const float* __restrict__ Bt, const float* __restrict__ bias,
         const float* __restrict__ wts, float* __restrict__ C,
         int M, int N, int K)
{
    extern __shared__ float sm[];
    float* A0s    = sm;                       // 2*128*AST
    float* A1s    = sm + 2 * 128 * AST;       // 2*128*AST
    float* Bs     = sm + 4 * 128 * AST;       // 2*128*BST2
    float* bias_s = sm + 4 * 128 * AST + 2 * 128 * BST2;

    const int tid  = threadIdx.x;
    const int lane = tid & 31;
    const int warp = tid >> 5;
    const int wm   = warp & 3;
    const int wn   = warp >> 2;
    const int g    = lane >> 2;
    const int t    = lane & 3;
    const int bRow = blockIdx.y * 128;
    const int bCol = blockIdx.x * 128;

    if (tid < 128) bias_s[tid] = bias[bCol + tid];
    const float w0 = wts[0], w1 = wts[1];

    float acc[2][8][4];
#pragma unroll
    for (int mi = 0; mi < 2; mi++)
#pragma unroll
        for (int ni = 0; ni < 8; ni++)
#pragma unroll
            for (int r = 0; r < 4; r++) acc[mi][ni][r] = 0.f;

    auto issue = [&](int k0, int buf) {
        float* a0_dst = A0s + buf * 128 * AST;
        float* a1_dst = A1s + buf * 128 * AST;
        float* b_dst  = Bs + buf * 128 * BST2;
#pragma unroll
        for (int it = 0; it < 4; it++) {
            int idx = it * 256 + tid;
            int row = idx >> 3, ch = idx & 7;
            int sz = (bRow + row < M) ? 16 : 0;
            const float* src0 = A0 + (size_t)(bRow + row) * K + k0 + ch * 4;
            unsigned d0 = (unsigned)__cvta_generic_to_shared(a0_dst + row * AST + ch * 4);
            asm volatile("cp.async.ca.shared.global [%0], [%1], 16, %2;"
                         :: "r"(d0), "l"(src0), "r"(sz));
            const float* src1 = A1 + (size_t)(bRow + row) * K + k0 + ch * 4;
            unsigned d1 = (unsigned)__cvta_generic_to_shared(a1_dst + row * AST + ch * 4);
            asm volatile("cp.async.ca.shared.global [%0], [%1], 16, %2;"
                         :: "r"(d1), "l"(src1), "r"(sz));
        }
        const int kt = k0 >> 5;
#pragma unroll
        for (int it = 0; it < 4; it++) {
            int idx = it * 256 + tid;
            int n = idx >> 3, c = idx & 7;
            const float* src = Bt + ((size_t)kt * N + bCol + n) * 32 + c * 4;
            unsigned d = (unsigned)__cvta_generic_to_shared(b_dst + n * BST2 + c * 4);
            asm volatile("cp.async.ca.shared.global [%0], [%1], 16;"
                         :: "r"(d), "l"(src));
        }
        asm volatile("cp.async.commit_group;");
    };

    const int S = K / 32;
    issue(0, 0);
    int buf = 0;

    for (int s = 0; s < S; s++) {
        asm volatile("cp.async.wait_group 0;");
        __syncthreads();
        if (s + 1 < S) issue((s + 1) * 32, buf ^ 1);

        const float* a0p = A0s + buf * 128 * AST;
        const float* a1p = A1s + buf * 128 * AST;
        const float* bp  = Bs + buf * 128 * BST2;
#pragma unroll
        for (int ks = 0; ks < 4; ks++) {
            uint32_t af[2][4];
#pragma unroll
            for (int mi = 0; mi < 2; mi++) {
                const int mr = wm * 32 + mi * 16;
                const int o0 = (mr + g)     * AST + ks * 8 + t;
                const int o1 = (mr + g + 8) * AST + ks * 8 + t;
                float v0 = w0 * fmaxf(a0p[o0], 0.f)     + w1 * fmaxf(a1p[o0], 0.f);
                float v1 = w0 * fmaxf(a0p[o1], 0.f)     + w1 * fmaxf(a1p[o1], 0.f);
                float v2 = w0 * fmaxf(a0p[o0 + 4], 0.f) + w1 * fmaxf(a1p[o0 + 4], 0.f);
                float v3 = w0 * fmaxf(a0p[o1 + 4], 0.f) + w1 * fmaxf(a1p[o1 + 4], 0.f);
                af[mi][0] = f2tf(v0); af[mi][1] = f2tf(v1);
                af[mi][2] = f2tf(v2); af[mi][3] = f2tf(v3);
            }
#pragma unroll
            for (int ni = 0; ni < 8; ni++) {
                const int n8 = wn * 8 + ni;
                float2 bv = *(const float2*)&bp[(n8 * 8 + g) * BST2 + ks * 8 + t * 2];
                uint32_t bx = __float_as_uint(bv.x), by = __float_as_uint(bv.y);
#pragma unroll
                for (int mi = 0; mi < 2; mi++) {
                    asm volatile(
                        "mma.sync.aligned.m16n8k8.row.col.f32.tf32.tf32.f32 "
                        "{%0,%1,%2,%3}, {%4,%5,%6,%7}, {%8,%9}, {%0,%1,%2,%3};"
                        : "+f"(acc[mi][ni][0]), "+f"(acc[mi][ni][1]),
                          "+f"(acc[mi][ni][2]), "+f"(acc[mi][ni][3])
                        : "r"(af[mi][0]), "r"(af[mi][1]), "r"(af[mi][2]), "r"(af[mi][3]),
                          "r"(bx), "r"(by));
                }
            }
        }
        buf ^= 1;
    }

#pragma unroll
    for (int mi = 0; mi < 2; mi++) {
        const int r0 = bRow + wm * 32 + mi * 16 + g;
#pragma unroll
        for (int ni = 0; ni < 8; ni++) {
            const int cl = wn * 64 + ni * 8 + t * 2;
            const int c0 = bCol + cl;
            if (r0 < M) {
                float2 v = make_float2(acc[mi][ni][0] + bias_s[cl],
                                       acc[mi][ni][1] + bias_s[cl + 1]);
                *(float2*)&C[(size_t)r0 * N + c0] = v;
            }
            if (r0 + 8 < M) {
                float2 v = make_float2(acc[mi][ni][2] + bias_s[cl],
                                       acc[mi][ni][3] + bias_s[cl + 1]);
                *(float2*)&C[(size_t)(r0 + 8) * N + c0] = v;
            }
        }
    }
}

// ================= fused CSR build ==========================================
__global__ void hist4_k(const int* __restrict__ d0, const int* __restrict__ d1,
                        const int* __restrict__ d2, const int* __restrict__ d3,
                        int* __restrict__ cnt)
{
    int i = blockIdx.x * blockDim.x + threadIdx.x;
    if (i < E_RD)                     atomicAdd(&cnt[d0[i]], 1);
    else if (i < E_RD + E_DR)         atomicAdd(&cnt[N_D + d1[i - E_RD]], 1);
    else if (i < E_RD + E_DR + E_RR)  atomicAdd(&cnt[N_D + N_R + d2[i - E_RD - E_DR]], 1);
    else if (i < E_TOT)               atomicAdd(&cnt[N_D + 2 * N_R + d3[i - E_RD - E_DR - E_RR]], 1);
}

__global__ void __launch_bounds__(1024)
scan4_k(const int* __restrict__ cnt, int* __restrict__ rptr_all)
{
    __shared__ int wsum[32];
    __shared__ int s_carry;
    const int b = blockIdx.x;
    const int n    = (b == 0 || b == 3) ? N_D : N_R;
    const int cofs = (b == 0) ? 0 : (b == 1) ? N_D : (b == 2) ? (N_D + N_R) : (N_D + 2 * N_R);
    const int* c = cnt + cofs;
    int* rptr = rptr_all + b * (N_R + 1);

    const int tid = threadIdx.x;
    const int lane = tid & 31, wid = tid >> 5;
    if (tid == 0) s_carry = 0;
    __syncthreads();
    for (int base = 0; base < n; base += 1024) {
        int i = base + tid;
        int v = (i < n) ? c[i] : 0;
        int x = v;
#pragma unroll
        for (int o = 1; o < 32; o <<= 1) {
            int y = __shfl_up_sync(0xffffffffu, x, o);
            if (lane >= o) x += y;
        }
        if (lane == 31) wsum[wid] = x;
        __syncthreads();
        if (wid == 0) {
            int tv = wsum[lane];
#pragma unroll
            for (int o = 1; o < 32; o <<= 1) {
                int y = __shfl_up_sync(0xffffffffu, tv, o);
                if (lane >= o) tv += y;
            }
            wsum[lane] = tv;
        }
        __syncthreads();
        int incl = x + (wid > 0 ? wsum[wid - 1] : 0);
        int carry = s_carry;
        if (i < n) rptr[i] = carry + incl - v;
        __syncthreads();
        if (tid == 1023) s_carry = carry + incl;
        __syncthreads();
    }
    if (tid == 0) rptr[n] = s_carry;
}

__global__ void scatter4_k(const int* __restrict__ s0, const int* __restrict__ d0,
                           const int* __restrict__ s1, const int* __restrict__ d1,
                           const int* __restrict__ s2, const int* __restrict__ d2,
                           const int* __restrict__ s3, const int* __restrict__ d3,
                           const int* __restrict__ rptr_all,
                           int* __restrict__ fill, int* __restrict__ ssort)
{
    int i = blockIdx.x * blockDim.x + threadIdx.x;
    const int* sp; const int* dp; const int* rp; int* fl; int* ss; int e;
    if (i < E_RD) {
        e = i; sp = s0; dp = d0; rp = rptr_all; fl = fill; ss = ssort;
    } else if (i < E_RD + E_DR) {
        e = i - E_RD; sp = s1; dp = d1; rp = rptr_all + (N_R + 1);
        fl = fill + N_D; ss = ssort + E_RD;
    } else if (i < E_RD + E_DR + E_RR) {
        e = i - E_RD - E_DR; sp = s2; dp = d2; rp = rptr_all + 2 * (N_R + 1);
        fl = fill + N_D + N_R; ss = ssort + E_RD + E_DR;
    } else if (i < E_TOT) {
        e = i - E_RD - E_DR - E_RR; sp = s3; dp = d3; rp = rptr_all + 3 * (N_R + 1);
        fl = fill + N_D + 2 * N_R; ss = ssort + E_RD + E_DR + E_RR;
    } else return;
    int d = dp[e];
    int pos = rp[d] + atomicAdd(&fl[d], 1);
    ss[pos] = sp[e];
}

// ============ edge aggregation: exact max pass + parallel sum pass ==========
__device__ __forceinline__ float lrelu(float x) { return x > 0.f ? x : 0.2f * x; }

__global__ void __launch_bounds__(256)
agg_csr_k(const int* __restrict__ rptr, const int* __restrict__ ssort,
          const float* __restrict__ ssrc, const float* __restrict__ sdst,
          const float* __restrict__ x, float* __restrict__ out, int Nd)
{
    const int warp = (blockIdx.x * blockDim.x + threadIdx.x) >> 5;
    const int lane = threadIdx.x & 31;
    if (warp >= Nd) return;
    const int beg = rptr[warp], end = rptr[warp + 1];

    const int h1 = lane & 7;
    const int j  = lane >> 3;
    const float sd1 = sdst[warp * HH + h1];
    float mloc = -INFINITY;
    for (int p = beg + j; p < end; p += 4) {
        int src = ssort[p];
        mloc = fmaxf(mloc, lrelu(ssrc[src * HH + h1] + sd1));
    }
    mloc = fmaxf(mloc, __shfl_xor_sync(0xffffffffu, mloc, 8));
    mloc = fmaxf(mloc, __shfl_xor_sync(0xffffffffu, mloc, 16));

    const int h2 = lane >> 2;
    const float m2  = __shfl_sync(0xffffffffu, mloc, h2);
    const float sd2 = __shfl_sync(0xffffffffu, sd1, h2);

    float s = 0.f;
    float a0 = 0.f, a1 = 0.f, a2 = 0.f, a3 = 0.f;
    float a4 = 0.f, a5 = 0.f, a6 = 0.f, a7 = 0.f;
    for (int p = beg; p < end; p++) {
        int src = ssort[p];
        float w = expf(lrelu(ssrc[src * HH + h2] + sd2) - m2);
        s += w;
        const float4* xp = (const float4*)(x + (size_t)src * CC + lane * 8);
        float4 v0 = xp[0], v1 = xp[1];
        a0 += w * v0.x; a1 += w * v0.y; a2 += w * v0.z; a3 += w * v0.w;
        a4 += w * v1.x; a5 += w * v1.y; a6 += w * v1.z; a7 += w * v1.w;
    }
    float inv = 1.f / (s + 1e-16f);
    float* op = out + (size_t)warp * CC + lane * 8;
    *(float4*)op       = make_float4(a0 * inv, a1 * inv, a2 * inv, a3 * inv);
    *(float4*)(op + 4) = make_float4(a4 * inv, a5 * inv, a6 * inv, a7 * inv);
}

__global__ void softmax2_k(const float* __restrict__ scores, float* __restrict__ attn,
                           float invNr, float invNd)
{
    if (threadIdx.x == 0 && blockIdx.x == 0) {
        float s0 = scores[0] * invNr, s1 = scores[1] * invNr;
        float mx = fmaxf(s0, s1);
        float e0 = expf(s0 - mx), e1 = expf(s1 - mx);
        attn[0] = e0 / (e0 + e1);
        attn[1] = e1 / (e0 + e1);
        s0 = scores[2] * invNd; s1 = scores[3] * invNd;
        mx = fmaxf(s0, s1);
        e0 = expf(s0 - mx); e1 = expf(s1 - mx);
        attn[2] = e0 / (e0 + e1);
        attn[3] = e1 / (e0 + e1);
    }
}

// ---------------------------------------------------------------------------
extern "C" void kernel_launch(void* const* d_in, const int* in_sizes, int n_in,
                              void* d_out, int out_size)
{
    const float* x_rna   = (const float*)d_in[0];
    const float* x_dis   = (const float*)d_in[1];
    const float* W_d     = (const float*)d_in[2];
    const float* b_d     = (const float*)d_in[3];
    const float* Wp_rna  = (const float*)d_in[4];
    const float* bp_rna  = (const float*)d_in[5];
    const float* Wp_dis  = (const float*)d_in[6];
    const float* bp_dis  = (const float*)d_in[7];
    const float* a_src_rd = (const float*)d_in[8];
    const float* a_dst_rd = (const float*)d_in[9];
    const float* a_src_dr = (const float*)d_in[10];
    const float* a_dst_dr = (const float*)d_in[11];
    const float* a_src_rr = (const float*)d_in[12];
    const float* a_dst_rr = (const float*)d_in[13];
    const float* a_src_dd = (const float*)d_in[14];
    const float* a_dst_dd = (const float*)d_in[15];
    const float* kW      = (const float*)d_in[16];
    const float* kb      = (const float*)d_in[17];
    const float* qv      = (const float*)d_in[18];
    const float* W_out   = (const float*)d_in[19];
    const float* b_out   = (const float*)d_in[20];
    const int* rd_src = (const int*)d_in[21];
    const int* rd_dst = (const int*)d_in[22];
    const int* dr_src = (const int*)d_in[23];
    const int* dr_dst = (const int*)d_in[24];
    const int* rr_src = (const int*)d_in[25];
    const int* rr_dst = (const int*)d_in[26];
    const int* dd_src = (const int*)d_in[27];
    const int* dd_dst = (const int*)d_in[28];

    float* out = (float*)d_out;

    float *p_xd, *p_hr, *p_hd, *p_ord, *p_odr, *p_orr, *p_odd;
    float *p_sr, *p_sd, *p_scores, *p_attn;
    float *p_wdt, *p_wprt, *p_wpdt, *p_kwt, *p_wot;
    int *p_cnt, *p_fill, *p_rptr, *p_ssort;
    cudaGetSymbolAddress((void**)&p_xd, g_xd);
    cudaGetSymbolAddress((void**)&p_hr, g_hr);
    cudaGetSymbolAddress((void**)&p_hd, g_hd);
    cudaGetSymbolAddress((void**)&p_ord, g_out_rd);
    cudaGetSymbolAddress((void**)&p_odr, g_out_dr);
    cudaGetSymbolAddress((void**)&p_orr, g_out_rr);
    cudaGetSymbolAddress((void**)&p_odd, g_out_dd);
    cudaGetSymbolAddress((void**)&p_sr, g_s_rna);
    cudaGetSymbolAddress((void**)&p_sd, g_s_dis);
    cudaGetSymbolAddress((void**)&p_cnt, g_cnt);
    cudaGetSymbolAddress((void**)&p_fill, g_fill);
    cudaGetSymbolAddress((void**)&p_rptr, g_rptr);
    cudaGetSymbolAddress((void**)&p_ssort, g_ssort);
    cudaGetSymbolAddress((void**)&p_scores, g_scores);
    cudaGetSymbolAddress((void**)&p_attn, g_attn);
    cudaGetSymbolAddress((void**)&p_wdt, g_wd_t);
    cudaGetSymbolAddress((void**)&p_wprt, g_wpr_t);
    cudaGetSymbolAddress((void**)&p_wpdt, g_wpd_t);
    cudaGetSymbolAddress((void**)&p_kwt, g_kw_t);
    cudaGetSymbolAddress((void**)&p_wot, g_wo_t);

    cudaFuncSetAttribute(gemm_ca<0>, cudaFuncAttributeMaxDynamicSharedMemorySize, SMEM_CA);
    cudaFuncSetAttribute(gemm_ca<1>, cudaFuncAttributeMaxDynamicSharedMemorySize, SMEM_CA);
    cudaFuncSetAttribute(gemm_ca<3>, cudaFuncAttributeMaxDynamicSharedMemorySize, SMEM_CA);
    cudaFuncSetAttribute(gemm_ca2, cudaFuncAttributeMaxDynamicSharedMemorySize, SMEM_CA2);

    const dim3 thr(256);
    const int mbr = (N_R + 127) / 128;   // 391
    const int mbd = (N_D + 127) / 128;   // 79

    int* rp_rd = p_rptr + 0 * (N_R + 1);
    int* rp_dr = p_rptr + 1 * (N_R + 1);
    int* rp_rr = p_rptr + 2 * (N_R + 1);
    int* rp_dd = p_rptr + 3 * (N_R + 1);
    int* ss_rd = p_ssort;
    int* ss_dr = ss_rd + E_RD;
    int* ss_rr = ss_dr + E_DR;
    int* ss_dd = ss_rr + E_RR;

    cudaStream_t st0 = 0, st1, st2;
    cudaStreamCreateWithFlags(&st1, cudaStreamNonBlocking);
    cudaStreamCreateWithFlags(&st2, cudaStreamNonBlocking);
    cudaEvent_t ev[10];
    for (int i = 0; i < 10; i++) cudaEventCreateWithFlags(&ev[i], cudaEventDisableTiming);

    // fork for CSR (independent of weight prep)
    cudaEventRecord(ev[0], st0);
    cudaStreamWaitEvent(st2, ev[0], 0);

    // st0: weight prep first, then fork to st1
    prep_w_k<<<96, thr, 0, st0>>>(W_d, Wp_rna, Wp_dis, kW, W_out,
                                  p_wdt, p_wprt, p_wpdt, p_kwt, p_wot);
    cudaEventRecord(ev[8], st0);
    cudaStreamWaitEvent(st1, ev[8], 0);

    // st2: CSR build + score clear
    cudaMemsetAsync(p_cnt, 0, CNT_TOT * sizeof(int), st2);
    cudaMemsetAsync(p_fill, 0, CNT_TOT * sizeof(int), st2);
    cudaMemsetAsync(p_scores, 0, 4 * sizeof(float), st2);
    hist4_k<<<(E_TOT + 255) / 256, thr, 0, st2>>>(rd_dst, dr_dst, rr_dst, dd_dst, p_cnt);
    scan4_k<<<4, 1024, 0, st2>>>(p_cnt, p_rptr);
    scatter4_k<<<(E_TOT + 255) / 256, thr, 0, st2>>>(rd_src, rd_dst, dr_src, dr_dst,
                                                     rr_src, rr_dst, dd_src, dd_dst,
                                                     p_rptr, p_fill, p_ssort);

    // st0: disease chain (xd -> hd with fused scores)
    gemm_ca<0><<<dim3(2, mbd), thr, SMEM_CA, st0>>>(x_dis, p_wdt, b_d, nullptr,
                                                    p_xd, nullptr,
                                                    nullptr, nullptr, nullptr, nullptr,
                                                    nullptr, nullptr, nullptr, nullptr,
                                                    N_D, RNA_IN, D_FEAT);
    gemm_ca<3><<<dim3(2, mbd), thr, SMEM_CA, st0>>>(p_xd, p_wpdt, bp_dis, nullptr,
                                                    p_hd, nullptr,
                                                    a_dst_rd, a_src_dr, a_src_dd, a_dst_dd,
                                                    p_sd + 0 * N_D * HH, p_sd + 1 * N_D * HH,
                                                    p_sd + 2 * N_D * HH, p_sd + 3 * N_D * HH,
                                                    N_D, CC, RNA_IN);

    // st1: rna chain (hr with fused scores)
    gemm_ca<3><<<dim3(2, mbr), thr, SMEM_CA, st1>>>(x_rna, p_wprt, bp_rna, nullptr,
                                                    p_hr, nullptr,
                                                    a_src_rd, a_dst_dr, a_src_rr, a_dst_rr,
                                                    p_sr + 0 * N_R * HH, p_sr + 1 * N_R * HH,
                                                    p_sr + 2 * N_R * HH, p_sr + 3 * N_R * HH,
                                                    N_R, CC, RNA_IN);

    // join before aggs
    cudaEventRecord(ev[1], st0);
    cudaEventRecord(ev[2], st1);
    cudaEventRecord(ev[3], st2);
    cudaStreamWaitEvent(st0, ev[2], 0); cudaStreamWaitEvent(st0, ev[3], 0);
    cudaStreamWaitEvent(st1, ev[1], 0); cudaStreamWaitEvent(st1, ev[3], 0);
    cudaStreamWaitEvent(st2, ev[1], 0); cudaStreamWaitEvent(st2, ev[2], 0);

    // st1: rr
    agg_csr_k<<<(N_R * 32 + 255) / 256, thr, 0, st1>>>(rp_rr, ss_rr,
                                                       p_sr + 2 * N_R * HH, p_sr + 3 * N_R * HH,
                                                       p_hr, p_orr, N_R);
    gemm_ca<1><<<dim3(2, mbr), thr, SMEM_CA, st1>>>(p_orr, p_kwt, kb, qv,
                                                    nullptr, p_scores + 1,
                                                    nullptr, nullptr, nullptr, nullptr,
                                                    nullptr, nullptr, nullptr, nullptr,
                                                    N_R, CC, CC);
    // st0: dr
    agg_csr_k<<<(N_R * 32 + 255) / 256, thr, 0, st0>>>(rp_dr, ss_dr,
                                                       p_sd + 1 * N_D * HH, p_sr + 1 * N_R * HH,
                                                       p_hd, p_odr, N_R);
    gemm_ca<1><<<dim3(2, mbr), thr, SMEM_CA, st0>>>(p_odr, p_kwt, kb, qv,
                                                    nullptr, p_scores + 0,
                                                    nullptr, nullptr, nullptr, nullptr,
                                                    nullptr, nullptr, nullptr, nullptr,
                                                    N_R, CC, CC);
    // st2: rd + dd
    agg_csr_k<<<(N_D * 32 + 255) / 256, thr, 0, st2>>>(rp_rd, ss_rd,
                                                       p_sr + 0 * N_R * HH, p_sd + 0 * N_D * HH,
                                                       p_hr, p_ord, N_D);
    agg_csr_k<<<(N_D * 32 + 255) / 256, thr, 0, st2>>>(rp_dd, ss_dd,
                                                       p_sd + 2 * N_D * HH, p_sd + 3 * N_D * HH,
                                                       p_hd, p_odd, N_D);
    gemm_ca<1><<<dim3(2, mbd), thr, SMEM_CA, st2>>>(p_ord, p_kwt, kb, qv,
                                                    nullptr, p_scores + 2,
                                                    nullptr, nullptr, nullptr, nullptr,
                                                    nullptr, nullptr, nullptr, nullptr,
                                                    N_D, CC, CC);
    gemm_ca<1><<<dim3(2, mbd), thr, SMEM_CA, st2>>>(p_odd, p_kwt, kb, qv,
                                                    nullptr, p_scores + 3,
                                                    nullptr, nullptr, nullptr, nullptr,
                                                    nullptr, nullptr, nullptr, nullptr,
                                                    N_D, CC, CC);

    // join for softmax
    cudaEventRecord(ev[4], st1);
    cudaEventRecord(ev[5], st2);
    cudaStreamWaitEvent(st0, ev[4], 0);
    cudaStreamWaitEvent(st0, ev[5], 0);
    softmax2_k<<<1, 32, 0, st0>>>(p_scores, p_attn, 1.f / N_R, 1.f / N_D);

    // fork for final GEMMs
    cudaEventRecord(ev[6], st0);
    cudaStreamWaitEvent(st1, ev[6], 0);

    gemm_ca2<<<dim3(2, mbr), thr, SMEM_CA2, st0>>>(p_odr, p_orr, p_wot, b_out,
                                                   p_attn + 0, out, N_R, CC, CC);
    gemm_ca2<<<dim3(2, mbd), thr, SMEM_CA2, st1>>>(p_ord, p_odd, p_wot, b_out,
                                                   p_attn + 2, out + (size_t)N_R * CC,
                                                   N_D, CC, CC);

    // final join
    cudaEventRecord(ev[7], st1);
    cudaStreamWaitEvent(st0, ev[7], 0);

    for (int i = 0; i < 10; i++) cudaEventDestroy(ev[i]);
    cudaStreamDestroy(st1);
    cudaStreamDestroy(st2);
}

// round 10
// speedup vs baseline: 6.2124x; 1.0142x over previous
#include <cuda_runtime.h>
#include <cstdint>
#include <math.h>

#define N_R 50000
#define N_D 10000
#define HH  8
#define DH  32
#define CC  256
#define RNA_IN 256
#define D_FEAT 512
#define E_RD 200000
#define E_DR 200000
#define E_RR 400000
#define E_DD 50000
#define E_TOT (E_RD + E_DR + E_RR + E_DD)
#define CNT_TOT (2 * N_R + 2 * N_D)
#define MP 50048                  // 128-aligned pad boundary (391*128)
#define MT (MP + N_D)             // 60048 total concatenated rows

// ---------------- static device scratch ------------------------------------
__device__ float    g_xd[N_D * RNA_IN];
__device__ float    g_hr[N_R * CC];
__device__ float    g_hd[N_D * CC];
__device__ float    g_bufA[(size_t)MT * CC];   // [out_dr | pad | out_rd]
__device__ float    g_bufB[(size_t)MT * CC];   // [out_rr | pad | out_dd]
__device__ float    g_s_rna[4 * N_R * HH];
__device__ float    g_s_dis[4 * N_D * HH];
__device__ int      g_cnt[CNT_TOT];
__device__ int      g_fill[CNT_TOT];
__device__ int      g_rptr[4 * (N_R + 1)];
__device__ int      g_ssort[E_TOT];
__device__ float    g_scores[4];
__device__ float    g_attn[4];
// transformed weights (tf32-rounded, mma-native blocked layout)
__device__ float    g_wd_t[D_FEAT * RNA_IN];
__device__ float    g_wpr_t[RNA_IN * CC];
__device__ float    g_wpd_t[RNA_IN * CC];
__device__ float    g_kw_t[CC * CC];
__device__ float    g_wo_t[CC * CC];

__device__ __forceinline__ uint32_t f2tf(float f) {
    uint32_t u;
    asm("cvt.rna.tf32.f32 %0, %1;" : "=r"(u) : "f"(f));
    return u;
}

// ================= weight prep: W[K][N] -> blocked n-major tf32 ==============
__global__ void __launch_bounds__(256)
prep_w_k(const float* __restrict__ wd,  const float* __restrict__ wpr,
         const float* __restrict__ wpd, const float* __restrict__ kw,
         const float* __restrict__ wo,
         float* __restrict__ wdt, float* __restrict__ wprt,
         float* __restrict__ wpdt, float* __restrict__ kwt,
         float* __restrict__ wot)
{
    __shared__ float tile[32][129];
    int b = blockIdx.x;
    const float* src; float* dst; int N, base;
    if (b < 32)      { src = wd;  dst = wdt;  N = RNA_IN; base = 0;  }
    else if (b < 48) { src = wpr; dst = wprt; N = CC;     base = 32; }
    else if (b < 64) { src = wpd; dst = wpdt; N = CC;     base = 48; }
    else if (b < 80) { src = kw;  dst = kwt;  N = CC;     base = 64; }
    else             { src = wo;  dst = wot;  N = CC;     base = 80; }
    int lb = b - base;
    int ntl = N / 128;
    int kt = lb / ntl, nb = lb % ntl;
    int k0 = kt * 32, n0 = nb * 128;
    int tid = threadIdx.x;
#pragma unroll
    for (int it = 0; it < 16; it++) {
        int idx = it * 256 + tid;
        int k = idx >> 7, n = idx & 127;
        tile[k][n] = src[(size_t)(k0 + k) * N + n0 + n];
    }
    __syncthreads();
#pragma unroll
    for (int it = 0; it < 4; it++) {
        int cidx = it * 256 + tid;
        int n = cidx >> 3, c = cidx & 7;
        float4 v;
        float* vp = (float*)&v;
#pragma unroll
        for (int q = 0; q < 4; q++) {
            int kp = c * 4 + q;
            int ks = kp >> 3, r = kp & 7;
            int kl = ks * 8 + (r >> 1) + 4 * (r & 1);
            vp[q] = __uint_as_float(f2tf(tile[kl][n]));
        }
        *(float4*)&dst[((size_t)kt * N + n0 + n) * 32 + c * 4] = v;
    }
}

// =============================================================================
// GEMM (MODE 0/1/3): cp.async, BK=32, B pre-transformed tf32
// MODE 0: C = A0 @ B + bias
// MODE 1: merged semantic reduction over concatenated [rna|pad|dis] buffer:
//         rna blocks (bRow<MP, rows<Mv1) -> atomicAdd(score); dis -> score2
// MODE 3: MODE 0 + fused per-head attention scores for 4 vectors
// =============================================================================
#define AST 36
#define BST2 40
#define SMEM_CA ((2 * 128 * AST + 2 * 128 * BST2 + 128 + 128 + 256 + 512) * 4)

template <int MODE>
__global__ void __launch_bounds__(256, 2)
gemm_ca(const float* __restrict__ A0, const float* __restrict__ Bt,
        const float* __restrict__ bias, const float* __restrict__ qv,
        float* __restrict__ C, float* __restrict__ score, float* __restrict__ score2,
        const float* __restrict__ av0, const float* __restrict__ av1,
        const float* __restrict__ av2, const float* __restrict__ av3,
        float* __restrict__ s0, float* __restrict__ s1,
        float* __restrict__ s2, float* __restrict__ s3,
        int M, int N, int K, int Mv1)
{
    extern __shared__ float sm[];
    float* As     = sm;
    float* Bs     = sm + 2 * 128 * AST;
    float* bias_s = sm + 2 * 128 * AST + 2 * 128 * BST2;
    float* q_s    = bias_s + 128;
    float* red    = q_s + 128;
    float* avs    = red + 256;

    const int tid  = threadIdx.x;
    const int lane = tid & 31;
    const int warp = tid >> 5;
    const int wm   = warp & 3;
    const int wn   = warp >> 2;
    const int g    = lane >> 2;
    const int t    = lane & 3;
    const int bRow = blockIdx.y * 128;
    const int bCol = blockIdx.x * 128;

    // merged MODE1 block routing
    int Mlim = M;
    float* sc = score;
    if (MODE == 1) {
        if (bRow >= MP) sc = score2;
        else Mlim = Mv1;
    }

    if (tid < 128) {
        bias_s[tid] = bias[bCol + tid];
        if (MODE == 1) q_s[tid] = qv[bCol + tid];
        if (MODE == 3) {
            avs[tid]       = av0[bCol + tid];
            avs[128 + tid] = av1[bCol + tid];
            avs[256 + tid] = av2[bCol + tid];
            avs[384 + tid] = av3[bCol + tid];
        }
    }

    float acc[2][8][4];
#pragma unroll
    for (int mi = 0; mi < 2; mi++)
#pragma unroll
        for (int ni = 0; ni < 8; ni++)
#pragma unroll
            for (int r = 0; r < 4; r++) acc[mi][ni][r] = 0.f;

    auto issue = [&](int k0, int buf) {
        float* a_dst = As + buf * 128 * AST;
        float* b_dst = Bs + buf * 128 * BST2;
#pragma unroll
        for (int it = 0; it < 4; it++) {
            int idx = it * 256 + tid;
            int row = idx >> 3, ch = idx & 7;
            const float* src = A0 + (size_t)(bRow + row) * K + k0 + ch * 4;
            unsigned d = (unsigned)__cvta_generic_to_shared(a_dst + row * AST + ch * 4);
            int sz = (bRow + row < Mlim) ? 16 : 0;
            asm volatile("cp.async.ca.shared.global [%0], [%1], 16, %2;"
                         :: "r"(d), "l"(src), "r"(sz));
        }
        const int kt = k0 >> 5;
#pragma unroll
        for (int it = 0; it < 4; it++) {
            int idx = it * 256 + tid;
            int n = idx >> 3, c = idx & 7;
            const float* src = Bt + ((size_t)kt * N + bCol + n) * 32 + c * 4;
            unsigned d = (unsigned)__cvta_generic_to_shared(b_dst + n * BST2 + c * 4);
            asm volatile("cp.async.ca.shared.global [%0], [%1], 16;"
                         :: "r"(d), "l"(src));
        }
        asm volatile("cp.async.commit_group;");
    };

    const int S = K / 32;
    issue(0, 0);
    int buf = 0;

    for (int s = 0; s < S; s++) {
        asm volatile("cp.async.wait_group 0;");
        __syncthreads();
        if (s + 1 < S) issue((s + 1) * 32, buf ^ 1);

        const float* ap = As + buf * 128 * AST;
        const float* bp = Bs + buf * 128 * BST2;
#pragma unroll
        for (int ks = 0; ks < 4; ks++) {
            uint32_t af[2][4];
#pragma unroll
            for (int mi = 0; mi < 2; mi++) {
                const int mr = wm * 32 + mi * 16;
                float v0 = ap[(mr + g)     * AST + ks * 8 + t];
                float v1 = ap[(mr + g + 8) * AST + ks * 8 + t];
                float v2 = ap[(mr + g)     * AST + ks * 8 + t + 4];
                float v3 = ap[(mr + g + 8) * AST + ks * 8 + t + 4];
                if (MODE == 1) {
                    v0 = fmaxf(v0, 0.f); v1 = fmaxf(v1, 0.f);
                    v2 = fmaxf(v2, 0.f); v3 = fmaxf(v3, 0.f);
                }
                af[mi][0] = f2tf(v0); af[mi][1] = f2tf(v1);
                af[mi][2] = f2tf(v2); af[mi][3] = f2tf(v3);
            }
#pragma unroll
            for (int ni = 0; ni < 8; ni++) {
                const int n8 = wn * 8 + ni;
                float2 bv = *(const float2*)&bp[(n8 * 8 + g) * BST2 + ks * 8 + t * 2];
                uint32_t bx = __float_as_uint(bv.x), by = __float_as_uint(bv.y);
#pragma unroll
                for (int mi = 0; mi < 2; mi++) {
                    asm volatile(
                        "mma.sync.aligned.m16n8k8.row.col.f32.tf32.tf32.f32 "
                        "{%0,%1,%2,%3}, {%4,%5,%6,%7}, {%8,%9}, {%0,%1,%2,%3};"
                        : "+f"(acc[mi][ni][0]), "+f"(acc[mi][ni][1]),
                          "+f"(acc[mi][ni][2]), "+f"(acc[mi][ni][3])
                        : "r"(af[mi][0]), "r"(af[mi][1]), "r"(af[mi][2]), "r"(af[mi][3]),
                          "r"(bx), "r"(by));
                }
            }
        }
        buf ^= 1;
    }

    if (MODE == 0 || MODE == 3) {
#pragma unroll
        for (int mi = 0; mi < 2; mi++) {
            const int r0 = bRow + wm * 32 + mi * 16 + g;
#pragma unroll
            for (int ni = 0; ni < 8; ni++) {
                const int cl = wn * 64 + ni * 8 + t * 2;
                const int c0 = bCol + cl;
                if (r0 < M) {
                    float2 v = make_float2(acc[mi][ni][0] + bias_s[cl],
                                           acc[mi][ni][1] + bias_s[cl + 1]);
                    *(float2*)&C[(size_t)r0 * N + c0] = v;
                }
                if (r0 + 8 < M) {
                    float2 v = make_float2(acc[mi][ni][2] + bias_s[cl],
                                           acc[mi][ni][3] + bias_s[cl + 1]);
                    *(float2*)&C[(size_t)(r0 + 8) * N + c0] = v;
                }
            }
        }
        if (MODE == 3) {
            float* svs[4] = {s0, s1, s2, s3};
            const int headbase = 4 * blockIdx.x + wn * 2;
#pragma unroll
            for (int v = 0; v < 4; v++) {
#pragma unroll
                for (int mi = 0; mi < 2; mi++) {
                    float sA0 = 0.f, sA1 = 0.f, sB0 = 0.f, sB1 = 0.f;
#pragma unroll
                    for (int ni = 0; ni < 8; ni++) {
                        const int cl = wn * 64 + ni * 8 + t * 2;
                        float a0v = avs[v * 128 + cl];
                        float a1v = avs[v * 128 + cl + 1];
                        float dA = (acc[mi][ni][0] + bias_s[cl]) * a0v +
                                   (acc[mi][ni][1] + bias_s[cl + 1]) * a1v;
                        float dB = (acc[mi][ni][2] + bias_s[cl]) * a0v +
                                   (acc[mi][ni][3] + bias_s[cl + 1]) * a1v;
                        if (ni < 4) { sA0 += dA; sB0 += dB; }
                        else        { sA1 += dA; sB1 += dB; }
                    }
                    sA0 += __shfl_xor_sync(0xffffffffu, sA0, 1);
                    sA0 += __shfl_xor_sync(0xffffffffu, sA0, 2);
                    sA1 += __shfl_xor_sync(0xffffffffu, sA1, 1);
                    sA1 += __shfl_xor_sync(0xffffffffu, sA1, 2);
                    sB0 += __shfl_xor_sync(0xffffffffu, sB0, 1);
                    sB0 += __shfl_xor_sync(0xffffffffu, sB0, 2);
                    sB1 += __shfl_xor_sync(0xffffffffu, sB1, 1);
                    sB1 += __shfl_xor_sync(0xffffffffu, sB1, 2);
                    if (t == 0) {
                        int nodeA = bRow + wm * 32 + mi * 16 + g;
                        int nodeB = nodeA + 8;
                        if (nodeA < M) {
                            svs[v][nodeA * HH + headbase]     = sA0;
                            svs[v][nodeA * HH + headbase + 1] = sA1;
                        }
                        if (nodeB < M) {
                            svs[v][nodeB * HH + headbase]     = sB0;
                            svs[v][nodeB * HH + headbase + 1] = sB1;
                        }
                    }
                }
            }
        }
    } else {
        float local = 0.f;
#pragma unroll
        for (int mi = 0; mi < 2; mi++) {
            const int r0 = bRow + wm * 32 + mi * 16 + g;
#pragma unroll
            for (int ni = 0; ni < 8; ni++) {
                const int cl = wn * 64 + ni * 8 + t * 2;
                if (r0 < Mlim)
                    local += q_s[cl]     * tanhf(acc[mi][ni][0] + bias_s[cl]) +
                             q_s[cl + 1] * tanhf(acc[mi][ni][1] + bias_s[cl + 1]);
                if (r0 + 8 < Mlim)
                    local += q_s[cl]     * tanhf(acc[mi][ni][2] + bias_s[cl]) +
                             q_s[cl + 1] * tanhf(acc[mi][ni][3] + bias_s[cl + 1]);
            }
        }
        red[tid] = local;
        __syncthreads();
        for (int st = 128; st > 0; st >>= 1) {
            if (tid < st) red[tid] += red[tid + st];
            __syncthreads();
        }
        if (tid == 0) atomicAdd(sc, red[0]);
    }
}

// =============================================================================
// MODE2 merged tail GEMM over concatenated buffers:
// rows < Mv1 (rna): C[r] = (attn0*relu(A0)+attn1*relu(A1)) @ B + bias
// rows >= MP (dis): C[r-48] = (attn2*relu(A0)+attn3*relu(A1)) @ B + bias
// =============================================================================
#define SMEM_CA2 ((2 * 2 * 128 * AST + 2 * 128 * BST2 + 128) * 4)

__global__ void __launch_bounds__(256, 1)
gemm_ca2(const float* __restrict__ A0, const float* __restrict__ A1,
         const float* __restrict__ Bt, const float* __restrict__ bias,
         const float* __restrict__ attn, float* __restrict__ C,
         int M, int N, int K, int Mv1)
{
    extern __shared__ float sm[];
    float* A0s    = sm;
    float* A1s    = sm + 2 * 128 * AST;
    float* Bs     = sm + 4 * 128 * AST;
    float* bias_s = sm + 4 * 128 * AST + 2 * 128 * BST2;

    const int tid  = threadIdx.x;
    const int lane = tid & 31;
    const int warp = tid >> 5;
    const int wm   = warp & 3;
    const int wn   = warp >> 2;
    const int g    = lane >> 2;
    const int t    = lane & 3;
    const int bRow = blockIdx.y * 128;
    const int bCol = blockIdx.x * 128;

    const bool isDis = (bRow >= MP);
    const int Mlim = isDis ? M : Mv1;
    const int rshift = isDis ? (MP - Mv1) : 0;

    if (tid < 128) bias_s[tid] = bias[bCol + tid];
    const float w0 = attn[isDis ? 2 : 0];
    const float w1 = attn[isDis ? 3 : 1];

    float acc[2][8][4];
#pragma unroll
    for (int mi = 0; mi < 2; mi++)
#pragma unroll
        for (int ni = 0; ni < 8; ni++)
#pragma unroll
            for (int r = 0; r < 4; r++) acc[mi][ni][r] = 0.f;

    auto issue = [&](int k0, int buf) {
        float* a0_dst = A0s + buf * 128 * AST;
        float* a1_dst = A1s + buf * 128 * AST;
        float* b_dst  = Bs + buf * 128 * BST2;
#pragma unroll
        for (int it = 0; it < 4; it++) {
            int idx = it * 256 + tid;
            int row = idx >> 3, ch = idx & 7;
            int sz = (bRow + row < Mlim) ? 16 : 0;
            const float* src0 = A0 + (size_t)(bRow + row) * K + k0 + ch * 4;
            unsigned d0 = (unsigned)__cvta_generic_to_shared(a0_dst + row * AST + ch * 4);
            asm volatile("cp.async.ca.shared.global [%0], [%1], 16, %2;"
                         :: "r"(d0), "l"(src0), "r"(sz));
            const float* src1 = A1 + (size_t)(bRow + row) * K + k0 + ch * 4;
            unsigned d1 = (unsigned)__cvta_generic_to_shared(a1_dst + row * AST + ch * 4);
            asm volatile("cp.async.ca.shared.global [%0], [%1], 16, %2;"
                         :: "r"(d1), "l"(src1), "r"(sz));
        }
        const int kt = k0 >> 5;
#pragma unroll
        for (int it = 0; it < 4; it++) {
            int idx = it * 256 + tid;
            int n = idx >> 3, c = idx & 7;
            const float* src = Bt + ((size_t)kt * N + bCol + n) * 32 + c * 4;
            unsigned d = (unsigned)__cvta_generic_to_shared(b_dst + n * BST2 + c * 4);
            asm volatile("cp.async.ca.shared.global [%0], [%1], 16;"
                         :: "r"(d), "l"(src));
        }
        asm volatile("cp.async.commit_group;");
    };

    const int S = K / 32;
    issue(0, 0);
    int buf = 0;

    for (int s = 0; s < S; s++) {
        asm volatile("cp.async.wait_group 0;");
        __syncthreads();
        if (s + 1 < S) issue((s + 1) * 32, buf ^ 1);

        const float* a0p = A0s + buf * 128 * AST;
        const float* a1p = A1s + buf * 128 * AST;
        const float* bp  = Bs + buf * 128 * BST2;
#pragma unroll
        for (int ks = 0; ks < 4; ks++) {
            uint32_t af[2][4];
#pragma unroll
            for (int mi = 0; mi < 2; mi++) {
                const int mr = wm * 32 + mi * 16;
                const int o0 = (mr + g)     * AST + ks * 8 + t;
                const int o1 = (mr + g + 8) * AST + ks * 8 + t;
                float v0 = w0 * fmaxf(a0p[o0], 0.f)     + w1 * fmaxf(a1p[o0], 0.f);
                float v1 = w0 * fmaxf(a0p[o1], 0.f)     + w1 * fmaxf(a1p[o1], 0.f);
                float v2 = w0 * fmaxf(a0p[o0 + 4], 0.f) + w1 * fmaxf(a1p[o0 + 4], 0.f);
                float v3 = w0 * fmaxf(a0p[o1 + 4], 0.f) + w1 * fmaxf(a1p[o1 + 4], 0.f);
                af[mi][0] = f2tf(v0); af[mi][1] = f2tf(v1);
                af[mi][2] = f2tf(v2); af[mi][3] = f2tf(v3);
            }
#pragma unroll
            for (int ni = 0; ni < 8; ni++) {
                const int n8 = wn * 8 + ni;
                float2 bv = *(const float2*)&bp[(n8 * 8 + g) * BST2 + ks * 8 + t * 2];
                uint32_t bx = __float_as_uint(bv.x), by = __float_as_uint(bv.y);
#pragma unroll
                for (int mi = 0; mi < 2; mi++) {
                    asm volatile(
                        "mma.sync.aligned.m16n8k8.row.col.f32.tf32.tf32.f32 "
                        "{%0,%1,%2,%3}, {%4,%5,%6,%7}, {%8,%9}, {%0,%1,%2,%3};"
                        : "+f"(acc[mi][ni][0]), "+f"(acc[mi][ni][1]),
                          "+f"(acc[mi][ni][2]), "+f"(acc[mi][ni][3])
                        : "r"(af[mi][0]), "r"(af[mi][1]), "r"(af[mi][2]), "r"(af[mi][3]),
                          "r"(bx), "r"(by));
                }
            }
        }
        buf ^= 1;
    }

#pragma unroll
    for (int mi = 0; mi < 2; mi++) {
        const int r0 = bRow + wm * 32 + mi * 16 + g;
#pragma unroll
        for (int ni = 0; ni < 8; ni++) {
            const int cl = wn * 64 + ni * 8 + t * 2;
            const int c0 = bCol + cl;
            if (r0 < Mlim) {
                float2 v = make_float2(acc[mi][ni][0] + bias_s[cl],
                                       acc[mi][ni][1] + bias_s[cl + 1]);
                *(float2*)&C[(size_t)(r0 - rshift) * N + c0] = v;
            }
            if (r0 + 8 < Mlim) {
                float2 v = make_float2(acc[mi][ni][2] + bias_s[cl],
                                       acc[mi][ni][3] + bias_s[cl + 1]);
                *(float2*)&C[(size_t)(r0 + 8 - rshift) * N + c0] = v;
            }
        }
    }
}

// ================= fused CSR build ==========================================
__global__ void hist4_k(const int* __restrict__ d0, const int* __restrict__ d1,
                        const int* __restrict__ d2, const int* __restrict__ d3,
                        int* __restrict__ cnt)
{
    int i = blockIdx.x * blockDim.x + threadIdx.x;
    if (i < E_RD)                     atomicAdd(&cnt[d0[i]], 1);
    else if (i < E_RD + E_DR)         atomicAdd(&cnt[N_D + d1[i - E_RD]], 1);
    else if (i < E_RD + E_DR + E_RR)  atomicAdd(&cnt[N_D + N_R + d2[i - E_RD - E_DR]], 1);
    else if (i < E_TOT)               atomicAdd(&cnt[N_D + 2 * N_R + d3[i - E_RD - E_DR - E_RR]], 1);
}

__global__ void __launch_bounds__(1024)
scan4_k(const int* __restrict__ cnt, int* __restrict__ rptr_all)
{
    __shared__ int wsum[32];
    __shared__ int s_carry;
    const int b = blockIdx.x;
    const int n    = (b == 0 || b == 3) ? N_D : N_R;
    const int cofs = (b == 0) ? 0 : (b == 1) ? N_D : (b == 2) ? (N_D + N_R) : (N_D + 2 * N_R);
    const int* c = cnt + cofs;
    int* rptr = rptr_all + b * (N_R + 1);

    const int tid = threadIdx.x;
    const int lane = tid & 31, wid = tid >> 5;
    if (tid == 0) s_carry = 0;
    __syncthreads();
    for (int base = 0; base < n; base += 1024) {
        int i = base + tid;
        int v = (i < n) ? c[i] : 0;
        int x = v;
#pragma unroll
        for (int o = 1; o < 32; o <<= 1) {
            int y = __shfl_up_sync(0xffffffffu, x, o);
            if (lane >= o) x += y;
        }
        if (lane == 31) wsum[wid] = x;
        __syncthreads();
        if (wid == 0) {
            int tv = wsum[lane];
#pragma unroll
            for (int o = 1; o < 32; o <<= 1) {
                int y = __shfl_up_sync(0xffffffffu, tv, o);
                if (lane >= o) tv += y;
            }
            wsum[lane] = tv;
        }
        __syncthreads();
        int incl = x + (wid > 0 ? wsum[wid - 1] : 0);
        int carry = s_carry;
        if (i < n) rptr[i] = carry + incl - v;
        __syncthreads();
        if (tid == 1023) s_carry = carry + incl;
        __syncthreads();
    }
    if (tid == 0) rptr[n] = s_carry;
}

__global__ void scatter4_k(const int* __restrict__ s0, const int* __restrict__ d0,
                           const int* __restrict__ s1, const int* __restrict__ d1,
                           const int* __restrict__ s2, const int* __restrict__ d2,
                           const int* __restrict__ s3, const int* __restrict__ d3,
                           const int* __restrict__ rptr_all,
                           int* __restrict__ fill, int* __restrict__ ssort)
{
    int i = blockIdx.x * blockDim.x + threadIdx.x;
    const int* sp; const int* dp; const int* rp; int* fl; int* ss; int e;
    if (i < E_RD) {
        e = i; sp = s0; dp = d0; rp = rptr_all; fl = fill; ss = ssort;
    } else if (i < E_RD + E_DR) {
        e = i - E_RD; sp = s1; dp = d1; rp = rptr_all + (N_R + 1);
        fl = fill + N_D; ss = ssort + E_RD;
    } else if (i < E_RD + E_DR + E_RR) {
        e = i - E_RD - E_DR; sp = s2; dp = d2; rp = rptr_all + 2 * (N_R + 1);
        fl = fill + N_D + N_R; ss = ssort + E_RD + E_DR;
    } else if (i < E_TOT) {
        e = i - E_RD - E_DR - E_RR; sp = s3; dp = d3; rp = rptr_all + 3 * (N_R + 1);
        fl = fill + N_D + 2 * N_R; ss = ssort + E_RD + E_DR + E_RR;
    } else return;
    int d = dp[e];
    int pos = rp[d] + atomicAdd(&fl[d], 1);
    ss[pos] = sp[e];
}

// ============ edge aggregation: exact max pass + parallel sum pass ==========
__device__ __forceinline__ float lrelu(float x) { return x > 0.f ? x : 0.2f * x; }

__global__ void __launch_bounds__(256)
agg_csr_k(const int* __restrict__ rptr, const int* __restrict__ ssort,
          const float* __restrict__ ssrc, const float* __restrict__ sdst,
          const float* __restrict__ x, float* __restrict__ out, int Nd)
{
    const int warp = (blockIdx.x * blockDim.x + threadIdx.x) >> 5;
    const int lane = threadIdx.x & 31;
    if (warp >= Nd) return;
    const int beg = rptr[warp], end = rptr[warp + 1];

    const int h1 = lane & 7;
    const int j  = lane >> 3;
    const float sd1 = sdst[warp * HH + h1];
    float mloc = -INFINITY;
    for (int p = beg + j; p < end; p += 4) {
        int src = ssort[p];
        mloc = fmaxf(mloc, lrelu(ssrc[src * HH + h1] + sd1));
    }
    mloc = fmaxf(mloc, __shfl_xor_sync(0xffffffffu, mloc, 8));
    mloc = fmaxf(mloc, __shfl_xor_sync(0xffffffffu, mloc, 16));

    const int h2 = lane >> 2;
    const float m2  = __shfl_sync(0xffffffffu, mloc, h2);
    const float sd2 = __shfl_sync(0xffffffffu, sd1, h2);

    float s = 0.f;
    float a0 = 0.f, a1 = 0.f, a2 = 0.f, a3 = 0.f;
    float a4 = 0.f, a5 = 0.f, a6 = 0.f, a7 = 0.f;
    for (int p = beg; p < end; p++) {
        int src = ssort[p];
        float w = expf(lrelu(ssrc[src * HH + h2] + sd2) - m2);
        s += w;
        const float4* xp = (const float4*)(x + (size_t)src * CC + lane * 8);
        float4 v0 = xp[0], v1 = xp[1];
        a0 += w * v0.x; a1 += w * v0.y; a2 += w * v0.z; a3 += w * v0.w;
        a4 += w * v1.x; a5 += w * v1.y; a6 += w * v1.z; a7 += w * v1.w;
    }
    float inv = 1.f / (s + 1e-16f);
    float* op = out + (size_t)warp * CC + lane * 8;
    *(float4*)op       = make_float4(a0 * inv, a1 * inv, a2 * inv, a3 * inv);
    *(float4*)(op + 4) = make_float4(a4 * inv, a5 * inv, a6 * inv, a7 * inv);
}

__global__ void softmax2_k(const float* __restrict__ scores, float* __restrict__ attn,
                           float invNr, float invNd)
{
    if (threadIdx.x == 0 && blockIdx.x == 0) {
        float s0 = scores[0] * invNr, s1 = scores[1] * invNr;
        float mx = fmaxf(s0, s1);
        float e0 = expf(s0 - mx), e1 = expf(s1 - mx);
        attn[0] = e0 / (e0 + e1);
        attn[1] = e1 / (e0 + e1);
        s0 = scores[2] * invNd; s1 = scores[3] * invNd;
        mx = fmaxf(s0, s1);
        e0 = expf(s0 - mx); e1 = expf(s1 - mx);
        attn[2] = e0 / (e0 + e1);
        attn[3] = e1 / (e0 + e1);
    }
}

// ---------------------------------------------------------------------------
extern "C" void kernel_launch(void* const* d_in, const int* in_sizes, int n_in,
                              void* d_out, int out_size)
{
    const float* x_rna   = (const float*)d_in[0];
    const float* x_dis   = (const float*)d_in[1];
    const float* W_d     = (const float*)d_in[2];
    const float* b_d     = (const float*)d_in[3];
    const float* Wp_rna  = (const float*)d_in[4];
    const float* bp_rna  = (const float*)d_in[5];
    const float* Wp_dis  = (const float*)d_in[6];
    const float* bp_dis  = (const float*)d_in[7];
    const float* a_src_rd = (const float*)d_in[8];
    const float* a_dst_rd = (const float*)d_in[9];
    const float* a_src_dr = (const float*)d_in[10];
    const float* a_dst_dr = (const float*)d_in[11];
    const float* a_src_rr = (const float*)d_in[12];
    const float* a_dst_rr = (const float*)d_in[13];
    const float* a_src_dd = (const float*)d_in[14];
    const float* a_dst_dd = (const float*)d_in[15];
    const float* kW      = (const float*)d_in[16];
    const float* kb      = (const float*)d_in[17];
    const float* qv      = (const float*)d_in[18];
    const float* W_out   = (const float*)d_in[19];
    const float* b_out   = (const float*)d_in[20];
    const int* rd_src = (const int*)d_in[21];
    const int* rd_dst = (const int*)d_in[22];
    const int* dr_src = (const int*)d_in[23];
    const int* dr_dst = (const int*)d_in[24];
    const int* rr_src = (const int*)d_in[25];
    const int* rr_dst = (const int*)d_in[26];
    const int* dd_src = (const int*)d_in[27];
    const int* dd_dst = (const int*)d_in[28];

    float* out = (float*)d_out;

    float *p_xd, *p_hr, *p_hd, *p_bufA, *p_bufB;
    float *p_sr, *p_sd, *p_scores, *p_attn;
    float *p_wdt, *p_wprt, *p_wpdt, *p_kwt, *p_wot;
    int *p_cnt, *p_fill, *p_rptr, *p_ssort;
    cudaGetSymbolAddress((void**)&p_xd, g_xd);
    cudaGetSymbolAddress((void**)&p_hr, g_hr);
    cudaGetSymbolAddress((void**)&p_hd, g_hd);
    cudaGetSymbolAddress((void**)&p_bufA, g_bufA);
    cudaGetSymbolAddress((void**)&p_bufB, g_bufB);
    cudaGetSymbolAddress((void**)&p_sr, g_s_rna);
    cudaGetSymbolAddress((void**)&p_sd, g_s_dis);
    cudaGetSymbolAddress((void**)&p_cnt, g_cnt);
    cudaGetSymbolAddress((void**)&p_fill, g_fill);
    cudaGetSymbolAddress((void**)&p_rptr, g_rptr);
    cudaGetSymbolAddress((void**)&p_ssort, g_ssort);
    cudaGetSymbolAddress((void**)&p_scores, g_scores);
    cudaGetSymbolAddress((void**)&p_attn, g_attn);
    cudaGetSymbolAddress((void**)&p_wdt, g_wd_t);
    cudaGetSymbolAddress((void**)&p_wprt, g_wpr_t);
    cudaGetSymbolAddress((void**)&p_wpdt, g_wpd_t);
    cudaGetSymbolAddress((void**)&p_kwt, g_kw_t);
    cudaGetSymbolAddress((void**)&p_wot, g_wo_t);

    cudaFuncSetAttribute(gemm_ca<0>, cudaFuncAttributeMaxDynamicSharedMemorySize, SMEM_CA);
    cudaFuncSetAttribute(gemm_ca<1>, cudaFuncAttributeMaxDynamicSharedMemorySize, SMEM_CA);
    cudaFuncSetAttribute(gemm_ca<3>, cudaFuncAttributeMaxDynamicSharedMemorySize, SMEM_CA);
    cudaFuncSetAttribute(gemm_ca2, cudaFuncAttributeMaxDynamicSharedMemorySize, SMEM_CA2);

    const dim3 thr(256);
    const int mbr = (N_R + 127) / 128;   // 391
    const int mbd = (N_D + 127) / 128;   // 79
    const int mbt = (MT + 127) / 128;    // 470

    // concatenated attention-output slices
    float* p_odr = p_bufA;                       // rna rows of bufA
    float* p_ord = p_bufA + (size_t)MP * CC;     // dis rows of bufA
    float* p_orr = p_bufB;
    float* p_odd = p_bufB + (size_t)MP * CC;

    int* rp_rd = p_rptr + 0 * (N_R + 1);
    int* rp_dr = p_rptr + 1 * (N_R + 1);
    int* rp_rr = p_rptr + 2 * (N_R + 1);
    int* rp_dd = p_rptr + 3 * (N_R + 1);
    int* ss_rd = p_ssort;
    int* ss_dr = ss_rd + E_RD;
    int* ss_rr = ss_dr + E_DR;
    int* ss_dd = ss_rr + E_RR;

    cudaStream_t st0 = 0, st1, st2;
    cudaStreamCreateWithFlags(&st1, cudaStreamNonBlocking);
    cudaStreamCreateWithFlags(&st2, cudaStreamNonBlocking);
    cudaEvent_t ev[10];
    for (int i = 0; i < 10; i++) cudaEventCreateWithFlags(&ev[i], cudaEventDisableTiming);

    // fork for CSR
    cudaEventRecord(ev[0], st0);
    cudaStreamWaitEvent(st2, ev[0], 0);

    // st0: weight prep, then fork to st1
    prep_w_k<<<96, thr, 0, st0>>>(W_d, Wp_rna, Wp_dis, kW, W_out,
                                  p_wdt, p_wprt, p_wpdt, p_kwt, p_wot);
    cudaEventRecord(ev[8], st0);
    cudaStreamWaitEvent(st1, ev[8], 0);

    // st2: CSR build + score clear
    cudaMemsetAsync(p_cnt, 0, CNT_TOT * sizeof(int), st2);
    cudaMemsetAsync(p_fill, 0, CNT_TOT * sizeof(int), st2);
    cudaMemsetAsync(p_scores, 0, 4 * sizeof(float), st2);
    hist4_k<<<(E_TOT + 255) / 256, thr, 0, st2>>>(rd_dst, dr_dst, rr_dst, dd_dst, p_cnt);
    scan4_k<<<4, 1024, 0, st2>>>(p_cnt, p_rptr);
    scatter4_k<<<(E_TOT + 255) / 256, thr, 0, st2>>>(rd_src, rd_dst, dr_src, dr_dst,
                                                     rr_src, rr_dst, dd_src, dd_dst,
                                                     p_rptr, p_fill, p_ssort);

    // st0: disease chain
    gemm_ca<0><<<dim3(2, mbd), thr, SMEM_CA, st0>>>(x_dis, p_wdt, b_d, nullptr,
                                                    p_xd, nullptr, nullptr,
                                                    nullptr, nullptr, nullptr, nullptr,
                                                    nullptr, nullptr, nullptr, nullptr,
                                                    N_D, RNA_IN, D_FEAT, N_D);
    gemm_ca<3><<<dim3(2, mbd), thr, SMEM_CA, st0>>>(p_xd, p_wpdt, bp_dis, nullptr,
                                                    p_hd, nullptr, nullptr,
                                                    a_dst_rd, a_src_dr, a_src_dd, a_dst_dd,
                                                    p_sd + 0 * N_D * HH, p_sd + 1 * N_D * HH,
                                                    p_sd + 2 * N_D * HH, p_sd + 3 * N_D * HH,
                                                    N_D, CC, RNA_IN, N_D);

    // st1: rna chain
    gemm_ca<3><<<dim3(2, mbr), thr, SMEM_CA, st1>>>(x_rna, p_wprt, bp_rna, nullptr,
                                                    p_hr, nullptr, nullptr,
                                                    a_src_rd, a_dst_dr, a_src_rr, a_dst_rr,
                                                    p_sr + 0 * N_R * HH, p_sr + 1 * N_R * HH,
                                                    p_sr + 2 * N_R * HH, p_sr + 3 * N_R * HH,
                                                    N_R, CC, RNA_IN, N_R);

    // join before aggs
    cudaEventRecord(ev[1], st0);
    cudaEventRecord(ev[2], st1);
    cudaEventRecord(ev[3], st2);
    cudaStreamWaitEvent(st0, ev[2], 0); cudaStreamWaitEvent(st0, ev[3], 0);
    cudaStreamWaitEvent(st1, ev[1], 0); cudaStreamWaitEvent(st1, ev[3], 0);
    cudaStreamWaitEvent(st2, ev[1], 0); cudaStreamWaitEvent(st2, ev[2], 0);

    // aggs across 3 streams
    agg_csr_k<<<(N_R * 32 + 255) / 256, thr, 0, st1>>>(rp_rr, ss_rr,
                                                       p_sr + 2 * N_R * HH, p_sr + 3 * N_R * HH,
                                                       p_hr, p_orr, N_R);
    agg_csr_k<<<(N_R * 32 + 255) / 256, thr, 0, st0>>>(rp_dr, ss_dr,
                                                       p_sd + 1 * N_D * HH, p_sr + 1 * N_R * HH,
                                                       p_hd, p_odr, N_R);
    agg_csr_k<<<(N_D * 32 + 255) / 256, thr, 0, st2>>>(rp_rd, ss_rd,
                                                       p_sr + 0 * N_R * HH, p_sd + 0 * N_D * HH,
                                                       p_hr, p_ord, N_D);
    agg_csr_k<<<(N_D * 32 + 255) / 256, thr, 0, st2>>>(rp_dd, ss_dd,
                                                       p_sd + 2 * N_D * HH, p_sd + 3 * N_D * HH,
                                                       p_hd, p_odd, N_D);

    // join aggs -> merged MODE1 on st0/st1
    cudaEventRecord(ev[4], st0);
    cudaEventRecord(ev[5], st1);
    cudaEventRecord(ev[6], st2);
    cudaStreamWaitEvent(st0, ev[5], 0); cudaStreamWaitEvent(st0, ev[6], 0);
    cudaStreamWaitEvent(st1, ev[4], 0); cudaStreamWaitEvent(st1, ev[6], 0);

    // merged MODE1: bufA -> scores{0,2}, bufB -> scores{1,3}
    gemm_ca<1><<<dim3(2, mbt), thr, SMEM_CA, st0>>>(p_bufA, p_kwt, kb, qv,
                                                    nullptr, p_scores + 0, p_scores + 2,
                                                    nullptr, nullptr, nullptr, nullptr,
                                                    nullptr, nullptr, nullptr, nullptr,
                                                    MT, CC, CC, N_R);
    gemm_ca<1><<<dim3(2, mbt), thr, SMEM_CA, st1>>>(p_bufB, p_kwt, kb, qv,
                                                    nullptr, p_scores + 1, p_scores + 3,
                                                    nullptr, nullptr, nullptr, nullptr,
                                                    nullptr, nullptr, nullptr, nullptr,
                                                    MT, CC, CC, N_R);

    // join for softmax, then merged tail GEMM on st0
    cudaEventRecord(ev[7], st1);
    cudaStreamWaitEvent(st0, ev[7], 0);
    softmax2_k<<<1, 32, 0, st0>>>(p_scores, p_attn, 1.f / N_R, 1.f / N_D);

    gemm_ca2<<<dim3(2, mbt), thr, SMEM_CA2, st0>>>(p_bufA, p_bufB, p_wot, b_out,
                                                   p_attn, out, MT, CC, CC, N_R);

    for (int i = 0; i < 10; i++) cudaEventDestroy(ev[i]);
    cudaStreamDestroy(st1);
    cudaStreamDestroy(st2);
}

// round 11
// speedup vs baseline: 6.3026x; 1.0145x over previous
#include <cuda_runtime.h>
#include <cstdint>
#include <math.h>

#define N_R 50000
#define N_D 10000
#define HH  8
#define DH  32
#define CC  256
#define RNA_IN 256
#define D_FEAT 512
#define E_RD 200000
#define E_DR 200000
#define E_RR 400000
#define E_DD 50000
#define E_TOT (E_RD + E_DR + E_RR + E_DD)
#define CNT_TOT (2 * N_R + 2 * N_D)
#define MP 50048                  // 128-aligned pad boundary (391*128)
#define MT (MP + N_D)             // 60048 total concatenated rows

// ---------------- static device scratch ------------------------------------
__device__ float    g_xd[N_D * RNA_IN];
__device__ float    g_hr[N_R * CC];
__device__ float    g_hd[N_D * CC];
__device__ float    g_bufA[(size_t)MT * CC];   // [out_dr | pad | out_rd]
__device__ float    g_bufB[(size_t)MT * CC];   // [out_rr | pad | out_dd]
__device__ float    g_s_rna[4 * N_R * HH];
__device__ float    g_s_dis[4 * N_D * HH];
__device__ int      g_cnt[CNT_TOT];
__device__ int      g_fill[CNT_TOT];
__device__ int      g_rptr[4 * (N_R + 1)];
__device__ int      g_ssort[E_TOT];
__device__ float    g_scores[4];
// transformed weights (tf32-rounded, mma-native blocked layout)
__device__ float    g_wd_t[D_FEAT * RNA_IN];
__device__ float    g_wpr_t[RNA_IN * CC];
__device__ float    g_wpd_t[RNA_IN * CC];
__device__ float    g_kw_t[CC * CC];
__device__ float    g_wo_t[CC * CC];

__device__ __forceinline__ uint32_t f2tf(float f) {
    uint32_t u;
    asm("cvt.rna.tf32.f32 %0, %1;" : "=r"(u) : "f"(f));
    return u;
}

// ================= weight prep: W[K][N] -> blocked n-major tf32 ==============
__global__ void __launch_bounds__(256)
prep_w_k(const float* __restrict__ wd,  const float* __restrict__ wpr,
         const float* __restrict__ wpd, const float* __restrict__ kw,
         const float* __restrict__ wo,
         float* __restrict__ wdt, float* __restrict__ wprt,
         float* __restrict__ wpdt, float* __restrict__ kwt,
         float* __restrict__ wot)
{
    __shared__ float tile[32][129];
    int b = blockIdx.x;
    const float* src; float* dst; int N, base;
    if (b < 32)      { src = wd;  dst = wdt;  N = RNA_IN; base = 0;  }
    else if (b < 48) { src = wpr; dst = wprt; N = CC;     base = 32; }
    else if (b < 64) { src = wpd; dst = wpdt; N = CC;     base = 48; }
    else if (b < 80) { src = kw;  dst = kwt;  N = CC;     base = 64; }
    else             { src = wo;  dst = wot;  N = CC;     base = 80; }
    int lb = b - base;
    int ntl = N / 128;
    int kt = lb / ntl, nb = lb % ntl;
    int k0 = kt * 32, n0 = nb * 128;
    int tid = threadIdx.x;
#pragma unroll
    for (int it = 0; it < 16; it++) {
        int idx = it * 256 + tid;
        int k = idx >> 7, n = idx & 127;
        tile[k][n] = src[(size_t)(k0 + k) * N + n0 + n];
    }
    __syncthreads();
#pragma unroll
    for (int it = 0; it < 4; it++) {
        int cidx = it * 256 + tid;
        int n = cidx >> 3, c = cidx & 7;
        float4 v;
        float* vp = (float*)&v;
#pragma unroll
        for (int q = 0; q < 4; q++) {
            int kp = c * 4 + q;
            int ks = kp >> 3, r = kp & 7;
            int kl = ks * 8 + (r >> 1) + 4 * (r & 1);
            vp[q] = __uint_as_float(f2tf(tile[kl][n]));
        }
        *(float4*)&dst[((size_t)kt * N + n0 + n) * 32 + c * 4] = v;
    }
}

// =============================================================================
// GEMM (MODE 0/1/3): cp.async, BK=32, B pre-transformed tf32
// =============================================================================
#define AST 36
#define BST2 40
#define SMEM_CA ((2 * 128 * AST + 2 * 128 * BST2 + 128 + 128 + 256 + 512) * 4)

template <int MODE>
__global__ void __launch_bounds__(256, 2)
gemm_ca(const float* __restrict__ A0, const float* __restrict__ Bt,
        const float* __restrict__ bias, const float* __restrict__ qv,
        float* __restrict__ C, float* __restrict__ score, float* __restrict__ score2,
        const float* __restrict__ av0, const float* __restrict__ av1,
        const float* __restrict__ av2, const float* __restrict__ av3,
        float* __restrict__ s0, float* __restrict__ s1,
        float* __restrict__ s2, float* __restrict__ s3,
        int M, int N, int K, int Mv1)
{
    extern __shared__ float sm[];
    float* As     = sm;
    float* Bs     = sm + 2 * 128 * AST;
    float* bias_s = sm + 2 * 128 * AST + 2 * 128 * BST2;
    float* q_s    = bias_s + 128;
    float* red    = q_s + 128;
    float* avs    = red + 256;

    const int tid  = threadIdx.x;
    const int lane = tid & 31;
    const int warp = tid >> 5;
    const int wm   = warp & 3;
    const int wn   = warp >> 2;
    const int g    = lane >> 2;
    const int t    = lane & 3;
    const int bRow = blockIdx.y * 128;
    const int bCol = blockIdx.x * 128;

    int Mlim = M;
    float* sc = score;
    if (MODE == 1) {
        if (bRow >= MP) sc = score2;
        else Mlim = Mv1;
    }

    if (tid < 128) {
        bias_s[tid] = bias[bCol + tid];
        if (MODE == 1) q_s[tid] = qv[bCol + tid];
        if (MODE == 3) {
            avs[tid]       = av0[bCol + tid];
            avs[128 + tid] = av1[bCol + tid];
            avs[256 + tid] = av2[bCol + tid];
            avs[384 + tid] = av3[bCol + tid];
        }
    }

    float acc[2][8][4];
#pragma unroll
    for (int mi = 0; mi < 2; mi++)
#pragma unroll
        for (int ni = 0; ni < 8; ni++)
#pragma unroll
            for (int r = 0; r < 4; r++) acc[mi][ni][r] = 0.f;

    auto issue = [&](int k0, int buf) {
        float* a_dst = As + buf * 128 * AST;
        float* b_dst = Bs + buf * 128 * BST2;
#pragma unroll
        for (int it = 0; it < 4; it++) {
            int idx = it * 256 + tid;
            int row = idx >> 3, ch = idx & 7;
            const float* src = A0 + (size_t)(bRow + row) * K + k0 + ch * 4;
            unsigned d = (unsigned)__cvta_generic_to_shared(a_dst + row * AST + ch * 4);
            int sz = (bRow + row < Mlim) ? 16 : 0;
            asm volatile("cp.async.ca.shared.global [%0], [%1], 16, %2;"
                         :: "r"(d), "l"(src), "r"(sz));
        }
        const int kt = k0 >> 5;
#pragma unroll
        for (int it = 0; it < 4; it++) {
            int idx = it * 256 + tid;
            int n = idx >> 3, c = idx & 7;
            const float* src = Bt + ((size_t)kt * N + bCol + n) * 32 + c * 4;
            unsigned d = (unsigned)__cvta_generic_to_shared(b_dst + n * BST2 + c * 4);
            asm volatile("cp.async.ca.shared.global [%0], [%1], 16;"
                         :: "r"(d), "l"(src));
        }
        asm volatile("cp.async.commit_group;");
    };

    const int S = K / 32;
    issue(0, 0);
    int buf = 0;

    for (int s = 0; s < S; s++) {
        asm volatile("cp.async.wait_group 0;");
        __syncthreads();
        if (s + 1 < S) issue((s + 1) * 32, buf ^ 1);

        const float* ap = As + buf * 128 * AST;
        const float* bp = Bs + buf * 128 * BST2;
#pragma unroll
        for (int ks = 0; ks < 4; ks++) {
            uint32_t af[2][4];
#pragma unroll
            for (int mi = 0; mi < 2; mi++) {
                const int mr = wm * 32 + mi * 16;
                float v0 = ap[(mr + g)     * AST + ks * 8 + t];
                float v1 = ap[(mr + g + 8) * AST + ks * 8 + t];
                float v2 = ap[(mr + g)     * AST + ks * 8 + t + 4];
                float v3 = ap[(mr + g + 8) * AST + ks * 8 + t + 4];
                if (MODE == 1) {
                    v0 = fmaxf(v0, 0.f); v1 = fmaxf(v1, 0.f);
                    v2 = fmaxf(v2, 0.f); v3 = fmaxf(v3, 0.f);
                }
                af[mi][0] = f2tf(v0); af[mi][1] = f2tf(v1);
                af[mi][2] = f2tf(v2); af[mi][3] = f2tf(v3);
            }
#pragma unroll
            for (int ni = 0; ni < 8; ni++) {
                const int n8 = wn * 8 + ni;
                float2 bv = *(const float2*)&bp[(n8 * 8 + g) * BST2 + ks * 8 + t * 2];
                uint32_t bx = __float_as_uint(bv.x), by = __float_as_uint(bv.y);
#pragma unroll
                for (int mi = 0; mi < 2; mi++) {
                    asm volatile(
                        "mma.sync.aligned.m16n8k8.row.col.f32.tf32.tf32.f32 "
                        "{%0,%1,%2,%3}, {%4,%5,%6,%7}, {%8,%9}, {%0,%1,%2,%3};"
                        : "+f"(acc[mi][ni][0]), "+f"(acc[mi][ni][1]),
                          "+f"(acc[mi][ni][2]), "+f"(acc[mi][ni][3])
                        : "r"(af[mi][0]), "r"(af[mi][1]), "r"(af[mi][2]), "r"(af[mi][3]),
                          "r"(bx), "r"(by));
                }
            }
        }
        buf ^= 1;
    }

    if (MODE == 0 || MODE == 3) {
#pragma unroll
        for (int mi = 0; mi < 2; mi++) {
            const int r0 = bRow + wm * 32 + mi * 16 + g;
#pragma unroll
            for (int ni = 0; ni < 8; ni++) {
                const int cl = wn * 64 + ni * 8 + t * 2;
                const int c0 = bCol + cl;
                if (r0 < M) {
                    float2 v = make_float2(acc[mi][ni][0] + bias_s[cl],
                                           acc[mi][ni][1] + bias_s[cl + 1]);
                    *(float2*)&C[(size_t)r0 * N + c0] = v;
                }
                if (r0 + 8 < M) {
                    float2 v = make_float2(acc[mi][ni][2] + bias_s[cl],
                                           acc[mi][ni][3] + bias_s[cl + 1]);
                    *(float2*)&C[(size_t)(r0 + 8) * N + c0] = v;
                }
            }
        }
        if (MODE == 3) {
            float* svs[4] = {s0, s1, s2, s3};
            const int headbase = 4 * blockIdx.x + wn * 2;
#pragma unroll
            for (int v = 0; v < 4; v++) {
#pragma unroll
                for (int mi = 0; mi < 2; mi++) {
                    float sA0 = 0.f, sA1 = 0.f, sB0 = 0.f, sB1 = 0.f;
#pragma unroll
                    for (int ni = 0; ni < 8; ni++) {
                        const int cl = wn * 64 + ni * 8 + t * 2;
                        float a0v = avs[v * 128 + cl];
                        float a1v = avs[v * 128 + cl + 1];
                        float dA = (acc[mi][ni][0] + bias_s[cl]) * a0v +
                                   (acc[mi][ni][1] + bias_s[cl + 1]) * a1v;
                        float dB = (acc[mi][ni][2] + bias_s[cl]) * a0v +
                                   (acc[mi][ni][3] + bias_s[cl + 1]) * a1v;
                        if (ni < 4) { sA0 += dA; sB0 += dB; }
                        else        { sA1 += dA; sB1 += dB; }
                    }
                    sA0 += __shfl_xor_sync(0xffffffffu, sA0, 1);
                    sA0 += __shfl_xor_sync(0xffffffffu, sA0, 2);
                    sA1 += __shfl_xor_sync(0xffffffffu, sA1, 1);
                    sA1 += __shfl_xor_sync(0xffffffffu, sA1, 2);
                    sB0 += __shfl_xor_sync(0xffffffffu, sB0, 1);
                    sB0 += __shfl_xor_sync(0xffffffffu, sB0, 2);
                    sB1 += __shfl_xor_sync(0xffffffffu, sB1, 1);
                    sB1 += __shfl_xor_sync(0xffffffffu, sB1, 2);
                    if (t == 0) {
                        int nodeA = bRow + wm * 32 + mi * 16 + g;
                        int nodeB = nodeA + 8;
                        if (nodeA < M) {
                            svs[v][nodeA * HH + headbase]     = sA0;
                            svs[v][nodeA * HH + headbase + 1] = sA1;
                        }
                        if (nodeB < M) {
                            svs[v][nodeB * HH + headbase]     = sB0;
                            svs[v][nodeB * HH + headbase + 1] = sB1;
                        }
                    }
                }
            }
        }
    } else {
        float local = 0.f;
#pragma unroll
        for (int mi = 0; mi < 2; mi++) {
            const int r0 = bRow + wm * 32 + mi * 16 + g;
#pragma unroll
            for (int ni = 0; ni < 8; ni++) {
                const int cl = wn * 64 + ni * 8 + t * 2;
                if (r0 < Mlim)
                    local += q_s[cl]     * tanhf(acc[mi][ni][0] + bias_s[cl]) +
                             q_s[cl + 1] * tanhf(acc[mi][ni][1] + bias_s[cl + 1]);
                if (r0 + 8 < Mlim)
                    local += q_s[cl]     * tanhf(acc[mi][ni][2] + bias_s[cl]) +
                             q_s[cl + 1] * tanhf(acc[mi][ni][3] + bias_s[cl + 1]);
            }
        }
        red[tid] = local;
        __syncthreads();
        for (int st = 128; st > 0; st >>= 1) {
            if (tid < st) red[tid] += red[tid + st];
            __syncthreads();
        }
        if (tid == 0) atomicAdd(sc, red[0]);
    }
}

// =============================================================================
// MODE2 merged tail GEMM, softmax computed in-kernel from scores
// =============================================================================
#define SMEM_CA2 ((2 * 2 * 128 * AST + 2 * 128 * BST2 + 128) * 4)

__global__ void __launch_bounds__(256, 1)
gemm_ca2(const float* __restrict__ A0, const float* __restrict__ A1,
         const float* __restrict__ Bt, const float* __restrict__ bias,
         const float* __restrict__ scores, float* __restrict__ C,
         int M, int N, int K, int Mv1, float invNr, float invNd)
{
    extern __shared__ float sm[];
    float* A0s    = sm;
    float* A1s    = sm + 2 * 128 * AST;
    float* Bs     = sm + 4 * 128 * AST;
    float* bias_s = sm + 4 * 128 * AST + 2 * 128 * BST2;

    const int tid  = threadIdx.x;
    const int lane = tid & 31;
    const int warp = tid >> 5;
    const int wm   = warp & 3;
    const int wn   = warp >> 2;
    const int g    = lane >> 2;
    const int t    = lane & 3;
    const int bRow = blockIdx.y * 128;
    const int bCol = blockIdx.x * 128;

    const bool isDis = (bRow >= MP);
    const int Mlim = isDis ? M : Mv1;
    const int rshift = isDis ? (MP - Mv1) : 0;

    if (tid < 128) bias_s[tid] = bias[bCol + tid];

    // fused 2-way softmax (identical math to softmax2_k)
    float invN = isDis ? invNd : invNr;
    float sa = scores[isDis ? 2 : 0] * invN;
    float sb = scores[isDis ? 3 : 1] * invN;
    float mx = fmaxf(sa, sb);
    float e0 = expf(sa - mx), e1 = expf(sb - mx);
    const float w0 = e0 / (e0 + e1);
    const float w1 = e1 / (e0 + e1);

    float acc[2][8][4];
#pragma unroll
    for (int mi = 0; mi < 2; mi++)
#pragma unroll
        for (int ni = 0; ni < 8; ni++)
#pragma unroll
            for (int r = 0; r < 4; r++) acc[mi][ni][r] = 0.f;

    auto issue = [&](int k0, int buf) {
        float* a0_dst = A0s + buf * 128 * AST;
        float* a1_dst = A1s + buf * 128 * AST;
        float* b_dst  = Bs + buf * 128 * BST2;
#pragma unroll
        for (int it = 0; it < 4; it++) {
            int idx = it * 256 + tid;
            int row = idx >> 3, ch = idx & 7;
            int sz = (bRow + row < Mlim) ? 16 : 0;
            const float* src0 = A0 + (size_t)(bRow + row) * K + k0 + ch * 4;
            unsigned d0 = (unsigned)__cvta_generic_to_shared(a0_dst + row * AST + ch * 4);
            asm volatile("cp.async.ca.shared.global [%0], [%1], 16, %2;"
                         :: "r"(d0), "l"(src0), "r"(sz));
            const float* src1 = A1 + (size_t)(bRow + row) * K + k0 + ch * 4;
            unsigned d1 = (unsigned)__cvta_generic_to_shared(a1_dst + row * AST + ch * 4);
            asm volatile("cp.async.ca.shared.global [%0], [%1], 16, %2;"
                         :: "r"(d1), "l"(src1), "r"(sz));
        }
        const int kt = k0 >> 5;
#pragma unroll
        for (int it = 0; it < 4; it++) {
            int idx = it * 256 + tid;
            int n = idx >> 3, c = idx & 7;
            const float* src = Bt + ((size_t)kt * N + bCol + n) * 32 + c * 4;
            unsigned d = (unsigned)__cvta_generic_to_shared(b_dst + n * BST2 + c * 4);
            asm volatile("cp.async.ca.shared.global [%0], [%1], 16;"
                         :: "r"(d), "l"(src));
        }
        asm volatile("cp.async.commit_group;");
    };

    const int S = K / 32;
    issue(0, 0);
    int buf = 0;

    for (int s = 0; s < S; s++) {
        asm volatile("cp.async.wait_group 0;");
        __syncthreads();
        if (s + 1 < S) issue((s + 1) * 32, buf ^ 1);

        const float* a0p = A0s + buf * 128 * AST;
        const float* a1p = A1s + buf * 128 * AST;
        const float* bp  = Bs + buf * 128 * BST2;
#pragma unroll
        for (int ks = 0; ks < 4; ks++) {
            uint32_t af[2][4];
#pragma unroll
            for (int mi = 0; mi < 2; mi++) {
                const int mr = wm * 32 + mi * 16;
                const int o0 = (mr + g)     * AST + ks * 8 + t;
                const int o1 = (mr + g + 8) * AST + ks * 8 + t;
                float v0 = w0 * fmaxf(a0p[o0], 0.f)     + w1 * fmaxf(a1p[o0], 0.f);
                float v1 = w0 * fmaxf(a0p[o1], 0.f)     + w1 * fmaxf(a1p[o1], 0.f);
                float v2 = w0 * fmaxf(a0p[o0 + 4], 0.f) + w1 * fmaxf(a1p[o0 + 4], 0.f);
                float v3 = w0 * fmaxf(a0p[o1 + 4], 0.f) + w1 * fmaxf(a1p[o1 + 4], 0.f);
                af[mi][0] = f2tf(v0); af[mi][1] = f2tf(v1);
                af[mi][2] = f2tf(v2); af[mi][3] = f2tf(v3);
            }
#pragma unroll
            for (int ni = 0; ni < 8; ni++) {
                const int n8 = wn * 8 + ni;
                float2 bv = *(const float2*)&bp[(n8 * 8 + g) * BST2 + ks * 8 + t * 2];
                uint32_t bx = __float_as_uint(bv.x), by = __float_as_uint(bv.y);
#pragma unroll
                for (int mi = 0; mi < 2; mi++) {
                    asm volatile(
                        "mma.sync.aligned.m16n8k8.row.col.f32.tf32.tf32.f32 "
                        "{%0,%1,%2,%3}, {%4,%5,%6,%7}, {%8,%9}, {%0,%1,%2,%3};"
                        : "+f"(acc[mi][ni][0]), "+f"(acc[mi][ni][1]),
                          "+f"(acc[mi][ni][2]), "+f"(acc[mi][ni][3])
                        : "r"(af[mi][0]), "r"(af[mi][1]), "r"(af[mi][2]), "r"(af[mi][3]),
                          "r"(bx), "r"(by));
                }
            }
        }
        buf ^= 1;
    }

#pragma unroll
    for (int mi = 0; mi < 2; mi++) {
        const int r0 = bRow + wm * 32 + mi * 16 + g;
#pragma unroll
        for (int ni = 0; ni < 8; ni++) {
            const int cl = wn * 64 + ni * 8 + t * 2;
            const int c0 = bCol + cl;
            if (r0 < Mlim) {
                float2 v = make_float2(acc[mi][ni][0] + bias_s[cl],
                                       acc[mi][ni][1] + bias_s[cl + 1]);
                *(float2*)&C[(size_t)(r0 - rshift) * N + c0] = v;
            }
            if (r0 + 8 < Mlim) {
                float2 v = make_float2(acc[mi][ni][2] + bias_s[cl],
                                       acc[mi][ni][3] + bias_s[cl + 1]);
                *(float2*)&C[(size_t)(r0 + 8 - rshift) * N + c0] = v;
            }
        }
    }
}

// ================= fused CSR build ==========================================
__global__ void hist4_k(const int* __restrict__ d0, const int* __restrict__ d1,
                        const int* __restrict__ d2, const int* __restrict__ d3,
                        int* __restrict__ cnt)
{
    int i = blockIdx.x * blockDim.x + threadIdx.x;
    if (i < E_RD)                     atomicAdd(&cnt[d0[i]], 1);
    else if (i < E_RD + E_DR)         atomicAdd(&cnt[N_D + d1[i - E_RD]], 1);
    else if (i < E_RD + E_DR + E_RR)  atomicAdd(&cnt[N_D + N_R + d2[i - E_RD - E_DR]], 1);
    else if (i < E_TOT)               atomicAdd(&cnt[N_D + 2 * N_R + d3[i - E_RD - E_DR - E_RR]], 1);
}

__global__ void __launch_bounds__(1024)
scan4_k(const int* __restrict__ cnt, int* __restrict__ rptr_all)
{
    __shared__ int wsum[32];
    __shared__ int s_carry;
    const int b = blockIdx.x;
    const int n    = (b == 0 || b == 3) ? N_D : N_R;
    const int cofs = (b == 0) ? 0 : (b == 1) ? N_D : (b == 2) ? (N_D + N_R) : (N_D + 2 * N_R);
    const int* c = cnt + cofs;
    int* rptr = rptr_all + b * (N_R + 1);

    const int tid = threadIdx.x;
    const int lane = tid & 31, wid = tid >> 5;
    if (tid == 0) s_carry = 0;
    __syncthreads();
    for (int base = 0; base < n; base += 1024) {
        int i = base + tid;
        int v = (i < n) ? c[i] : 0;
        int x = v;
#pragma unroll
        for (int o = 1; o < 32; o <<= 1) {
            int y = __shfl_up_sync(0xffffffffu, x, o);
            if (lane >= o) x += y;
        }
        if (lane == 31) wsum[wid] = x;
        __syncthreads();
        if (wid == 0) {
            int tv = wsum[lane];
#pragma unroll
            for (int o = 1; o < 32; o <<= 1) {
                int y = __shfl_up_sync(0xffffffffu, tv, o);
                if (lane >= o) tv += y;
            }
            wsum[lane] = tv;
        }
        __syncthreads();
        int incl = x + (wid > 0 ? wsum[wid - 1] : 0);
        int carry = s_carry;
        if (i < n) rptr[i] = carry + incl - v;
        __syncthreads();
        if (tid == 1023) s_carry = carry + incl;
        __syncthreads();
    }
    if (tid == 0) rptr[n] = s_carry;
}

__global__ void scatter4_k(const int* __restrict__ s0, const int* __restrict__ d0,
                           const int* __restrict__ s1, const int* __restrict__ d1,
                           const int* __restrict__ s2, const int* __restrict__ d2,
                           const int* __restrict__ s3, const int* __restrict__ d3,
                           const int* __restrict__ rptr_all,
                           int* __restrict__ fill, int* __restrict__ ssort)
{
    int i = blockIdx.x * blockDim.x + threadIdx.x;
    const int* sp; const int* dp; const int* rp; int* fl; int* ss; int e;
    if (i < E_RD) {
        e = i; sp = s0; dp = d0; rp = rptr_all; fl = fill; ss = ssort;
    } else if (i < E_RD + E_DR) {
        e = i - E_RD; sp = s1; dp = d1; rp = rptr_all + (N_R + 1);
        fl = fill + N_D; ss = ssort + E_RD;
    } else if (i < E_RD + E_DR + E_RR) {
        e = i - E_RD - E_DR; sp = s2; dp = d2; rp = rptr_all + 2 * (N_R + 1);
        fl = fill + N_D + N_R; ss = ssort + E_RD + E_DR;
    } else if (i < E_TOT) {
        e = i - E_RD - E_DR - E_RR; sp = s3; dp = d3; rp = rptr_all + 3 * (N_R + 1);
        fl = fill + N_D + 2 * N_R; ss = ssort + E_RD + E_DR + E_RR;
    } else return;
    int d = dp[e];
    int pos = rp[d] + atomicAdd(&fl[d], 1);
    ss[pos] = sp[e];
}

// ============ edge aggregation: exact max pass + parallel sum pass ==========
__device__ __forceinline__ float lrelu(float x) { return x > 0.f ? x : 0.2f * x; }

__global__ void __launch_bounds__(256)
agg_csr_k(const int* __restrict__ rptr, const int* __restrict__ ssort,
          const float* __restrict__ ssrc, const float* __restrict__ sdst,
          const float* __restrict__ x, float* __restrict__ out, int Nd)
{
    const int warp = (blockIdx.x * blockDim.x + threadIdx.x) >> 5;
    const int lane = threadIdx.x & 31;
    if (warp >= Nd) return;
    const int beg = rptr[warp], end = rptr[warp + 1];

    const int h1 = lane & 7;
    const int j  = lane >> 3;
    const float sd1 = sdst[warp * HH + h1];
    float mloc = -INFINITY;
    for (int p = beg + j; p < end; p += 4) {
        int src = ssort[p];
        mloc = fmaxf(mloc, lrelu(ssrc[src * HH + h1] + sd1));
    }
    mloc = fmaxf(mloc, __shfl_xor_sync(0xffffffffu, mloc, 8));
    mloc = fmaxf(mloc, __shfl_xor_sync(0xffffffffu, mloc, 16));

    const int h2 = lane >> 2;
    const float m2  = __shfl_sync(0xffffffffu, mloc, h2);
    const float sd2 = __shfl_sync(0xffffffffu, sd1, h2);

    float s = 0.f;
    float a0 = 0.f, a1 = 0.f, a2 = 0.f, a3 = 0.f;
    float a4 = 0.f, a5 = 0.f, a6 = 0.f, a7 = 0.f;
    for (int p = beg; p < end; p++) {
        int src = ssort[p];
        float w = expf(lrelu(ssrc[src * HH + h2] + sd2) - m2);
        s += w;
        const float4* xp = (const float4*)(x + (size_t)src * CC + lane * 8);
        float4 v0 = xp[0], v1 = xp[1];
        a0 += w * v0.x; a1 += w * v0.y; a2 += w * v0.z; a3 += w * v0.w;
        a4 += w * v1.x; a5 += w * v1.y; a6 += w * v1.z; a7 += w * v1.w;
    }
    float inv = 1.f / (s + 1e-16f);
    float* op = out + (size_t)warp * CC + lane * 8;
    *(float4*)op       = make_float4(a0 * inv, a1 * inv, a2 * inv, a3 * inv);
    *(float4*)(op + 4) = make_float4(a4 * inv, a5 * inv, a6 * inv, a7 * inv);
}

// ---------------------------------------------------------------------------
extern "C" void kernel_launch(void* const* d_in, const int* in_sizes, int n_in,
                              void* d_out, int out_size)
{
    const float* x_rna   = (const float*)d_in[0];
    const float* x_dis   = (const float*)d_in[1];
    const float* W_d     = (const float*)d_in[2];
    const float* b_d     = (const float*)d_in[3];
    const float* Wp_rna  = (const float*)d_in[4];
    const float* bp_rna  = (const float*)d_in[5];
    const float* Wp_dis  = (const float*)d_in[6];
    const float* bp_dis  = (const float*)d_in[7];
    const float* a_src_rd = (const float*)d_in[8];
    const float* a_dst_rd = (const float*)d_in[9];
    const float* a_src_dr = (const float*)d_in[10];
    const float* a_dst_dr = (const float*)d_in[11];
    const float* a_src_rr = (const float*)d_in[12];
    const float* a_dst_rr = (const float*)d_in[13];
    const float* a_src_dd = (const float*)d_in[14];
    const float* a_dst_dd = (const float*)d_in[15];
    const float* kW      = (const float*)d_in[16];
    const float* kb      = (const float*)d_in[17];
    const float* qv      = (const float*)d_in[18];
    const float* W_out   = (const float*)d_in[19];
    const float* b_out   = (const float*)d_in[20];
    const int* rd_src = (const int*)d_in[21];
    const int* rd_dst = (const int*)d_in[22];
    const int* dr_src = (const int*)d_in[23];
    const int* dr_dst = (const int*)d_in[24];
    const int* rr_src = (const int*)d_in[25];
    const int* rr_dst = (const int*)d_in[26];
    const int* dd_src = (const int*)d_in[27];
    const int* dd_dst = (const int*)d_in[28];

    float* out = (float*)d_out;

    float *p_xd, *p_hr, *p_hd, *p_bufA, *p_bufB;
    float *p_sr, *p_sd, *p_scores;
    float *p_wdt, *p_wprt, *p_wpdt, *p_kwt, *p_wot;
    int *p_cnt, *p_fill, *p_rptr, *p_ssort;
    cudaGetSymbolAddress((void**)&p_xd, g_xd);
    cudaGetSymbolAddress((void**)&p_hr, g_hr);
    cudaGetSymbolAddress((void**)&p_hd, g_hd);
    cudaGetSymbolAddress((void**)&p_bufA, g_bufA);
    cudaGetSymbolAddress((void**)&p_bufB, g_bufB);
    cudaGetSymbolAddress((void**)&p_sr, g_s_rna);
    cudaGetSymbolAddress((void**)&p_sd, g_s_dis);
    cudaGetSymbolAddress((void**)&p_cnt, g_cnt);
    cudaGetSymbolAddress((void**)&p_fill, g_fill);
    cudaGetSymbolAddress((void**)&p_rptr, g_rptr);
    cudaGetSymbolAddress((void**)&p_ssort, g_ssort);
    cudaGetSymbolAddress((void**)&p_scores, g_scores);
    cudaGetSymbolAddress((void**)&p_wdt, g_wd_t);
    cudaGetSymbolAddress((void**)&p_wprt, g_wpr_t);
    cudaGetSymbolAddress((void**)&p_wpdt, g_wpd_t);
    cudaGetSymbolAddress((void**)&p_kwt, g_kw_t);
    cudaGetSymbolAddress((void**)&p_wot, g_wo_t);

    cudaFuncSetAttribute(gemm_ca<0>, cudaFuncAttributeMaxDynamicSharedMemorySize, SMEM_CA);
    cudaFuncSetAttribute(gemm_ca<1>, cudaFuncAttributeMaxDynamicSharedMemorySize, SMEM_CA);
    cudaFuncSetAttribute(gemm_ca<3>, cudaFuncAttributeMaxDynamicSharedMemorySize, SMEM_CA);
    cudaFuncSetAttribute(gemm_ca2, cudaFuncAttributeMaxDynamicSharedMemorySize, SMEM_CA2);

    const dim3 thr(256);
    const int mbr = (N_R + 127) / 128;   // 391
    const int mbd = (N_D + 127) / 128;   // 79
    const int mbt = (MT + 127) / 128;    // 470

    float* p_odr = p_bufA;
    float* p_ord = p_bufA + (size_t)MP * CC;
    float* p_orr = p_bufB;
    float* p_odd = p_bufB + (size_t)MP * CC;

    int* rp_rd = p_rptr + 0 * (N_R + 1);
    int* rp_dr = p_rptr + 1 * (N_R + 1);
    int* rp_rr = p_rptr + 2 * (N_R + 1);
    int* rp_dd = p_rptr + 3 * (N_R + 1);
    int* ss_rd = p_ssort;
    int* ss_dr = ss_rd + E_RD;
    int* ss_rr = ss_dr + E_DR;
    int* ss_dd = ss_rr + E_RR;

    cudaStream_t st0 = 0, st1, st2;
    cudaStreamCreateWithFlags(&st1, cudaStreamNonBlocking);
    cudaStreamCreateWithFlags(&st2, cudaStreamNonBlocking);
    cudaEvent_t ev[8];
    for (int i = 0; i < 8; i++) cudaEventCreateWithFlags(&ev[i], cudaEventDisableTiming);

    // fork: st2 does CSR (independent of prep)
    cudaEventRecord(ev[0], st0);
    cudaStreamWaitEvent(st2, ev[0], 0);

    // st0: weight prep, fork to st1
    prep_w_k<<<96, thr, 0, st0>>>(W_d, Wp_rna, Wp_dis, kW, W_out,
                                  p_wdt, p_wprt, p_wpdt, p_kwt, p_wot);
    cudaEventRecord(ev[1], st0);
    cudaStreamWaitEvent(st1, ev[1], 0);

    // st2: CSR build + score clear
    cudaMemsetAsync(p_cnt, 0, CNT_TOT * sizeof(int), st2);
    cudaMemsetAsync(p_fill, 0, CNT_TOT * sizeof(int), st2);
    cudaMemsetAsync(p_scores, 0, 4 * sizeof(float), st2);
    hist4_k<<<(E_TOT + 255) / 256, thr, 0, st2>>>(rd_dst, dr_dst, rr_dst, dd_dst, p_cnt);
    scan4_k<<<4, 1024, 0, st2>>>(p_cnt, p_rptr);
    scatter4_k<<<(E_TOT + 255) / 256, thr, 0, st2>>>(rd_src, rd_dst, dr_src, dr_dst,
                                                     rr_src, rr_dst, dd_src, dd_dst,
                                                     p_rptr, p_fill, p_ssort);
    cudaEventRecord(ev[2], st2);     // CSR done

    // st0: disease chain (xd -> hd + dis scores)
    gemm_ca<0><<<dim3(2, mbd), thr, SMEM_CA, st0>>>(x_dis, p_wdt, b_d, nullptr,
                                                    p_xd, nullptr, nullptr,
                                                    nullptr, nullptr, nullptr, nullptr,
                                                    nullptr, nullptr, nullptr, nullptr,
                                                    N_D, RNA_IN, D_FEAT, N_D);
    gemm_ca<3><<<dim3(2, mbd), thr, SMEM_CA, st0>>>(p_xd, p_wpdt, bp_dis, nullptr,
                                                    p_hd, nullptr, nullptr,
                                                    a_dst_rd, a_src_dr, a_src_dd, a_dst_dd,
                                                    p_sd + 0 * N_D * HH, p_sd + 1 * N_D * HH,
                                                    p_sd + 2 * N_D * HH, p_sd + 3 * N_D * HH,
                                                    N_D, CC, RNA_IN, N_D);
    cudaEventRecord(ev[3], st0);     // hd + dis scores ready

    // st1: rna chain (hr + rna scores)
    gemm_ca<3><<<dim3(2, mbr), thr, SMEM_CA, st1>>>(x_rna, p_wprt, bp_rna, nullptr,
                                                    p_hr, nullptr, nullptr,
                                                    a_src_rd, a_dst_dr, a_src_rr, a_dst_rr,
                                                    p_sr + 0 * N_R * HH, p_sr + 1 * N_R * HH,
                                                    p_sr + 2 * N_R * HH, p_sr + 3 * N_R * HH,
                                                    N_R, CC, RNA_IN, N_R);
    cudaEventRecord(ev[4], st1);     // hr + rna scores ready

    // st1: agg_rr — needs only own chain + CSR; overlaps disease side
    cudaStreamWaitEvent(st1, ev[2], 0);
    agg_csr_k<<<(N_R * 32 + 255) / 256, thr, 0, st1>>>(rp_rr, ss_rr,
                                                       p_sr + 2 * N_R * HH, p_sr + 3 * N_R * HH,
                                                       p_hr, p_orr, N_R);

    // st0: agg_dr — needs rna scores (ev4) + CSR (ev2)
    cudaStreamWaitEvent(st0, ev[4], 0);
    cudaStreamWaitEvent(st0, ev[2], 0);
    agg_csr_k<<<(N_R * 32 + 255) / 256, thr, 0, st0>>>(rp_dr, ss_dr,
                                                       p_sd + 1 * N_D * HH, p_sr + 1 * N_R * HH,
                                                       p_hd, p_odr, N_R);

    // st2: agg_dd then agg_rd — need hd/hr chains
    cudaStreamWaitEvent(st2, ev[3], 0);
    agg_csr_k<<<(N_D * 32 + 255) / 256, thr, 0, st2>>>(rp_dd, ss_dd,
                                                       p_sd + 2 * N_D * HH, p_sd + 3 * N_D * HH,
                                                       p_hd, p_odd, N_D);
    cudaEventRecord(ev[5], st2);     // agg_dd done
    cudaStreamWaitEvent(st2, ev[4], 0);
    agg_csr_k<<<(N_D * 32 + 255) / 256, thr, 0, st2>>>(rp_rd, ss_rd,
                                                       p_sr + 0 * N_R * HH, p_sd + 0 * N_D * HH,
                                                       p_hr, p_ord, N_D);
    cudaEventRecord(ev[6], st2);     // agg_rd done

    // st0: MODE1(bufA) — needs agg_dr (in-order) + agg_rd (ev6)
    cudaStreamWaitEvent(st0, ev[6], 0);
    gemm_ca<1><<<dim3(2, mbt), thr, SMEM_CA, st0>>>(p_bufA, p_kwt, kb, qv,
                                                    nullptr, p_scores + 0, p_scores + 2,
                                                    nullptr, nullptr, nullptr, nullptr,
                                                    nullptr, nullptr, nullptr, nullptr,
                                                    MT, CC, CC, N_R);

    // st1: MODE1(bufB) — needs agg_rr (in-order) + agg_dd (ev5)
    cudaStreamWaitEvent(st1, ev[5], 0);
    gemm_ca<1><<<dim3(2, mbt), thr, SMEM_CA, st1>>>(p_bufB, p_kwt, kb, qv,
                                                    nullptr, p_scores + 1, p_scores + 3,
                                                    nullptr, nullptr, nullptr, nullptr,
                                                    nullptr, nullptr, nullptr, nullptr,
                                                    MT, CC, CC, N_R);
    cudaEventRecord(ev[7], st1);

    // st0: merged tail GEMM with in-kernel softmax (waits both MODE1s)
    cudaStreamWaitEvent(st0, ev[7], 0);
    gemm_ca2<<<dim3(2, mbt), thr, SMEM_CA2, st0>>>(p_bufA, p_bufB, p_wot, b_out,
                                                   p_scores, out, MT, CC, CC, N_R,
                                                   1.f / N_R, 1.f / N_D);

    for (int i = 0; i < 8; i++) cudaEventDestroy(ev[i]);
    cudaStreamDestroy(st1);
    cudaStreamDestroy(st2);
}

// round 12
// speedup vs baseline: 6.4544x; 1.0241x over previous
#include <cuda_runtime.h>
#include <cstdint>
#include <math.h>

#define N_R 50000
#define N_D 10000
#define HH  8
#define DH  32
#define CC  256
#define RNA_IN 256
#define D_FEAT 512
#define E_RD 200000
#define E_DR 200000
#define E_RR 400000
#define E_DD 50000
#define E_TOT (E_RD + E_DR + E_RR + E_DD)
#define CNT_TOT (2 * N_R + 2 * N_D)
#define MP 50048                  // 128-aligned pad boundary (391*128)
#define MT (MP + N_D)             // 60048 total concatenated rows

// ---------------- static device scratch ------------------------------------
__device__ float    g_xd[N_D * RNA_IN];
__device__ float    g_hr[N_R * CC];
__device__ float    g_hd[N_D * CC];
__device__ float    g_bufA[(size_t)MT * CC];   // [relu(out_dr) | pad | relu(out_rd)], tf32
__device__ float    g_bufB[(size_t)MT * CC];   // [relu(out_rr) | pad | relu(out_dd)], tf32
__device__ float    g_s_rna[4 * N_R * HH];
__device__ float    g_s_dis[4 * N_D * HH];
__device__ int      g_cnt[CNT_TOT];
__device__ int      g_fill[CNT_TOT];
__device__ int      g_rptr[4 * (N_R + 1)];
__device__ int      g_ssort[E_TOT];
__device__ float    g_scores[4];
// transformed weights (tf32-rounded, mma-native blocked layout)
__device__ float    g_wd_t[D_FEAT * RNA_IN];
__device__ float    g_wpr_t[RNA_IN * CC];
__device__ float    g_wpd_t[RNA_IN * CC];
__device__ float    g_kw_t[CC * CC];
__device__ float    g_wo_t[CC * CC];

__device__ __forceinline__ uint32_t f2tf(float f) {
    uint32_t u;
    asm("cvt.rna.tf32.f32 %0, %1;" : "=r"(u) : "f"(f));
    return u;
}

// ================= weight prep: W[K][N] -> blocked n-major tf32 ==============
__global__ void __launch_bounds__(256)
prep_w_k(const float* __restrict__ wd,  const float* __restrict__ wpr,
         const float* __restrict__ wpd, const float* __restrict__ kw,
         const float* __restrict__ wo,
         float* __restrict__ wdt, float* __restrict__ wprt,
         float* __restrict__ wpdt, float* __restrict__ kwt,
         float* __restrict__ wot)
{
    __shared__ float tile[32][129];
    int b = blockIdx.x;
    const float* src; float* dst; int N, base;
    if (b < 32)      { src = wd;  dst = wdt;  N = RNA_IN; base = 0;  }
    else if (b < 48) { src = wpr; dst = wprt; N = CC;     base = 32; }
    else if (b < 64) { src = wpd; dst = wpdt; N = CC;     base = 48; }
    else if (b < 80) { src = kw;  dst = kwt;  N = CC;     base = 64; }
    else             { src = wo;  dst = wot;  N = CC;     base = 80; }
    int lb = b - base;
    int ntl = N / 128;
    int kt = lb / ntl, nb = lb % ntl;
    int k0 = kt * 32, n0 = nb * 128;
    int tid = threadIdx.x;
#pragma unroll
    for (int it = 0; it < 16; it++) {
        int idx = it * 256 + tid;
        int k = idx >> 7, n = idx & 127;
        tile[k][n] = src[(size_t)(k0 + k) * N + n0 + n];
    }
    __syncthreads();
#pragma unroll
    for (int it = 0; it < 4; it++) {
        int cidx = it * 256 + tid;
        int n = cidx >> 3, c = cidx & 7;
        float4 v;
        float* vp = (float*)&v;
#pragma unroll
        for (int q = 0; q < 4; q++) {
            int kp = c * 4 + q;
            int ks = kp >> 3, r = kp & 7;
            int kl = ks * 8 + (r >> 1) + 4 * (r & 1);
            vp[q] = __uint_as_float(f2tf(tile[kl][n]));
        }
        *(float4*)&dst[((size_t)kt * N + n0 + n) * 32 + c * 4] = v;
    }
}

// =============================================================================
// GEMM (MODE 0/1/3): cp.async, BK=32, B pre-transformed tf32
// MODE 1: A already tf32(relu(.)) -> bare LDS, no relu/cvt in hot loop
// =============================================================================
#define AST 36
#define BST2 40
#define SMEM_CA ((2 * 128 * AST + 2 * 128 * BST2 + 128 + 128 + 256 + 512) * 4)

template <int MODE>
__global__ void __launch_bounds__(256, 2)
gemm_ca(const float* __restrict__ A0, const float* __restrict__ Bt,
        const float* __restrict__ bias, const float* __restrict__ qv,
        float* __restrict__ C, float* __restrict__ score, float* __restrict__ score2,
        const float* __restrict__ av0, const float* __restrict__ av1,
        const float* __restrict__ av2, const float* __restrict__ av3,
        float* __restrict__ s0, float* __restrict__ s1,
        float* __restrict__ s2, float* __restrict__ s3,
        int M, int N, int K, int Mv1)
{
    extern __shared__ float sm[];
    float* As     = sm;
    float* Bs     = sm + 2 * 128 * AST;
    float* bias_s = sm + 2 * 128 * AST + 2 * 128 * BST2;
    float* q_s    = bias_s + 128;
    float* red    = q_s + 128;
    float* avs    = red + 256;

    const int tid  = threadIdx.x;
    const int lane = tid & 31;
    const int warp = tid >> 5;
    const int wm   = warp & 3;
    const int wn   = warp >> 2;
    const int g    = lane >> 2;
    const int t    = lane & 3;
    const int bRow = blockIdx.y * 128;
    const int bCol = blockIdx.x * 128;

    int Mlim = M;
    float* sc = score;
    if (MODE == 1) {
        if (bRow >= MP) sc = score2;
        else Mlim = Mv1;
    }

    if (tid < 128) {
        bias_s[tid] = bias[bCol + tid];
        if (MODE == 1) q_s[tid] = qv[bCol + tid];
        if (MODE == 3) {
            avs[tid]       = av0[bCol + tid];
            avs[128 + tid] = av1[bCol + tid];
            avs[256 + tid] = av2[bCol + tid];
            avs[384 + tid] = av3[bCol + tid];
        }
    }

    float acc[2][8][4];
#pragma unroll
    for (int mi = 0; mi < 2; mi++)
#pragma unroll
        for (int ni = 0; ni < 8; ni++)
#pragma unroll
            for (int r = 0; r < 4; r++) acc[mi][ni][r] = 0.f;

    auto issue = [&](int k0, int buf) {
        float* a_dst = As + buf * 128 * AST;
        float* b_dst = Bs + buf * 128 * BST2;
#pragma unroll
        for (int it = 0; it < 4; it++) {
            int idx = it * 256 + tid;
            int row = idx >> 3, ch = idx & 7;
            const float* src = A0 + (size_t)(bRow + row) * K + k0 + ch * 4;
            unsigned d = (unsigned)__cvta_generic_to_shared(a_dst + row * AST + ch * 4);
            int sz = (bRow + row < Mlim) ? 16 : 0;
            asm volatile("cp.async.ca.shared.global [%0], [%1], 16, %2;"
                         :: "r"(d), "l"(src), "r"(sz));
        }
        const int kt = k0 >> 5;
#pragma unroll
        for (int it = 0; it < 4; it++) {
            int idx = it * 256 + tid;
            int n = idx >> 3, c = idx & 7;
            const float* src = Bt + ((size_t)kt * N + bCol + n) * 32 + c * 4;
            unsigned d = (unsigned)__cvta_generic_to_shared(b_dst + n * BST2 + c * 4);
            asm volatile("cp.async.ca.shared.global [%0], [%1], 16;"
                         :: "r"(d), "l"(src));
        }
        asm volatile("cp.async.commit_group;");
    };

    const int S = K / 32;
    issue(0, 0);
    int buf = 0;

    for (int s = 0; s < S; s++) {
        asm volatile("cp.async.wait_group 0;");
        __syncthreads();
        if (s + 1 < S) issue((s + 1) * 32, buf ^ 1);

        const float* ap = As + buf * 128 * AST;
        const float* bp = Bs + buf * 128 * BST2;
#pragma unroll
        for (int ks = 0; ks < 4; ks++) {
            uint32_t af[2][4];
#pragma unroll
            for (int mi = 0; mi < 2; mi++) {
                const int mr = wm * 32 + mi * 16;
                float v0 = ap[(mr + g)     * AST + ks * 8 + t];
                float v1 = ap[(mr + g + 8) * AST + ks * 8 + t];
                float v2 = ap[(mr + g)     * AST + ks * 8 + t + 4];
                float v3 = ap[(mr + g + 8) * AST + ks * 8 + t + 4];
                if (MODE == 1) {
                    // A already tf32(relu(.)) bit patterns
                    af[mi][0] = __float_as_uint(v0); af[mi][1] = __float_as_uint(v1);
                    af[mi][2] = __float_as_uint(v2); af[mi][3] = __float_as_uint(v3);
                } else {
                    af[mi][0] = f2tf(v0); af[mi][1] = f2tf(v1);
                    af[mi][2] = f2tf(v2); af[mi][3] = f2tf(v3);
                }
            }
#pragma unroll
            for (int ni = 0; ni < 8; ni++) {
                const int n8 = wn * 8 + ni;
                float2 bv = *(const float2*)&bp[(n8 * 8 + g) * BST2 + ks * 8 + t * 2];
                uint32_t bx = __float_as_uint(bv.x), by = __float_as_uint(bv.y);
#pragma unroll
                for (int mi = 0; mi < 2; mi++) {
                    asm volatile(
                        "mma.sync.aligned.m16n8k8.row.col.f32.tf32.tf32.f32 "
                        "{%0,%1,%2,%3}, {%4,%5,%6,%7}, {%8,%9}, {%0,%1,%2,%3};"
                        : "+f"(acc[mi][ni][0]), "+f"(acc[mi][ni][1]),
                          "+f"(acc[mi][ni][2]), "+f"(acc[mi][ni][3])
                        : "r"(af[mi][0]), "r"(af[mi][1]), "r"(af[mi][2]), "r"(af[mi][3]),
                          "r"(bx), "r"(by));
                }
            }
        }
        buf ^= 1;
    }

    if (MODE == 0 || MODE == 3) {
#pragma unroll
        for (int mi = 0; mi < 2; mi++) {
            const int r0 = bRow + wm * 32 + mi * 16 + g;
#pragma unroll
            for (int ni = 0; ni < 8; ni++) {
                const int cl = wn * 64 + ni * 8 + t * 2;
                const int c0 = bCol + cl;
                if (r0 < M) {
                    float2 v = make_float2(acc[mi][ni][0] + bias_s[cl],
                                           acc[mi][ni][1] + bias_s[cl + 1]);
                    *(float2*)&C[(size_t)r0 * N + c0] = v;
                }
                if (r0 + 8 < M) {
                    float2 v = make_float2(acc[mi][ni][2] + bias_s[cl],
                                           acc[mi][ni][3] + bias_s[cl + 1]);
                    *(float2*)&C[(size_t)(r0 + 8) * N + c0] = v;
                }
            }
        }
        if (MODE == 3) {
            float* svs[4] = {s0, s1, s2, s3};
            const int headbase = 4 * blockIdx.x + wn * 2;
#pragma unroll
            for (int v = 0; v < 4; v++) {
#pragma unroll
                for (int mi = 0; mi < 2; mi++) {
                    float sA0 = 0.f, sA1 = 0.f, sB0 = 0.f, sB1 = 0.f;
#pragma unroll
                    for (int ni = 0; ni < 8; ni++) {
                        const int cl = wn * 64 + ni * 8 + t * 2;
                        float a0v = avs[v * 128 + cl];
                        float a1v = avs[v * 128 + cl + 1];
                        float dA = (acc[mi][ni][0] + bias_s[cl]) * a0v +
                                   (acc[mi][ni][1] + bias_s[cl + 1]) * a1v;
                        float dB = (acc[mi][ni][2] + bias_s[cl]) * a0v +
                                   (acc[mi][ni][3] + bias_s[cl + 1]) * a1v;
                        if (ni < 4) { sA0 += dA; sB0 += dB; }
                        else        { sA1 += dA; sB1 += dB; }
                    }
                    sA0 += __shfl_xor_sync(0xffffffffu, sA0, 1);
                    sA0 += __shfl_xor_sync(0xffffffffu, sA0, 2);
                    sA1 += __shfl_xor_sync(0xffffffffu, sA1, 1);
                    sA1 += __shfl_xor_sync(0xffffffffu, sA1, 2);
                    sB0 += __shfl_xor_sync(0xffffffffu, sB0, 1);
                    sB0 += __shfl_xor_sync(0xffffffffu, sB0, 2);
                    sB1 += __shfl_xor_sync(0xffffffffu, sB1, 1);
                    sB1 += __shfl_xor_sync(0xffffffffu, sB1, 2);
                    if (t == 0) {
                        int nodeA = bRow + wm * 32 + mi * 16 + g;
                        int nodeB = nodeA + 8;
                        if (nodeA < M) {
                            svs[v][nodeA * HH + headbase]     = sA0;
                            svs[v][nodeA * HH + headbase + 1] = sA1;
                        }
                        if (nodeB < M) {
                            svs[v][nodeB * HH + headbase]     = sB0;
                            svs[v][nodeB * HH + headbase + 1] = sB1;
                        }
                    }
                }
            }
        }
    } else {
        float local = 0.f;
#pragma unroll
        for (int mi = 0; mi < 2; mi++) {
            const int r0 = bRow + wm * 32 + mi * 16 + g;
#pragma unroll
            for (int ni = 0; ni < 8; ni++) {
                const int cl = wn * 64 + ni * 8 + t * 2;
                if (r0 < Mlim)
                    local += q_s[cl]     * tanhf(acc[mi][ni][0] + bias_s[cl]) +
                             q_s[cl + 1] * tanhf(acc[mi][ni][1] + bias_s[cl + 1]);
                if (r0 + 8 < Mlim)
                    local += q_s[cl]     * tanhf(acc[mi][ni][2] + bias_s[cl]) +
                             q_s[cl + 1] * tanhf(acc[mi][ni][3] + bias_s[cl + 1]);
            }
        }
        red[tid] = local;
        __syncthreads();
        for (int st = 128; st > 0; st >>= 1) {
            if (tid < st) red[tid] += red[tid + st];
            __syncthreads();
        }
        if (tid == 0) atomicAdd(sc, red[0]);
    }
}

// =============================================================================
// MODE2 merged tail GEMM, softmax in-kernel; A buffers already relu'd (tf32)
// =============================================================================
#define SMEM_CA2 ((2 * 2 * 128 * AST + 2 * 128 * BST2 + 128) * 4)

__global__ void __launch_bounds__(256, 1)
gemm_ca2(const float* __restrict__ A0, const float* __restrict__ A1,
         const float* __restrict__ Bt, const float* __restrict__ bias,
         const float* __restrict__ scores, float* __restrict__ C,
         int M, int N, int K, int Mv1, float invNr, float invNd)
{
    extern __shared__ float sm[];
    float* A0s    = sm;
    float* A1s    = sm + 2 * 128 * AST;
    float* Bs     = sm + 4 * 128 * AST;
    float* bias_s = sm + 4 * 128 * AST + 2 * 128 * BST2;

    const int tid  = threadIdx.x;
    const int lane = tid & 31;
    const int warp = tid >> 5;
    const int wm   = warp & 3;
    const int wn   = warp >> 2;
    const int g    = lane >> 2;
    const int t    = lane & 3;
    const int bRow = blockIdx.y * 128;
    const int bCol = blockIdx.x * 128;

    const bool isDis = (bRow >= MP);
    const int Mlim = isDis ? M : Mv1;
    const int rshift = isDis ? (MP - Mv1) : 0;

    if (tid < 128) bias_s[tid] = bias[bCol + tid];

    float invN = isDis ? invNd : invNr;
    float sa = scores[isDis ? 2 : 0] * invN;
    float sb = scores[isDis ? 3 : 1] * invN;
    float mx = fmaxf(sa, sb);
    float e0 = expf(sa - mx), e1 = expf(sb - mx);
    const float w0 = e0 / (e0 + e1);
    const float w1 = e1 / (e0 + e1);

    float acc[2][8][4];
#pragma unroll
    for (int mi = 0; mi < 2; mi++)
#pragma unroll
        for (int ni = 0; ni < 8; ni++)
#pragma unroll
            for (int r = 0; r < 4; r++) acc[mi][ni][r] = 0.f;

    auto issue = [&](int k0, int buf) {
        float* a0_dst = A0s + buf * 128 * AST;
        float* a1_dst = A1s + buf * 128 * AST;
        float* b_dst  = Bs + buf * 128 * BST2;
#pragma unroll
        for (int it = 0; it < 4; it++) {
            int idx = it * 256 + tid;
            int row = idx >> 3, ch = idx & 7;
            int sz = (bRow + row < Mlim) ? 16 : 0;
            const float* src0 = A0 + (size_t)(bRow + row) * K + k0 + ch * 4;
            unsigned d0 = (unsigned)__cvta_generic_to_shared(a0_dst + row * AST + ch * 4);
            asm volatile("cp.async.ca.shared.global [%0], [%1], 16, %2;"
                         :: "r"(d0), "l"(src0), "r"(sz));
            const float* src1 = A1 + (size_t)(bRow + row) * K + k0 + ch * 4;
            unsigned d1 = (unsigned)__cvta_generic_to_shared(a1_dst + row * AST + ch * 4);
            asm volatile("cp.async.ca.shared.global [%0], [%1], 16, %2;"
                         :: "r"(d1), "l"(src1), "r"(sz));
        }
        const int kt = k0 >> 5;
#pragma unroll
        for (int it = 0; it < 4; it++) {
            int idx = it * 256 + tid;
            int n = idx >> 3, c = idx & 7;
            const float* src = Bt + ((size_t)kt * N + bCol + n) * 32 + c * 4;
            unsigned d = (unsigned)__cvta_generic_to_shared(b_dst + n * BST2 + c * 4);
            asm volatile("cp.async.ca.shared.global [%0], [%1], 16;"
                         :: "r"(d), "l"(src));
        }
        asm volatile("cp.async.commit_group;");
    };

    const int S = K / 32;
    issue(0, 0);
    int buf = 0;

    for (int s = 0; s < S; s++) {
        asm volatile("cp.async.wait_group 0;");
        __syncthreads();
        if (s + 1 < S) issue((s + 1) * 32, buf ^ 1);

        const float* a0p = A0s + buf * 128 * AST;
        const float* a1p = A1s + buf * 128 * AST;
        const float* bp  = Bs + buf * 128 * BST2;
#pragma unroll
        for (int ks = 0; ks < 4; ks++) {
            uint32_t af[2][4];
#pragma unroll
            for (int mi = 0; mi < 2; mi++) {
                const int mr = wm * 32 + mi * 16;
                const int o0 = (mr + g)     * AST + ks * 8 + t;
                const int o1 = (mr + g + 8) * AST + ks * 8 + t;
                // A already relu'd: just combine + round
                af[mi][0] = f2tf(w0 * a0p[o0]     + w1 * a1p[o0]);
                af[mi][1] = f2tf(w0 * a0p[o1]     + w1 * a1p[o1]);
                af[mi][2] = f2tf(w0 * a0p[o0 + 4] + w1 * a1p[o0 + 4]);
                af[mi][3] = f2tf(w0 * a0p[o1 + 4] + w1 * a1p[o1 + 4]);
            }
#pragma unroll
            for (int ni = 0; ni < 8; ni++) {
                const int n8 = wn * 8 + ni;
                float2 bv = *(const float2*)&bp[(n8 * 8 + g) * BST2 + ks * 8 + t * 2];
                uint32_t bx = __float_as_uint(bv.x), by = __float_as_uint(bv.y);
#pragma unroll
                for (int mi = 0; mi < 2; mi++) {
                    asm volatile(
                        "mma.sync.aligned.m16n8k8.row.col.f32.tf32.tf32.f32 "
                        "{%0,%1,%2,%3}, {%4,%5,%6,%7}, {%8,%9}, {%0,%1,%2,%3};"
                        : "+f"(acc[mi][ni][0]), "+f"(acc[mi][ni][1]),
                          "+f"(acc[mi][ni][2]), "+f"(acc[mi][ni][3])
                        : "r"(af[mi][0]), "r"(af[mi][1]), "r"(af[mi][2]), "r"(af[mi][3]),
                          "r"(bx), "r"(by));
                }
            }
        }
        buf ^= 1;
    }

#pragma unroll
    for (int mi = 0; mi < 2; mi++) {
        const int r0 = bRow + wm * 32 + mi * 16 + g;
#pragma unroll
        for (int ni = 0; ni < 8; ni++) {
            const int cl = wn * 64 + ni * 8 + t * 2;
            const int c0 = bCol + cl;
            if (r0 < Mlim) {
                float2 v = make_float2(acc[mi][ni][0] + bias_s[cl],
                                       acc[mi][ni][1] + bias_s[cl + 1]);
                *(float2*)&C[(size_t)(r0 - rshift) * N + c0] = v;
            }
            if (r0 + 8 < Mlim) {
                float2 v = make_float2(acc[mi][ni][2] + bias_s[cl],
                                       acc[mi][ni][3] + bias_s[cl + 1]);
                *(float2*)&C[(size_t)(r0 + 8 - rshift) * N + c0] = v;
            }
        }
    }
}

// ================= fused CSR build ==========================================
__global__ void hist4_k(const int* __restrict__ d0, const int* __restrict__ d1,
                        const int* __restrict__ d2, const int* __restrict__ d3,
                        int* __restrict__ cnt)
{
    int i = blockIdx.x * blockDim.x + threadIdx.x;
    if (i < E_RD)                     atomicAdd(&cnt[d0[i]], 1);
    else if (i < E_RD + E_DR)         atomicAdd(&cnt[N_D + d1[i - E_RD]], 1);
    else if (i < E_RD + E_DR + E_RR)  atomicAdd(&cnt[N_D + N_R + d2[i - E_RD - E_DR]], 1);
    else if (i < E_TOT)               atomicAdd(&cnt[N_D + 2 * N_R + d3[i - E_RD - E_DR - E_RR]], 1);
}

__global__ void __launch_bounds__(1024)
scan4_k(const int* __restrict__ cnt, int* __restrict__ rptr_all)
{
    __shared__ int wsum[32];
    __shared__ int s_carry;
    const int b = blockIdx.x;
    const int n    = (b == 0 || b == 3) ? N_D : N_R;
    const int cofs = (b == 0) ? 0 : (b == 1) ? N_D : (b == 2) ? (N_D + N_R) : (N_D + 2 * N_R);
    const int* c = cnt + cofs;
    int* rptr = rptr_all + b * (N_R + 1);

    const int tid = threadIdx.x;
    const int lane = tid & 31, wid = tid >> 5;
    if (tid == 0) s_carry = 0;
    __syncthreads();
    for (int base = 0; base < n; base += 1024) {
        int i = base + tid;
        int v = (i < n) ? c[i] : 0;
        int x = v;
#pragma unroll
        for (int o = 1; o < 32; o <<= 1) {
            int y = __shfl_up_sync(0xffffffffu, x, o);
            if (lane >= o) x += y;
        }
        if (lane == 31) wsum[wid] = x;
        __syncthreads();
        if (wid == 0) {
            int tv = wsum[lane];
#pragma unroll
            for (int o = 1; o < 32; o <<= 1) {
                int y = __shfl_up_sync(0xffffffffu, tv, o);
                if (lane >= o) tv += y;
            }
            wsum[lane] = tv;
        }
        __syncthreads();
        int incl = x + (wid > 0 ? wsum[wid - 1] : 0);
        int carry = s_carry;
        if (i < n) rptr[i] = carry + incl - v;
        __syncthreads();
        if (tid == 1023) s_carry = carry + incl;
        __syncthreads();
    }
    if (tid == 0) rptr[n] = s_carry;
}

__global__ void scatter4_k(const int* __restrict__ s0, const int* __restrict__ d0,
                           const int* __restrict__ s1, const int* __restrict__ d1,
                           const int* __restrict__ s2, const int* __restrict__ d2,
                           const int* __restrict__ s3, const int* __restrict__ d3,
                           const int* __restrict__ rptr_all,
                           int* __restrict__ fill, int* __restrict__ ssort)
{
    int i = blockIdx.x * blockDim.x + threadIdx.x;
    const int* sp; const int* dp; const int* rp; int* fl; int* ss; int e;
    if (i < E_RD) {
        e = i; sp = s0; dp = d0; rp = rptr_all; fl = fill; ss = ssort;
    } else if (i < E_RD + E_DR) {
        e = i - E_RD; sp = s1; dp = d1; rp = rptr_all + (N_R + 1);
        fl = fill + N_D; ss = ssort + E_RD;
    } else if (i < E_RD + E_DR + E_RR) {
        e = i - E_RD - E_DR; sp = s2; dp = d2; rp = rptr_all + 2 * (N_R + 1);
        fl = fill + N_D + N_R; ss = ssort + E_RD + E_DR;
    } else if (i < E_TOT) {
        e = i - E_RD - E_DR - E_RR; sp = s3; dp = d3; rp = rptr_all + 3 * (N_R + 1);
        fl = fill + N_D + 2 * N_R; ss = ssort + E_RD + E_DR + E_RR;
    } else return;
    int d = dp[e];
    int pos = rp[d] + atomicAdd(&fl[d], 1);
    ss[pos] = sp[e];
}

// ============ edge aggregation: single pass (softmax shift-invariant) =======
__device__ __forceinline__ float lrelu(float x) { return x > 0.f ? x : 0.2f * x; }

__global__ void __launch_bounds__(256)
agg_csr_k(const int* __restrict__ rptr, const int* __restrict__ ssort,
          const float* __restrict__ ssrc, const float* __restrict__ sdst,
          const float* __restrict__ x, float* __restrict__ out, int Nd)
{
    const int warp = (blockIdx.x * blockDim.x + threadIdx.x) >> 5;
    const int lane = threadIdx.x & 31;
    if (warp >= Nd) return;
    const int beg = rptr[warp], end = rptr[warp + 1];

    const int h2 = lane >> 2;
    const float sd2 = sdst[warp * HH + h2];

    float s = 0.f;
    float a0 = 0.f, a1 = 0.f, a2 = 0.f, a3 = 0.f;
    float a4 = 0.f, a5 = 0.f, a6 = 0.f, a7 = 0.f;
    for (int p = beg; p < end; p++) {
        int src = ssort[p];
        float w = expf(lrelu(ssrc[src * HH + h2] + sd2));  // scores tiny: no shift needed
        s += w;
        const float4* xp = (const float4*)(x + (size_t)src * CC + lane * 8);
        float4 v0 = xp[0], v1 = xp[1];
        a0 += w * v0.x; a1 += w * v0.y; a2 += w * v0.z; a3 += w * v0.w;
        a4 += w * v1.x; a5 += w * v1.y; a6 += w * v1.z; a7 += w * v1.w;
    }
    float inv = 1.f / (s + 1e-16f);
    // write relu'd, tf32-rounded values (consumers use only tf32(relu(.)))
    float* op = out + (size_t)warp * CC + lane * 8;
    float4 r0, r1;
    r0.x = __uint_as_float(f2tf(fmaxf(a0 * inv, 0.f)));
    r0.y = __uint_as_float(f2tf(fmaxf(a1 * inv, 0.f)));
    r0.z = __uint_as_float(f2tf(fmaxf(a2 * inv, 0.f)));
    r0.w = __uint_as_float(f2tf(fmaxf(a3 * inv, 0.f)));
    r1.x = __uint_as_float(f2tf(fmaxf(a4 * inv, 0.f)));
    r1.y = __uint_as_float(f2tf(fmaxf(a5 * inv, 0.f)));
    r1.z = __uint_as_float(f2tf(fmaxf(a6 * inv, 0.f)));
    r1.w = __uint_as_float(f2tf(fmaxf(a7 * inv, 0.f)));
    *(float4*)op       = r0;
    *(float4*)(op + 4) = r1;
}

// ---------------------------------------------------------------------------
extern "C" void kernel_launch(void* const* d_in, const int* in_sizes, int n_in,
                              void* d_out, int out_size)
{
    const float* x_rna   = (const float*)d_in[0];
    const float* x_dis   = (const float*)d_in[1];
    const float* W_d     = (const float*)d_in[2];
    const float* b_d     = (const float*)d_in[3];
    const float* Wp_rna  = (const float*)d_in[4];
    const float* bp_rna  = (const float*)d_in[5];
    const float* Wp_dis  = (const float*)d_in[6];
    const float* bp_dis  = (const float*)d_in[7];
    const float* a_src_rd = (const float*)d_in[8];
    const float* a_dst_rd = (const float*)d_in[9];
    const float* a_src_dr = (const float*)d_in[10];
    const float* a_dst_dr = (const float*)d_in[11];
    const float* a_src_rr = (const float*)d_in[12];
    const float* a_dst_rr = (const float*)d_in[13];
    const float* a_src_dd = (const float*)d_in[14];
    const float* a_dst_dd = (const float*)d_in[15];
    const float* kW      = (const float*)d_in[16];
    const float* kb      = (const float*)d_in[17];
    const float* qv      = (const float*)d_in[18];
    const float* W_out   = (const float*)d_in[19];
    const float* b_out   = (const float*)d_in[20];
    const int* rd_src = (const int*)d_in[21];
    const int* rd_dst = (const int*)d_in[22];
    const int* dr_src = (const int*)d_in[23];
    const int* dr_dst = (const int*)d_in[24];
    const int* rr_src = (const int*)d_in[25];
    const int* rr_dst = (const int*)d_in[26];
    const int* dd_src = (const int*)d_in[27];
    const int* dd_dst = (const int*)d_in[28];

    float* out = (float*)d_out;

    float *p_xd, *p_hr, *p_hd, *p_bufA, *p_bufB;
    float *p_sr, *p_sd, *p_scores;
    float *p_wdt, *p_wprt, *p_wpdt, *p_kwt, *p_wot;
    int *p_cnt, *p_fill, *p_rptr, *p_ssort;
    cudaGetSymbolAddress((void**)&p_xd, g_xd);
    cudaGetSymbolAddress((void**)&p_hr, g_hr);
    cudaGetSymbolAddress((void**)&p_hd, g_hd);
    cudaGetSymbolAddress((void**)&p_bufA, g_bufA);
    cudaGetSymbolAddress((void**)&p_bufB, g_bufB);
    cudaGetSymbolAddress((void**)&p_sr, g_s_rna);
    cudaGetSymbolAddress((void**)&p_sd, g_s_dis);
    cudaGetSymbolAddress((void**)&p_cnt, g_cnt);
    cudaGetSymbolAddress((void**)&p_fill, g_fill);
    cudaGetSymbolAddress((void**)&p_rptr, g_rptr);
    cudaGetSymbolAddress((void**)&p_ssort, g_ssort);
    cudaGetSymbolAddress((void**)&p_scores, g_scores);
    cudaGetSymbolAddress((void**)&p_wdt, g_wd_t);
    cudaGetSymbolAddress((void**)&p_wprt, g_wpr_t);
    cudaGetSymbolAddress((void**)&p_wpdt, g_wpd_t);
    cudaGetSymbolAddress((void**)&p_kwt, g_kw_t);
    cudaGetSymbolAddress((void**)&p_wot, g_wo_t);

    cudaFuncSetAttribute(gemm_ca<0>, cudaFuncAttributeMaxDynamicSharedMemorySize, SMEM_CA);
    cudaFuncSetAttribute(gemm_ca<1>, cudaFuncAttributeMaxDynamicSharedMemorySize, SMEM_CA);
    cudaFuncSetAttribute(gemm_ca<3>, cudaFuncAttributeMaxDynamicSharedMemorySize, SMEM_CA);
    cudaFuncSetAttribute(gemm_ca2, cudaFuncAttributeMaxDynamicSharedMemorySize, SMEM_CA2);

    const dim3 thr(256);
    const int mbr = (N_R + 127) / 128;   // 391
    const int mbd = (N_D + 127) / 128;   // 79
    const int mbt = (MT + 127) / 128;    // 470

    float* p_odr = p_bufA;
    float* p_ord = p_bufA + (size_t)MP * CC;
    float* p_orr = p_bufB;
    float* p_odd = p_bufB + (size_t)MP * CC;

    int* rp_rd = p_rptr + 0 * (N_R + 1);
    int* rp_dr = p_rptr + 1 * (N_R + 1);
    int* rp_rr = p_rptr + 2 * (N_R + 1);
    int* rp_dd = p_rptr + 3 * (N_R + 1);
    int* ss_rd = p_ssort;
    int* ss_dr = ss_rd + E_RD;
    int* ss_rr = ss_dr + E_DR;
    int* ss_dd = ss_rr + E_RR;

    cudaStream_t st0 = 0, st1, st2;
    cudaStreamCreateWithFlags(&st1, cudaStreamNonBlocking);
    cudaStreamCreateWithFlags(&st2, cudaStreamNonBlocking);
    cudaEvent_t ev[8];
    for (int i = 0; i < 8; i++) cudaEventCreateWithFlags(&ev[i], cudaEventDisableTiming);

    // fork: st2 does CSR (independent of prep)
    cudaEventRecord(ev[0], st0);
    cudaStreamWaitEvent(st2, ev[0], 0);

    // st0: weight prep, fork to st1
    prep_w_k<<<96, thr, 0, st0>>>(W_d, Wp_rna, Wp_dis, kW, W_out,
                                  p_wdt, p_wprt, p_wpdt, p_kwt, p_wot);
    cudaEventRecord(ev[1], st0);
    cudaStreamWaitEvent(st1, ev[1], 0);

    // st2: CSR build + score clear
    cudaMemsetAsync(p_cnt, 0, CNT_TOT * sizeof(int), st2);
    cudaMemsetAsync(p_fill, 0, CNT_TOT * sizeof(int), st2);
    cudaMemsetAsync(p_scores, 0, 4 * sizeof(float), st2);
    hist4_k<<<(E_TOT + 255) / 256, thr, 0, st2>>>(rd_dst, dr_dst, rr_dst, dd_dst, p_cnt);
    scan4_k<<<4, 1024, 0, st2>>>(p_cnt, p_rptr);
    scatter4_k<<<(E_TOT + 255) / 256, thr, 0, st2>>>(rd_src, rd_dst, dr_src, dr_dst,
                                                     rr_src, rr_dst, dd_src, dd_dst,
                                                     p_rptr, p_fill, p_ssort);
    cudaEventRecord(ev[2], st2);     // CSR done

    // st0: disease chain (xd -> hd + dis scores)
    gemm_ca<0><<<dim3(2, mbd), thr, SMEM_CA, st0>>>(x_dis, p_wdt, b_d, nullptr,
                                                    p_xd, nullptr, nullptr,
                                                    nullptr, nullptr, nullptr, nullptr,
                                                    nullptr, nullptr, nullptr, nullptr,
                                                    N_D, RNA_IN, D_FEAT, N_D);
    gemm_ca<3><<<dim3(2, mbd), thr, SMEM_CA, st0>>>(p_xd, p_wpdt, bp_dis, nullptr,
                                                    p_hd, nullptr, nullptr,
                                                    a_dst_rd, a_src_dr, a_src_dd, a_dst_dd,
                                                    p_sd + 0 * N_D * HH, p_sd + 1 * N_D * HH,
                                                    p_sd + 2 * N_D * HH, p_sd + 3 * N_D * HH,
                                                    N_D, CC, RNA_IN, N_D);
    cudaEventRecord(ev[3], st0);     // hd + dis scores ready

    // st1: rna chain (hr + rna scores)
    gemm_ca<3><<<dim3(2, mbr), thr, SMEM_CA, st1>>>(x_rna, p_wprt, bp_rna, nullptr,
                                                    p_hr, nullptr, nullptr,
                                                    a_src_rd, a_dst_dr, a_src_rr, a_dst_rr,
                                                    p_sr + 0 * N_R * HH, p_sr + 1 * N_R * HH,
                                                    p_sr + 2 * N_R * HH, p_sr + 3 * N_R * HH,
                                                    N_R, CC, RNA_IN, N_R);
    cudaEventRecord(ev[4], st1);     // hr + rna scores ready

    // st1: agg_rr — needs only own chain + CSR
    cudaStreamWaitEvent(st1, ev[2], 0);
    agg_csr_k<<<(N_R * 32 + 255) / 256, thr, 0, st1>>>(rp_rr, ss_rr,
                                                       p_sr + 2 * N_R * HH, p_sr + 3 * N_R * HH,
                                                       p_hr, p_orr, N_R);

    // st0: agg_dr — needs rna scores + CSR
    cudaStreamWaitEvent(st0, ev[4], 0);
    cudaStreamWaitEvent(st0, ev[2], 0);
    agg_csr_k<<<(N_R * 32 + 255) / 256, thr, 0, st0>>>(rp_dr, ss_dr,
                                                       p_sd + 1 * N_D * HH, p_sr + 1 * N_R * HH,
                                                       p_hd, p_odr, N_R);

    // st2: agg_dd then agg_rd
    cudaStreamWaitEvent(st2, ev[3], 0);
    agg_csr_k<<<(N_D * 32 + 255) / 256, thr, 0, st2>>>(rp_dd, ss_dd,
                                                       p_sd + 2 * N_D * HH, p_sd + 3 * N_D * HH,
                                                       p_hd, p_odd, N_D);
    cudaEventRecord(ev[5], st2);     // agg_dd done
    cudaStreamWaitEvent(st2, ev[4], 0);
    agg_csr_k<<<(N_D * 32 + 255) / 256, thr, 0, st2>>>(rp_rd, ss_rd,
                                                       p_sr + 0 * N_R * HH, p_sd + 0 * N_D * HH,
                                                       p_hr, p_ord, N_D);
    cudaEventRecord(ev[6], st2);     // agg_rd done

    // st0: MODE1(bufA) — needs agg_dr (in-order) + agg_rd
    cudaStreamWaitEvent(st0, ev[6], 0);
    gemm_ca<1><<<dim3(2, mbt), thr, SMEM_CA, st0>>>(p_bufA, p_kwt, kb, qv,
                                                    nullptr, p_scores + 0, p_scores + 2,
                                                    nullptr, nullptr, nullptr, nullptr,
                                                    nullptr, nullptr, nullptr, nullptr,
                                                    MT, CC, CC, N_R);

    // st1: MODE1(bufB) — needs agg_rr (in-order) + agg_dd
    cudaStreamWaitEvent(st1, ev[5], 0);
    gemm_ca<1><<<dim3(2, mbt), thr, SMEM_CA, st1>>>(p_bufB, p_kwt, kb, qv,
                                                    nullptr, p_scores + 1, p_scores + 3,
                                                    nullptr, nullptr, nullptr, nullptr,
                                                    nullptr, nullptr, nullptr, nullptr,
                                                    MT, CC, CC, N_R);
    cudaEventRecord(ev[7], st1);

    // st0: merged tail GEMM with in-kernel softmax
    cudaStreamWaitEvent(st0, ev[7], 0);
    gemm_ca2<<<dim3(2, mbt), thr, SMEM_CA2, st0>>>(p_bufA, p_bufB, p_wot, b_out,
                                                   p_scores, out, MT, CC, CC, N_R,
                                                   1.f / N_R, 1.f / N_D);

    for (int i = 0; i < 8; i++) cudaEventDestroy(ev[i]);
    cudaStreamDestroy(st1);
    cudaStreamDestroy(st2);
}

// round 13
// speedup vs baseline: 7.7012x; 1.1932x over previous
#include <cuda_runtime.h>
#include <cuda_fp16.h>
#include <cstdint>
#include <math.h>

#define N_R 50000
#define N_D 10000
#define HH  8
#define DH  32
#define CC  256
#define RNA_IN 256
#define D_FEAT 512
#define E_RD 200000
#define E_DR 200000
#define E_RR 400000
#define E_DD 50000
#define E_TOT (E_RD + E_DR + E_RR + E_DD)
#define CNT_TOT (2 * N_R + 2 * N_D)
#define MP 50048
#define MT (MP + N_D)

// ---------------- static device scratch ------------------------------------
__device__ float    g_xd[N_D * RNA_IN];
__device__ float    g_hr[N_R * CC];
__device__ float    g_hd[N_D * CC];
__device__ __half   g_bufA[(size_t)MT * CC];   // fp16 [relu(out_dr) | pad | relu(out_rd)]
__device__ __half   g_bufB[(size_t)MT * CC];   // fp16 [relu(out_rr) | pad | relu(out_dd)]
__device__ float    g_s_rna[4 * N_R * HH];
__device__ float    g_s_dis[4 * N_D * HH];
__device__ int      g_cnt[CNT_TOT];
__device__ int      g_fill[CNT_TOT];
__device__ int      g_rptr[4 * (N_R + 1)];
__device__ int      g_ssort[E_TOT];
__device__ float    g_scores[4];
// transformed weights
__device__ float    g_wd_t[D_FEAT * RNA_IN];   // tf32 blocked (projections)
__device__ float    g_wpr_t[RNA_IN * CC];
__device__ float    g_wpd_t[RNA_IN * CC];
__device__ __half   g_kw_h[CC * CC];           // fp16 k-linear (semantic)
__device__ __half   g_wo_h[CC * CC];           // fp16 k-linear (tail)

__device__ __forceinline__ uint32_t f2tf(float f) {
    uint32_t u;
    asm("cvt.rna.tf32.f32 %0, %1;" : "=r"(u) : "f"(f));
    return u;
}

// ================= weight prep ===============================================
// tf32 blocked (b<64):  Wt[((k/32)*N+n)*32 + k'], k' interleave for m16n8k8
// fp16 k-linear (b>=64): Wh[((k/32)*N+n)*32 + k%32]
__global__ void __launch_bounds__(256)
prep_w_k(const float* __restrict__ wd,  const float* __restrict__ wpr,
         const float* __restrict__ wpd, const float* __restrict__ kw,
         const float* __restrict__ wo,
         float* __restrict__ wdt, float* __restrict__ wprt,
         float* __restrict__ wpdt,
         __half* __restrict__ kwh, __half* __restrict__ woh)
{
    __shared__ float tile[32][129];
    int b = blockIdx.x;
    const float* src; float* dstf = nullptr; __half* dsth = nullptr; int N, base;
    if (b < 32)      { src = wd;  dstf = wdt;  N = RNA_IN; base = 0;  }
    else if (b < 48) { src = wpr; dstf = wprt; N = CC;     base = 32; }
    else if (b < 64) { src = wpd; dstf = wpdt; N = CC;     base = 48; }
    else if (b < 80) { src = kw;  dsth = kwh;  N = CC;     base = 64; }
    else             { src = wo;  dsth = woh;  N = CC;     base = 80; }
    int lb = b - base;
    int ntl = N / 128;
    int kt = lb / ntl, nb = lb % ntl;
    int k0 = kt * 32, n0 = nb * 128;
    int tid = threadIdx.x;
#pragma unroll
    for (int it = 0; it < 16; it++) {
        int idx = it * 256 + tid;
        int k = idx >> 7, n = idx & 127;
        tile[k][n] = src[(size_t)(k0 + k) * N + n0 + n];
    }
    __syncthreads();
    if (dstf) {
#pragma unroll
        for (int it = 0; it < 4; it++) {
            int cidx = it * 256 + tid;
            int n = cidx >> 3, c = cidx & 7;
            float4 v;
            float* vp = (float*)&v;
#pragma unroll
            for (int q = 0; q < 4; q++) {
                int kp = c * 4 + q;
                int ks = kp >> 3, r = kp & 7;
                int kl = ks * 8 + (r >> 1) + 4 * (r & 1);
                vp[q] = __uint_as_float(f2tf(tile[kl][n]));
            }
            *(float4*)&dstf[((size_t)kt * N + n0 + n) * 32 + c * 4] = v;
        }
    } else {
#pragma unroll
        for (int it = 0; it < 2; it++) {
            int cidx = it * 256 + tid;
            int n = cidx >> 2, cg = cidx & 3;
            __half hb[8];
#pragma unroll
            for (int j = 0; j < 8; j++) hb[j] = __float2half_rn(tile[cg * 8 + j][n]);
            *(uint4*)&dsth[((size_t)kt * N + n0 + n) * 32 + cg * 8] = *(uint4*)hb;
        }
    }
}

// =============================================================================
// tf32 GEMM (MODE 0/3): projections (A fp32 gmem)
// =============================================================================
#define AST 36
#define BST2 40
#define SMEM_CA ((2 * 128 * AST + 2 * 128 * BST2 + 128 + 512 + 512) * 4)

template <int MODE>
__global__ void __launch_bounds__(256, 2)
gemm_ca(const float* __restrict__ A0, const float* __restrict__ Bt,
        const float* __restrict__ bias,
        float* __restrict__ C,
        const float* __restrict__ av0, const float* __restrict__ av1,
        const float* __restrict__ av2, const float* __restrict__ av3,
        float* __restrict__ s0, float* __restrict__ s1,
        float* __restrict__ s2, float* __restrict__ s3,
        int M, int N, int K)
{
    extern __shared__ float sm[];
    float* As     = sm;
    float* Bs     = sm + 2 * 128 * AST;
    float* bias_s = sm + 2 * 128 * AST + 2 * 128 * BST2;
    float* avs    = bias_s + 128;

    const int tid  = threadIdx.x;
    const int lane = tid & 31;
    const int warp = tid >> 5;
    const int wm   = warp & 3;
    const int wn   = warp >> 2;
    const int g    = lane >> 2;
    const int t    = lane & 3;
    const int bRow = blockIdx.y * 128;
    const int bCol = blockIdx.x * 128;

    if (tid < 128) {
        bias_s[tid] = bias[bCol + tid];
        if (MODE == 3) {
            avs[tid]       = av0[bCol + tid];
            avs[128 + tid] = av1[bCol + tid];
            avs[256 + tid] = av2[bCol + tid];
            avs[384 + tid] = av3[bCol + tid];
        }
    }

    float acc[2][8][4];
#pragma unroll
    for (int mi = 0; mi < 2; mi++)
#pragma unroll
        for (int ni = 0; ni < 8; ni++)
#pragma unroll
            for (int r = 0; r < 4; r++) acc[mi][ni][r] = 0.f;

    auto issue = [&](int k0, int buf) {
        float* a_dst = As + buf * 128 * AST;
        float* b_dst = Bs + buf * 128 * BST2;
#pragma unroll
        for (int it = 0; it < 4; it++) {
            int idx = it * 256 + tid;
            int row = idx >> 3, ch = idx & 7;
            const float* src = A0 + (size_t)(bRow + row) * K + k0 + ch * 4;
            unsigned d = (unsigned)__cvta_generic_to_shared(a_dst + row * AST + ch * 4);
            int sz = (bRow + row < M) ? 16 : 0;
            asm volatile("cp.async.ca.shared.global [%0], [%1], 16, %2;"
                         :: "r"(d), "l"(src), "r"(sz));
        }
        const int kt = k0 >> 5;
#pragma unroll
        for (int it = 0; it < 4; it++) {
            int idx = it * 256 + tid;
            int n = idx >> 3, c = idx & 7;
            const float* src = Bt + ((size_t)kt * N + bCol + n) * 32 + c * 4;
            unsigned d = (unsigned)__cvta_generic_to_shared(b_dst + n * BST2 + c * 4);
            asm volatile("cp.async.ca.shared.global [%0], [%1], 16;"
                         :: "r"(d), "l"(src));
        }
        asm volatile("cp.async.commit_group;");
    };

    const int S = K / 32;
    issue(0, 0);
    int buf = 0;

    for (int s = 0; s < S; s++) {
        asm volatile("cp.async.wait_group 0;");
        __syncthreads();
        if (s + 1 < S) issue((s + 1) * 32, buf ^ 1);

        const float* ap = As + buf * 128 * AST;
        const float* bp = Bs + buf * 128 * BST2;
#pragma unroll
        for (int ks = 0; ks < 4; ks++) {
            uint32_t af[2][4];
#pragma unroll
            for (int mi = 0; mi < 2; mi++) {
                const int mr = wm * 32 + mi * 16;
                af[mi][0] = f2tf(ap[(mr + g)     * AST + ks * 8 + t]);
                af[mi][1] = f2tf(ap[(mr + g + 8) * AST + ks * 8 + t]);
                af[mi][2] = f2tf(ap[(mr + g)     * AST + ks * 8 + t + 4]);
                af[mi][3] = f2tf(ap[(mr + g + 8) * AST + ks * 8 + t + 4]);
            }
#pragma unroll
            for (int ni = 0; ni < 8; ni++) {
                const int n8 = wn * 8 + ni;
                float2 bv = *(const float2*)&bp[(n8 * 8 + g) * BST2 + ks * 8 + t * 2];
                uint32_t bx = __float_as_uint(bv.x), by = __float_as_uint(bv.y);
#pragma unroll
                for (int mi = 0; mi < 2; mi++) {
                    asm volatile(
                        "mma.sync.aligned.m16n8k8.row.col.f32.tf32.tf32.f32 "
                        "{%0,%1,%2,%3}, {%4,%5,%6,%7}, {%8,%9}, {%0,%1,%2,%3};"
                        : "+f"(acc[mi][ni][0]), "+f"(acc[mi][ni][1]),
                          "+f"(acc[mi][ni][2]), "+f"(acc[mi][ni][3])
                        : "r"(af[mi][0]), "r"(af[mi][1]), "r"(af[mi][2]), "r"(af[mi][3]),
                          "r"(bx), "r"(by));
                }
            }
        }
        buf ^= 1;
    }

#pragma unroll
    for (int mi = 0; mi < 2; mi++) {
        const int r0 = bRow + wm * 32 + mi * 16 + g;
#pragma unroll
        for (int ni = 0; ni < 8; ni++) {
            const int cl = wn * 64 + ni * 8 + t * 2;
            const int c0 = bCol + cl;
            if (r0 < M) {
                float2 v = make_float2(acc[mi][ni][0] + bias_s[cl],
                                       acc[mi][ni][1] + bias_s[cl + 1]);
                *(float2*)&C[(size_t)r0 * N + c0] = v;
            }
            if (r0 + 8 < M) {
                float2 v = make_float2(acc[mi][ni][2] + bias_s[cl],
                                       acc[mi][ni][3] + bias_s[cl + 1]);
                *(float2*)&C[(size_t)(r0 + 8) * N + c0] = v;
            }
        }
    }
    if (MODE == 3) {
        float* svs[4] = {s0, s1, s2, s3};
        const int headbase = 4 * blockIdx.x + wn * 2;
#pragma unroll
        for (int v = 0; v < 4; v++) {
#pragma unroll
            for (int mi = 0; mi < 2; mi++) {
                float sA0 = 0.f, sA1 = 0.f, sB0 = 0.f, sB1 = 0.f;
#pragma unroll
                for (int ni = 0; ni < 8; ni++) {
                    const int cl = wn * 64 + ni * 8 + t * 2;
                    float a0v = avs[v * 128 + cl];
                    float a1v = avs[v * 128 + cl + 1];
                    float dA = (acc[mi][ni][0] + bias_s[cl]) * a0v +
                               (acc[mi][ni][1] + bias_s[cl + 1]) * a1v;
                    float dB = (acc[mi][ni][2] + bias_s[cl]) * a0v +
                               (acc[mi][ni][3] + bias_s[cl + 1]) * a1v;
                    if (ni < 4) { sA0 += dA; sB0 += dB; }
                    else        { sA1 += dA; sB1 += dB; }
                }
                sA0 += __shfl_xor_sync(0xffffffffu, sA0, 1);
                sA0 += __shfl_xor_sync(0xffffffffu, sA0, 2);
                sA1 += __shfl_xor_sync(0xffffffffu, sA1, 1);
                sA1 += __shfl_xor_sync(0xffffffffu, sA1, 2);
                sB0 += __shfl_xor_sync(0xffffffffu, sB0, 1);
                sB0 += __shfl_xor_sync(0xffffffffu, sB0, 2);
                sB1 += __shfl_xor_sync(0xffffffffu, sB1, 1);
                sB1 += __shfl_xor_sync(0xffffffffu, sB1, 2);
                if (t == 0) {
                    int nodeA = bRow + wm * 32 + mi * 16 + g;
                    int nodeB = nodeA + 8;
                    if (nodeA < M) {
                        svs[v][nodeA * HH + headbase]     = sA0;
                        svs[v][nodeA * HH + headbase + 1] = sA1;
                    }
                    if (nodeB < M) {
                        svs[v][nodeB * HH + headbase]     = sB0;
                        svs[v][nodeB * HH + headbase + 1] = sB1;
                    }
                }
            }
        }
    }
}

// =============================================================================
// fp16 GEMM h1: merged semantic reduction  score += sum q*tanh(A@B + kb)
// A fp16 (bufX), B fp16 k-linear. mma.m16n8k16.f16, fp32 accumulate.
// =============================================================================
#define AHH 40   // smem stride in halves (80B): conflict-free
#define SMEM_H1 ((4 * 128 * AHH) * 2 + (128 + 128 + 256) * 4)

__global__ void __launch_bounds__(256, 2)
gemm_h1(const __half* __restrict__ A0, const __half* __restrict__ Bt,
        const float* __restrict__ bias, const float* __restrict__ qv,
        float* __restrict__ score, float* __restrict__ score2,
        int M, int N, int K, int Mv1)
{
    extern __shared__ char smh[];
    __half* Ah = (__half*)smh;                        // 2*128*AHH
    __half* Bh = Ah + 2 * 128 * AHH;                  // 2*128*AHH
    float* bias_s = (float*)(Bh + 2 * 128 * AHH);
    float* q_s    = bias_s + 128;
    float* red    = q_s + 128;

    const int tid  = threadIdx.x;
    const int lane = tid & 31;
    const int warp = tid >> 5;
    const int wm   = warp & 3;
    const int wn   = warp >> 2;
    const int g    = lane >> 2;
    const int t    = lane & 3;
    const int bRow = blockIdx.y * 128;
    const int bCol = blockIdx.x * 128;

    int Mlim = M;
    float* sc = score;
    if (bRow >= MP) sc = score2;
    else Mlim = Mv1;

    if (tid < 128) {
        bias_s[tid] = bias[bCol + tid];
        q_s[tid] = qv[bCol + tid];
    }

    float acc[2][8][4];
#pragma unroll
    for (int mi = 0; mi < 2; mi++)
#pragma unroll
        for (int ni = 0; ni < 8; ni++)
#pragma unroll
            for (int r = 0; r < 4; r++) acc[mi][ni][r] = 0.f;

    auto issue = [&](int k0, int buf) {
        __half* a_dst = Ah + buf * 128 * AHH;
        __half* b_dst = Bh + buf * 128 * AHH;
#pragma unroll
        for (int it = 0; it < 2; it++) {
            int idx = it * 256 + tid;
            int row = idx >> 2, ch = idx & 3;
            const __half* src = A0 + (size_t)(bRow + row) * K + k0 + ch * 8;
            unsigned d = (unsigned)__cvta_generic_to_shared(a_dst + row * AHH + ch * 8);
            int sz = (bRow + row < Mlim) ? 16 : 0;
            asm volatile("cp.async.ca.shared.global [%0], [%1], 16, %2;"
                         :: "r"(d), "l"(src), "r"(sz));
        }
        const int kt = k0 >> 5;
#pragma unroll
        for (int it = 0; it < 2; it++) {
            int idx = it * 256 + tid;
            int n = idx >> 2, ch = idx & 3;
            const __half* src = Bt + ((size_t)kt * N + bCol + n) * 32 + ch * 8;
            unsigned d = (unsigned)__cvta_generic_to_shared(b_dst + n * AHH + ch * 8);
            asm volatile("cp.async.ca.shared.global [%0], [%1], 16;"
                         :: "r"(d), "l"(src));
        }
        asm volatile("cp.async.commit_group;");
    };

    const int S = K / 32;
    issue(0, 0);
    int buf = 0;

    for (int s = 0; s < S; s++) {
        asm volatile("cp.async.wait_group 0;");
        __syncthreads();
        if (s + 1 < S) issue((s + 1) * 32, buf ^ 1);

        const __half* ah = Ah + buf * 128 * AHH;
        const __half* bh = Bh + buf * 128 * AHH;
#pragma unroll
        for (int ks = 0; ks < 2; ks++) {
            uint32_t af[2][4];
#pragma unroll
            for (int mi = 0; mi < 2; mi++) {
                const int mr = wm * 32 + mi * 16;
                af[mi][0] = *(const uint32_t*)&ah[(mr + g)     * AHH + ks * 16 + 2 * t];
                af[mi][1] = *(const uint32_t*)&ah[(mr + g + 8) * AHH + ks * 16 + 2 * t];
                af[mi][2] = *(const uint32_t*)&ah[(mr + g)     * AHH + ks * 16 + 2 * t + 8];
                af[mi][3] = *(const uint32_t*)&ah[(mr + g + 8) * AHH + ks * 16 + 2 * t + 8];
            }
#pragma unroll
            for (int ni = 0; ni < 8; ni++) {
                const int n8 = wn * 8 + ni;
                uint32_t b0 = *(const uint32_t*)&bh[(n8 * 8 + g) * AHH + ks * 16 + 2 * t];
                uint32_t b1 = *(const uint32_t*)&bh[(n8 * 8 + g) * AHH + ks * 16 + 2 * t + 8];
#pragma unroll
                for (int mi = 0; mi < 2; mi++) {
                    asm volatile(
                        "mma.sync.aligned.m16n8k16.row.col.f32.f16.f16.f32 "
                        "{%0,%1,%2,%3}, {%4,%5,%6,%7}, {%8,%9}, {%0,%1,%2,%3};"
                        : "+f"(acc[mi][ni][0]), "+f"(acc[mi][ni][1]),
                          "+f"(acc[mi][ni][2]), "+f"(acc[mi][ni][3])
                        : "r"(af[mi][0]), "r"(af[mi][1]), "r"(af[mi][2]), "r"(af[mi][3]),
                          "r"(b0), "r"(b1));
                }
            }
        }
        buf ^= 1;
    }

    float local = 0.f;
#pragma unroll
    for (int mi = 0; mi < 2; mi++) {
        const int r0 = bRow + wm * 32 + mi * 16 + g;
#pragma unroll
        for (int ni = 0; ni < 8; ni++) {
            const int cl = wn * 64 + ni * 8 + t * 2;
            if (r0 < Mlim)
                local += q_s[cl]     * tanhf(acc[mi][ni][0] + bias_s[cl]) +
                         q_s[cl + 1] * tanhf(acc[mi][ni][1] + bias_s[cl + 1]);
            if (r0 + 8 < Mlim)
                local += q_s[cl]     * tanhf(acc[mi][ni][2] + bias_s[cl]) +
                         q_s[cl + 1] * tanhf(acc[mi][ni][3] + bias_s[cl + 1]);
        }
    }
    red[tid] = local;
    __syncthreads();
    for (int st = 128; st > 0; st >>= 1) {
        if (tid < st) red[tid] += red[tid + st];
        __syncthreads();
    }
    if (tid == 0) atomicAdd(sc, red[0]);
}

// =============================================================================
// fp16 GEMM h2: merged tail, softmax in-kernel, A = w0*A0 + w1*A1 (fp32 combine)
// =============================================================================
#define SMEM_H2 ((6 * 128 * AHH) * 2 + 128 * 4)

__global__ void __launch_bounds__(256, 2)
gemm_h2(const __half* __restrict__ A0, const __half* __restrict__ A1,
        const __half* __restrict__ Bt, const float* __restrict__ bias,
        const float* __restrict__ scores, float* __restrict__ C,
        int M, int N, int K, int Mv1, float invNr, float invNd)
{
    extern __shared__ char smh[];
    __half* A0h = (__half*)smh;
    __half* A1h = A0h + 2 * 128 * AHH;
    __half* Bh  = A1h + 2 * 128 * AHH;
    float* bias_s = (float*)(Bh + 2 * 128 * AHH);

    const int tid  = threadIdx.x;
    const int lane = tid & 31;
    const int warp = tid >> 5;
    const int wm   = warp & 3;
    const int wn   = warp >> 2;
    const int g    = lane >> 2;
    const int t    = lane & 3;
    const int bRow = blockIdx.y * 128;
    const int bCol = blockIdx.x * 128;

    const bool isDis = (bRow >= MP);
    const int Mlim = isDis ? M : Mv1;
    const int rshift = isDis ? (MP - Mv1) : 0;

    if (tid < 128) bias_s[tid] = bias[bCol + tid];

    float invN = isDis ? invNd : invNr;
    float sa = scores[isDis ? 2 : 0] * invN;
    float sb = scores[isDis ? 3 : 1] * invN;
    float mx = fmaxf(sa, sb);
    float e0 = expf(sa - mx), e1 = expf(sb - mx);
    const float w0 = e0 / (e0 + e1);
    const float w1 = e1 / (e0 + e1);

    float acc[2][8][4];
#pragma unroll
    for (int mi = 0; mi < 2; mi++)
#pragma unroll
        for (int ni = 0; ni < 8; ni++)
#pragma unroll
            for (int r = 0; r < 4; r++) acc[mi][ni][r] = 0.f;

    auto issue = [&](int k0, int buf) {
        __half* a0_dst = A0h + buf * 128 * AHH;
        __half* a1_dst = A1h + buf * 128 * AHH;
        __half* b_dst  = Bh + buf * 128 * AHH;
#pragma unroll
        for (int it = 0; it < 2; it++) {
            int idx = it * 256 + tid;
            int row = idx >> 2, ch = idx & 3;
            int sz = (bRow + row < Mlim) ? 16 : 0;
            const __half* s0 = A0 + (size_t)(bRow + row) * K + k0 + ch * 8;
            unsigned d0 = (unsigned)__cvta_generic_to_shared(a0_dst + row * AHH + ch * 8);
            asm volatile("cp.async.ca.shared.global [%0], [%1], 16, %2;"
                         :: "r"(d0), "l"(s0), "r"(sz));
            const __half* s1 = A1 + (size_t)(bRow + row) * K + k0 + ch * 8;
            unsigned d1 = (unsigned)__cvta_generic_to_shared(a1_dst + row * AHH + ch * 8);
            asm volatile("cp.async.ca.shared.global [%0], [%1], 16, %2;"
                         :: "r"(d1), "l"(s1), "r"(sz));
        }
        const int kt = k0 >> 5;
#pragma unroll
        for (int it = 0; it < 2; it++) {
            int idx = it * 256 + tid;
            int n = idx >> 2, ch = idx & 3;
            const __half* src = Bt + ((size_t)kt * N + bCol + n) * 32 + ch * 8;
            unsigned d = (unsigned)__cvta_generic_to_shared(b_dst + n * AHH + ch * 8);
            asm volatile("cp.async.ca.shared.global [%0], [%1], 16;"
                         :: "r"(d), "l"(src));
        }
        asm volatile("cp.async.commit_group;");
    };

    const int S = K / 32;
    issue(0, 0);
    int buf = 0;

    for (int s = 0; s < S; s++) {
        asm volatile("cp.async.wait_group 0;");
        __syncthreads();
        if (s + 1 < S) issue((s + 1) * 32, buf ^ 1);

        const __half* a0p = A0h + buf * 128 * AHH;
        const __half* a1p = A1h + buf * 128 * AHH;
        const __half* bh  = Bh + buf * 128 * AHH;
#pragma unroll
        for (int ks = 0; ks < 2; ks++) {
            uint32_t af[2][4];
#pragma unroll
            for (int mi = 0; mi < 2; mi++) {
                const int mr = wm * 32 + mi * 16;
                const int o[4] = {(mr + g) * AHH + ks * 16 + 2 * t,
                                  (mr + g + 8) * AHH + ks * 16 + 2 * t,
                                  (mr + g) * AHH + ks * 16 + 2 * t + 8,
                                  (mr + g + 8) * AHH + ks * 16 + 2 * t + 8};
#pragma unroll
                for (int r = 0; r < 4; r++) {
                    __half2 x0 = *(const __half2*)&a0p[o[r]];
                    __half2 x1 = *(const __half2*)&a1p[o[r]];
                    float2 f0 = __half22float2(x0);
                    float2 f1 = __half22float2(x1);
                    float2 fr = make_float2(w0 * f0.x + w1 * f1.x,
                                            w0 * f0.y + w1 * f1.y);
                    __half2 hr = __floats2half2_rn(fr.x, fr.y);
                    af[mi][r] = *(uint32_t*)&hr;
                }
            }
#pragma unroll
            for (int ni = 0; ni < 8; ni++) {
                const int n8 = wn * 8 + ni;
                uint32_t b0 = *(const uint32_t*)&bh[(n8 * 8 + g) * AHH + ks * 16 + 2 * t];
                uint32_t b1 = *(const uint32_t*)&bh[(n8 * 8 + g) * AHH + ks * 16 + 2 * t + 8];
#pragma unroll
                for (int mi = 0; mi < 2; mi++) {
                    asm volatile(
                        "mma.sync.aligned.m16n8k16.row.col.f32.f16.f16.f32 "
                        "{%0,%1,%2,%3}, {%4,%5,%6,%7}, {%8,%9}, {%0,%1,%2,%3};"
                        : "+f"(acc[mi][ni][0]), "+f"(acc[mi][ni][1]),
                          "+f"(acc[mi][ni][2]), "+f"(acc[mi][ni][3])
                        : "r"(af[mi][0]), "r"(af[mi][1]), "r"(af[mi][2]), "r"(af[mi][3]),
                          "r"(b0), "r"(b1));
                }
            }
        }
        buf ^= 1;
    }

#pragma unroll
    for (int mi = 0; mi < 2; mi++) {
        const int r0 = bRow + wm * 32 + mi * 16 + g;
#pragma unroll
        for (int ni = 0; ni < 8; ni++) {
            const int cl = wn * 64 + ni * 8 + t * 2;
            const int c0 = bCol + cl;
            if (r0 < Mlim) {
                float2 v = make_float2(acc[mi][ni][0] + bias_s[cl],
                                       acc[mi][ni][1] + bias_s[cl + 1]);
                *(float2*)&C[(size_t)(r0 - rshift) * N + c0] = v;
            }
            if (r0 + 8 < Mlim) {
                float2 v = make_float2(acc[mi][ni][2] + bias_s[cl],
                                       acc[mi][ni][3] + bias_s[cl + 1]);
                *(float2*)&C[(size_t)(r0 + 8 - rshift) * N + c0] = v;
            }
        }
    }
}

// ================= fused CSR build ==========================================
__global__ void hist4_k(const int* __restrict__ d0, const int* __restrict__ d1,
                        const int* __restrict__ d2, const int* __restrict__ d3,
                        int* __restrict__ cnt)
{
    int i = blockIdx.x * blockDim.x + threadIdx.x;
    if (i < E_RD)                     atomicAdd(&cnt[d0[i]], 1);
    else if (i < E_RD + E_DR)         atomicAdd(&cnt[N_D + d1[i - E_RD]], 1);
    else if (i < E_RD + E_DR + E_RR)  atomicAdd(&cnt[N_D + N_R + d2[i - E_RD - E_DR]], 1);
    else if (i < E_TOT)               atomicAdd(&cnt[N_D + 2 * N_R + d3[i - E_RD - E_DR - E_RR]], 1);
}

__global__ void __launch_bounds__(1024)
scan4_k(const int* __restrict__ cnt, int* __restrict__ rptr_all)
{
    __shared__ int wsum[32];
    __shared__ int s_carry;
    const int b = blockIdx.x;
    const int n    = (b == 0 || b == 3) ? N_D : N_R;
    const int cofs = (b == 0) ? 0 : (b == 1) ? N_D : (b == 2) ? (N_D + N_R) : (N_D + 2 * N_R);
    const int* c = cnt + cofs;
    int* rptr = rptr_all + b * (N_R + 1);

    const int tid = threadIdx.x;
    const int lane = tid & 31, wid = tid >> 5;
    if (tid == 0) s_carry = 0;
    __syncthreads();
    for (int base = 0; base < n; base += 1024) {
        int i = base + tid;
        int v = (i < n) ? c[i] : 0;
        int x = v;
#pragma unroll
        for (int o = 1; o < 32; o <<= 1) {
            int y = __shfl_up_sync(0xffffffffu, x, o);
            if (lane >= o) x += y;
        }
        if (lane == 31) wsum[wid] = x;
        __syncthreads();
        if (wid == 0) {
            int tv = wsum[lane];
#pragma unroll
            for (int o = 1; o < 32; o <<= 1) {
                int y = __shfl_up_sync(0xffffffffu, tv, o);
                if (lane >= o) tv += y;
            }
            wsum[lane] = tv;
        }
        __syncthreads();
        int incl = x + (wid > 0 ? wsum[wid - 1] : 0);
        int carry = s_carry;
        if (i < n) rptr[i] = carry + incl - v;
        __syncthreads();
        if (tid == 1023) s_carry = carry + incl;
        __syncthreads();
    }
    if (tid == 0) rptr[n] = s_carry;
}

__global__ void scatter4_k(const int* __restrict__ s0, const int* __restrict__ d0,
                           const int* __restrict__ s1, const int* __restrict__ d1,
                           const int* __restrict__ s2, const int* __restrict__ d2,
                           const int* __restrict__ s3, const int* __restrict__ d3,
                           const int* __restrict__ rptr_all,
                           int* __restrict__ fill, int* __restrict__ ssort)
{
    int i = blockIdx.x * blockDim.x + threadIdx.x;
    const int* sp; const int* dp; const int* rp; int* fl; int* ss; int e;
    if (i < E_RD) {
        e = i; sp = s0; dp = d0; rp = rptr_all; fl = fill; ss = ssort;
    } else if (i < E_RD + E_DR) {
        e = i - E_RD; sp = s1; dp = d1; rp = rptr_all + (N_R + 1);
        fl = fill + N_D; ss = ssort + E_RD;
    } else if (i < E_RD + E_DR + E_RR) {
        e = i - E_RD - E_DR; sp = s2; dp = d2; rp = rptr_all + 2 * (N_R + 1);
        fl = fill + N_D + N_R; ss = ssort + E_RD + E_DR;
    } else if (i < E_TOT) {
        e = i - E_RD - E_DR - E_RR; sp = s3; dp = d3; rp = rptr_all + 3 * (N_R + 1);
        fl = fill + N_D + 2 * N_R; ss = ssort + E_RD + E_DR + E_RR;
    } else return;
    int d = dp[e];
    int pos = rp[d] + atomicAdd(&fl[d], 1);
    ss[pos] = sp[e];
}

// ============ edge aggregation: single pass, fp16 output ====================
__device__ __forceinline__ float lrelu(float x) { return x > 0.f ? x : 0.2f * x; }

__global__ void __launch_bounds__(256)
agg_csr_k(const int* __restrict__ rptr, const int* __restrict__ ssort,
          const float* __restrict__ ssrc, const float* __restrict__ sdst,
          const float* __restrict__ x, __half* __restrict__ out, int Nd)
{
    const int warp = (blockIdx.x * blockDim.x + threadIdx.x) >> 5;
    const int lane = threadIdx.x & 31;
    if (warp >= Nd) return;
    const int beg = rptr[warp], end = rptr[warp + 1];

    const int h2 = lane >> 2;
    const float sd2 = sdst[warp * HH + h2];

    float s = 0.f;
    float a0 = 0.f, a1 = 0.f, a2 = 0.f, a3 = 0.f;
    float a4 = 0.f, a5 = 0.f, a6 = 0.f, a7 = 0.f;
    for (int p = beg; p < end; p++) {
        int src = ssort[p];
        float w = expf(lrelu(ssrc[src * HH + h2] + sd2));
        s += w;
        const float4* xp = (const float4*)(x + (size_t)src * CC + lane * 8);
        float4 v0 = xp[0], v1 = xp[1];
        a0 += w * v0.x; a1 += w * v0.y; a2 += w * v0.z; a3 += w * v0.w;
        a4 += w * v1.x; a5 += w * v1.y; a6 += w * v1.z; a7 += w * v1.w;
    }
    float inv = 1.f / (s + 1e-16f);
    __half2 h0 = __floats2half2_rn(fmaxf(a0 * inv, 0.f), fmaxf(a1 * inv, 0.f));
    __half2 h1 = __floats2half2_rn(fmaxf(a2 * inv, 0.f), fmaxf(a3 * inv, 0.f));
    __half2 hh2 = __floats2half2_rn(fmaxf(a4 * inv, 0.f), fmaxf(a5 * inv, 0.f));
    __half2 h3 = __floats2half2_rn(fmaxf(a6 * inv, 0.f), fmaxf(a7 * inv, 0.f));
    uint4 pk;
    pk.x = *(uint32_t*)&h0; pk.y = *(uint32_t*)&h1;
    pk.z = *(uint32_t*)&hh2; pk.w = *(uint32_t*)&h3;
    *(uint4*)(out + (size_t)warp * CC + lane * 8) = pk;
}

// ---------------------------------------------------------------------------
extern "C" void kernel_launch(void* const* d_in, const int* in_sizes, int n_in,
                              void* d_out, int out_size)
{
    const float* x_rna   = (const float*)d_in[0];
    const float* x_dis   = (const float*)d_in[1];
    const float* W_d     = (const float*)d_in[2];
    const float* b_d     = (const float*)d_in[3];
    const float* Wp_rna  = (const float*)d_in[4];
    const float* bp_rna  = (const float*)d_in[5];
    const float* Wp_dis  = (const float*)d_in[6];
    const float* bp_dis  = (const float*)d_in[7];
    const float* a_src_rd = (const float*)d_in[8];
    const float* a_dst_rd = (const float*)d_in[9];
    const float* a_src_dr = (const float*)d_in[10];
    const float* a_dst_dr = (const float*)d_in[11];
    const float* a_src_rr = (const float*)d_in[12];
    const float* a_dst_rr = (const float*)d_in[13];
    const float* a_src_dd = (const float*)d_in[14];
    const float* a_dst_dd = (const float*)d_in[15];
    const float* kW      = (const float*)d_in[16];
    const float* kb      = (const float*)d_in[17];
    const float* qv      = (const float*)d_in[18];
    const float* W_out   = (const float*)d_in[19];
    const float* b_out   = (const float*)d_in[20];
    const int* rd_src = (const int*)d_in[21];
    const int* rd_dst = (const int*)d_in[22];
    const int* dr_src = (const int*)d_in[23];
    const int* dr_dst = (const int*)d_in[24];
    const int* rr_src = (const int*)d_in[25];
    const int* rr_dst = (const int*)d_in[26];
    const int* dd_src = (const int*)d_in[27];
    const int* dd_dst = (const int*)d_in[28];

    float* out = (float*)d_out;

    float *p_xd, *p_hr, *p_hd, *p_sr, *p_sd, *p_scores;
    float *p_wdt, *p_wprt, *p_wpdt;
    __half *p_bufA, *p_bufB, *p_kwh, *p_woh;
    int *p_cnt, *p_fill, *p_rptr, *p_ssort;
    cudaGetSymbolAddress((void**)&p_xd, g_xd);
    cudaGetSymbolAddress((void**)&p_hr, g_hr);
    cudaGetSymbolAddress((void**)&p_hd, g_hd);
    cudaGetSymbolAddress((void**)&p_bufA, g_bufA);
    cudaGetSymbolAddress((void**)&p_bufB, g_bufB);
    cudaGetSymbolAddress((void**)&p_sr, g_s_rna);
    cudaGetSymbolAddress((void**)&p_sd, g_s_dis);
    cudaGetSymbolAddress((void**)&p_cnt, g_cnt);
    cudaGetSymbolAddress((void**)&p_fill, g_fill);
    cudaGetSymbolAddress((void**)&p_rptr, g_rptr);
    cudaGetSymbolAddress((void**)&p_ssort, g_ssort);
    cudaGetSymbolAddress((void**)&p_scores, g_scores);
    cudaGetSymbolAddress((void**)&p_wdt, g_wd_t);
    cudaGetSymbolAddress((void**)&p_wprt, g_wpr_t);
    cudaGetSymbolAddress((void**)&p_wpdt, g_wpd_t);
    cudaGetSymbolAddress((void**)&p_kwh, g_kw_h);
    cudaGetSymbolAddress((void**)&p_woh, g_wo_h);

    cudaFuncSetAttribute(gemm_ca<0>, cudaFuncAttributeMaxDynamicSharedMemorySize, SMEM_CA);
    cudaFuncSetAttribute(gemm_ca<3>, cudaFuncAttributeMaxDynamicSharedMemorySize, SMEM_CA);
    cudaFuncSetAttribute(gemm_h1, cudaFuncAttributeMaxDynamicSharedMemorySize, SMEM_H1);
    cudaFuncSetAttribute(gemm_h2, cudaFuncAttributeMaxDynamicSharedMemorySize, SMEM_H2);

    const dim3 thr(256);
    const int mbr = (N_R + 127) / 128;   // 391
    const int mbd = (N_D + 127) / 128;   // 79
    const int mbt = (MT + 127) / 128;    // 470

    __half* p_odr = p_bufA;
    __half* p_ord = p_bufA + (size_t)MP * CC;
    __half* p_orr = p_bufB;
    __half* p_odd = p_bufB + (size_t)MP * CC;

    int* rp_rd = p_rptr + 0 * (N_R + 1);
    int* rp_dr = p_rptr + 1 * (N_R + 1);
    int* rp_rr = p_rptr + 2 * (N_R + 1);
    int* rp_dd = p_rptr + 3 * (N_R + 1);
    int* ss_rd = p_ssort;
    int* ss_dr = ss_rd + E_RD;
    int* ss_rr = ss_dr + E_DR;
    int* ss_dd = ss_rr + E_RR;

    cudaStream_t st0 = 0, st1, st2;
    cudaStreamCreateWithFlags(&st1, cudaStreamNonBlocking);
    cudaStreamCreateWithFlags(&st2, cudaStreamNonBlocking);
    cudaEvent_t ev[8];
    for (int i = 0; i < 8; i++) cudaEventCreateWithFlags(&ev[i], cudaEventDisableTiming);

    // fork: st2 does CSR
    cudaEventRecord(ev[0], st0);
    cudaStreamWaitEvent(st2, ev[0], 0);

    // st0: weight prep, fork to st1
    prep_w_k<<<96, thr, 0, st0>>>(W_d, Wp_rna, Wp_dis, kW, W_out,
                                  p_wdt, p_wprt, p_wpdt, p_kwh, p_woh);
    cudaEventRecord(ev[1], st0);
    cudaStreamWaitEvent(st1, ev[1], 0);

    // st2: CSR build + score clear
    cudaMemsetAsync(p_cnt, 0, CNT_TOT * sizeof(int), st2);
    cudaMemsetAsync(p_fill, 0, CNT_TOT * sizeof(int), st2);
    cudaMemsetAsync(p_scores, 0, 4 * sizeof(float), st2);
    hist4_k<<<(E_TOT + 255) / 256, thr, 0, st2>>>(rd_dst, dr_dst, rr_dst, dd_dst, p_cnt);
    scan4_k<<<4, 1024, 0, st2>>>(p_cnt, p_rptr);
    scatter4_k<<<(E_TOT + 255) / 256, thr, 0, st2>>>(rd_src, rd_dst, dr_src, dr_dst,
                                                     rr_src, rr_dst, dd_src, dd_dst,
                                                     p_rptr, p_fill, p_ssort);
    cudaEventRecord(ev[2], st2);

    // st0: disease chain
    gemm_ca<0><<<dim3(2, mbd), thr, SMEM_CA, st0>>>(x_dis, p_wdt, b_d, p_xd,
                                                    nullptr, nullptr, nullptr, nullptr,
                                                    nullptr, nullptr, nullptr, nullptr,
                                                    N_D, RNA_IN, D_FEAT);
    gemm_ca<3><<<dim3(2, mbd), thr, SMEM_CA, st0>>>(p_xd, p_wpdt, bp_dis, p_hd,
                                                    a_dst_rd, a_src_dr, a_src_dd, a_dst_dd,
                                                    p_sd + 0 * N_D * HH, p_sd + 1 * N_D * HH,
                                                    p_sd + 2 * N_D * HH, p_sd + 3 * N_D * HH,
                                                    N_D, CC, RNA_IN);
    cudaEventRecord(ev[3], st0);

    // st1: rna chain
    gemm_ca<3><<<dim3(2, mbr), thr, SMEM_CA, st1>>>(x_rna, p_wprt, bp_rna, p_hr,
                                                    a_src_rd, a_dst_dr, a_src_rr, a_dst_rr,
                                                    p_sr + 0 * N_R * HH, p_sr + 1 * N_R * HH,
                                                    p_sr + 2 * N_R * HH, p_sr + 3 * N_R * HH,
                                                    N_R, CC, RNA_IN);
    cudaEventRecord(ev[4], st1);

    // st1: agg_rr
    cudaStreamWaitEvent(st1, ev[2], 0);
    agg_csr_k<<<(N_R * 32 + 255) / 256, thr, 0, st1>>>(rp_rr, ss_rr,
                                                       p_sr + 2 * N_R * HH, p_sr + 3 * N_R * HH,
                                                       p_hr, p_orr, N_R);

    // st0: agg_dr
    cudaStreamWaitEvent(st0, ev[4], 0);
    cudaStreamWaitEvent(st0, ev[2], 0);
    agg_csr_k<<<(N_R * 32 + 255) / 256, thr, 0, st0>>>(rp_dr, ss_dr,
                                                       p_sd + 1 * N_D * HH, p_sr + 1 * N_R * HH,
                                                       p_hd, p_odr, N_R);

    // st2: agg_dd then agg_rd
    cudaStreamWaitEvent(st2, ev[3], 0);
    agg_csr_k<<<(N_D * 32 + 255) / 256, thr, 0, st2>>>(rp_dd, ss_dd,
                                                       p_sd + 2 * N_D * HH, p_sd + 3 * N_D * HH,
                                                       p_hd, p_odd, N_D);
    cudaEventRecord(ev[5], st2);
    cudaStreamWaitEvent(st2, ev[4], 0);
    agg_csr_k<<<(N_D * 32 + 255) / 256, thr, 0, st2>>>(rp_rd, ss_rd,
                                                       p_sr + 0 * N_R * HH, p_sd + 0 * N_D * HH,
                                                       p_hr, p_ord, N_D);
    cudaEventRecord(ev[6], st2);

    // st0: semantic(bufA)
    cudaStreamWaitEvent(st0, ev[6], 0);
    gemm_h1<<<dim3(2, mbt), thr, SMEM_H1, st0>>>(p_bufA, p_kwh, kb, qv,
                                                 p_scores + 0, p_scores + 2,
                                                 MT, CC, CC, N_R);

    // st1: semantic(bufB)
    cudaStreamWaitEvent(st1, ev[5], 0);
    gemm_h1<<<dim3(2, mbt), thr, SMEM_H1, st1>>>(p_bufB, p_kwh, kb, qv,
                                                 p_scores + 1, p_scores + 3,
                                                 MT, CC, CC, N_R);
    cudaEventRecord(ev[7], st1);

    // st0: merged tail GEMM with in-kernel softmax
    cudaStreamWaitEvent(st0, ev[7], 0);
    gemm_h2<<<dim3(2, mbt), thr, SMEM_H2, st0>>>(p_bufA, p_bufB, p_woh, b_out,
                                                 p_scores, out, MT, CC, CC, N_R,
                                                 1.f / N_R, 1.f / N_D);

    for (int i = 0; i < 8; i++) cudaEventDestroy(ev[i]);
    cudaStreamDestroy(st1);
    cudaStreamDestroy(st2);
}

// round 14
// speedup vs baseline: 8.1871x; 1.0631x over previous
#include <cuda_runtime.h>
#include <cuda_fp16.h>
#include <cstdint>
#include <math.h>

#define N_R 50000
#define N_D 10000
#define HH  8
#define DH  32
#define CC  256
#define RNA_IN 256
#define D_FEAT 512
#define E_RD 200000
#define E_DR 200000
#define E_RR 400000
#define E_DD 50000
#define E_TOT (E_RD + E_DR + E_RR + E_DD)
#define CNT_TOT (2 * N_R + 2 * N_D)
#define MP 50048
#define MT (MP + N_D)

// ---------------- static device scratch ------------------------------------
__device__ float    g_xd[N_D * RNA_IN];
__device__ __half   g_hr[N_R * CC];            // fp16 (consumed only by agg gathers)
__device__ __half   g_hd[N_D * CC];
__device__ __half   g_bufA[(size_t)MT * CC];   // fp16 [relu(out_dr) | pad | relu(out_rd)]
__device__ __half   g_bufB[(size_t)MT * CC];   // fp16 [relu(out_rr) | pad | relu(out_dd)]
__device__ float    g_s_rna[4 * N_R * HH];
__device__ float    g_s_dis[4 * N_D * HH];
__device__ int      g_cnt[CNT_TOT];
__device__ int      g_fill[CNT_TOT];
__device__ int      g_rptr[4 * (N_R + 1)];
__device__ int      g_ssort[E_TOT];
__device__ float    g_scores[4];
// transformed weights
__device__ float    g_wd_t[D_FEAT * RNA_IN];   // tf32 blocked (projections)
__device__ float    g_wpr_t[RNA_IN * CC];
__device__ float    g_wpd_t[RNA_IN * CC];
__device__ __half   g_kw_h[CC * CC];           // fp16 k-linear (semantic)
__device__ __half   g_wo_h[CC * CC];           // fp16 k-linear (tail)

__device__ __forceinline__ uint32_t f2tf(float f) {
    uint32_t u;
    asm("cvt.rna.tf32.f32 %0, %1;" : "=r"(u) : "f"(f));
    return u;
}

// ================= weight prep ===============================================
__global__ void __launch_bounds__(256)
prep_w_k(const float* __restrict__ wd,  const float* __restrict__ wpr,
         const float* __restrict__ wpd, const float* __restrict__ kw,
         const float* __restrict__ wo,
         float* __restrict__ wdt, float* __restrict__ wprt,
         float* __restrict__ wpdt,
         __half* __restrict__ kwh, __half* __restrict__ woh)
{
    __shared__ float tile[32][129];
    int b = blockIdx.x;
    const float* src; float* dstf = nullptr; __half* dsth = nullptr; int N, base;
    if (b < 32)      { src = wd;  dstf = wdt;  N = RNA_IN; base = 0;  }
    else if (b < 48) { src = wpr; dstf = wprt; N = CC;     base = 32; }
    else if (b < 64) { src = wpd; dstf = wpdt; N = CC;     base = 48; }
    else if (b < 80) { src = kw;  dsth = kwh;  N = CC;     base = 64; }
    else             { src = wo;  dsth = woh;  N = CC;     base = 80; }
    int lb = b - base;
    int ntl = N / 128;
    int kt = lb / ntl, nb = lb % ntl;
    int k0 = kt * 32, n0 = nb * 128;
    int tid = threadIdx.x;
#pragma unroll
    for (int it = 0; it < 16; it++) {
        int idx = it * 256 + tid;
        int k = idx >> 7, n = idx & 127;
        tile[k][n] = src[(size_t)(k0 + k) * N + n0 + n];
    }
    __syncthreads();
    if (dstf) {
#pragma unroll
        for (int it = 0; it < 4; it++) {
            int cidx = it * 256 + tid;
            int n = cidx >> 3, c = cidx & 7;
            float4 v;
            float* vp = (float*)&v;
#pragma unroll
            for (int q = 0; q < 4; q++) {
                int kp = c * 4 + q;
                int ks = kp >> 3, r = kp & 7;
                int kl = ks * 8 + (r >> 1) + 4 * (r & 1);
                vp[q] = __uint_as_float(f2tf(tile[kl][n]));
            }
            *(float4*)&dstf[((size_t)kt * N + n0 + n) * 32 + c * 4] = v;
        }
    } else {
#pragma unroll
        for (int it = 0; it < 2; it++) {
            int cidx = it * 256 + tid;
            int n = cidx >> 2, cg = cidx & 3;
            __half hb[8];
#pragma unroll
            for (int j = 0; j < 8; j++) hb[j] = __float2half_rn(tile[cg * 8 + j][n]);
            *(uint4*)&dsth[((size_t)kt * N + n0 + n) * 32 + cg * 8] = *(uint4*)hb;
        }
    }
}

// =============================================================================
// tf32 GEMM: MODE 0 (fp32 C, for xd), MODE 3 (fp16 C + fused scores, for hr/hd)
// =============================================================================
#define AST 36
#define BST2 40
#define SMEM_CA ((2 * 128 * AST + 2 * 128 * BST2 + 128 + 512 + 512) * 4)

template <int MODE>
__global__ void __launch_bounds__(256, 2)
gemm_ca(const float* __restrict__ A0, const float* __restrict__ Bt,
        const float* __restrict__ bias,
        void* __restrict__ Craw,
        const float* __restrict__ av0, const float* __restrict__ av1,
        const float* __restrict__ av2, const float* __restrict__ av3,
        float* __restrict__ s0, float* __restrict__ s1,
        float* __restrict__ s2, float* __restrict__ s3,
        int M, int N, int K)
{
    extern __shared__ float sm[];
    float* As     = sm;
    float* Bs     = sm + 2 * 128 * AST;
    float* bias_s = sm + 2 * 128 * AST + 2 * 128 * BST2;
    float* avs    = bias_s + 128;

    const int tid  = threadIdx.x;
    const int lane = tid & 31;
    const int warp = tid >> 5;
    const int wm   = warp & 3;
    const int wn   = warp >> 2;
    const int g    = lane >> 2;
    const int t    = lane & 3;
    const int bRow = blockIdx.y * 128;
    const int bCol = blockIdx.x * 128;

    if (tid < 128) {
        bias_s[tid] = bias[bCol + tid];
        if (MODE == 3) {
            avs[tid]       = av0[bCol + tid];
            avs[128 + tid] = av1[bCol + tid];
            avs[256 + tid] = av2[bCol + tid];
            avs[384 + tid] = av3[bCol + tid];
        }
    }

    float acc[2][8][4];
#pragma unroll
    for (int mi = 0; mi < 2; mi++)
#pragma unroll
        for (int ni = 0; ni < 8; ni++)
#pragma unroll
            for (int r = 0; r < 4; r++) acc[mi][ni][r] = 0.f;

    auto issue = [&](int k0, int buf) {
        float* a_dst = As + buf * 128 * AST;
        float* b_dst = Bs + buf * 128 * BST2;
#pragma unroll
        for (int it = 0; it < 4; it++) {
            int idx = it * 256 + tid;
            int row = idx >> 3, ch = idx & 7;
            const float* src = A0 + (size_t)(bRow + row) * K + k0 + ch * 4;
            unsigned d = (unsigned)__cvta_generic_to_shared(a_dst + row * AST + ch * 4);
            int sz = (bRow + row < M) ? 16 : 0;
            asm volatile("cp.async.ca.shared.global [%0], [%1], 16, %2;"
                         :: "r"(d), "l"(src), "r"(sz));
        }
        const int kt = k0 >> 5;
#pragma unroll
        for (int it = 0; it < 4; it++) {
            int idx = it * 256 + tid;
            int n = idx >> 3, c = idx & 7;
            const float* src = Bt + ((size_t)kt * N + bCol + n) * 32 + c * 4;
            unsigned d = (unsigned)__cvta_generic_to_shared(b_dst + n * BST2 + c * 4);
            asm volatile("cp.async.ca.shared.global [%0], [%1], 16;"
                         :: "r"(d), "l"(src));
        }
        asm volatile("cp.async.commit_group;");
    };

    const int S = K / 32;
    issue(0, 0);
    int buf = 0;

    for (int s = 0; s < S; s++) {
        asm volatile("cp.async.wait_group 0;");
        __syncthreads();
        if (s + 1 < S) issue((s + 1) * 32, buf ^ 1);

        const float* ap = As + buf * 128 * AST;
        const float* bp = Bs + buf * 128 * BST2;
#pragma unroll
        for (int ks = 0; ks < 4; ks++) {
            uint32_t af[2][4];
#pragma unroll
            for (int mi = 0; mi < 2; mi++) {
                const int mr = wm * 32 + mi * 16;
                af[mi][0] = f2tf(ap[(mr + g)     * AST + ks * 8 + t]);
                af[mi][1] = f2tf(ap[(mr + g + 8) * AST + ks * 8 + t]);
                af[mi][2] = f2tf(ap[(mr + g)     * AST + ks * 8 + t + 4]);
                af[mi][3] = f2tf(ap[(mr + g + 8) * AST + ks * 8 + t + 4]);
            }
#pragma unroll
            for (int ni = 0; ni < 8; ni++) {
                const int n8 = wn * 8 + ni;
                float2 bv = *(const float2*)&bp[(n8 * 8 + g) * BST2 + ks * 8 + t * 2];
                uint32_t bx = __float_as_uint(bv.x), by = __float_as_uint(bv.y);
#pragma unroll
                for (int mi = 0; mi < 2; mi++) {
                    asm volatile(
                        "mma.sync.aligned.m16n8k8.row.col.f32.tf32.tf32.f32 "
                        "{%0,%1,%2,%3}, {%4,%5,%6,%7}, {%8,%9}, {%0,%1,%2,%3};"
                        : "+f"(acc[mi][ni][0]), "+f"(acc[mi][ni][1]),
                          "+f"(acc[mi][ni][2]), "+f"(acc[mi][ni][3])
                        : "r"(af[mi][0]), "r"(af[mi][1]), "r"(af[mi][2]), "r"(af[mi][3]),
                          "r"(bx), "r"(by));
                }
            }
        }
        buf ^= 1;
    }

#pragma unroll
    for (int mi = 0; mi < 2; mi++) {
        const int r0 = bRow + wm * 32 + mi * 16 + g;
#pragma unroll
        for (int ni = 0; ni < 8; ni++) {
            const int cl = wn * 64 + ni * 8 + t * 2;
            const int c0 = bCol + cl;
            if (MODE == 0) {
                float* C = (float*)Craw;
                if (r0 < M) {
                    float2 v = make_float2(acc[mi][ni][0] + bias_s[cl],
                                           acc[mi][ni][1] + bias_s[cl + 1]);
                    *(float2*)&C[(size_t)r0 * N + c0] = v;
                }
                if (r0 + 8 < M) {
                    float2 v = make_float2(acc[mi][ni][2] + bias_s[cl],
                                           acc[mi][ni][3] + bias_s[cl + 1]);
                    *(float2*)&C[(size_t)(r0 + 8) * N + c0] = v;
                }
            } else {
                __half* C = (__half*)Craw;
                if (r0 < M) {
                    __half2 v = __floats2half2_rn(acc[mi][ni][0] + bias_s[cl],
                                                  acc[mi][ni][1] + bias_s[cl + 1]);
                    *(__half2*)&C[(size_t)r0 * N + c0] = v;
                }
                if (r0 + 8 < M) {
                    __half2 v = __floats2half2_rn(acc[mi][ni][2] + bias_s[cl],
                                                  acc[mi][ni][3] + bias_s[cl + 1]);
                    *(__half2*)&C[(size_t)(r0 + 8) * N + c0] = v;
                }
            }
        }
    }
    if (MODE == 3) {
        float* svs[4] = {s0, s1, s2, s3};
        const int headbase = 4 * blockIdx.x + wn * 2;
#pragma unroll
        for (int v = 0; v < 4; v++) {
#pragma unroll
            for (int mi = 0; mi < 2; mi++) {
                float sA0 = 0.f, sA1 = 0.f, sB0 = 0.f, sB1 = 0.f;
#pragma unroll
                for (int ni = 0; ni < 8; ni++) {
                    const int cl = wn * 64 + ni * 8 + t * 2;
                    float a0v = avs[v * 128 + cl];
                    float a1v = avs[v * 128 + cl + 1];
                    float dA = (acc[mi][ni][0] + bias_s[cl]) * a0v +
                               (acc[mi][ni][1] + bias_s[cl + 1]) * a1v;
                    float dB = (acc[mi][ni][2] + bias_s[cl]) * a0v +
                               (acc[mi][ni][3] + bias_s[cl + 1]) * a1v;
                    if (ni < 4) { sA0 += dA; sB0 += dB; }
                    else        { sA1 += dA; sB1 += dB; }
                }
                sA0 += __shfl_xor_sync(0xffffffffu, sA0, 1);
                sA0 += __shfl_xor_sync(0xffffffffu, sA0, 2);
                sA1 += __shfl_xor_sync(0xffffffffu, sA1, 1);
                sA1 += __shfl_xor_sync(0xffffffffu, sA1, 2);
                sB0 += __shfl_xor_sync(0xffffffffu, sB0, 1);
                sB0 += __shfl_xor_sync(0xffffffffu, sB0, 2);
                sB1 += __shfl_xor_sync(0xffffffffu, sB1, 1);
                sB1 += __shfl_xor_sync(0xffffffffu, sB1, 2);
                if (t == 0) {
                    int nodeA = bRow + wm * 32 + mi * 16 + g;
                    int nodeB = nodeA + 8;
                    if (nodeA < M) {
                        svs[v][nodeA * HH + headbase]     = sA0;
                        svs[v][nodeA * HH + headbase + 1] = sA1;
                    }
                    if (nodeB < M) {
                        svs[v][nodeB * HH + headbase]     = sB0;
                        svs[v][nodeB * HH + headbase + 1] = sB1;
                    }
                }
            }
        }
    }
}

// =============================================================================
// fp16 GEMM h1: merged semantic reduction
// =============================================================================
#define AHH 40
#define SMEM_H1 ((4 * 128 * AHH) * 2 + (128 + 128 + 256) * 4)

__global__ void __launch_bounds__(256, 2)
gemm_h1(const __half* __restrict__ A0, const __half* __restrict__ Bt,
        const float* __restrict__ bias, const float* __restrict__ qv,
        float* __restrict__ score, float* __restrict__ score2,
        int M, int N, int K, int Mv1)
{
    extern __shared__ char smh[];
    __half* Ah = (__half*)smh;
    __half* Bh = Ah + 2 * 128 * AHH;
    float* bias_s = (float*)(Bh + 2 * 128 * AHH);
    float* q_s    = bias_s + 128;
    float* red    = q_s + 128;

    const int tid  = threadIdx.x;
    const int lane = tid & 31;
    const int warp = tid >> 5;
    const int wm   = warp & 3;
    const int wn   = warp >> 2;
    const int g    = lane >> 2;
    const int t    = lane & 3;
    const int bRow = blockIdx.y * 128;
    const int bCol = blockIdx.x * 128;

    int Mlim = M;
    float* sc = score;
    if (bRow >= MP) sc = score2;
    else Mlim = Mv1;

    if (tid < 128) {
        bias_s[tid] = bias[bCol + tid];
        q_s[tid] = qv[bCol + tid];
    }

    float acc[2][8][4];
#pragma unroll
    for (int mi = 0; mi < 2; mi++)
#pragma unroll
        for (int ni = 0; ni < 8; ni++)
#pragma unroll
            for (int r = 0; r < 4; r++) acc[mi][ni][r] = 0.f;

    auto issue = [&](int k0, int buf) {
        __half* a_dst = Ah + buf * 128 * AHH;
        __half* b_dst = Bh + buf * 128 * AHH;
#pragma unroll
        for (int it = 0; it < 2; it++) {
            int idx = it * 256 + tid;
            int row = idx >> 2, ch = idx & 3;
            const __half* src = A0 + (size_t)(bRow + row) * K + k0 + ch * 8;
            unsigned d = (unsigned)__cvta_generic_to_shared(a_dst + row * AHH + ch * 8);
            int sz = (bRow + row < Mlim) ? 16 : 0;
            asm volatile("cp.async.ca.shared.global [%0], [%1], 16, %2;"
                         :: "r"(d), "l"(src), "r"(sz));
        }
        const int kt = k0 >> 5;
#pragma unroll
        for (int it = 0; it < 2; it++) {
            int idx = it * 256 + tid;
            int n = idx >> 2, ch = idx & 3;
            const __half* src = Bt + ((size_t)kt * N + bCol + n) * 32 + ch * 8;
            unsigned d = (unsigned)__cvta_generic_to_shared(b_dst + n * AHH + ch * 8);
            asm volatile("cp.async.ca.shared.global [%0], [%1], 16;"
                         :: "r"(d), "l"(src));
        }
        asm volatile("cp.async.commit_group;");
    };

    const int S = K / 32;
    issue(0, 0);
    int buf = 0;

    for (int s = 0; s < S; s++) {
        asm volatile("cp.async.wait_group 0;");
        __syncthreads();
        if (s + 1 < S) issue((s + 1) * 32, buf ^ 1);

        const __half* ah = Ah + buf * 128 * AHH;
        const __half* bh = Bh + buf * 128 * AHH;
#pragma unroll
        for (int ks = 0; ks < 2; ks++) {
            uint32_t af[2][4];
#pragma unroll
            for (int mi = 0; mi < 2; mi++) {
                const int mr = wm * 32 + mi * 16;
                af[mi][0] = *(const uint32_t*)&ah[(mr + g)     * AHH + ks * 16 + 2 * t];
                af[mi][1] = *(const uint32_t*)&ah[(mr + g + 8) * AHH + ks * 16 + 2 * t];
                af[mi][2] = *(const uint32_t*)&ah[(mr + g)     * AHH + ks * 16 + 2 * t + 8];
                af[mi][3] = *(const uint32_t*)&ah[(mr + g + 8) * AHH + ks * 16 + 2 * t + 8];
            }
#pragma unroll
            for (int ni = 0; ni < 8; ni++) {
                const int n8 = wn * 8 + ni;
                uint32_t b0 = *(const uint32_t*)&bh[(n8 * 8 + g) * AHH + ks * 16 + 2 * t];
                uint32_t b1 = *(const uint32_t*)&bh[(n8 * 8 + g) * AHH + ks * 16 + 2 * t + 8];
#pragma unroll
                for (int mi = 0; mi < 2; mi++) {
                    asm volatile(
                        "mma.sync.aligned.m16n8k16.row.col.f32.f16.f16.f32 "
                        "{%0,%1,%2,%3}, {%4,%5,%6,%7}, {%8,%9}, {%0,%1,%2,%3};"
                        : "+f"(acc[mi][ni][0]), "+f"(acc[mi][ni][1]),
                          "+f"(acc[mi][ni][2]), "+f"(acc[mi][ni][3])
                        : "r"(af[mi][0]), "r"(af[mi][1]), "r"(af[mi][2]), "r"(af[mi][3]),
                          "r"(b0), "r"(b1));
                }
            }
        }
        buf ^= 1;
    }

    float local = 0.f;
#pragma unroll
    for (int mi = 0; mi < 2; mi++) {
        const int r0 = bRow + wm * 32 + mi * 16 + g;
#pragma unroll
        for (int ni = 0; ni < 8; ni++) {
            const int cl = wn * 64 + ni * 8 + t * 2;
            if (r0 < Mlim)
                local += q_s[cl]     * tanhf(acc[mi][ni][0] + bias_s[cl]) +
                         q_s[cl + 1] * tanhf(acc[mi][ni][1] + bias_s[cl + 1]);
            if (r0 + 8 < Mlim)
                local += q_s[cl]     * tanhf(acc[mi][ni][2] + bias_s[cl]) +
                         q_s[cl + 1] * tanhf(acc[mi][ni][3] + bias_s[cl + 1]);
        }
    }
    red[tid] = local;
    __syncthreads();
    for (int st = 128; st > 0; st >>= 1) {
        if (tid < st) red[tid] += red[tid + st];
        __syncthreads();
    }
    if (tid == 0) atomicAdd(sc, red[0]);
}

// =============================================================================
// fp16 GEMM h2: merged tail, softmax in-kernel
// =============================================================================
#define SMEM_H2 ((6 * 128 * AHH) * 2 + 128 * 4)

__global__ void __launch_bounds__(256, 2)
gemm_h2(const __half* __restrict__ A0, const __half* __restrict__ A1,
        const __half* __restrict__ Bt, const float* __restrict__ bias,
        const float* __restrict__ scores, float* __restrict__ C,
        int M, int N, int K, int Mv1, float invNr, float invNd)
{
    extern __shared__ char smh[];
    __half* A0h = (__half*)smh;
    __half* A1h = A0h + 2 * 128 * AHH;
    __half* Bh  = A1h + 2 * 128 * AHH;
    float* bias_s = (float*)(Bh + 2 * 128 * AHH);

    const int tid  = threadIdx.x;
    const int lane = tid & 31;
    const int warp = tid >> 5;
    const int wm   = warp & 3;
    const int wn   = warp >> 2;
    const int g    = lane >> 2;
    const int t    = lane & 3;
    const int bRow = blockIdx.y * 128;
    const int bCol = blockIdx.x * 128;

    const bool isDis = (bRow >= MP);
    const int Mlim = isDis ? M : Mv1;
    const int rshift = isDis ? (MP - Mv1) : 0;

    if (tid < 128) bias_s[tid] = bias[bCol + tid];

    float invN = isDis ? invNd : invNr;
    float sa = scores[isDis ? 2 : 0] * invN;
    float sb = scores[isDis ? 3 : 1] * invN;
    float mx = fmaxf(sa, sb);
    float e0 = expf(sa - mx), e1 = expf(sb - mx);
    const float w0 = e0 / (e0 + e1);
    const float w1 = e1 / (e0 + e1);

    float acc[2][8][4];
#pragma unroll
    for (int mi = 0; mi < 2; mi++)
#pragma unroll
        for (int ni = 0; ni < 8; ni++)
#pragma unroll
            for (int r = 0; r < 4; r++) acc[mi][ni][r] = 0.f;

    auto issue = [&](int k0, int buf) {
        __half* a0_dst = A0h + buf * 128 * AHH;
        __half* a1_dst = A1h + buf * 128 * AHH;
        __half* b_dst  = Bh + buf * 128 * AHH;
#pragma unroll
        for (int it = 0; it < 2; it++) {
            int idx = it * 256 + tid;
            int row = idx >> 2, ch = idx & 3;
            int sz = (bRow + row < Mlim) ? 16 : 0;
            const __half* s0 = A0 + (size_t)(bRow + row) * K + k0 + ch * 8;
            unsigned d0 = (unsigned)__cvta_generic_to_shared(a0_dst + row * AHH + ch * 8);
            asm volatile("cp.async.ca.shared.global [%0], [%1], 16, %2;"
                         :: "r"(d0), "l"(s0), "r"(sz));
            const __half* s1 = A1 + (size_t)(bRow + row) * K + k0 + ch * 8;
            unsigned d1 = (unsigned)__cvta_generic_to_shared(a1_dst + row * AHH + ch * 8);
            asm volatile("cp.async.ca.shared.global [%0], [%1], 16, %2;"
                         :: "r"(d1), "l"(s1), "r"(sz));
        }
        const int kt = k0 >> 5;
#pragma unroll
        for (int it = 0; it < 2; it++) {
            int idx = it * 256 + tid;
            int n = idx >> 2, ch = idx & 3;
            const __half* src = Bt + ((size_t)kt * N + bCol + n) * 32 + ch * 8;
            unsigned d = (unsigned)__cvta_generic_to_shared(b_dst + n * AHH + ch * 8);
            asm volatile("cp.async.ca.shared.global [%0], [%1], 16;"
                         :: "r"(d), "l"(src));
        }
        asm volatile("cp.async.commit_group;");
    };

    const int S = K / 32;
    issue(0, 0);
    int buf = 0;

    for (int s = 0; s < S; s++) {
        asm volatile("cp.async.wait_group 0;");
        __syncthreads();
        if (s + 1 < S) issue((s + 1) * 32, buf ^ 1);

        const __half* a0p = A0h + buf * 128 * AHH;
        const __half* a1p = A1h + buf * 128 * AHH;
        const __half* bh  = Bh + buf * 128 * AHH;
#pragma unroll
        for (int ks = 0; ks < 2; ks++) {
            uint32_t af[2][4];
#pragma unroll
            for (int mi = 0; mi < 2; mi++) {
                const int mr = wm * 32 + mi * 16;
                const int o[4] = {(mr + g) * AHH + ks * 16 + 2 * t,
                                  (mr + g + 8) * AHH + ks * 16 + 2 * t,
                                  (mr + g) * AHH + ks * 16 + 2 * t + 8,
                                  (mr + g + 8) * AHH + ks * 16 + 2 * t + 8};
#pragma unroll
                for (int r = 0; r < 4; r++) {
                    __half2 x0 = *(const __half2*)&a0p[o[r]];
                    __half2 x1 = *(const __half2*)&a1p[o[r]];
                    float2 f0 = __half22float2(x0);
                    float2 f1 = __half22float2(x1);
                    __half2 hr = __floats2half2_rn(w0 * f0.x + w1 * f1.x,
                                                   w0 * f0.y + w1 * f1.y);
                    af[mi][r] = *(uint32_t*)&hr;
                }
            }
#pragma unroll
            for (int ni = 0; ni < 8; ni++) {
                const int n8 = wn * 8 + ni;
                uint32_t b0 = *(const uint32_t*)&bh[(n8 * 8 + g) * AHH + ks * 16 + 2 * t];
                uint32_t b1 = *(const uint32_t*)&bh[(n8 * 8 + g) * AHH + ks * 16 + 2 * t + 8];
#pragma unroll
                for (int mi = 0; mi < 2; mi++) {
                    asm volatile(
                        "mma.sync.aligned.m16n8k16.row.col.f32.f16.f16.f32 "
                        "{%0,%1,%2,%3}, {%4,%5,%6,%7}, {%8,%9}, {%0,%1,%2,%3};"
                        : "+f"(acc[mi][ni][0]), "+f"(acc[mi][ni][1]),
                          "+f"(acc[mi][ni][2]), "+f"(acc[mi][ni][3])
                        : "r"(af[mi][0]), "r"(af[mi][1]), "r"(af[mi][2]), "r"(af[mi][3]),
                          "r"(b0), "r"(b1));
                }
            }
        }
        buf ^= 1;
    }

#pragma unroll
    for (int mi = 0; mi < 2; mi++) {
        const int r0 = bRow + wm * 32 + mi * 16 + g;
#pragma unroll
        for (int ni = 0; ni < 8; ni++) {
            const int cl = wn * 64 + ni * 8 + t * 2;
            const int c0 = bCol + cl;
            if (r0 < Mlim) {
                float2 v = make_float2(acc[mi][ni][0] + bias_s[cl],
                                       acc[mi][ni][1] + bias_s[cl + 1]);
                *(float2*)&C[(size_t)(r0 - rshift) * N + c0] = v;
            }
            if (r0 + 8 < Mlim) {
                float2 v = make_float2(acc[mi][ni][2] + bias_s[cl],
                                       acc[mi][ni][3] + bias_s[cl + 1]);
                *(float2*)&C[(size_t)(r0 + 8 - rshift) * N + c0] = v;
            }
        }
    }
}

// ================= fused CSR build ==========================================
__global__ void hist4_k(const int* __restrict__ d0, const int* __restrict__ d1,
                        const int* __restrict__ d2, const int* __restrict__ d3,
                        int* __restrict__ cnt)
{
    int i = blockIdx.x * blockDim.x + threadIdx.x;
    if (i < E_RD)                     atomicAdd(&cnt[d0[i]], 1);
    else if (i < E_RD + E_DR)         atomicAdd(&cnt[N_D + d1[i - E_RD]], 1);
    else if (i < E_RD + E_DR + E_RR)  atomicAdd(&cnt[N_D + N_R + d2[i - E_RD - E_DR]], 1);
    else if (i < E_TOT)               atomicAdd(&cnt[N_D + 2 * N_R + d3[i - E_RD - E_DR - E_RR]], 1);
}

__global__ void __launch_bounds__(1024)
scan4_k(const int* __restrict__ cnt, int* __restrict__ rptr_all)
{
    __shared__ int wsum[32];
    __shared__ int s_carry;
    const int b = blockIdx.x;
    const int n    = (b == 0 || b == 3) ? N_D : N_R;
    const int cofs = (b == 0) ? 0 : (b == 1) ? N_D : (b == 2) ? (N_D + N_R) : (N_D + 2 * N_R);
    const int* c = cnt + cofs;
    int* rptr = rptr_all + b * (N_R + 1);

    const int tid = threadIdx.x;
    const int lane = tid & 31, wid = tid >> 5;
    if (tid == 0) s_carry = 0;
    __syncthreads();
    for (int base = 0; base < n; base += 1024) {
        int i = base + tid;
        int v = (i < n) ? c[i] : 0;
        int x = v;
#pragma unroll
        for (int o = 1; o < 32; o <<= 1) {
            int y = __shfl_up_sync(0xffffffffu, x, o);
            if (lane >= o) x += y;
        }
        if (lane == 31) wsum[wid] = x;
        __syncthreads();
        if (wid == 0) {
            int tv = wsum[lane];
#pragma unroll
            for (int o = 1; o < 32; o <<= 1) {
                int y = __shfl_up_sync(0xffffffffu, tv, o);
                if (lane >= o) tv += y;
            }
            wsum[lane] = tv;
        }
        __syncthreads();
        int incl = x + (wid > 0 ? wsum[wid - 1] : 0);
        int carry = s_carry;
        if (i < n) rptr[i] = carry + incl - v;
        __syncthreads();
        if (tid == 1023) s_carry = carry + incl;
        __syncthreads();
    }
    if (tid == 0) rptr[n] = s_carry;
}

__global__ void scatter4_k(const int* __restrict__ s0, const int* __restrict__ d0,
                           const int* __restrict__ s1, const int* __restrict__ d1,
                           const int* __restrict__ s2, const int* __restrict__ d2,
                           const int* __restrict__ s3, const int* __restrict__ d3,
                           const int* __restrict__ rptr_all,
                           int* __restrict__ fill, int* __restrict__ ssort)
{
    int i = blockIdx.x * blockDim.x + threadIdx.x;
    const int* sp; const int* dp; const int* rp; int* fl; int* ss; int e;
    if (i < E_RD) {
        e = i; sp = s0; dp = d0; rp = rptr_all; fl = fill; ss = ssort;
    } else if (i < E_RD + E_DR) {
        e = i - E_RD; sp = s1; dp = d1; rp = rptr_all + (N_R + 1);
        fl = fill + N_D; ss = ssort + E_RD;
    } else if (i < E_RD + E_DR + E_RR) {
        e = i - E_RD - E_DR; sp = s2; dp = d2; rp = rptr_all + 2 * (N_R + 1);
        fl = fill + N_D + N_R; ss = ssort + E_RD + E_DR;
    } else if (i < E_TOT) {
        e = i - E_RD - E_DR - E_RR; sp = s3; dp = d3; rp = rptr_all + 3 * (N_R + 1);
        fl = fill + N_D + 2 * N_R; ss = ssort + E_RD + E_DR + E_RR;
    } else return;
    int d = dp[e];
    int pos = rp[d] + atomicAdd(&fl[d], 1);
    ss[pos] = sp[e];
}

// ============ edge aggregation: single pass, fp16 gather + fp16 output ======
__device__ __forceinline__ float lrelu(float x) { return x > 0.f ? x : 0.2f * x; }

__global__ void __launch_bounds__(256)
agg_csr_k(const int* __restrict__ rptr, const int* __restrict__ ssort,
          const float* __restrict__ ssrc, const float* __restrict__ sdst,
          const __half* __restrict__ x, __half* __restrict__ out, int Nd)
{
    const int warp = (blockIdx.x * blockDim.x + threadIdx.x) >> 5;
    const int lane = threadIdx.x & 31;
    if (warp >= Nd) return;
    const int beg = rptr[warp], end = rptr[warp + 1];

    const int h2 = lane >> 2;
    const float sd2 = sdst[warp * HH + h2];

    float s = 0.f;
    float a0 = 0.f, a1 = 0.f, a2 = 0.f, a3 = 0.f;
    float a4 = 0.f, a5 = 0.f, a6 = 0.f, a7 = 0.f;
    for (int p = beg; p < end; p++) {
        int src = ssort[p];
        float w = expf(lrelu(ssrc[src * HH + h2] + sd2));
        s += w;
        uint4 pk = *(const uint4*)(x + (size_t)src * CC + lane * 8);
        float2 f0 = __half22float2(*(__half2*)&pk.x);
        float2 f1 = __half22float2(*(__half2*)&pk.y);
        float2 f2 = __half22float2(*(__half2*)&pk.z);
        float2 f3 = __half22float2(*(__half2*)&pk.w);
        a0 += w * f0.x; a1 += w * f0.y; a2 += w * f1.x; a3 += w * f1.y;
        a4 += w * f2.x; a5 += w * f2.y; a6 += w * f3.x; a7 += w * f3.y;
    }
    float inv = 1.f / (s + 1e-16f);
    __half2 h0 = __floats2half2_rn(fmaxf(a0 * inv, 0.f), fmaxf(a1 * inv, 0.f));
    __half2 h1 = __floats2half2_rn(fmaxf(a2 * inv, 0.f), fmaxf(a3 * inv, 0.f));
    __half2 hh = __floats2half2_rn(fmaxf(a4 * inv, 0.f), fmaxf(a5 * inv, 0.f));
    __half2 h3 = __floats2half2_rn(fmaxf(a6 * inv, 0.f), fmaxf(a7 * inv, 0.f));
    uint4 pk;
    pk.x = *(uint32_t*)&h0; pk.y = *(uint32_t*)&h1;
    pk.z = *(uint32_t*)&hh; pk.w = *(uint32_t*)&h3;
    *(uint4*)(out + (size_t)warp * CC + lane * 8) = pk;
}

// ---------------------------------------------------------------------------
extern "C" void kernel_launch(void* const* d_in, const int* in_sizes, int n_in,
                              void* d_out, int out_size)
{
    const float* x_rna   = (const float*)d_in[0];
    const float* x_dis   = (const float*)d_in[1];
    const float* W_d     = (const float*)d_in[2];
    const float* b_d     = (const float*)d_in[3];
    const float* Wp_rna  = (const float*)d_in[4];
    const float* bp_rna  = (const float*)d_in[5];
    const float* Wp_dis  = (const float*)d_in[6];
    const float* bp_dis  = (const float*)d_in[7];
    const float* a_src_rd = (const float*)d_in[8];
    const float* a_dst_rd = (const float*)d_in[9];
    const float* a_src_dr = (const float*)d_in[10];
    const float* a_dst_dr = (const float*)d_in[11];
    const float* a_src_rr = (const float*)d_in[12];
    const float* a_dst_rr = (const float*)d_in[13];
    const float* a_src_dd = (const float*)d_in[14];
    const float* a_dst_dd = (const float*)d_in[15];
    const float* kW      = (const float*)d_in[16];
    const float* kb      = (const float*)d_in[17];
    const float* qv      = (const float*)d_in[18];
    const float* W_out   = (const float*)d_in[19];
    const float* b_out   = (const float*)d_in[20];
    const int* rd_src = (const int*)d_in[21];
    const int* rd_dst = (const int*)d_in[22];
    const int* dr_src = (const int*)d_in[23];
    const int* dr_dst = (const int*)d_in[24];
    const int* rr_src = (const int*)d_in[25];
    const int* rr_dst = (const int*)d_in[26];
    const int* dd_src = (const int*)d_in[27];
    const int* dd_dst = (const int*)d_in[28];

    float* out = (float*)d_out;

    float *p_xd, *p_sr, *p_sd, *p_scores;
    float *p_wdt, *p_wprt, *p_wpdt;
    __half *p_hr, *p_hd, *p_bufA, *p_bufB, *p_kwh, *p_woh;
    int *p_cnt, *p_fill, *p_rptr, *p_ssort;
    cudaGetSymbolAddress((void**)&p_xd, g_xd);
    cudaGetSymbolAddress((void**)&p_hr, g_hr);
    cudaGetSymbolAddress((void**)&p_hd, g_hd);
    cudaGetSymbolAddress((void**)&p_bufA, g_bufA);
    cudaGetSymbolAddress((void**)&p_bufB, g_bufB);
    cudaGetSymbolAddress((void**)&p_sr, g_s_rna);
    cudaGetSymbolAddress((void**)&p_sd, g_s_dis);
    cudaGetSymbolAddress((void**)&p_cnt, g_cnt);
    cudaGetSymbolAddress((void**)&p_fill, g_fill);
    cudaGetSymbolAddress((void**)&p_rptr, g_rptr);
    cudaGetSymbolAddress((void**)&p_ssort, g_ssort);
    cudaGetSymbolAddress((void**)&p_scores, g_scores);
    cudaGetSymbolAddress((void**)&p_wdt, g_wd_t);
    cudaGetSymbolAddress((void**)&p_wprt, g_wpr_t);
    cudaGetSymbolAddress((void**)&p_wpdt, g_wpd_t);
    cudaGetSymbolAddress((void**)&p_kwh, g_kw_h);
    cudaGetSymbolAddress((void**)&p_woh, g_wo_h);

    cudaFuncSetAttribute(gemm_ca<0>, cudaFuncAttributeMaxDynamicSharedMemorySize, SMEM_CA);
    cudaFuncSetAttribute(gemm_ca<3>, cudaFuncAttributeMaxDynamicSharedMemorySize, SMEM_CA);
    cudaFuncSetAttribute(gemm_h1, cudaFuncAttributeMaxDynamicSharedMemorySize, SMEM_H1);
    cudaFuncSetAttribute(gemm_h2, cudaFuncAttributeMaxDynamicSharedMemorySize, SMEM_H2);

    const dim3 thr(256);
    const int mbr = (N_R + 127) / 128;   // 391
    const int mbd = (N_D + 127) / 128;   // 79
    const int mbt = (MT + 127) / 128;    // 470

    __half* p_odr = p_bufA;
    __half* p_ord = p_bufA + (size_t)MP * CC;
    __half* p_orr = p_bufB;
    __half* p_odd = p_bufB + (size_t)MP * CC;

    int* rp_rd = p_rptr + 0 * (N_R + 1);
    int* rp_dr = p_rptr + 1 * (N_R + 1);
    int* rp_rr = p_rptr + 2 * (N_R + 1);
    int* rp_dd = p_rptr + 3 * (N_R + 1);
    int* ss_rd = p_ssort;
    int* ss_dr = ss_rd + E_RD;
    int* ss_rr = ss_dr + E_DR;
    int* ss_dd = ss_rr + E_RR;

    cudaStream_t st0 = 0, st1, st2;
    cudaStreamCreateWithFlags(&st1, cudaStreamNonBlocking);
    cudaStreamCreateWithFlags(&st2, cudaStreamNonBlocking);
    cudaEvent_t ev[8];
    for (int i = 0; i < 8; i++) cudaEventCreateWithFlags(&ev[i], cudaEventDisableTiming);

    // fork: st2 does CSR
    cudaEventRecord(ev[0], st0);
    cudaStreamWaitEvent(st2, ev[0], 0);

    // st0: weight prep, fork to st1
    prep_w_k<<<96, thr, 0, st0>>>(W_d, Wp_rna, Wp_dis, kW, W_out,
                                  p_wdt, p_wprt, p_wpdt, p_kwh, p_woh);
    cudaEventRecord(ev[1], st0);
    cudaStreamWaitEvent(st1, ev[1], 0);

    // st2: CSR build + score clear
    cudaMemsetAsync(p_cnt, 0, CNT_TOT * sizeof(int), st2);
    cudaMemsetAsync(p_fill, 0, CNT_TOT * sizeof(int), st2);
    cudaMemsetAsync(p_scores, 0, 4 * sizeof(float), st2);
    hist4_k<<<(E_TOT + 255) / 256, thr, 0, st2>>>(rd_dst, dr_dst, rr_dst, dd_dst, p_cnt);
    scan4_k<<<4, 1024, 0, st2>>>(p_cnt, p_rptr);
    scatter4_k<<<(E_TOT + 255) / 256, thr, 0, st2>>>(rd_src, rd_dst, dr_src, dr_dst,
                                                     rr_src, rr_dst, dd_src, dd_dst,
                                                     p_rptr, p_fill, p_ssort);
    cudaEventRecord(ev[2], st2);

    // st0: disease chain
    gemm_ca<0><<<dim3(2, mbd), thr, SMEM_CA, st0>>>(x_dis, p_wdt, b_d, p_xd,
                                                    nullptr, nullptr, nullptr, nullptr,
                                                    nullptr, nullptr, nullptr, nullptr,
                                                    N_D, RNA_IN, D_FEAT);
    gemm_ca<3><<<dim3(2, mbd), thr, SMEM_CA, st0>>>(p_xd, p_wpdt, bp_dis, p_hd,
                                                    a_dst_rd, a_src_dr, a_src_dd, a_dst_dd,
                                                    p_sd + 0 * N_D * HH, p_sd + 1 * N_D * HH,
                                                    p_sd + 2 * N_D * HH, p_sd + 3 * N_D * HH,
                                                    N_D, CC, RNA_IN);
    cudaEventRecord(ev[3], st0);

    // st1: rna chain
    gemm_ca<3><<<dim3(2, mbr), thr, SMEM_CA, st1>>>(x_rna, p_wprt, bp_rna, p_hr,
                                                    a_src_rd, a_dst_dr, a_src_rr, a_dst_rr,
                                                    p_sr + 0 * N_R * HH, p_sr + 1 * N_R * HH,
                                                    p_sr + 2 * N_R * HH, p_sr + 3 * N_R * HH,
                                                    N_R, CC, RNA_IN);
    cudaEventRecord(ev[4], st1);

    // st1: agg_rr
    cudaStreamWaitEvent(st1, ev[2], 0);
    agg_csr_k<<<(N_R * 32 + 255) / 256, thr, 0, st1>>>(rp_rr, ss_rr,
                                                       p_sr + 2 * N_R * HH, p_sr + 3 * N_R * HH,
                                                       p_hr, p_orr, N_R);

    // st0: agg_dr
    cudaStreamWaitEvent(st0, ev[4], 0);
    cudaStreamWaitEvent(st0, ev[2], 0);
    agg_csr_k<<<(N_R * 32 + 255) / 256, thr, 0, st0>>>(rp_dr, ss_dr,
                                                       p_sd + 1 * N_D * HH, p_sr + 1 * N_R * HH,
                                                       p_hd, p_odr, N_R);

    // st2: agg_dd then agg_rd
    cudaStreamWaitEvent(st2, ev[3], 0);
    agg_csr_k<<<(N_D * 32 + 255) / 256, thr, 0, st2>>>(rp_dd, ss_dd,
                                                       p_sd + 2 * N_D * HH, p_sd + 3 * N_D * HH,
                                                       p_hd, p_odd, N_D);
    cudaEventRecord(ev[5], st2);
    cudaStreamWaitEvent(st2, ev[4], 0);
    agg_csr_k<<<(N_D * 32 + 255) / 256, thr, 0, st2>>>(rp_rd, ss_rd,
                                                       p_sr + 0 * N_R * HH, p_sd + 0 * N_D * HH,
                                                       p_hr, p_ord, N_D);
    cudaEventRecord(ev[6], st2);

    // st0: semantic(bufA)
    cudaStreamWaitEvent(st0, ev[6], 0);
    gemm_h1<<<dim3(2, mbt), thr, SMEM_H1, st0>>>(p_bufA, p_kwh, kb, qv,
                                                 p_scores + 0, p_scores + 2,
                                                 MT, CC, CC, N_R);

    // st1: semantic(bufB)
    cudaStreamWaitEvent(st1, ev[5], 0);
    gemm_h1<<<dim3(2, mbt), thr, SMEM_H1, st1>>>(p_bufB, p_kwh, kb, qv,
                                                 p_scores + 1, p_scores + 3,
                                                 MT, CC, CC, N_R);
    cudaEventRecord(ev[7], st1);

    // st0: merged tail GEMM with in-kernel softmax
    cudaStreamWaitEvent(st0, ev[7], 0);
    gemm_h2<<<dim3(2, mbt), thr, SMEM_H2, st0>>>(p_bufA, p_bufB, p_woh, b_out,
                                                 p_scores, out, MT, CC, CC, N_R,
                                                 1.f / N_R, 1.f / N_D);

    for (int i = 0; i < 8; i++) cudaEventDestroy(ev[i]);
    cudaStreamDestroy(st1);
    cudaStreamDestroy(st2);
}